// round 1
// baseline (speedup 1.0000x reference)
#include <cuda_runtime.h>
#include <math.h>

#define Bq 32
#define Sq 196
#define Dq 768
#define Hq 12
#define Eq 8
#define Fq 3072
#define DHq 64
#define NTOK (Bq*Sq)   // 6272

// ---------------- scratch (device globals; no allocation allowed) -------------
__device__ float d_qh [NTOK*Dq];
__device__ float d_kh [NTOK*Dq];
__device__ float d_vh [NTOK*Dq];
__device__ float d_ctx[NTOK*Dq];
__device__ float d_tmp[NTOK*Dq];   // q + attn_out
__device__ float d_x  [NTOK*Dq];   // LN1 output
__device__ float d_moe[NTOK*Dq];   // gate-weighted expert accumulation
__device__ float d_hbuf[NTOK*Fq];  // per-expert hidden
__device__ float d_gates[NTOK*Eq];

// ---------------- generic 128x128x8 fp32 GEMM with fused epilogues ------------
// MODE 0: C = A@W + bias
// MODE 1: C = A@W + bias + res          (O-projection + residual)
// MODE 2: C = gelu_exact(A@W + bias)    (MoE up-proj)
// MODE 3: C (+)= gates[row,e] * (A@W + bias)   (MoE down-proj, accumulate)
template<int MODE>
__global__ void __launch_bounds__(256)
gemm128(const float* __restrict__ A,    // M x K
        const float* __restrict__ W,    // K x N
        const float* __restrict__ bias, // N
        const float* __restrict__ res,  // M x N (MODE 1)
        const float* __restrict__ gates,// M x E (MODE 3)
        float* __restrict__ C,          // M x N
        int M, int N, int K, int expert, int first)
{
    __shared__ float As[8][128];
    __shared__ float Bs[8][128];

    const int tid = threadIdx.x;
    const int bm  = blockIdx.y * 128;
    const int bn  = blockIdx.x * 128;

    // A-tile: 128 rows x 8 cols -> one float4 per thread
    const int a_row  = tid >> 1;
    const int a_col4 = (tid & 1) * 4;
    // B-tile: 8 rows x 128 cols -> one float4 per thread
    const int b_row  = tid >> 5;
    const int b_col4 = (tid & 31) * 4;

    const int tx = tid & 15, ty = tid >> 4;
    const int mr = ty * 8, nr = tx * 8;

    const float* Aptr = A + (long)(bm + a_row) * K + a_col4;
    const float* Bptr = W + (long)b_row * N + bn + b_col4;

    float acc[8][8];
#pragma unroll
    for (int i = 0; i < 8; i++)
#pragma unroll
        for (int j = 0; j < 8; j++) acc[i][j] = 0.f;

    for (int k0 = 0; k0 < K; k0 += 8) {
        float4 av = *(const float4*)(Aptr + k0);
        As[a_col4 + 0][a_row] = av.x;
        As[a_col4 + 1][a_row] = av.y;
        As[a_col4 + 2][a_row] = av.z;
        As[a_col4 + 3][a_row] = av.w;
        float4 bv = *(const float4*)(Bptr + (long)k0 * N);
        *(float4*)&Bs[b_row][b_col4] = bv;
        __syncthreads();

#pragma unroll
        for (int kk = 0; kk < 8; kk++) {
            float a0[8], b0[8];
#pragma unroll
            for (int i = 0; i < 8; i++) a0[i] = As[kk][mr + i];
#pragma unroll
            for (int j = 0; j < 8; j++) b0[j] = Bs[kk][nr + j];
#pragma unroll
            for (int i = 0; i < 8; i++)
#pragma unroll
                for (int j = 0; j < 8; j++)
                    acc[i][j] = fmaf(a0[i], b0[j], acc[i][j]);
        }
        __syncthreads();
    }

#pragma unroll
    for (int i = 0; i < 8; i++) {
        const int row = bm + mr + i;
        float g = 0.f;
        if (MODE == 3) g = gates[(long)row * Eq + expert];
#pragma unroll
        for (int j = 0; j < 8; j++) {
            const int col = bn + nr + j;
            const long idx = (long)row * N + col;
            float v = acc[i][j] + bias[col];
            if (MODE == 0) {
                C[idx] = v;
            } else if (MODE == 1) {
                C[idx] = v + res[idx];
            } else if (MODE == 2) {
                C[idx] = 0.5f * v * (1.f + erff(v * 0.70710678118654752f));
            } else { // MODE 3
                float out = g * v;
                if (first) C[idx] = out;
                else       C[idx] += out;
            }
        }
    }
}

// ---------------- attention: one CTA per (b,h), K/V resident in smem ----------
#define KPAD 65
__global__ void __launch_bounds__(256)
attn_kernel(const float* __restrict__ qh, const float* __restrict__ kh,
            const float* __restrict__ vh, float* __restrict__ ctx)
{
    const int b = blockIdx.x / Hq;
    const int h = blockIdx.x % Hq;
    extern __shared__ float sm[];
    float* Ks = sm;                    // 196 * 65
    float* Vs = Ks + Sq * KPAD;        // 196 * 64
    float* Ps = Vs + Sq * DHq;         // 8 warps * 208
    float* Qs = Ps + 8 * 208;          // 8 warps * 64

    const int tid = threadIdx.x;
    // load K,V for this (b,h)
    for (int i = tid; i < Sq * DHq; i += 256) {
        int s = i / DHq, d = i % DHq;
        long gidx = (long)(b * Sq + s) * Dq + h * DHq + d;
        Ks[s * KPAD + d] = kh[gidx];
        Vs[s * DHq  + d] = vh[gidx];
    }
    __syncthreads();

    const int warp = tid >> 5, lane = tid & 31;
    float* p    = Ps + warp * 208;
    float* qrow = Qs + warp * DHq;

    for (int q = warp; q < Sq; q += 8) {
        // stage the query row
        for (int d = lane; d < DHq; d += 32)
            qrow[d] = qh[(long)(b * Sq + q) * Dq + h * DHq + d];
        __syncwarp();

        float lmax = -1e30f;
        for (int col = lane; col < Sq; col += 32) {
            float s = 0.f;
            const float* kr = Ks + col * KPAD;
#pragma unroll 16
            for (int d = 0; d < DHq; d++) s = fmaf(qrow[d], kr[d], s);
            s *= 0.125f; // 1/sqrt(64)
            p[col] = s;
            lmax = fmaxf(lmax, s);
        }
#pragma unroll
        for (int o = 16; o; o >>= 1) lmax = fmaxf(lmax, __shfl_xor_sync(0xffffffffu, lmax, o));

        float lsum = 0.f;
        for (int col = lane; col < Sq; col += 32) {
            float e = expf(p[col] - lmax);
            p[col] = e;
            lsum += e;
        }
#pragma unroll
        for (int o = 16; o; o >>= 1) lsum += __shfl_xor_sync(0xffffffffu, lsum, o);
        const float inv = 1.f / lsum;
        __syncwarp();

        for (int d = lane; d < DHq; d += 32) {
            float a = 0.f;
            for (int k = 0; k < Sq; k++) a = fmaf(p[k], Vs[k * DHq + d], a);
            ctx[(long)(b * Sq + q) * Dq + h * DHq + d] = a * inv;
        }
        __syncwarp();
    }
}

// ---------------- gate: warp per token, logits -> softmax ---------------------
__global__ void __launch_bounds__(256)
gate_kernel(const float* __restrict__ x, const float* __restrict__ Wg,
            const float* __restrict__ bg, float* __restrict__ gates)
{
    const int warp = (blockIdx.x * 256 + threadIdx.x) >> 5;
    const int lane = threadIdx.x & 31;
    if (warp >= NTOK) return;
    const float* xr = x + (long)warp * Dq;
    float lg[Eq];
#pragma unroll
    for (int e = 0; e < Eq; e++) lg[e] = 0.f;
    for (int d = lane; d < Dq; d += 32) {
        float xv = xr[d];
#pragma unroll
        for (int e = 0; e < Eq; e++) lg[e] = fmaf(xv, Wg[d * Eq + e], lg[e]);
    }
#pragma unroll
    for (int e = 0; e < Eq; e++)
#pragma unroll
        for (int o = 16; o; o >>= 1) lg[e] += __shfl_xor_sync(0xffffffffu, lg[e], o);
    if (lane == 0) {
        float m = -1e30f;
#pragma unroll
        for (int e = 0; e < Eq; e++) { lg[e] += bg[e]; m = fmaxf(m, lg[e]); }
        float s = 0.f;
#pragma unroll
        for (int e = 0; e < Eq; e++) { lg[e] = expf(lg[e] - m); s += lg[e]; }
        float inv = 1.f / s;
#pragma unroll
        for (int e = 0; e < Eq; e++) gates[(long)warp * Eq + e] = lg[e] * inv;
    }
}

// ---------------- layernorm: CTA per token, optional second addend ------------
__global__ void __launch_bounds__(256)
ln_kernel(const float* __restrict__ a, const float* __restrict__ b,
          const float* __restrict__ g, const float* __restrict__ be,
          float* __restrict__ out)
{
    const int row = blockIdx.x;
    const float* ar = a + (long)row * Dq;
    const float* br = b ? b + (long)row * Dq : nullptr;
    float v[3];
    float s = 0.f, s2 = 0.f;
#pragma unroll
    for (int i = 0; i < 3; i++) {
        int d = threadIdx.x + i * 256;
        float x = ar[d];
        if (br) x += br[d];
        v[i] = x;
        s += x; s2 = fmaf(x, x, s2);
    }
    // block reduce (8 warps)
    __shared__ float rs[8], rs2[8];
#pragma unroll
    for (int o = 16; o; o >>= 1) { s += __shfl_xor_sync(0xffffffffu, s, o); s2 += __shfl_xor_sync(0xffffffffu, s2, o); }
    const int warp = threadIdx.x >> 5, lane = threadIdx.x & 31;
    if (lane == 0) { rs[warp] = s; rs2[warp] = s2; }
    __syncthreads();
    if (warp == 0) {
        float t  = (lane < 8) ? rs[lane]  : 0.f;
        float t2 = (lane < 8) ? rs2[lane] : 0.f;
#pragma unroll
        for (int o = 4; o; o >>= 1) { t += __shfl_xor_sync(0xffffffffu, t, o); t2 += __shfl_xor_sync(0xffffffffu, t2, o); }
        if (lane == 0) { rs[0] = t; rs2[0] = t2; }
    }
    __syncthreads();
    const float mu  = rs[0] * (1.f / Dq);
    const float var = rs2[0] * (1.f / Dq) - mu * mu;
    const float inv = rsqrtf(var + 1e-5f);
#pragma unroll
    for (int i = 0; i < 3; i++) {
        int d = threadIdx.x + i * 256;
        out[(long)row * Dq + d] = (v[i] - mu) * inv * g[d] + be[d];
    }
}

// -------------------------------------------------------------------------------
extern "C" void kernel_launch(void* const* d_in, const int* in_sizes, int n_in,
                              void* d_out, int out_size)
{
    const float* q   = (const float*)d_in[0];
    const float* k   = (const float*)d_in[1];
    const float* v   = (const float*)d_in[2];
    const float* Wq  = (const float*)d_in[3];
    const float* bq  = (const float*)d_in[4];
    const float* Wk  = (const float*)d_in[5];
    const float* bk  = (const float*)d_in[6];
    const float* Wv  = (const float*)d_in[7];
    const float* bv  = (const float*)d_in[8];
    const float* Wo  = (const float*)d_in[9];
    const float* bo  = (const float*)d_in[10];
    const float* ln1g= (const float*)d_in[11];
    const float* ln1b= (const float*)d_in[12];
    const float* ln2g= (const float*)d_in[13];
    const float* ln2b= (const float*)d_in[14];
    const float* Wg  = (const float*)d_in[15];
    const float* bg  = (const float*)d_in[16];
    const float* W1  = (const float*)d_in[17];
    const float* b1  = (const float*)d_in[18];
    const float* W2  = (const float*)d_in[19];
    const float* b2  = (const float*)d_in[20];
    float* out = (float*)d_out;

    float *p_qh, *p_kh, *p_vh, *p_ctx, *p_tmp, *p_x, *p_moe, *p_h, *p_gates;
    cudaGetSymbolAddress((void**)&p_qh,   d_qh);
    cudaGetSymbolAddress((void**)&p_kh,   d_kh);
    cudaGetSymbolAddress((void**)&p_vh,   d_vh);
    cudaGetSymbolAddress((void**)&p_ctx,  d_ctx);
    cudaGetSymbolAddress((void**)&p_tmp,  d_tmp);
    cudaGetSymbolAddress((void**)&p_x,    d_x);
    cudaGetSymbolAddress((void**)&p_moe,  d_moe);
    cudaGetSymbolAddress((void**)&p_h,    d_hbuf);
    cudaGetSymbolAddress((void**)&p_gates,d_gates);

    const dim3 blk(256);
    const dim3 gD(Dq / 128, NTOK / 128);   // N=768
    const dim3 gF(Fq / 128, NTOK / 128);   // N=3072

    // --- QKV projections ---
    gemm128<0><<<gD, blk>>>(q, Wq, bq, nullptr, nullptr, p_qh, NTOK, Dq, Dq, 0, 0);
    gemm128<0><<<gD, blk>>>(k, Wk, bk, nullptr, nullptr, p_kh, NTOK, Dq, Dq, 0, 0);
    gemm128<0><<<gD, blk>>>(v, Wv, bv, nullptr, nullptr, p_vh, NTOK, Dq, Dq, 0, 0);

    // --- attention ---
    const int smem = (Sq * KPAD + Sq * DHq + 8 * 208 + 8 * DHq) * (int)sizeof(float);
    cudaFuncSetAttribute(attn_kernel, cudaFuncAttributeMaxDynamicSharedMemorySize, smem);
    attn_kernel<<<Bq * Hq, blk, smem>>>(p_qh, p_kh, p_vh, p_ctx);

    // --- O projection + residual(q), then LN1 ---
    gemm128<1><<<gD, blk>>>(p_ctx, Wo, bo, q, nullptr, p_tmp, NTOK, Dq, Dq, 0, 0);
    ln_kernel<<<NTOK, blk>>>(p_tmp, nullptr, ln1g, ln1b, p_x);

    // --- gate softmax ---
    gate_kernel<<<(NTOK * 32 + 255) / 256, blk>>>(p_x, Wg, bg, p_gates);

    // --- MoE experts (sequential; accumulate gate-weighted outputs) ---
    for (int e = 0; e < Eq; e++) {
        gemm128<2><<<gF, blk>>>(p_x, W1 + (long)e * Dq * Fq, b1 + (long)e * Fq,
                                nullptr, nullptr, p_h, NTOK, Fq, Dq, e, 0);
        gemm128<3><<<gD, blk>>>(p_h, W2 + (long)e * Fq * Dq, b2 + (long)e * Dq,
                                nullptr, p_gates, p_moe, NTOK, Dq, Fq, e, e == 0);
    }

    // --- residual + LN2 -> output ---
    ln_kernel<<<NTOK, blk>>>(p_x, p_moe, ln2g, ln2b, out);
}

// round 3
// speedup vs baseline: 1.4628x; 1.4628x over previous
#include <cuda_runtime.h>
#include <cuda_bf16.h>
#include <math.h>
#include <stdint.h>

#define Bq 32
#define Sq 196
#define Dq 768
#define Hq 12
#define Eq 8
#define Fq 3072
#define DHq 64
#define NTOK (Bq*Sq)   // 6272

#define HAS_TCGEN05 (defined(__CUDA_ARCH_FEAT_SM103_ALL) || defined(__CUDA_ARCH_FEAT_SM100_ALL))

// ---------------- scratch (device globals; no allocation allowed) -------------
__device__ __align__(256) float d_qh [NTOK*Dq];
__device__ __align__(256) float d_kh [NTOK*Dq];
__device__ __align__(256) float d_vh [NTOK*Dq];
__device__ __align__(256) float d_ctx[NTOK*Dq];
__device__ __align__(256) float d_tmp[NTOK*Dq];
__device__ __align__(256) float d_x  [NTOK*Dq];
__device__ __align__(256) float d_moe[NTOK*Dq];
__device__ __align__(256) float d_gates[NTOK*Eq];

__device__ __align__(256) __nv_bfloat16 d_xhi[NTOK*Dq];
__device__ __align__(256) __nv_bfloat16 d_xlo[NTOK*Dq];
__device__ __align__(256) __nv_bfloat16 d_hhi[NTOK*Fq];
__device__ __align__(256) __nv_bfloat16 d_hlo[NTOK*Fq];
__device__ __align__(256) __nv_bfloat16 d_w1t_hi[Eq*Fq*Dq]; // [E][F][D] rows N-major, K contiguous
__device__ __align__(256) __nv_bfloat16 d_w1t_lo[Eq*Fq*Dq];
__device__ __align__(256) __nv_bfloat16 d_w2t_hi[Eq*Dq*Fq]; // [E][D][F]
__device__ __align__(256) __nv_bfloat16 d_w2t_lo[Eq*Dq*Fq];

// ======================= PTX helpers ==========================================
__device__ __forceinline__ uint32_t smem_u32(const void* p) {
    uint32_t a;
    asm("{ .reg .u64 t; cvta.to.shared.u64 t, %1; cvt.u32.u64 %0, t; }" : "=r"(a) : "l"(p));
    return a;
}

#if HAS_TCGEN05
__device__ __forceinline__ bool elect_one() {
    uint32_t p;
    asm volatile("{\n .reg .pred p;\n elect.sync _|p, 0xFFFFFFFF;\n selp.b32 %0,1,0,p;\n}" : "=r"(p));
    return p != 0;
}
#define MBARRIER_INIT(addr, cnt) \
    asm volatile("mbarrier.init.shared.b64 [%0], %1;" :: "r"((uint32_t)(addr)), "r"((uint32_t)(cnt)) : "memory")
#define MBARRIER_INVAL(addr) \
    asm volatile("mbarrier.inval.shared.b64 [%0];" :: "r"((uint32_t)(addr)) : "memory")
#define MBARRIER_WAIT_PARITY(mbar_smem_addr, phase_parity) do { \
    uint32_t _mbar = (uint32_t)(mbar_smem_addr); \
    uint32_t _parity = (uint32_t)(phase_parity); \
    uint32_t _done; \
    asm volatile( \
        "{\n\t.reg .pred p;\n\t" \
        "mbarrier.try_wait.parity.acquire.cta.shared::cta.b64 p, [%1], %2;\n\t" \
        "selp.b32 %0, 1, 0, p;\n\t}" \
        : "=r"(_done) : "r"(_mbar), "r"(_parity) : "memory"); \
    if (!_done) { \
        asm volatile( \
            "{\n\t.reg .pred P1;\n\t" \
            "WAIT_LOOP_%=:\n\t" \
            "mbarrier.try_wait.parity.acquire.cta.shared::cta.b64 P1, [%0], %1, 0x989680;\n\t" \
            "@P1 bra.uni WAIT_DONE_%=;\n\t" \
            "bra.uni WAIT_LOOP_%=;\n\t" \
            "WAIT_DONE_%=:\n\t}" \
            :: "r"(_mbar), "r"(_parity) : "memory"); \
    } \
} while(0)
#define TCGEN05_ALLOC(smem_result_addr, nCols) \
    asm volatile("tcgen05.alloc.cta_group::1.sync.aligned.shared::cta.b32 [%0], %1;" \
        :: "r"((uint32_t)(smem_result_addr)), "r"((uint32_t)(nCols)) : "memory")
#define TCGEN05_DEALLOC(tmem_addr, nCols) \
    asm volatile("tcgen05.dealloc.cta_group::1.sync.aligned.b32 %0, %1;" :: "r"(tmem_addr), "r"(nCols))
#define TCGEN05_RELINQ() \
    asm volatile("tcgen05.relinquish_alloc_permit.cta_group::1.sync.aligned;")
#define TCGEN05_COMMIT(mbar_smem_addr) \
    asm volatile("tcgen05.commit.cta_group::1.mbarrier::arrive::one.shared::cluster.b64 [%0];" \
        :: "r"((uint32_t)(mbar_smem_addr)) : "memory")
#define TCGEN05_FENCE_AFTER()  asm volatile("tcgen05.fence::after_thread_sync;" ::: "memory")
#define TCGEN05_FENCE_BEFORE() asm volatile("tcgen05.fence::before_thread_sync;" ::: "memory")
#define TCGEN05_WAIT_LD() asm volatile("tcgen05.wait::ld.sync.aligned;" ::: "memory")
#define FENCE_ASYNC_SHARED() asm volatile("fence.proxy.async.shared::cta;" ::: "memory")
#define TCGEN05_LD_32X32B_X32(r, tmem_addr) \
    asm volatile( \
        "tcgen05.ld.sync.aligned.32x32b.x32.b32 " \
        "{%0, %1, %2, %3, %4, %5, %6, %7, " \
        " %8, %9, %10, %11, %12, %13, %14, %15, " \
        " %16, %17, %18, %19, %20, %21, %22, %23, " \
        " %24, %25, %26, %27, %28, %29, %30, %31}, [%32];" \
        : "=r"((r)[0]),  "=r"((r)[1]),  "=r"((r)[2]),  "=r"((r)[3]), \
          "=r"((r)[4]),  "=r"((r)[5]),  "=r"((r)[6]),  "=r"((r)[7]), \
          "=r"((r)[8]),  "=r"((r)[9]),  "=r"((r)[10]), "=r"((r)[11]), \
          "=r"((r)[12]), "=r"((r)[13]), "=r"((r)[14]), "=r"((r)[15]), \
          "=r"((r)[16]), "=r"((r)[17]), "=r"((r)[18]), "=r"((r)[19]), \
          "=r"((r)[20]), "=r"((r)[21]), "=r"((r)[22]), "=r"((r)[23]), \
          "=r"((r)[24]), "=r"((r)[25]), "=r"((r)[26]), "=r"((r)[27]), \
          "=r"((r)[28]), "=r"((r)[29]), "=r"((r)[30]), "=r"((r)[31]) \
        : "r"(tmem_addr))

// SW128 K-major descriptor: layout=2, version=1, SBO=64, LBO=1
static constexpr uint64_t DESC_BASE =
    (uint64_t(2) << 61) | (uint64_t(1) << 46) | (uint64_t(64) << 32) | (uint64_t(1) << 16);
#define MK_DESC(a) (DESC_BASE | ((uint64_t)((a) >> 4) & 0x3FFF))

__device__ __forceinline__ void mma_bf16_ss(uint32_t d, uint64_t ad, uint64_t bd,
                                            uint32_t idesc, uint32_t en) {
    asm volatile(
        "{\n\t.reg .pred p;\n\tsetp.ne.u32 p, %5, 0;\n\t"
        "tcgen05.mma.cta_group::1.kind::f16 [%0], %1, %2, %3, {%4,%4,%4,%4}, p;\n\t}"
        :: "r"(d), "l"(ad), "l"(bd), "r"(idesc), "r"(0u), "r"(en) : "memory");
}
#endif // HAS_TCGEN05

// ======================= tensor-core 3xBF16 GEMM ==============================
// C[M,N] = A[M,K] @ B[N,K]^T with A=Ahi+Alo, B=Bhi+Blo (bf16 splits of fp32)
// MODE 0: gelu(acc + bias) -> split-bf16 Chi/Clo    (MoE up-proj)
// MODE 1: Cf (+)= gates[row,e] * (acc + bias)       (MoE down-proj)
#define TM 128
#define TN 256
#define TK 64
#define STAGE_BYTES 98304
#define SM_A_HI 0
#define SM_A_LO 16384
#define SM_B_HI 32768
#define SM_B_LO 65536
#define SM_DATA 1024
#define TC_SMEM (SM_DATA + 2*STAGE_BYTES)   // 197632 bytes

#if HAS_TCGEN05
static constexpr uint32_t IDESC_BF16 =
    (1u << 4) | (1u << 7) | (1u << 10) | ((TN / 8) << 17) | ((TM / 16) << 24);

__device__ __forceinline__ void load_slab(
    char* smx, int stage,
    const __nv_bfloat16* __restrict__ Ahi, const __nv_bfloat16* __restrict__ Alo,
    const __nv_bfloat16* __restrict__ Bhi, const __nv_bfloat16* __restrict__ Blo,
    int m0, int n0, int k0, int K)
{
    const int tid = threadIdx.x;
    char* base = smx + SM_DATA + stage * STAGE_BYTES;
#pragma unroll
    for (int i = 0; i < 4; i++) {
        int idx = i * 256 + tid;           // 0..1023
        int row = idx >> 3, c4 = idx & 7;
        int off = row * 128 + c4 * 16;
        int sw  = off ^ ((off >> 3) & 0x70);
        size_t g = (size_t)(m0 + row) * K + k0;
        *(uint4*)(base + SM_A_HI + sw) = ((const uint4*)(Ahi + g))[c4];
        *(uint4*)(base + SM_A_LO + sw) = ((const uint4*)(Alo + g))[c4];
    }
#pragma unroll
    for (int i = 0; i < 8; i++) {
        int idx = i * 256 + tid;           // 0..2047
        int row = idx >> 3, c4 = idx & 7;
        int off = row * 128 + c4 * 16;
        int sw  = off ^ ((off >> 3) & 0x70);
        size_t g = (size_t)(n0 + row) * K + k0;
        *(uint4*)(base + SM_B_HI + sw) = ((const uint4*)(Bhi + g))[c4];
        *(uint4*)(base + SM_B_LO + sw) = ((const uint4*)(Blo + g))[c4];
    }
}
#endif

template<int MODE>
__global__ void __launch_bounds__(256)
tc_gemm(const __nv_bfloat16* __restrict__ Ahi, const __nv_bfloat16* __restrict__ Alo,
        const __nv_bfloat16* __restrict__ Bhi, const __nv_bfloat16* __restrict__ Blo,
        const float* __restrict__ bias, const float* __restrict__ gates,
        float* __restrict__ Cf,
        __nv_bfloat16* __restrict__ Chi, __nv_bfloat16* __restrict__ Clo,
        int M, int N, int K, int expert, int first)
{
    extern __shared__ char smx[];
#if HAS_TCGEN05
    // ---------------- tcgen05 fast path ----------------
    const uint32_t sb = smem_u32(smx);
    const int tid = threadIdx.x;
    const int wid = tid >> 5, lane = tid & 31;
    const int m0 = blockIdx.y * TM, n0 = blockIdx.x * TN;

    if (wid == 0) { TCGEN05_ALLOC(sb, 256); TCGEN05_RELINQ(); }
    if (tid == 0) { MBARRIER_INIT(sb + 8, 1); MBARRIER_INIT(sb + 16, 1); }
    __syncthreads();
    uint32_t tmem;
    asm volatile("ld.shared.b32 %0, [%1];" : "=r"(tmem) : "r"(sb));

    const int NS = K / TK;
    load_slab(smx, 0, Ahi, Alo, Bhi, Blo, m0, n0, 0, K);
    FENCE_ASYNC_SHARED();
    __syncthreads();

    int ph0 = 0, ph1 = 0;
    for (int s = 0; s < NS; s++) {
        const int buf = s & 1;
        if (wid == 0) {
            TCGEN05_FENCE_AFTER();
            if (elect_one()) {
                const uint32_t tb = sb + SM_DATA + buf * STAGE_BYTES;
                const uint64_t ah = MK_DESC(tb + SM_A_HI);
                const uint64_t al = MK_DESC(tb + SM_A_LO);
                const uint64_t bh = MK_DESC(tb + SM_B_HI);
                const uint64_t bl = MK_DESC(tb + SM_B_LO);
#pragma unroll
                for (int ks = 0; ks < 4; ks++) {
                    const uint32_t en0 = (s == 0 && ks == 0) ? 0u : 1u;
                    mma_bf16_ss(tmem, ah + ks * 2, bh + ks * 2, IDESC_BF16, en0);
                    mma_bf16_ss(tmem, ah + ks * 2, bl + ks * 2, IDESC_BF16, 1u);
                    mma_bf16_ss(tmem, al + ks * 2, bh + ks * 2, IDESC_BF16, 1u);
                }
                TCGEN05_COMMIT(sb + 8 + buf * 8);
            }
        }
        if (s + 1 < NS) {
            const int nb = 1 - buf;
            if (s >= 1) {
                if (nb == 0) { MBARRIER_WAIT_PARITY(sb + 8,  ph0); ph0 ^= 1; }
                else         { MBARRIER_WAIT_PARITY(sb + 16, ph1); ph1 ^= 1; }
            }
            load_slab(smx, nb, Ahi, Alo, Bhi, Blo, m0, n0, (s + 1) * TK, K);
            FENCE_ASYNC_SHARED();
        }
        __syncthreads();
    }
    {
        const int lb = (NS - 1) & 1;
        if (lb == 0) { MBARRIER_WAIT_PARITY(sb + 8,  ph0); }
        else         { MBARRIER_WAIT_PARITY(sb + 16, ph1); }
    }
    TCGEN05_FENCE_AFTER();

    // epilogue: warps 0-3 cols [0,128), warps 4-7 cols [128,256)
    const int sub = wid & 3;
    const int cg  = wid >> 2;
    const int row = m0 + sub * 32 + lane;
#pragma unroll
    for (int ch = 0; ch < 4; ch++) {
        const int colb = cg * 128 + ch * 32;
        uint32_t r[32];
        TCGEN05_LD_32X32B_X32(r, tmem + colb);
        TCGEN05_WAIT_LD();
        if (MODE == 0) {
#pragma unroll
            for (int c = 0; c < 32; c++) {
                const int col = n0 + colb + c;
                float v = __uint_as_float(r[c]) + bias[col];
                float g = 0.5f * v * (1.f + erff(v * 0.70710678118654752f));
                __nv_bfloat16 h = __float2bfloat16(g);
                float lo = g - __bfloat162float(h);
                const size_t idx = (size_t)row * N + col;
                Chi[idx] = h;
                Clo[idx] = __float2bfloat16(lo);
            }
        } else {
            const float gate = gates[(size_t)row * Eq + expert];
#pragma unroll
            for (int c = 0; c < 32; c++) {
                const int col = n0 + colb + c;
                float v = __uint_as_float(r[c]) + bias[col];
                float o = gate * v;
                const size_t idx = (size_t)row * N + col;
                if (first) Cf[idx] = o;
                else       Cf[idx] += o;
            }
        }
    }
    TCGEN05_FENCE_BEFORE();
    __syncthreads();
    if (tid == 0) { MBARRIER_INVAL(sb + 8); MBARRIER_INVAL(sb + 16); }
    __syncthreads();
    if (wid == 0) TCGEN05_DEALLOC(tmem, 256);
#else
    // ---------------- correct SIMT fallback (compute_103 pass) ----------------
    float* As = (float*)smx;            // [16][128]
    float* Bs = As + 16 * 128;          // [16][128]
    const int tid = threadIdx.x;
    const int m0 = blockIdx.y * TM, n0x = blockIdx.x * TN;
    const int tx = tid & 15, ty = tid >> 4;
    const int mr = ty * 8, nr = tx * 8;

    for (int half = 0; half < TN / 128; half++) {
        const int n0 = n0x + half * 128;
        float acc[8][8];
#pragma unroll
        for (int i = 0; i < 8; i++)
#pragma unroll
            for (int j = 0; j < 8; j++) acc[i][j] = 0.f;
        for (int k0 = 0; k0 < K; k0 += 16) {
            __syncthreads();
#pragma unroll
            for (int i = 0; i < 8; i++) {
                int idx = i * 256 + tid;      // 0..2047
                int kk = idx >> 7, mm = idx & 127;
                size_t ga = (size_t)(m0 + mm) * K + k0 + kk;
                size_t gb = (size_t)(n0 + mm) * K + k0 + kk;
                As[kk * 128 + mm] = __bfloat162float(Ahi[ga]) + __bfloat162float(Alo[ga]);
                Bs[kk * 128 + mm] = __bfloat162float(Bhi[gb]) + __bfloat162float(Blo[gb]);
            }
            __syncthreads();
#pragma unroll
            for (int kk = 0; kk < 16; kk++) {
                float a0[8], b0[8];
#pragma unroll
                for (int i = 0; i < 8; i++) a0[i] = As[kk * 128 + mr + i];
#pragma unroll
                for (int j = 0; j < 8; j++) b0[j] = Bs[kk * 128 + nr + j];
#pragma unroll
                for (int i = 0; i < 8; i++)
#pragma unroll
                    for (int j = 0; j < 8; j++)
                        acc[i][j] = fmaf(a0[i], b0[j], acc[i][j]);
            }
        }
#pragma unroll
        for (int i = 0; i < 8; i++) {
            const int row = m0 + mr + i;
#pragma unroll
            for (int j = 0; j < 8; j++) {
                const int col = n0 + nr + j;
                const size_t idx = (size_t)row * N + col;
                float v = acc[i][j] + bias[col];
                if (MODE == 0) {
                    float g = 0.5f * v * (1.f + erff(v * 0.70710678118654752f));
                    __nv_bfloat16 h = __float2bfloat16(g);
                    Chi[idx] = h;
                    Clo[idx] = __float2bfloat16(g - __bfloat162float(h));
                } else {
                    const float gate = gates[(size_t)row * Eq + expert];
                    float o = gate * v;
                    if (first) Cf[idx] = o;
                    else       Cf[idx] += o;
                }
            }
        }
    }
#endif
}

// ---------------- transpose + bf16 split: W[e][K][N] -> T[e][N][K] -------------
__global__ void __launch_bounds__(256)
transpose_split(const float* __restrict__ W, __nv_bfloat16* __restrict__ Thi,
                __nv_bfloat16* __restrict__ Tlo, int K, int N)
{
    __shared__ float t[32][33];
    const int e = blockIdx.z;
    const float* Wp = W + (size_t)e * K * N;
    __nv_bfloat16* th = Thi + (size_t)e * K * N;
    __nv_bfloat16* tl = Tlo + (size_t)e * K * N;
    const int k0 = blockIdx.x * 32, n0 = blockIdx.y * 32;
    const int x = threadIdx.x & 31, y = threadIdx.x >> 5;
#pragma unroll
    for (int i = 0; i < 32; i += 8)
        t[y + i][x] = Wp[(size_t)(k0 + y + i) * N + n0 + x];
    __syncthreads();
#pragma unroll
    for (int i = 0; i < 32; i += 8) {
        float v = t[x][y + i];
        __nv_bfloat16 h = __float2bfloat16(v);
        float lo = v - __bfloat162float(h);
        const size_t idx = (size_t)(n0 + y + i) * K + k0 + x;
        th[idx] = h;
        tl[idx] = __float2bfloat16(lo);
    }
}

// ---------------- fp32 SIMT GEMM (QKV / O-proj) --------------------------------
template<int MODE>
__global__ void __launch_bounds__(256)
gemm128(const float* __restrict__ A, const float* __restrict__ W,
        const float* __restrict__ bias, const float* __restrict__ res,
        float* __restrict__ C, int M, int N, int K)
{
    __shared__ float As[8][128];
    __shared__ float Bs[8][128];
    const int tid = threadIdx.x;
    const int bm = blockIdx.y * 128, bn = blockIdx.x * 128;
    const int a_row = tid >> 1, a_col4 = (tid & 1) * 4;
    const int b_row = tid >> 5, b_col4 = (tid & 31) * 4;
    const int tx = tid & 15, ty = tid >> 4;
    const int mr = ty * 8, nr = tx * 8;
    const float* Aptr = A + (size_t)(bm + a_row) * K + a_col4;
    const float* Bptr = W + (size_t)b_row * N + bn + b_col4;
    float acc[8][8];
#pragma unroll
    for (int i = 0; i < 8; i++)
#pragma unroll
        for (int j = 0; j < 8; j++) acc[i][j] = 0.f;
    for (int k0 = 0; k0 < K; k0 += 8) {
        float4 av = *(const float4*)(Aptr + k0);
        As[a_col4 + 0][a_row] = av.x;  As[a_col4 + 1][a_row] = av.y;
        As[a_col4 + 2][a_row] = av.z;  As[a_col4 + 3][a_row] = av.w;
        *(float4*)&Bs[b_row][b_col4] = *(const float4*)(Bptr + (size_t)k0 * N);
        __syncthreads();
#pragma unroll
        for (int kk = 0; kk < 8; kk++) {
            float a0[8], b0[8];
#pragma unroll
            for (int i = 0; i < 8; i++) a0[i] = As[kk][mr + i];
#pragma unroll
            for (int j = 0; j < 8; j++) b0[j] = Bs[kk][nr + j];
#pragma unroll
            for (int i = 0; i < 8; i++)
#pragma unroll
                for (int j = 0; j < 8; j++)
                    acc[i][j] = fmaf(a0[i], b0[j], acc[i][j]);
        }
        __syncthreads();
    }
#pragma unroll
    for (int i = 0; i < 8; i++) {
        const int row = bm + mr + i;
#pragma unroll
        for (int j = 0; j < 8; j++) {
            const int col = bn + nr + j;
            const size_t idx = (size_t)row * N + col;
            float v = acc[i][j] + bias[col];
            if (MODE == 0) C[idx] = v;
            else           C[idx] = v + res[idx];
        }
    }
}

// ---------------- attention ----------------------------------------------------
#define KPAD 65
__global__ void __launch_bounds__(256)
attn_kernel(const float* __restrict__ qh, const float* __restrict__ kh,
            const float* __restrict__ vh, float* __restrict__ ctx)
{
    const int b = blockIdx.x / Hq;
    const int h = blockIdx.x % Hq;
    extern __shared__ float sm[];
    float* Ks = sm;
    float* Vs = Ks + Sq * KPAD;
    float* Ps = Vs + Sq * DHq;
    float* Qs = Ps + 8 * 208;
    const int tid = threadIdx.x;
    for (int i = tid; i < Sq * DHq; i += 256) {
        int s = i / DHq, d = i % DHq;
        size_t gidx = (size_t)(b * Sq + s) * Dq + h * DHq + d;
        Ks[s * KPAD + d] = kh[gidx];
        Vs[s * DHq  + d] = vh[gidx];
    }
    __syncthreads();
    const int warp = tid >> 5, lane = tid & 31;
    float* p    = Ps + warp * 208;
    float* qrow = Qs + warp * DHq;
    for (int q = warp; q < Sq; q += 8) {
        for (int d = lane; d < DHq; d += 32)
            qrow[d] = qh[(size_t)(b * Sq + q) * Dq + h * DHq + d];
        __syncwarp();
        float lmax = -1e30f;
        for (int col = lane; col < Sq; col += 32) {
            float s = 0.f;
            const float* kr = Ks + col * KPAD;
#pragma unroll 16
            for (int d = 0; d < DHq; d++) s = fmaf(qrow[d], kr[d], s);
            s *= 0.125f;
            p[col] = s;
            lmax = fmaxf(lmax, s);
        }
#pragma unroll
        for (int o = 16; o; o >>= 1) lmax = fmaxf(lmax, __shfl_xor_sync(0xffffffffu, lmax, o));
        float lsum = 0.f;
        for (int col = lane; col < Sq; col += 32) {
            float e = expf(p[col] - lmax);
            p[col] = e;
            lsum += e;
        }
#pragma unroll
        for (int o = 16; o; o >>= 1) lsum += __shfl_xor_sync(0xffffffffu, lsum, o);
        const float inv = 1.f / lsum;
        __syncwarp();
        for (int d = lane; d < DHq; d += 32) {
            float a = 0.f;
            for (int k = 0; k < Sq; k++) a = fmaf(p[k], Vs[k * DHq + d], a);
            ctx[(size_t)(b * Sq + q) * Dq + h * DHq + d] = a * inv;
        }
        __syncwarp();
    }
}

// ---------------- gate softmax --------------------------------------------------
__global__ void __launch_bounds__(256)
gate_kernel(const float* __restrict__ x, const float* __restrict__ Wg,
            const float* __restrict__ bg, float* __restrict__ gates)
{
    const int warp = (blockIdx.x * 256 + threadIdx.x) >> 5;
    const int lane = threadIdx.x & 31;
    if (warp >= NTOK) return;
    const float* xr = x + (size_t)warp * Dq;
    float lg[Eq];
#pragma unroll
    for (int e = 0; e < Eq; e++) lg[e] = 0.f;
    for (int d = lane; d < Dq; d += 32) {
        float xv = xr[d];
#pragma unroll
        for (int e = 0; e < Eq; e++) lg[e] = fmaf(xv, Wg[d * Eq + e], lg[e]);
    }
#pragma unroll
    for (int e = 0; e < Eq; e++)
#pragma unroll
        for (int o = 16; o; o >>= 1) lg[e] += __shfl_xor_sync(0xffffffffu, lg[e], o);
    if (lane == 0) {
        float m = -1e30f;
#pragma unroll
        for (int e = 0; e < Eq; e++) { lg[e] += bg[e]; m = fmaxf(m, lg[e]); }
        float s = 0.f;
#pragma unroll
        for (int e = 0; e < Eq; e++) { lg[e] = expf(lg[e] - m); s += lg[e]; }
        float inv = 1.f / s;
#pragma unroll
        for (int e = 0; e < Eq; e++) gates[(size_t)warp * Eq + e] = lg[e] * inv;
    }
}

// ---------------- layernorm (+ optional split-bf16 output) ----------------------
__global__ void __launch_bounds__(256)
ln_kernel(const float* __restrict__ a, const float* __restrict__ b,
          const float* __restrict__ g, const float* __restrict__ be,
          float* __restrict__ out, __nv_bfloat16* __restrict__ ohi,
          __nv_bfloat16* __restrict__ olo)
{
    const int row = blockIdx.x;
    const float* ar = a + (size_t)row * Dq;
    const float* br = b ? b + (size_t)row * Dq : nullptr;
    float v[3];
    float s = 0.f, s2 = 0.f;
#pragma unroll
    for (int i = 0; i < 3; i++) {
        int d = threadIdx.x + i * 256;
        float x = ar[d];
        if (br) x += br[d];
        v[i] = x;
        s += x; s2 = fmaf(x, x, s2);
    }
    __shared__ float rs[8], rs2[8];
#pragma unroll
    for (int o = 16; o; o >>= 1) { s += __shfl_xor_sync(0xffffffffu, s, o); s2 += __shfl_xor_sync(0xffffffffu, s2, o); }
    const int warp = threadIdx.x >> 5, lane = threadIdx.x & 31;
    if (lane == 0) { rs[warp] = s; rs2[warp] = s2; }
    __syncthreads();
    if (warp == 0) {
        float t  = (lane < 8) ? rs[lane]  : 0.f;
        float t2 = (lane < 8) ? rs2[lane] : 0.f;
#pragma unroll
        for (int o = 4; o; o >>= 1) { t += __shfl_xor_sync(0xffffffffu, t, o); t2 += __shfl_xor_sync(0xffffffffu, t2, o); }
        if (lane == 0) { rs[0] = t; rs2[0] = t2; }
    }
    __syncthreads();
    const float mu  = rs[0] * (1.f / Dq);
    const float var = rs2[0] * (1.f / Dq) - mu * mu;
    const float inv = rsqrtf(var + 1e-5f);
#pragma unroll
    for (int i = 0; i < 3; i++) {
        int d = threadIdx.x + i * 256;
        float y = (v[i] - mu) * inv * g[d] + be[d];
        const size_t idx = (size_t)row * Dq + d;
        out[idx] = y;
        if (ohi) {
            __nv_bfloat16 h = __float2bfloat16(y);
            ohi[idx] = h;
            olo[idx] = __float2bfloat16(y - __bfloat162float(h));
        }
    }
}

// =================================================================================
extern "C" void kernel_launch(void* const* d_in, const int* in_sizes, int n_in,
                              void* d_out, int out_size)
{
    const float* q   = (const float*)d_in[0];
    const float* k   = (const float*)d_in[1];
    const float* v   = (const float*)d_in[2];
    const float* Wq  = (const float*)d_in[3];
    const float* bq  = (const float*)d_in[4];
    const float* Wk  = (const float*)d_in[5];
    const float* bk  = (const float*)d_in[6];
    const float* Wv  = (const float*)d_in[7];
    const float* bv  = (const float*)d_in[8];
    const float* Wo  = (const float*)d_in[9];
    const float* bo  = (const float*)d_in[10];
    const float* ln1g= (const float*)d_in[11];
    const float* ln1b= (const float*)d_in[12];
    const float* ln2g= (const float*)d_in[13];
    const float* ln2b= (const float*)d_in[14];
    const float* Wg  = (const float*)d_in[15];
    const float* bg  = (const float*)d_in[16];
    const float* W1  = (const float*)d_in[17];
    const float* b1  = (const float*)d_in[18];
    const float* W2  = (const float*)d_in[19];
    const float* b2  = (const float*)d_in[20];
    float* out = (float*)d_out;

    float *p_qh, *p_kh, *p_vh, *p_ctx, *p_tmp, *p_x, *p_moe, *p_gates;
    __nv_bfloat16 *p_xhi, *p_xlo, *p_hhi, *p_hlo, *p_w1h, *p_w1l, *p_w2h, *p_w2l;
    cudaGetSymbolAddress((void**)&p_qh,   d_qh);
    cudaGetSymbolAddress((void**)&p_kh,   d_kh);
    cudaGetSymbolAddress((void**)&p_vh,   d_vh);
    cudaGetSymbolAddress((void**)&p_ctx,  d_ctx);
    cudaGetSymbolAddress((void**)&p_tmp,  d_tmp);
    cudaGetSymbolAddress((void**)&p_x,    d_x);
    cudaGetSymbolAddress((void**)&p_moe,  d_moe);
    cudaGetSymbolAddress((void**)&p_gates,d_gates);
    cudaGetSymbolAddress((void**)&p_xhi,  d_xhi);
    cudaGetSymbolAddress((void**)&p_xlo,  d_xlo);
    cudaGetSymbolAddress((void**)&p_hhi,  d_hhi);
    cudaGetSymbolAddress((void**)&p_hlo,  d_hlo);
    cudaGetSymbolAddress((void**)&p_w1h,  d_w1t_hi);
    cudaGetSymbolAddress((void**)&p_w1l,  d_w1t_lo);
    cudaGetSymbolAddress((void**)&p_w2h,  d_w2t_hi);
    cudaGetSymbolAddress((void**)&p_w2l,  d_w2t_lo);

    const dim3 blk(256);
    const dim3 gD(Dq / 128, NTOK / 128);

    // weight transpose + bf16 split (independent; issue first)
    transpose_split<<<dim3(Dq/32, Fq/32, Eq), blk>>>(W1, p_w1h, p_w1l, Dq, Fq);
    transpose_split<<<dim3(Fq/32, Dq/32, Eq), blk>>>(W2, p_w2h, p_w2l, Fq, Dq);

    // QKV projections (fp32 SIMT)
    gemm128<0><<<gD, blk>>>(q, Wq, bq, nullptr, p_qh, NTOK, Dq, Dq);
    gemm128<0><<<gD, blk>>>(k, Wk, bk, nullptr, p_kh, NTOK, Dq, Dq);
    gemm128<0><<<gD, blk>>>(v, Wv, bv, nullptr, p_vh, NTOK, Dq, Dq);

    // attention
    const int smem_attn = (Sq * KPAD + Sq * DHq + 8 * 208 + 8 * DHq) * (int)sizeof(float);
    cudaFuncSetAttribute(attn_kernel, cudaFuncAttributeMaxDynamicSharedMemorySize, smem_attn);
    attn_kernel<<<Bq * Hq, blk, smem_attn>>>(p_qh, p_kh, p_vh, p_ctx);

    // O projection + residual, LN1 (also emits split-bf16 x)
    gemm128<1><<<gD, blk>>>(p_ctx, Wo, bo, q, p_tmp, NTOK, Dq, Dq);
    ln_kernel<<<NTOK, blk>>>(p_tmp, nullptr, ln1g, ln1b, p_x, p_xhi, p_xlo);

    // gate softmax
    gate_kernel<<<(NTOK * 32 + 255) / 256, blk>>>(p_x, Wg, bg, p_gates);

    // MoE experts on tensor cores (3x-bf16 compensated)
    cudaFuncSetAttribute(tc_gemm<0>, cudaFuncAttributeMaxDynamicSharedMemorySize, TC_SMEM);
    cudaFuncSetAttribute(tc_gemm<1>, cudaFuncAttributeMaxDynamicSharedMemorySize, TC_SMEM);
    for (int e = 0; e < Eq; e++) {
        tc_gemm<0><<<dim3(Fq / TN, NTOK / TM), blk, TC_SMEM>>>(
            p_xhi, p_xlo,
            p_w1h + (size_t)e * Fq * Dq, p_w1l + (size_t)e * Fq * Dq,
            b1 + (size_t)e * Fq, nullptr, nullptr, p_hhi, p_hlo,
            NTOK, Fq, Dq, e, 0);
        tc_gemm<1><<<dim3(Dq / TN, NTOK / TM), blk, TC_SMEM>>>(
            p_hhi, p_hlo,
            p_w2h + (size_t)e * Dq * Fq, p_w2l + (size_t)e * Dq * Fq,
            b2 + (size_t)e * Dq, p_gates, p_moe, nullptr, nullptr,
            NTOK, Dq, Fq, e, e == 0);
    }

    // residual + LN2 -> output
    ln_kernel<<<NTOK, blk>>>(p_x, p_moe, ln2g, ln2b, out, nullptr, nullptr);
}

// round 4
// speedup vs baseline: 4.3223x; 2.9548x over previous
#include <cuda_runtime.h>
#include <cuda_bf16.h>
#include <math.h>
#include <stdint.h>

#define Bq 32
#define Sq 196
#define Dq 768
#define Hq 12
#define Eq 8
#define Fq 3072
#define DHq 64
#define NTOK (Bq*Sq)   // 6272

#define HAS_TCGEN05 (defined(__CUDA_ARCH_FEAT_SM103_ALL) || defined(__CUDA_ARCH_FEAT_SM100_ALL))

// ---------------- scratch (device globals; no allocation allowed) -------------
__device__ __align__(256) float d_qh [NTOK*Dq];
__device__ __align__(256) float d_kh [NTOK*Dq];
__device__ __align__(256) float d_vh [NTOK*Dq];
__device__ __align__(256) float d_ctx[NTOK*Dq];
__device__ __align__(256) float d_tmp[NTOK*Dq];
__device__ __align__(256) float d_x  [NTOK*Dq];
__device__ __align__(256) float d_moe[NTOK*Dq];
__device__ __align__(256) float d_gates[NTOK*Eq];

__device__ __align__(256) __nv_bfloat16 d_inhi[NTOK*Dq];   // reusable input split
__device__ __align__(256) __nv_bfloat16 d_inlo[NTOK*Dq];
__device__ __align__(256) __nv_bfloat16 d_xhi[NTOK*Dq];
__device__ __align__(256) __nv_bfloat16 d_xlo[NTOK*Dq];
__device__ __align__(256) __nv_bfloat16 d_hhi[NTOK*Fq];
__device__ __align__(256) __nv_bfloat16 d_hlo[NTOK*Fq];
__device__ __align__(256) __nv_bfloat16 d_w1t_hi[Eq*Fq*Dq]; // [E][F][D]
__device__ __align__(256) __nv_bfloat16 d_w1t_lo[Eq*Fq*Dq];
__device__ __align__(256) __nv_bfloat16 d_w2t_hi[Eq*Dq*Fq]; // [E][D][F]
__device__ __align__(256) __nv_bfloat16 d_w2t_lo[Eq*Dq*Fq];
__device__ __align__(256) __nv_bfloat16 d_wqt_hi[Dq*Dq];
__device__ __align__(256) __nv_bfloat16 d_wqt_lo[Dq*Dq];
__device__ __align__(256) __nv_bfloat16 d_wkt_hi[Dq*Dq];
__device__ __align__(256) __nv_bfloat16 d_wkt_lo[Dq*Dq];
__device__ __align__(256) __nv_bfloat16 d_wvt_hi[Dq*Dq];
__device__ __align__(256) __nv_bfloat16 d_wvt_lo[Dq*Dq];
__device__ __align__(256) __nv_bfloat16 d_wot_hi[Dq*Dq];
__device__ __align__(256) __nv_bfloat16 d_wot_lo[Dq*Dq];

// ======================= PTX helpers ==========================================
__device__ __forceinline__ uint32_t smem_u32(const void* p) {
    uint32_t a;
    asm("{ .reg .u64 t; cvta.to.shared.u64 t, %1; cvt.u32.u64 %0, t; }" : "=r"(a) : "l"(p));
    return a;
}

#if HAS_TCGEN05
__device__ __forceinline__ bool elect_one() {
    uint32_t p;
    asm volatile("{\n .reg .pred p;\n elect.sync _|p, 0xFFFFFFFF;\n selp.b32 %0,1,0,p;\n}" : "=r"(p));
    return p != 0;
}
#define MBARRIER_INIT(addr, cnt) \
    asm volatile("mbarrier.init.shared.b64 [%0], %1;" :: "r"((uint32_t)(addr)), "r"((uint32_t)(cnt)) : "memory")
#define MBARRIER_INVAL(addr) \
    asm volatile("mbarrier.inval.shared.b64 [%0];" :: "r"((uint32_t)(addr)) : "memory")
#define MBARRIER_WAIT_PARITY(mbar_smem_addr, phase_parity) do { \
    uint32_t _mbar = (uint32_t)(mbar_smem_addr); \
    uint32_t _parity = (uint32_t)(phase_parity); \
    uint32_t _done; \
    asm volatile( \
        "{\n\t.reg .pred p;\n\t" \
        "mbarrier.try_wait.parity.acquire.cta.shared::cta.b64 p, [%1], %2;\n\t" \
        "selp.b32 %0, 1, 0, p;\n\t}" \
        : "=r"(_done) : "r"(_mbar), "r"(_parity) : "memory"); \
    if (!_done) { \
        asm volatile( \
            "{\n\t.reg .pred P1;\n\t" \
            "WAIT_LOOP_%=:\n\t" \
            "mbarrier.try_wait.parity.acquire.cta.shared::cta.b64 P1, [%0], %1, 0x989680;\n\t" \
            "@P1 bra.uni WAIT_DONE_%=;\n\t" \
            "bra.uni WAIT_LOOP_%=;\n\t" \
            "WAIT_DONE_%=:\n\t}" \
            :: "r"(_mbar), "r"(_parity) : "memory"); \
    } \
} while(0)
#define TCGEN05_ALLOC(smem_result_addr, nCols) \
    asm volatile("tcgen05.alloc.cta_group::1.sync.aligned.shared::cta.b32 [%0], %1;" \
        :: "r"((uint32_t)(smem_result_addr)), "r"((uint32_t)(nCols)) : "memory")
#define TCGEN05_DEALLOC(tmem_addr, nCols) \
    asm volatile("tcgen05.dealloc.cta_group::1.sync.aligned.b32 %0, %1;" :: "r"(tmem_addr), "r"(nCols))
#define TCGEN05_RELINQ() \
    asm volatile("tcgen05.relinquish_alloc_permit.cta_group::1.sync.aligned;")
#define TCGEN05_COMMIT(mbar_smem_addr) \
    asm volatile("tcgen05.commit.cta_group::1.mbarrier::arrive::one.shared::cluster.b64 [%0];" \
        :: "r"((uint32_t)(mbar_smem_addr)) : "memory")
#define TCGEN05_FENCE_AFTER()  asm volatile("tcgen05.fence::after_thread_sync;" ::: "memory")
#define TCGEN05_FENCE_BEFORE() asm volatile("tcgen05.fence::before_thread_sync;" ::: "memory")
#define TCGEN05_WAIT_LD() asm volatile("tcgen05.wait::ld.sync.aligned;" ::: "memory")
#define FENCE_ASYNC_SHARED() asm volatile("fence.proxy.async.shared::cta;" ::: "memory")
#define CP_ASYNC16(dst, src) \
    asm volatile("cp.async.cg.shared.global [%0], [%1], 16;" :: "r"((uint32_t)(dst)), "l"(src))
#define CP_COMMIT() asm volatile("cp.async.commit_group;" ::: "memory")
#define CP_WAIT(n)  asm volatile("cp.async.wait_group %0;" :: "n"(n) : "memory")
#define TCGEN05_LD_32X32B_X32(r, tmem_addr) \
    asm volatile( \
        "tcgen05.ld.sync.aligned.32x32b.x32.b32 " \
        "{%0, %1, %2, %3, %4, %5, %6, %7, " \
        " %8, %9, %10, %11, %12, %13, %14, %15, " \
        " %16, %17, %18, %19, %20, %21, %22, %23, " \
        " %24, %25, %26, %27, %28, %29, %30, %31}, [%32];" \
        : "=r"((r)[0]),  "=r"((r)[1]),  "=r"((r)[2]),  "=r"((r)[3]), \
          "=r"((r)[4]),  "=r"((r)[5]),  "=r"((r)[6]),  "=r"((r)[7]), \
          "=r"((r)[8]),  "=r"((r)[9]),  "=r"((r)[10]), "=r"((r)[11]), \
          "=r"((r)[12]), "=r"((r)[13]), "=r"((r)[14]), "=r"((r)[15]), \
          "=r"((r)[16]), "=r"((r)[17]), "=r"((r)[18]), "=r"((r)[19]), \
          "=r"((r)[20]), "=r"((r)[21]), "=r"((r)[22]), "=r"((r)[23]), \
          "=r"((r)[24]), "=r"((r)[25]), "=r"((r)[26]), "=r"((r)[27]), \
          "=r"((r)[28]), "=r"((r)[29]), "=r"((r)[30]), "=r"((r)[31]) \
        : "r"(tmem_addr))

// SW128 K-major descriptor: layout=2, version=1, SBO=64, LBO=1
static constexpr uint64_t DESC_BASE =
    (uint64_t(2) << 61) | (uint64_t(1) << 46) | (uint64_t(64) << 32) | (uint64_t(1) << 16);
#define MK_DESC(a) (DESC_BASE | ((uint64_t)((a) >> 4) & 0x3FFF))

__device__ __forceinline__ void mma_bf16_ss(uint32_t d, uint64_t ad, uint64_t bd,
                                            uint32_t idesc, uint32_t en) {
    asm volatile(
        "{\n\t.reg .pred p;\n\tsetp.ne.u32 p, %5, 0;\n\t"
        "tcgen05.mma.cta_group::1.kind::f16 [%0], %1, %2, %3, {%4,%4,%4,%4}, p;\n\t}"
        :: "r"(d), "l"(ad), "l"(bd), "r"(idesc), "r"(0u), "r"(en) : "memory");
}
#endif // HAS_TCGEN05

// ======================= tensor-core 3xBF16 GEMM ==============================
// C[M,N] = A[M,K] @ B[N,K]^T with A=Ahi+Alo, B=Bhi+Blo (bf16 splits of fp32)
// MODE 0: gelu(acc + bias) -> split-bf16 Chi/Clo    (MoE up-proj)
// MODE 1: Cf (+)= gates[row,e] * (acc + bias)       (MoE down-proj)
// MODE 2: Cf = acc + bias                           (QKV projections)
// MODE 3: Cf = acc + bias + res                     (O-proj + residual)
#define TM 128
#define TN 256
#define TK 64
#define STAGE_BYTES 98304
#define SM_A_HI 0
#define SM_A_LO 16384
#define SM_B_HI 32768
#define SM_B_LO 65536
#define SM_DATA 1024
#define TC_SMEM (SM_DATA + 2*STAGE_BYTES)   // 197632 bytes

#if HAS_TCGEN05
static constexpr uint32_t IDESC_BF16 =
    (1u << 4) | (1u << 7) | (1u << 10) | ((TN / 8) << 17) | ((TM / 16) << 24);

__device__ __forceinline__ void load_slab_async(
    uint32_t sbase, int stage,
    const __nv_bfloat16* __restrict__ Ahi, const __nv_bfloat16* __restrict__ Alo,
    const __nv_bfloat16* __restrict__ Bhi, const __nv_bfloat16* __restrict__ Blo,
    int m0, int n0, int k0, int K)
{
    const int tid = threadIdx.x;
    const uint32_t base = sbase + SM_DATA + stage * STAGE_BYTES;
#pragma unroll
    for (int i = 0; i < 4; i++) {
        int idx = i * 256 + tid;           // 0..1023
        int row = idx >> 3, c4 = idx & 7;
        int off = row * 128 + c4 * 16;
        int sw  = off ^ ((off >> 3) & 0x70);
        size_t g = (size_t)(m0 + row) * K + k0 + c4 * 8;
        CP_ASYNC16(base + SM_A_HI + sw, Ahi + g);
        CP_ASYNC16(base + SM_A_LO + sw, Alo + g);
    }
#pragma unroll
    for (int i = 0; i < 8; i++) {
        int idx = i * 256 + tid;           // 0..2047
        int row = idx >> 3, c4 = idx & 7;
        int off = row * 128 + c4 * 16;
        int sw  = off ^ ((off >> 3) & 0x70);
        size_t g = (size_t)(n0 + row) * K + k0 + c4 * 8;
        CP_ASYNC16(base + SM_B_HI + sw, Bhi + g);
        CP_ASYNC16(base + SM_B_LO + sw, Blo + g);
    }
    CP_COMMIT();
}
#endif

template<int MODE>
__global__ void __launch_bounds__(256)
tc_gemm(const __nv_bfloat16* __restrict__ Ahi, const __nv_bfloat16* __restrict__ Alo,
        const __nv_bfloat16* __restrict__ Bhi, const __nv_bfloat16* __restrict__ Blo,
        const float* __restrict__ bias, const float* __restrict__ gates,
        const float* __restrict__ res, float* __restrict__ Cf,
        __nv_bfloat16* __restrict__ Chi, __nv_bfloat16* __restrict__ Clo,
        int M, int N, int K, int expert, int first)
{
    extern __shared__ char smx[];
#if HAS_TCGEN05
    // ---------------- tcgen05 fast path ----------------
    const uint32_t sb = smem_u32(smx);
    const int tid = threadIdx.x;
    const int wid = tid >> 5, lane = tid & 31;
    const int m0 = blockIdx.y * TM, n0 = blockIdx.x * TN;

    if (wid == 0) { TCGEN05_ALLOC(sb, 256); TCGEN05_RELINQ(); }
    if (tid == 0) { MBARRIER_INIT(sb + 8, 1); MBARRIER_INIT(sb + 16, 1); }
    __syncthreads();
    uint32_t tmem;
    asm volatile("ld.shared.b32 %0, [%1];" : "=r"(tmem) : "r"(sb));

    const int NS = K / TK;
    load_slab_async(sb, 0, Ahi, Alo, Bhi, Blo, m0, n0, 0, K);

    int ph0 = 0, ph1 = 0;
    for (int s = 0; s < NS; s++) {
        const int buf = s & 1;
        if (s + 1 < NS) {
            const int nb = 1 - buf;
            if (s >= 1) {
                if (nb == 0) { MBARRIER_WAIT_PARITY(sb + 8,  ph0); ph0 ^= 1; }
                else         { MBARRIER_WAIT_PARITY(sb + 16, ph1); ph1 ^= 1; }
            }
            load_slab_async(sb, nb, Ahi, Alo, Bhi, Blo, m0, n0, (s + 1) * TK, K);
            CP_WAIT(1);      // slab s resident
        } else {
            CP_WAIT(0);
        }
        FENCE_ASYNC_SHARED();
        __syncthreads();
        if (wid == 0) {
            TCGEN05_FENCE_AFTER();
            if (elect_one()) {
                const uint32_t tb = sb + SM_DATA + buf * STAGE_BYTES;
                const uint64_t ah = MK_DESC(tb + SM_A_HI);
                const uint64_t al = MK_DESC(tb + SM_A_LO);
                const uint64_t bh = MK_DESC(tb + SM_B_HI);
                const uint64_t bl = MK_DESC(tb + SM_B_LO);
#pragma unroll
                for (int ks = 0; ks < 4; ks++) {
                    const uint32_t en0 = (s == 0 && ks == 0) ? 0u : 1u;
                    mma_bf16_ss(tmem, ah + ks * 2, bh + ks * 2, IDESC_BF16, en0);
                    mma_bf16_ss(tmem, ah + ks * 2, bl + ks * 2, IDESC_BF16, 1u);
                    mma_bf16_ss(tmem, al + ks * 2, bh + ks * 2, IDESC_BF16, 1u);
                }
                TCGEN05_COMMIT(sb + 8 + buf * 8);
            }
        }
    }
    {
        const int lb = (NS - 1) & 1;
        if (lb == 0) { MBARRIER_WAIT_PARITY(sb + 8,  ph0); }
        else         { MBARRIER_WAIT_PARITY(sb + 16, ph1); }
    }
    TCGEN05_FENCE_AFTER();

    // ---- epilogue: lane owns one row, 32 consecutive cols -> vector stores ----
    const int sub = wid & 3;
    const int cg  = wid >> 2;
    const int row = m0 + sub * 32 + lane;
    const float gate = (MODE == 1) ? gates[(size_t)row * Eq + expert] : 0.f;
#pragma unroll
    for (int ch = 0; ch < 4; ch++) {
        const int colb = cg * 128 + ch * 32;
        uint32_t r[32];
        TCGEN05_LD_32X32B_X32(r, tmem + colb);
        TCGEN05_WAIT_LD();
        const size_t base = (size_t)row * N + n0 + colb;
        const float4* bv = (const float4*)(bias + n0 + colb);
        if (MODE == 0) {
            uint4* dh = (uint4*)(Chi + base);
            uint4* dl = (uint4*)(Clo + base);
#pragma unroll
            for (int i = 0; i < 4; i++) {      // 8 cols per iter
                uint32_t hp[4], lp[4];
#pragma unroll
                for (int p = 0; p < 4; p++) {  // pairs
                    float4 b4 = bv[i * 2 + (p >> 1)];
                    float b0 = (p & 1) ? b4.z : b4.x;
                    float b1 = (p & 1) ? b4.w : b4.y;
                    float v0 = __uint_as_float(r[i * 8 + p * 2 + 0]) + b0;
                    float v1 = __uint_as_float(r[i * 8 + p * 2 + 1]) + b1;
                    float g0 = 0.5f * v0 * (1.f + erff(v0 * 0.70710678118654752f));
                    float g1 = 0.5f * v1 * (1.f + erff(v1 * 0.70710678118654752f));
                    __nv_bfloat16 h0 = __float2bfloat16(g0);
                    __nv_bfloat16 h1 = __float2bfloat16(g1);
                    __nv_bfloat16 l0 = __float2bfloat16(g0 - __bfloat162float(h0));
                    __nv_bfloat16 l1 = __float2bfloat16(g1 - __bfloat162float(h1));
                    hp[p] = (uint32_t)__bfloat16_as_ushort(h0) |
                            ((uint32_t)__bfloat16_as_ushort(h1) << 16);
                    lp[p] = (uint32_t)__bfloat16_as_ushort(l0) |
                            ((uint32_t)__bfloat16_as_ushort(l1) << 16);
                }
                dh[i] = make_uint4(hp[0], hp[1], hp[2], hp[3]);
                dl[i] = make_uint4(lp[0], lp[1], lp[2], lp[3]);
            }
        } else {
            float4* dst = (float4*)(Cf + base);
            const float4* rv = (MODE == 3) ? (const float4*)(res + base) : nullptr;
#pragma unroll
            for (int i = 0; i < 8; i++) {      // 4 cols per iter
                float4 b4 = bv[i];
                float4 o;
                o.x = __uint_as_float(r[i * 4 + 0]) + b4.x;
                o.y = __uint_as_float(r[i * 4 + 1]) + b4.y;
                o.z = __uint_as_float(r[i * 4 + 2]) + b4.z;
                o.w = __uint_as_float(r[i * 4 + 3]) + b4.w;
                if (MODE == 1) {
                    o.x *= gate; o.y *= gate; o.z *= gate; o.w *= gate;
                    if (!first) {
                        float4 t = dst[i];
                        o.x += t.x; o.y += t.y; o.z += t.z; o.w += t.w;
                    }
                } else if (MODE == 3) {
                    float4 t = rv[i];
                    o.x += t.x; o.y += t.y; o.z += t.z; o.w += t.w;
                }
                dst[i] = o;
            }
        }
    }
    TCGEN05_FENCE_BEFORE();
    __syncthreads();
    if (tid == 0) { MBARRIER_INVAL(sb + 8); MBARRIER_INVAL(sb + 16); }
    __syncthreads();
    if (wid == 0) TCGEN05_DEALLOC(tmem, 256);
#else
    // ---------------- correct SIMT fallback (compute_103 pass) ----------------
    float* As = (float*)smx;            // [16][128]
    float* Bs = As + 16 * 128;          // [16][128]
    const int tid = threadIdx.x;
    const int m0 = blockIdx.y * TM, n0x = blockIdx.x * TN;
    const int tx = tid & 15, ty = tid >> 4;
    const int mr = ty * 8, nr = tx * 8;

    for (int half = 0; half < TN / 128; half++) {
        const int n0 = n0x + half * 128;
        float acc[8][8];
#pragma unroll
        for (int i = 0; i < 8; i++)
#pragma unroll
            for (int j = 0; j < 8; j++) acc[i][j] = 0.f;
        for (int k0 = 0; k0 < K; k0 += 16) {
            __syncthreads();
#pragma unroll
            for (int i = 0; i < 8; i++) {
                int idx = i * 256 + tid;
                int kk = idx >> 7, mm = idx & 127;
                size_t ga = (size_t)(m0 + mm) * K + k0 + kk;
                size_t gb = (size_t)(n0 + mm) * K + k0 + kk;
                As[kk * 128 + mm] = __bfloat162float(Ahi[ga]) + __bfloat162float(Alo[ga]);
                Bs[kk * 128 + mm] = __bfloat162float(Bhi[gb]) + __bfloat162float(Blo[gb]);
            }
            __syncthreads();
#pragma unroll
            for (int kk = 0; kk < 16; kk++) {
                float a0[8], b0[8];
#pragma unroll
                for (int i = 0; i < 8; i++) a0[i] = As[kk * 128 + mr + i];
#pragma unroll
                for (int j = 0; j < 8; j++) b0[j] = Bs[kk * 128 + nr + j];
#pragma unroll
                for (int i = 0; i < 8; i++)
#pragma unroll
                    for (int j = 0; j < 8; j++)
                        acc[i][j] = fmaf(a0[i], b0[j], acc[i][j]);
            }
        }
#pragma unroll
        for (int i = 0; i < 8; i++) {
            const int row = m0 + mr + i;
#pragma unroll
            for (int j = 0; j < 8; j++) {
                const int col = n0 + nr + j;
                const size_t idx = (size_t)row * N + col;
                float v = acc[i][j] + bias[col];
                if (MODE == 0) {
                    float g = 0.5f * v * (1.f + erff(v * 0.70710678118654752f));
                    __nv_bfloat16 h = __float2bfloat16(g);
                    Chi[idx] = h;
                    Clo[idx] = __float2bfloat16(g - __bfloat162float(h));
                } else if (MODE == 1) {
                    const float gate = gates[(size_t)row * Eq + expert];
                    float o = gate * v;
                    if (first) Cf[idx] = o;
                    else       Cf[idx] += o;
                } else if (MODE == 2) {
                    Cf[idx] = v;
                } else {
                    Cf[idx] = v + res[idx];
                }
            }
        }
    }
#endif
}

// ---------------- transpose + bf16 split: W[e][K][N] -> T[e][N][K] -------------
__global__ void __launch_bounds__(256)
transpose_split(const float* __restrict__ W, __nv_bfloat16* __restrict__ Thi,
                __nv_bfloat16* __restrict__ Tlo, int K, int N)
{
    __shared__ float t[32][33];
    const int e = blockIdx.z;
    const float* Wp = W + (size_t)e * K * N;
    __nv_bfloat16* th = Thi + (size_t)e * K * N;
    __nv_bfloat16* tl = Tlo + (size_t)e * K * N;
    const int k0 = blockIdx.x * 32, n0 = blockIdx.y * 32;
    const int x = threadIdx.x & 31, y = threadIdx.x >> 5;
#pragma unroll
    for (int i = 0; i < 32; i += 8)
        t[y + i][x] = Wp[(size_t)(k0 + y + i) * N + n0 + x];
    __syncthreads();
#pragma unroll
    for (int i = 0; i < 32; i += 8) {
        float v = t[x][y + i];
        __nv_bfloat16 h = __float2bfloat16(v);
        float lo = v - __bfloat162float(h);
        const size_t idx = (size_t)(n0 + y + i) * K + k0 + x;
        th[idx] = h;
        tl[idx] = __float2bfloat16(lo);
    }
}

// ---------------- fp32 -> split bf16 (hi/lo), vectorized ------------------------
__global__ void __launch_bounds__(256)
split_bf16(const float* __restrict__ x, __nv_bfloat16* __restrict__ hi,
           __nv_bfloat16* __restrict__ lo, int n4)
{
    int i = blockIdx.x * 256 + threadIdx.x;
    if (i >= n4) return;
    float4 v = ((const float4*)x)[i];
    __nv_bfloat16 h0 = __float2bfloat16(v.x), h1 = __float2bfloat16(v.y);
    __nv_bfloat16 h2 = __float2bfloat16(v.z), h3 = __float2bfloat16(v.w);
    uint2 hp, lp;
    hp.x = (uint32_t)__bfloat16_as_ushort(h0) | ((uint32_t)__bfloat16_as_ushort(h1) << 16);
    hp.y = (uint32_t)__bfloat16_as_ushort(h2) | ((uint32_t)__bfloat16_as_ushort(h3) << 16);
    __nv_bfloat16 l0 = __float2bfloat16(v.x - __bfloat162float(h0));
    __nv_bfloat16 l1 = __float2bfloat16(v.y - __bfloat162float(h1));
    __nv_bfloat16 l2 = __float2bfloat16(v.z - __bfloat162float(h2));
    __nv_bfloat16 l3 = __float2bfloat16(v.w - __bfloat162float(h3));
    lp.x = (uint32_t)__bfloat16_as_ushort(l0) | ((uint32_t)__bfloat16_as_ushort(l1) << 16);
    lp.y = (uint32_t)__bfloat16_as_ushort(l2) | ((uint32_t)__bfloat16_as_ushort(l3) << 16);
    ((uint2*)hi)[i] = hp;
    ((uint2*)lo)[i] = lp;
}

// ---------------- attention ----------------------------------------------------
#define KPAD 65
__global__ void __launch_bounds__(256)
attn_kernel(const float* __restrict__ qh, const float* __restrict__ kh,
            const float* __restrict__ vh, float* __restrict__ ctx)
{
    const int b = blockIdx.x / Hq;
    const int h = blockIdx.x % Hq;
    extern __shared__ float sm[];
    float* Ks = sm;
    float* Vs = Ks + Sq * KPAD;
    float* Ps = Vs + Sq * DHq;
    float* Qs = Ps + 8 * 208;
    const int tid = threadIdx.x;
    for (int i = tid; i < Sq * DHq; i += 256) {
        int s = i / DHq, d = i % DHq;
        size_t gidx = (size_t)(b * Sq + s) * Dq + h * DHq + d;
        Ks[s * KPAD + d] = kh[gidx];
        Vs[s * DHq  + d] = vh[gidx];
    }
    __syncthreads();
    const int warp = tid >> 5, lane = tid & 31;
    float* p    = Ps + warp * 208;
    float* qrow = Qs + warp * DHq;
    for (int q = warp; q < Sq; q += 8) {
        for (int d = lane; d < DHq; d += 32)
            qrow[d] = qh[(size_t)(b * Sq + q) * Dq + h * DHq + d];
        __syncwarp();
        float lmax = -1e30f;
        for (int col = lane; col < Sq; col += 32) {
            float s = 0.f;
            const float* kr = Ks + col * KPAD;
#pragma unroll 16
            for (int d = 0; d < DHq; d++) s = fmaf(qrow[d], kr[d], s);
            s *= 0.125f;
            p[col] = s;
            lmax = fmaxf(lmax, s);
        }
#pragma unroll
        for (int o = 16; o; o >>= 1) lmax = fmaxf(lmax, __shfl_xor_sync(0xffffffffu, lmax, o));
        float lsum = 0.f;
        for (int col = lane; col < Sq; col += 32) {
            float e = expf(p[col] - lmax);
            p[col] = e;
            lsum += e;
        }
#pragma unroll
        for (int o = 16; o; o >>= 1) lsum += __shfl_xor_sync(0xffffffffu, lsum, o);
        const float inv = 1.f / lsum;
        __syncwarp();
        for (int d = lane; d < DHq; d += 32) {
            float a = 0.f;
            for (int k = 0; k < Sq; k++) a = fmaf(p[k], Vs[k * DHq + d], a);
            ctx[(size_t)(b * Sq + q) * Dq + h * DHq + d] = a * inv;
        }
        __syncwarp();
    }
}

// ---------------- gate softmax --------------------------------------------------
__global__ void __launch_bounds__(256)
gate_kernel(const float* __restrict__ x, const float* __restrict__ Wg,
            const float* __restrict__ bg, float* __restrict__ gates)
{
    const int warp = (blockIdx.x * 256 + threadIdx.x) >> 5;
    const int lane = threadIdx.x & 31;
    if (warp >= NTOK) return;
    const float* xr = x + (size_t)warp * Dq;
    float lg[Eq];
#pragma unroll
    for (int e = 0; e < Eq; e++) lg[e] = 0.f;
    for (int d = lane; d < Dq; d += 32) {
        float xv = xr[d];
#pragma unroll
        for (int e = 0; e < Eq; e++) lg[e] = fmaf(xv, Wg[d * Eq + e], lg[e]);
    }
#pragma unroll
    for (int e = 0; e < Eq; e++)
#pragma unroll
        for (int o = 16; o; o >>= 1) lg[e] += __shfl_xor_sync(0xffffffffu, lg[e], o);
    if (lane == 0) {
        float m = -1e30f;
#pragma unroll
        for (int e = 0; e < Eq; e++) { lg[e] += bg[e]; m = fmaxf(m, lg[e]); }
        float s = 0.f;
#pragma unroll
        for (int e = 0; e < Eq; e++) { lg[e] = expf(lg[e] - m); s += lg[e]; }
        float inv = 1.f / s;
#pragma unroll
        for (int e = 0; e < Eq; e++) gates[(size_t)warp * Eq + e] = lg[e] * inv;
    }
}

// ---------------- layernorm (+ optional split-bf16 output) ----------------------
__global__ void __launch_bounds__(256)
ln_kernel(const float* __restrict__ a, const float* __restrict__ b,
          const float* __restrict__ g, const float* __restrict__ be,
          float* __restrict__ out, __nv_bfloat16* __restrict__ ohi,
          __nv_bfloat16* __restrict__ olo)
{
    const int row = blockIdx.x;
    const float* ar = a + (size_t)row * Dq;
    const float* br = b ? b + (size_t)row * Dq : nullptr;
    float v[3];
    float s = 0.f, s2 = 0.f;
#pragma unroll
    for (int i = 0; i < 3; i++) {
        int d = threadIdx.x + i * 256;
        float x = ar[d];
        if (br) x += br[d];
        v[i] = x;
        s += x; s2 = fmaf(x, x, s2);
    }
    __shared__ float rs[8], rs2[8];
#pragma unroll
    for (int o = 16; o; o >>= 1) { s += __shfl_xor_sync(0xffffffffu, s, o); s2 += __shfl_xor_sync(0xffffffffu, s2, o); }
    const int warp = threadIdx.x >> 5, lane = threadIdx.x & 31;
    if (lane == 0) { rs[warp] = s; rs2[warp] = s2; }
    __syncthreads();
    if (warp == 0) {
        float t  = (lane < 8) ? rs[lane]  : 0.f;
        float t2 = (lane < 8) ? rs2[lane] : 0.f;
#pragma unroll
        for (int o = 4; o; o >>= 1) { t += __shfl_xor_sync(0xffffffffu, t, o); t2 += __shfl_xor_sync(0xffffffffu, t2, o); }
        if (lane == 0) { rs[0] = t; rs2[0] = t2; }
    }
    __syncthreads();
    const float mu  = rs[0] * (1.f / Dq);
    const float var = rs2[0] * (1.f / Dq) - mu * mu;
    const float inv = rsqrtf(var + 1e-5f);
#pragma unroll
    for (int i = 0; i < 3; i++) {
        int d = threadIdx.x + i * 256;
        float y = (v[i] - mu) * inv * g[d] + be[d];
        const size_t idx = (size_t)row * Dq + d;
        out[idx] = y;
        if (ohi) {
            __nv_bfloat16 h = __float2bfloat16(y);
            ohi[idx] = h;
            olo[idx] = __float2bfloat16(y - __bfloat162float(h));
        }
    }
}

// =================================================================================
extern "C" void kernel_launch(void* const* d_in, const int* in_sizes, int n_in,
                              void* d_out, int out_size)
{
    const float* q   = (const float*)d_in[0];
    const float* k   = (const float*)d_in[1];
    const float* v   = (const float*)d_in[2];
    const float* Wq  = (const float*)d_in[3];
    const float* bq  = (const float*)d_in[4];
    const float* Wk  = (const float*)d_in[5];
    const float* bk  = (const float*)d_in[6];
    const float* Wv  = (const float*)d_in[7];
    const float* bv  = (const float*)d_in[8];
    const float* Wo  = (const float*)d_in[9];
    const float* bo  = (const float*)d_in[10];
    const float* ln1g= (const float*)d_in[11];
    const float* ln1b= (const float*)d_in[12];
    const float* ln2g= (const float*)d_in[13];
    const float* ln2b= (const float*)d_in[14];
    const float* Wg  = (const float*)d_in[15];
    const float* bg  = (const float*)d_in[16];
    const float* W1  = (const float*)d_in[17];
    const float* b1  = (const float*)d_in[18];
    const float* W2  = (const float*)d_in[19];
    const float* b2  = (const float*)d_in[20];
    float* out = (float*)d_out;

    float *p_qh, *p_kh, *p_vh, *p_ctx, *p_tmp, *p_x, *p_moe, *p_gates;
    __nv_bfloat16 *p_inhi, *p_inlo, *p_xhi, *p_xlo, *p_hhi, *p_hlo;
    __nv_bfloat16 *p_w1h, *p_w1l, *p_w2h, *p_w2l;
    __nv_bfloat16 *p_wqh, *p_wql, *p_wkh, *p_wkl, *p_wvh, *p_wvl, *p_woh, *p_wol;
    cudaGetSymbolAddress((void**)&p_qh,   d_qh);
    cudaGetSymbolAddress((void**)&p_kh,   d_kh);
    cudaGetSymbolAddress((void**)&p_vh,   d_vh);
    cudaGetSymbolAddress((void**)&p_ctx,  d_ctx);
    cudaGetSymbolAddress((void**)&p_tmp,  d_tmp);
    cudaGetSymbolAddress((void**)&p_x,    d_x);
    cudaGetSymbolAddress((void**)&p_moe,  d_moe);
    cudaGetSymbolAddress((void**)&p_gates,d_gates);
    cudaGetSymbolAddress((void**)&p_inhi, d_inhi);
    cudaGetSymbolAddress((void**)&p_inlo, d_inlo);
    cudaGetSymbolAddress((void**)&p_xhi,  d_xhi);
    cudaGetSymbolAddress((void**)&p_xlo,  d_xlo);
    cudaGetSymbolAddress((void**)&p_hhi,  d_hhi);
    cudaGetSymbolAddress((void**)&p_hlo,  d_hlo);
    cudaGetSymbolAddress((void**)&p_w1h,  d_w1t_hi);
    cudaGetSymbolAddress((void**)&p_w1l,  d_w1t_lo);
    cudaGetSymbolAddress((void**)&p_w2h,  d_w2t_hi);
    cudaGetSymbolAddress((void**)&p_w2l,  d_w2t_lo);
    cudaGetSymbolAddress((void**)&p_wqh,  d_wqt_hi);
    cudaGetSymbolAddress((void**)&p_wql,  d_wqt_lo);
    cudaGetSymbolAddress((void**)&p_wkh,  d_wkt_hi);
    cudaGetSymbolAddress((void**)&p_wkl,  d_wkt_lo);
    cudaGetSymbolAddress((void**)&p_wvh,  d_wvt_hi);
    cudaGetSymbolAddress((void**)&p_wvl,  d_wvt_lo);
    cudaGetSymbolAddress((void**)&p_woh,  d_wot_hi);
    cudaGetSymbolAddress((void**)&p_wol,  d_wot_lo);

    const dim3 blk(256);
    const dim3 gridD(Dq / TN, NTOK / TM);   // (3, 49)
    const dim3 gridF(Fq / TN, NTOK / TM);   // (12, 49)
    const int n4 = NTOK * Dq / 4;
    const int sgrid = (n4 + 255) / 256;

    cudaFuncSetAttribute(tc_gemm<0>, cudaFuncAttributeMaxDynamicSharedMemorySize, TC_SMEM);
    cudaFuncSetAttribute(tc_gemm<1>, cudaFuncAttributeMaxDynamicSharedMemorySize, TC_SMEM);
    cudaFuncSetAttribute(tc_gemm<2>, cudaFuncAttributeMaxDynamicSharedMemorySize, TC_SMEM);
    cudaFuncSetAttribute(tc_gemm<3>, cudaFuncAttributeMaxDynamicSharedMemorySize, TC_SMEM);

    // weight transpose + bf16 split
    transpose_split<<<dim3(Dq/32, Dq/32, 1), blk>>>(Wq, p_wqh, p_wql, Dq, Dq);
    transpose_split<<<dim3(Dq/32, Dq/32, 1), blk>>>(Wk, p_wkh, p_wkl, Dq, Dq);
    transpose_split<<<dim3(Dq/32, Dq/32, 1), blk>>>(Wv, p_wvh, p_wvl, Dq, Dq);
    transpose_split<<<dim3(Dq/32, Dq/32, 1), blk>>>(Wo, p_woh, p_wol, Dq, Dq);
    transpose_split<<<dim3(Dq/32, Fq/32, Eq), blk>>>(W1, p_w1h, p_w1l, Dq, Fq);
    transpose_split<<<dim3(Fq/32, Dq/32, Eq), blk>>>(W2, p_w2h, p_w2l, Fq, Dq);

    // QKV projections on tensor cores
    split_bf16<<<sgrid, blk>>>(q, p_inhi, p_inlo, n4);
    tc_gemm<2><<<gridD, blk, TC_SMEM>>>(p_inhi, p_inlo, p_wqh, p_wql, bq,
                                        nullptr, nullptr, p_qh, nullptr, nullptr,
                                        NTOK, Dq, Dq, 0, 0);
    split_bf16<<<sgrid, blk>>>(k, p_inhi, p_inlo, n4);
    tc_gemm<2><<<gridD, blk, TC_SMEM>>>(p_inhi, p_inlo, p_wkh, p_wkl, bk,
                                        nullptr, nullptr, p_kh, nullptr, nullptr,
                                        NTOK, Dq, Dq, 0, 0);
    split_bf16<<<sgrid, blk>>>(v, p_inhi, p_inlo, n4);
    tc_gemm<2><<<gridD, blk, TC_SMEM>>>(p_inhi, p_inlo, p_wvh, p_wvl, bv,
                                        nullptr, nullptr, p_vh, nullptr, nullptr,
                                        NTOK, Dq, Dq, 0, 0);

    // attention
    const int smem_attn = (Sq * KPAD + Sq * DHq + 8 * 208 + 8 * DHq) * (int)sizeof(float);
    cudaFuncSetAttribute(attn_kernel, cudaFuncAttributeMaxDynamicSharedMemorySize, smem_attn);
    attn_kernel<<<Bq * Hq, blk, smem_attn>>>(p_qh, p_kh, p_vh, p_ctx);

    // O projection + residual(q), then LN1 (emits split-bf16 x)
    split_bf16<<<sgrid, blk>>>(p_ctx, p_inhi, p_inlo, n4);
    tc_gemm<3><<<gridD, blk, TC_SMEM>>>(p_inhi, p_inlo, p_woh, p_wol, bo,
                                        nullptr, q, p_tmp, nullptr, nullptr,
                                        NTOK, Dq, Dq, 0, 0);
    ln_kernel<<<NTOK, blk>>>(p_tmp, nullptr, ln1g, ln1b, p_x, p_xhi, p_xlo);

    // gate softmax
    gate_kernel<<<(NTOK * 32 + 255) / 256, blk>>>(p_x, Wg, bg, p_gates);

    // MoE experts on tensor cores (3x-bf16 compensated)
    for (int e = 0; e < Eq; e++) {
        tc_gemm<0><<<gridF, blk, TC_SMEM>>>(
            p_xhi, p_xlo,
            p_w1h + (size_t)e * Fq * Dq, p_w1l + (size_t)e * Fq * Dq,
            b1 + (size_t)e * Fq, nullptr, nullptr, nullptr, p_hhi, p_hlo,
            NTOK, Fq, Dq, e, 0);
        tc_gemm<1><<<gridD, blk, TC_SMEM>>>(
            p_hhi, p_hlo,
            p_w2h + (size_t)e * Dq * Fq, p_w2l + (size_t)e * Dq * Fq,
            b2 + (size_t)e * Dq, p_gates, nullptr, p_moe, nullptr, nullptr,
            NTOK, Dq, Fq, e, e == 0);
    }

    // residual + LN2 -> output
    ln_kernel<<<NTOK, blk>>>(p_x, p_moe, ln2g, ln2b, out, nullptr, nullptr);
}

// round 5
// speedup vs baseline: 4.7071x; 1.0890x over previous
#include <cuda_runtime.h>
#include <cuda_bf16.h>
#include <math.h>
#include <stdint.h>

#define Bq 32
#define Sq 196
#define Dq 768
#define Hq 12
#define Eq 8
#define Fq 3072
#define DHq 64
#define NTOK (Bq*Sq)   // 6272
#define MPAD 6400      // NTOK padded to multiple of 256

#define HAS_TCGEN05 (defined(__CUDA_ARCH_FEAT_SM103_ALL) || defined(__CUDA_ARCH_FEAT_SM100_ALL))

// ---------------- scratch (device globals; no allocation allowed) -------------
__device__ __align__(256) float d_qh [NTOK*Dq];
__device__ __align__(256) float d_kh [NTOK*Dq];
__device__ __align__(256) float d_vh [NTOK*Dq];
__device__ __align__(256) float d_ctx[NTOK*Dq];
__device__ __align__(256) float d_tmp[NTOK*Dq];
__device__ __align__(256) float d_x  [NTOK*Dq];
__device__ __align__(256) float d_y  [Eq*MPAD*Dq];      // per-expert FFN outputs
__device__ __align__(256) float d_gates[MPAD*Eq];

__device__ __align__(256) __nv_bfloat16 d_inhi[NTOK*Dq];
__device__ __align__(256) __nv_bfloat16 d_inlo[NTOK*Dq];
__device__ __align__(256) __nv_bfloat16 d_xhi[MPAD*Dq];
__device__ __align__(256) __nv_bfloat16 d_xlo[MPAD*Dq];
__device__ __align__(256) __nv_bfloat16 d_hhi[Eq*MPAD*Fq];
__device__ __align__(256) __nv_bfloat16 d_hlo[Eq*MPAD*Fq];
__device__ __align__(256) __nv_bfloat16 d_w1t_hi[Eq*Fq*Dq]; // [E][F][D]
__device__ __align__(256) __nv_bfloat16 d_w1t_lo[Eq*Fq*Dq];
__device__ __align__(256) __nv_bfloat16 d_w2t_hi[Eq*Dq*Fq]; // [E][D][F]
__device__ __align__(256) __nv_bfloat16 d_w2t_lo[Eq*Dq*Fq];
__device__ __align__(256) __nv_bfloat16 d_wqt_hi[Dq*Dq];
__device__ __align__(256) __nv_bfloat16 d_wqt_lo[Dq*Dq];
__device__ __align__(256) __nv_bfloat16 d_wkt_hi[Dq*Dq];
__device__ __align__(256) __nv_bfloat16 d_wkt_lo[Dq*Dq];
__device__ __align__(256) __nv_bfloat16 d_wvt_hi[Dq*Dq];
__device__ __align__(256) __nv_bfloat16 d_wvt_lo[Dq*Dq];
__device__ __align__(256) __nv_bfloat16 d_wot_hi[Dq*Dq];
__device__ __align__(256) __nv_bfloat16 d_wot_lo[Dq*Dq];

// ======================= PTX helpers ==========================================
__device__ __forceinline__ uint32_t smem_u32(const void* p) {
    uint32_t a;
    asm("{ .reg .u64 t; cvta.to.shared.u64 t, %1; cvt.u32.u64 %0, t; }" : "=r"(a) : "l"(p));
    return a;
}

#if HAS_TCGEN05
__device__ __forceinline__ bool elect_one() {
    uint32_t p;
    asm volatile("{\n .reg .pred p;\n elect.sync _|p, 0xFFFFFFFF;\n selp.b32 %0,1,0,p;\n}" : "=r"(p));
    return p != 0;
}
#define MBARRIER_INIT(addr, cnt) \
    asm volatile("mbarrier.init.shared.b64 [%0], %1;" :: "r"((uint32_t)(addr)), "r"((uint32_t)(cnt)) : "memory")
#define MBARRIER_INVAL(addr) \
    asm volatile("mbarrier.inval.shared.b64 [%0];" :: "r"((uint32_t)(addr)) : "memory")
#define MBARRIER_WAIT_PARITY(mbar_smem_addr, phase_parity) do { \
    uint32_t _mbar = (uint32_t)(mbar_smem_addr); \
    uint32_t _parity = (uint32_t)(phase_parity); \
    uint32_t _done; \
    asm volatile( \
        "{\n\t.reg .pred p;\n\t" \
        "mbarrier.try_wait.parity.acquire.cta.shared::cta.b64 p, [%1], %2;\n\t" \
        "selp.b32 %0, 1, 0, p;\n\t}" \
        : "=r"(_done) : "r"(_mbar), "r"(_parity) : "memory"); \
    if (!_done) { \
        asm volatile( \
            "{\n\t.reg .pred P1;\n\t" \
            "WAIT_LOOP_%=:\n\t" \
            "mbarrier.try_wait.parity.acquire.cta.shared::cta.b64 P1, [%0], %1, 0x989680;\n\t" \
            "@P1 bra.uni WAIT_DONE_%=;\n\t" \
            "bra.uni WAIT_LOOP_%=;\n\t" \
            "WAIT_DONE_%=:\n\t}" \
            :: "r"(_mbar), "r"(_parity) : "memory"); \
    } \
} while(0)
#define TCGEN05_ALLOC(smem_result_addr, nCols) \
    asm volatile("tcgen05.alloc.cta_group::1.sync.aligned.shared::cta.b32 [%0], %1;" \
        :: "r"((uint32_t)(smem_result_addr)), "r"((uint32_t)(nCols)) : "memory")
#define TCGEN05_DEALLOC(tmem_addr, nCols) \
    asm volatile("tcgen05.dealloc.cta_group::1.sync.aligned.b32 %0, %1;" :: "r"(tmem_addr), "r"(nCols))
#define TCGEN05_RELINQ() \
    asm volatile("tcgen05.relinquish_alloc_permit.cta_group::1.sync.aligned;")
#define TCGEN05_COMMIT(mbar_smem_addr) \
    asm volatile("tcgen05.commit.cta_group::1.mbarrier::arrive::one.shared::cluster.b64 [%0];" \
        :: "r"((uint32_t)(mbar_smem_addr)) : "memory")
#define TCGEN05_FENCE_AFTER()  asm volatile("tcgen05.fence::after_thread_sync;" ::: "memory")
#define TCGEN05_FENCE_BEFORE() asm volatile("tcgen05.fence::before_thread_sync;" ::: "memory")
#define TCGEN05_WAIT_LD() asm volatile("tcgen05.wait::ld.sync.aligned;" ::: "memory")
#define FENCE_ASYNC_SHARED() asm volatile("fence.proxy.async.shared::cta;" ::: "memory")
#define CP_ASYNC16(dst, src) \
    asm volatile("cp.async.cg.shared.global [%0], [%1], 16;" :: "r"((uint32_t)(dst)), "l"(src))
#define CP_COMMIT() asm volatile("cp.async.commit_group;" ::: "memory")
#define CP_WAIT(n)  asm volatile("cp.async.wait_group %0;" :: "n"(n) : "memory")
#define TCGEN05_LD_32X32B_X32(r, tmem_addr) \
    asm volatile( \
        "tcgen05.ld.sync.aligned.32x32b.x32.b32 " \
        "{%0, %1, %2, %3, %4, %5, %6, %7, " \
        " %8, %9, %10, %11, %12, %13, %14, %15, " \
        " %16, %17, %18, %19, %20, %21, %22, %23, " \
        " %24, %25, %26, %27, %28, %29, %30, %31}, [%32];" \
        : "=r"((r)[0]),  "=r"((r)[1]),  "=r"((r)[2]),  "=r"((r)[3]), \
          "=r"((r)[4]),  "=r"((r)[5]),  "=r"((r)[6]),  "=r"((r)[7]), \
          "=r"((r)[8]),  "=r"((r)[9]),  "=r"((r)[10]), "=r"((r)[11]), \
          "=r"((r)[12]), "=r"((r)[13]), "=r"((r)[14]), "=r"((r)[15]), \
          "=r"((r)[16]), "=r"((r)[17]), "=r"((r)[18]), "=r"((r)[19]), \
          "=r"((r)[20]), "=r"((r)[21]), "=r"((r)[22]), "=r"((r)[23]), \
          "=r"((r)[24]), "=r"((r)[25]), "=r"((r)[26]), "=r"((r)[27]), \
          "=r"((r)[28]), "=r"((r)[29]), "=r"((r)[30]), "=r"((r)[31]) \
        : "r"(tmem_addr))

// K-major SW128 descriptor (128B rows): layout=2, version=1, SBO=64, LBO=1
static constexpr uint64_t DESC_SW128 =
    (uint64_t(2) << 61) | (uint64_t(1) << 46) | (uint64_t(64) << 32) | (uint64_t(1) << 16);
// K-major SW64 descriptor (64B rows): layout=4, version=1, SBO=32, LBO=1
static constexpr uint64_t DESC_SW64 =
    (uint64_t(4) << 61) | (uint64_t(1) << 46) | (uint64_t(32) << 32) | (uint64_t(1) << 16);
#define MKD128(a) (DESC_SW128 | ((uint64_t)((a) >> 4) & 0x3FFF))
#define MKD64(a)  (DESC_SW64  | ((uint64_t)((a) >> 4) & 0x3FFF))

__device__ __forceinline__ void mma_bf16_ss(uint32_t d, uint64_t ad, uint64_t bd,
                                            uint32_t idesc, uint32_t en) {
    asm volatile(
        "{\n\t.reg .pred p;\n\tsetp.ne.u32 p, %5, 0;\n\t"
        "tcgen05.mma.cta_group::1.kind::f16 [%0], %1, %2, %3, {%4,%4,%4,%4}, p;\n\t}"
        :: "r"(d), "l"(ad), "l"(bd), "r"(idesc), "r"(0u), "r"(en) : "memory");
}
#endif // HAS_TCGEN05

// ======================= TM128 tc GEMM (QKV / O-proj) =========================
// MODE 2: Cf = acc + bias        MODE 3: Cf = acc + bias + res
#define TM 128
#define TN 256
#define TK 64
#define STAGE_BYTES 98304
#define SM_A_HI 0
#define SM_A_LO 16384
#define SM_B_HI 32768
#define SM_B_LO 65536
#define SM_DATA 1024
#define TC_SMEM (SM_DATA + 2*STAGE_BYTES)

#if HAS_TCGEN05
static constexpr uint32_t IDESC_BF16 =
    (1u << 4) | (1u << 7) | (1u << 10) | ((256 / 8) << 17) | ((128 / 16) << 24);

__device__ __forceinline__ void load_slab128(
    uint32_t sbase, int stage,
    const __nv_bfloat16* __restrict__ Ahi, const __nv_bfloat16* __restrict__ Alo,
    const __nv_bfloat16* __restrict__ Bhi, const __nv_bfloat16* __restrict__ Blo,
    int m0, int n0, int k0, int K)
{
    const int tid = threadIdx.x;
    const uint32_t base = sbase + SM_DATA + stage * STAGE_BYTES;
#pragma unroll
    for (int i = 0; i < 4; i++) {
        int idx = i * 256 + tid;
        int row = idx >> 3, c4 = idx & 7;
        int off = row * 128 + c4 * 16;
        int sw  = off ^ ((off >> 3) & 0x70);
        size_t g = (size_t)(m0 + row) * K + k0 + c4 * 8;
        CP_ASYNC16(base + SM_A_HI + sw, Ahi + g);
        CP_ASYNC16(base + SM_A_LO + sw, Alo + g);
    }
#pragma unroll
    for (int i = 0; i < 8; i++) {
        int idx = i * 256 + tid;
        int row = idx >> 3, c4 = idx & 7;
        int off = row * 128 + c4 * 16;
        int sw  = off ^ ((off >> 3) & 0x70);
        size_t g = (size_t)(n0 + row) * K + k0 + c4 * 8;
        CP_ASYNC16(base + SM_B_HI + sw, Bhi + g);
        CP_ASYNC16(base + SM_B_LO + sw, Blo + g);
    }
    CP_COMMIT();
}
#endif

template<int MODE>
__global__ void __launch_bounds__(256)
tc_gemm(const __nv_bfloat16* __restrict__ Ahi, const __nv_bfloat16* __restrict__ Alo,
        const __nv_bfloat16* __restrict__ Bhi, const __nv_bfloat16* __restrict__ Blo,
        const float* __restrict__ bias, const float* __restrict__ res,
        float* __restrict__ Cf, int M, int N, int K)
{
    extern __shared__ char smx[];
#if HAS_TCGEN05
    const uint32_t sb = smem_u32(smx);
    const int tid = threadIdx.x;
    const int wid = tid >> 5, lane = tid & 31;
    const int m0 = blockIdx.y * TM, n0 = blockIdx.x * TN;

    if (wid == 0) { TCGEN05_ALLOC(sb, 256); TCGEN05_RELINQ(); }
    if (tid == 0) { MBARRIER_INIT(sb + 8, 1); MBARRIER_INIT(sb + 16, 1); }
    __syncthreads();
    uint32_t tmem;
    asm volatile("ld.shared.b32 %0, [%1];" : "=r"(tmem) : "r"(sb));

    const int NS = K / TK;
    load_slab128(sb, 0, Ahi, Alo, Bhi, Blo, m0, n0, 0, K);

    int ph0 = 0, ph1 = 0;
    for (int s = 0; s < NS; s++) {
        const int buf = s & 1;
        if (s + 1 < NS) {
            const int nb = 1 - buf;
            if (s >= 1) {
                if (nb == 0) { MBARRIER_WAIT_PARITY(sb + 8,  ph0); ph0 ^= 1; }
                else         { MBARRIER_WAIT_PARITY(sb + 16, ph1); ph1 ^= 1; }
            }
            load_slab128(sb, nb, Ahi, Alo, Bhi, Blo, m0, n0, (s + 1) * TK, K);
            CP_WAIT(1);
        } else {
            CP_WAIT(0);
        }
        FENCE_ASYNC_SHARED();
        __syncthreads();
        if (wid == 0) {
            TCGEN05_FENCE_AFTER();
            if (elect_one()) {
                const uint32_t tb = sb + SM_DATA + buf * STAGE_BYTES;
                const uint64_t ah = MKD128(tb + SM_A_HI);
                const uint64_t al = MKD128(tb + SM_A_LO);
                const uint64_t bh = MKD128(tb + SM_B_HI);
                const uint64_t bl = MKD128(tb + SM_B_LO);
#pragma unroll
                for (int ks = 0; ks < 4; ks++) {
                    const uint32_t en0 = (s == 0 && ks == 0) ? 0u : 1u;
                    mma_bf16_ss(tmem, ah + ks * 2, bh + ks * 2, IDESC_BF16, en0);
                    mma_bf16_ss(tmem, ah + ks * 2, bl + ks * 2, IDESC_BF16, 1u);
                    mma_bf16_ss(tmem, al + ks * 2, bh + ks * 2, IDESC_BF16, 1u);
                }
                TCGEN05_COMMIT(sb + 8 + buf * 8);
            }
        }
    }
    {
        const int lb = (NS - 1) & 1;
        if (lb == 0) { MBARRIER_WAIT_PARITY(sb + 8,  ph0); }
        else         { MBARRIER_WAIT_PARITY(sb + 16, ph1); }
    }
    TCGEN05_FENCE_AFTER();

    const int sub = wid & 3;
    const int cg  = wid >> 2;
    const int row = m0 + sub * 32 + lane;
#pragma unroll
    for (int ch = 0; ch < 4; ch++) {
        const int colb = cg * 128 + ch * 32;
        uint32_t r[32];
        TCGEN05_LD_32X32B_X32(r, tmem + colb);
        TCGEN05_WAIT_LD();
        const size_t base = (size_t)row * N + n0 + colb;
        const float4* bv = (const float4*)(bias + n0 + colb);
        float4* dst = (float4*)(Cf + base);
        const float4* rv = (MODE == 3) ? (const float4*)(res + base) : nullptr;
#pragma unroll
        for (int i = 0; i < 8; i++) {
            float4 b4 = bv[i];
            float4 o;
            o.x = __uint_as_float(r[i * 4 + 0]) + b4.x;
            o.y = __uint_as_float(r[i * 4 + 1]) + b4.y;
            o.z = __uint_as_float(r[i * 4 + 2]) + b4.z;
            o.w = __uint_as_float(r[i * 4 + 3]) + b4.w;
            if (MODE == 3) {
                float4 t = rv[i];
                o.x += t.x; o.y += t.y; o.z += t.z; o.w += t.w;
            }
            dst[i] = o;
        }
    }
    TCGEN05_FENCE_BEFORE();
    __syncthreads();
    if (tid == 0) { MBARRIER_INVAL(sb + 8); MBARRIER_INVAL(sb + 16); }
    __syncthreads();
    if (wid == 0) TCGEN05_DEALLOC(tmem, 256);
#else
    // SIMT fallback
    float* As = (float*)smx;
    float* Bs = As + 16 * 128;
    const int tid = threadIdx.x;
    const int m0 = blockIdx.y * TM, n0x = blockIdx.x * TN;
    const int tx = tid & 15, ty = tid >> 4;
    const int mr = ty * 8, nr = tx * 8;
    for (int half = 0; half < 2; half++) {
        const int n0 = n0x + half * 128;
        float acc[8][8];
#pragma unroll
        for (int i = 0; i < 8; i++)
#pragma unroll
            for (int j = 0; j < 8; j++) acc[i][j] = 0.f;
        for (int k0 = 0; k0 < K; k0 += 16) {
            __syncthreads();
#pragma unroll
            for (int i = 0; i < 8; i++) {
                int idx = i * 256 + tid;
                int kk = idx >> 7, mm = idx & 127;
                size_t ga = (size_t)(m0 + mm) * K + k0 + kk;
                size_t gb = (size_t)(n0 + mm) * K + k0 + kk;
                As[kk * 128 + mm] = __bfloat162float(Ahi[ga]) + __bfloat162float(Alo[ga]);
                Bs[kk * 128 + mm] = __bfloat162float(Bhi[gb]) + __bfloat162float(Blo[gb]);
            }
            __syncthreads();
#pragma unroll
            for (int kk = 0; kk < 16; kk++) {
                float a0[8], b0[8];
#pragma unroll
                for (int i = 0; i < 8; i++) a0[i] = As[kk * 128 + mr + i];
#pragma unroll
                for (int j = 0; j < 8; j++) b0[j] = Bs[kk * 128 + nr + j];
#pragma unroll
                for (int i = 0; i < 8; i++)
#pragma unroll
                    for (int j = 0; j < 8; j++)
                        acc[i][j] = fmaf(a0[i], b0[j], acc[i][j]);
            }
        }
#pragma unroll
        for (int i = 0; i < 8; i++) {
            const int row = m0 + mr + i;
#pragma unroll
            for (int j = 0; j < 8; j++) {
                const int col = n0 + nr + j;
                const size_t idx = (size_t)row * N + col;
                float v = acc[i][j] + bias[col];
                if (MODE == 2) Cf[idx] = v;
                else           Cf[idx] = v + res[idx];
            }
        }
    }
#endif
}

// ======================= TM256 tc GEMM (MoE, z = expert) ======================
// two 128-row A tiles share the B slab; two accumulators (TMEM cols 0 / 256)
// MODE 0: gelu(acc+bias) -> split bf16 Chi/Clo   MODE 1: Cf = acc + bias
#define T2K 32
#define ST2_BYTES 65536
#define S2_A0HI 0
#define S2_A0LO 8192
#define S2_A1HI 16384
#define S2_A1LO 24576
#define S2_BHI  32768
#define S2_BLO  49152
#define TC2_SMEM (1024 + 3*ST2_BYTES)   // 197632

#if HAS_TCGEN05
__device__ __forceinline__ void load_slab256(
    uint32_t sbase, int stage,
    const __nv_bfloat16* __restrict__ Ahi, const __nv_bfloat16* __restrict__ Alo,
    const __nv_bfloat16* __restrict__ Bhi, const __nv_bfloat16* __restrict__ Blo,
    int m0, int n0, int k0, int K)
{
    const int tid = threadIdx.x;
    const uint32_t base = sbase + 1024 + stage * ST2_BYTES;
    // A: 256 rows x 32 bf16 (64B rows), SW64
#pragma unroll
    for (int i = 0; i < 4; i++) {
        int idx = i * 256 + tid;           // 0..1023
        int row = idx >> 2, c4 = idx & 3;  // row 0..255
        int off = (row & 127) * 64 + c4 * 16;
        int sw  = off ^ ((off >> 3) & 0x30);
        int tb  = (row >> 7) * 16384;      // A0 or A1 region
        size_t g = (size_t)(m0 + row) * K + k0 + c4 * 8;
        CP_ASYNC16(base + S2_A0HI + tb + sw, Ahi + g);
        CP_ASYNC16(base + S2_A0LO + tb + sw, Alo + g);
    }
    // B: 256 rows x 32 bf16
#pragma unroll
    for (int i = 0; i < 4; i++) {
        int idx = i * 256 + tid;
        int row = idx >> 2, c4 = idx & 3;
        int off = row * 64 + c4 * 16;
        int sw  = off ^ ((off >> 3) & 0x30);
        size_t g = (size_t)(n0 + row) * K + k0 + c4 * 8;
        CP_ASYNC16(base + S2_BHI + sw, Bhi + g);
        CP_ASYNC16(base + S2_BLO + sw, Blo + g);
    }
    CP_COMMIT();
}
#endif

template<int MODE>
__global__ void __launch_bounds__(256)
tc_gemm2(const __nv_bfloat16* __restrict__ Ahi, const __nv_bfloat16* __restrict__ Alo,
         const __nv_bfloat16* __restrict__ Bhi, const __nv_bfloat16* __restrict__ Blo,
         const float* __restrict__ bias, float* __restrict__ Cf,
         __nv_bfloat16* __restrict__ Chi, __nv_bfloat16* __restrict__ Clo,
         int N, int K, size_t sA, size_t sB, size_t sBias, size_t sC)
{
    extern __shared__ char smx[];
    const int z = blockIdx.z;
    Ahi += z * sA; Alo += z * sA;
    Bhi += z * sB; Blo += z * sB;
    bias += z * sBias;
    if (MODE == 0) { Chi += z * sC; Clo += z * sC; }
    else           { Cf  += z * sC; }
#if HAS_TCGEN05
    const uint32_t sb = smem_u32(smx);
    const int tid = threadIdx.x;
    const int wid = tid >> 5, lane = tid & 31;
    const int m0 = blockIdx.y * 256, n0 = blockIdx.x * 256;

    if (wid == 0) { TCGEN05_ALLOC(sb, 512); TCGEN05_RELINQ(); }
    if (tid == 0) {
        MBARRIER_INIT(sb + 8, 1); MBARRIER_INIT(sb + 16, 1); MBARRIER_INIT(sb + 24, 1);
    }
    __syncthreads();
    uint32_t tmem;
    asm volatile("ld.shared.b32 %0, [%1];" : "=r"(tmem) : "r"(sb));

    const int NS = K / T2K;
    load_slab256(sb, 0, Ahi, Alo, Bhi, Blo, m0, n0, 0, K);
    load_slab256(sb, 1, Ahi, Alo, Bhi, Blo, m0, n0, T2K, K);

    int phase[3] = {0, 0, 0};
    for (int s = 0; s < NS; s++) {
        const int st = s % 3;
        if (s + 2 < NS) {
            const int stn = (s + 2) % 3;
            if (s + 2 >= 3) {
                MBARRIER_WAIT_PARITY(sb + 8 + stn * 8, phase[stn]);
                phase[stn] ^= 1;
            }
            load_slab256(sb, stn, Ahi, Alo, Bhi, Blo, m0, n0, (s + 2) * T2K, K);
            CP_WAIT(2);
        } else if (s + 1 < NS) {
            CP_WAIT(1);
        } else {
            CP_WAIT(0);
        }
        FENCE_ASYNC_SHARED();
        __syncthreads();
        if (wid == 0) {
            TCGEN05_FENCE_AFTER();
            if (elect_one()) {
                const uint32_t tb = sb + 1024 + st * ST2_BYTES;
                const uint64_t a0h = MKD64(tb + S2_A0HI);
                const uint64_t a0l = MKD64(tb + S2_A0LO);
                const uint64_t a1h = MKD64(tb + S2_A1HI);
                const uint64_t a1l = MKD64(tb + S2_A1LO);
                const uint64_t bh  = MKD64(tb + S2_BHI);
                const uint64_t bl  = MKD64(tb + S2_BLO);
#pragma unroll
                for (int ks = 0; ks < 2; ks++) {
                    const uint32_t en0 = (s == 0 && ks == 0) ? 0u : 1u;
                    mma_bf16_ss(tmem,       a0h + ks * 2, bh + ks * 2, IDESC_BF16, en0);
                    mma_bf16_ss(tmem,       a0h + ks * 2, bl + ks * 2, IDESC_BF16, 1u);
                    mma_bf16_ss(tmem,       a0l + ks * 2, bh + ks * 2, IDESC_BF16, 1u);
                    mma_bf16_ss(tmem + 256, a1h + ks * 2, bh + ks * 2, IDESC_BF16, en0);
                    mma_bf16_ss(tmem + 256, a1h + ks * 2, bl + ks * 2, IDESC_BF16, 1u);
                    mma_bf16_ss(tmem + 256, a1l + ks * 2, bh + ks * 2, IDESC_BF16, 1u);
                }
                TCGEN05_COMMIT(sb + 8 + st * 8);
            }
        }
    }
    {
        const int stl = (NS - 1) % 3;
        MBARRIER_WAIT_PARITY(sb + 8 + stl * 8, phase[stl]);
    }
    TCGEN05_FENCE_AFTER();

    // epilogue: warps 0-3 -> acc0 (rows m0..+127), warps 4-7 -> acc1
    const int accSel = wid >> 2;
    const int sub = wid & 3;
    const int row = m0 + accSel * 128 + sub * 32 + lane;
    const uint32_t tacc = tmem + accSel * 256;
#pragma unroll
    for (int ch = 0; ch < 8; ch++) {
        const int colb = ch * 32;
        uint32_t r[32];
        TCGEN05_LD_32X32B_X32(r, tacc + colb);
        TCGEN05_WAIT_LD();
        const size_t base = (size_t)row * N + n0 + colb;
        const float4* bv = (const float4*)(bias + n0 + colb);
        if (MODE == 0) {
            uint4* dh = (uint4*)(Chi + base);
            uint4* dl = (uint4*)(Clo + base);
#pragma unroll
            for (int i = 0; i < 4; i++) {
                uint32_t hp[4], lp[4];
#pragma unroll
                for (int p = 0; p < 4; p++) {
                    float4 b4 = bv[i * 2 + (p >> 1)];
                    float b0 = (p & 1) ? b4.z : b4.x;
                    float b1 = (p & 1) ? b4.w : b4.y;
                    float v0 = __uint_as_float(r[i * 8 + p * 2 + 0]) + b0;
                    float v1 = __uint_as_float(r[i * 8 + p * 2 + 1]) + b1;
                    float g0 = 0.5f * v0 * (1.f + erff(v0 * 0.70710678118654752f));
                    float g1 = 0.5f * v1 * (1.f + erff(v1 * 0.70710678118654752f));
                    __nv_bfloat16 h0 = __float2bfloat16(g0);
                    __nv_bfloat16 h1 = __float2bfloat16(g1);
                    __nv_bfloat16 l0 = __float2bfloat16(g0 - __bfloat162float(h0));
                    __nv_bfloat16 l1 = __float2bfloat16(g1 - __bfloat162float(h1));
                    hp[p] = (uint32_t)__bfloat16_as_ushort(h0) |
                            ((uint32_t)__bfloat16_as_ushort(h1) << 16);
                    lp[p] = (uint32_t)__bfloat16_as_ushort(l0) |
                            ((uint32_t)__bfloat16_as_ushort(l1) << 16);
                }
                dh[i] = make_uint4(hp[0], hp[1], hp[2], hp[3]);
                dl[i] = make_uint4(lp[0], lp[1], lp[2], lp[3]);
            }
        } else {
            float4* dst = (float4*)(Cf + base);
#pragma unroll
            for (int i = 0; i < 8; i++) {
                float4 b4 = bv[i];
                float4 o;
                o.x = __uint_as_float(r[i * 4 + 0]) + b4.x;
                o.y = __uint_as_float(r[i * 4 + 1]) + b4.y;
                o.z = __uint_as_float(r[i * 4 + 2]) + b4.z;
                o.w = __uint_as_float(r[i * 4 + 3]) + b4.w;
                dst[i] = o;
            }
        }
    }
    TCGEN05_FENCE_BEFORE();
    __syncthreads();
    if (tid == 0) {
        MBARRIER_INVAL(sb + 8); MBARRIER_INVAL(sb + 16); MBARRIER_INVAL(sb + 24);
    }
    __syncthreads();
    if (wid == 0) TCGEN05_DEALLOC(tmem, 512);
#else
    // SIMT fallback: 4 sub-blocks of 128x128
    float* As = (float*)smx;
    float* Bs = As + 16 * 128;
    const int tid = threadIdx.x;
    const int tx = tid & 15, ty = tid >> 4;
    const int mr = ty * 8, nr = tx * 8;
    for (int mh = 0; mh < 2; mh++)
    for (int nh = 0; nh < 2; nh++) {
        const int m0 = blockIdx.y * 256 + mh * 128;
        const int n0 = blockIdx.x * 256 + nh * 128;
        float acc[8][8];
#pragma unroll
        for (int i = 0; i < 8; i++)
#pragma unroll
            for (int j = 0; j < 8; j++) acc[i][j] = 0.f;
        for (int k0 = 0; k0 < K; k0 += 16) {
            __syncthreads();
#pragma unroll
            for (int i = 0; i < 8; i++) {
                int idx = i * 256 + tid;
                int kk = idx >> 7, mm = idx & 127;
                size_t ga = (size_t)(m0 + mm) * K + k0 + kk;
                size_t gb = (size_t)(n0 + mm) * K + k0 + kk;
                As[kk * 128 + mm] = __bfloat162float(Ahi[ga]) + __bfloat162float(Alo[ga]);
                Bs[kk * 128 + mm] = __bfloat162float(Bhi[gb]) + __bfloat162float(Blo[gb]);
            }
            __syncthreads();
#pragma unroll
            for (int kk = 0; kk < 16; kk++) {
                float a0[8], b0[8];
#pragma unroll
                for (int i = 0; i < 8; i++) a0[i] = As[kk * 128 + mr + i];
#pragma unroll
                for (int j = 0; j < 8; j++) b0[j] = Bs[kk * 128 + nr + j];
#pragma unroll
                for (int i = 0; i < 8; i++)
#pragma unroll
                    for (int j = 0; j < 8; j++)
                        acc[i][j] = fmaf(a0[i], b0[j], acc[i][j]);
            }
        }
#pragma unroll
        for (int i = 0; i < 8; i++) {
            const int row = m0 + mr + i;
#pragma unroll
            for (int j = 0; j < 8; j++) {
                const int col = n0 + nr + j;
                const size_t idx = (size_t)row * N + col;
                float v = acc[i][j] + bias[col];
                if (MODE == 0) {
                    float g = 0.5f * v * (1.f + erff(v * 0.70710678118654752f));
                    __nv_bfloat16 h = __float2bfloat16(g);
                    Chi[idx] = h;
                    Clo[idx] = __float2bfloat16(g - __bfloat162float(h));
                } else {
                    Cf[idx] = v;
                }
            }
        }
    }
#endif
}

// ---------------- transpose + bf16 split: W[e][K][N] -> T[e][N][K] -------------
__global__ void __launch_bounds__(256)
transpose_split(const float* __restrict__ W, __nv_bfloat16* __restrict__ Thi,
                __nv_bfloat16* __restrict__ Tlo, int K, int N)
{
    __shared__ float t[32][33];
    const int e = blockIdx.z;
    const float* Wp = W + (size_t)e * K * N;
    __nv_bfloat16* th = Thi + (size_t)e * K * N;
    __nv_bfloat16* tl = Tlo + (size_t)e * K * N;
    const int k0 = blockIdx.x * 32, n0 = blockIdx.y * 32;
    const int x = threadIdx.x & 31, y = threadIdx.x >> 5;
#pragma unroll
    for (int i = 0; i < 32; i += 8)
        t[y + i][x] = Wp[(size_t)(k0 + y + i) * N + n0 + x];
    __syncthreads();
#pragma unroll
    for (int i = 0; i < 32; i += 8) {
        float v = t[x][y + i];
        __nv_bfloat16 h = __float2bfloat16(v);
        float lo = v - __bfloat162float(h);
        const size_t idx = (size_t)(n0 + y + i) * K + k0 + x;
        th[idx] = h;
        tl[idx] = __float2bfloat16(lo);
    }
}

// ---------------- fp32 -> split bf16 ---------------------------------------------
__global__ void __launch_bounds__(256)
split_bf16(const float* __restrict__ x, __nv_bfloat16* __restrict__ hi,
           __nv_bfloat16* __restrict__ lo, int n4)
{
    int i = blockIdx.x * 256 + threadIdx.x;
    if (i >= n4) return;
    float4 v = ((const float4*)x)[i];
    __nv_bfloat16 h0 = __float2bfloat16(v.x), h1 = __float2bfloat16(v.y);
    __nv_bfloat16 h2 = __float2bfloat16(v.z), h3 = __float2bfloat16(v.w);
    uint2 hp, lp;
    hp.x = (uint32_t)__bfloat16_as_ushort(h0) | ((uint32_t)__bfloat16_as_ushort(h1) << 16);
    hp.y = (uint32_t)__bfloat16_as_ushort(h2) | ((uint32_t)__bfloat16_as_ushort(h3) << 16);
    __nv_bfloat16 l0 = __float2bfloat16(v.x - __bfloat162float(h0));
    __nv_bfloat16 l1 = __float2bfloat16(v.y - __bfloat162float(h1));
    __nv_bfloat16 l2 = __float2bfloat16(v.z - __bfloat162float(h2));
    __nv_bfloat16 l3 = __float2bfloat16(v.w - __bfloat162float(h3));
    lp.x = (uint32_t)__bfloat16_as_ushort(l0) | ((uint32_t)__bfloat16_as_ushort(l1) << 16);
    lp.y = (uint32_t)__bfloat16_as_ushort(l2) | ((uint32_t)__bfloat16_as_ushort(l3) << 16);
    ((uint2*)hi)[i] = hp;
    ((uint2*)lo)[i] = lp;
}

// ---------------- attention: 2 CTAs per (b,h), 98 queries each ------------------
#define KPAD 65
__global__ void __launch_bounds__(256)
attn_kernel(const float* __restrict__ qh, const float* __restrict__ kh,
            const float* __restrict__ vh, float* __restrict__ ctx)
{
    const int b = blockIdx.x / Hq;
    const int h = blockIdx.x % Hq;
    const int qbase = blockIdx.y * 98;
    const int qend  = min(196, qbase + 98);
    extern __shared__ float sm[];
    float* Ks = sm;
    float* Vs = Ks + Sq * KPAD;
    float* Ps = Vs + Sq * DHq;
    float* Qs = Ps + 8 * 208;
    const int tid = threadIdx.x;
    for (int i = tid; i < Sq * DHq; i += 256) {
        int s = i / DHq, d = i % DHq;
        size_t gidx = (size_t)(b * Sq + s) * Dq + h * DHq + d;
        Ks[s * KPAD + d] = kh[gidx];
        Vs[s * DHq  + d] = vh[gidx];
    }
    __syncthreads();
    const int warp = tid >> 5, lane = tid & 31;
    float* p    = Ps + warp * 208;
    float* qrow = Qs + warp * DHq;
    for (int q = qbase + warp; q < qend; q += 8) {
        for (int d = lane; d < DHq; d += 32)
            qrow[d] = qh[(size_t)(b * Sq + q) * Dq + h * DHq + d];
        __syncwarp();
        float lmax = -1e30f;
        for (int col = lane; col < Sq; col += 32) {
            float s = 0.f;
            const float* kr = Ks + col * KPAD;
#pragma unroll 16
            for (int d = 0; d < DHq; d++) s = fmaf(qrow[d], kr[d], s);
            s *= 0.125f;
            p[col] = s;
            lmax = fmaxf(lmax, s);
        }
#pragma unroll
        for (int o = 16; o; o >>= 1) lmax = fmaxf(lmax, __shfl_xor_sync(0xffffffffu, lmax, o));
        float lsum = 0.f;
        for (int col = lane; col < Sq; col += 32) {
            float e = __expf(p[col] - lmax);
            p[col] = e;
            lsum += e;
        }
#pragma unroll
        for (int o = 16; o; o >>= 1) lsum += __shfl_xor_sync(0xffffffffu, lsum, o);
        const float inv = 1.f / lsum;
        __syncwarp();
        for (int d = lane; d < DHq; d += 32) {
            float a = 0.f;
            for (int k = 0; k < Sq; k++) a = fmaf(p[k], Vs[k * DHq + d], a);
            ctx[(size_t)(b * Sq + q) * Dq + h * DHq + d] = a * inv;
        }
        __syncwarp();
    }
}

// ---------------- gate softmax ----------------------------------------------------
__global__ void __launch_bounds__(256)
gate_kernel(const float* __restrict__ x, const float* __restrict__ Wg,
            const float* __restrict__ bg, float* __restrict__ gates)
{
    const int warp = (blockIdx.x * 256 + threadIdx.x) >> 5;
    const int lane = threadIdx.x & 31;
    if (warp >= NTOK) return;
    const float* xr = x + (size_t)warp * Dq;
    float lg[Eq];
#pragma unroll
    for (int e = 0; e < Eq; e++) lg[e] = 0.f;
    for (int d = lane; d < Dq; d += 32) {
        float xv = xr[d];
#pragma unroll
        for (int e = 0; e < Eq; e++) lg[e] = fmaf(xv, Wg[d * Eq + e], lg[e]);
    }
#pragma unroll
    for (int e = 0; e < Eq; e++)
#pragma unroll
        for (int o = 16; o; o >>= 1) lg[e] += __shfl_xor_sync(0xffffffffu, lg[e], o);
    if (lane == 0) {
        float m = -1e30f;
#pragma unroll
        for (int e = 0; e < Eq; e++) { lg[e] += bg[e]; m = fmaxf(m, lg[e]); }
        float s = 0.f;
#pragma unroll
        for (int e = 0; e < Eq; e++) { lg[e] = __expf(lg[e] - m); s += lg[e]; }
        float inv = 1.f / s;
#pragma unroll
        for (int e = 0; e < Eq; e++) gates[(size_t)warp * Eq + e] = lg[e] * inv;
    }
}

// ---------------- LN1 (emits split-bf16) -------------------------------------------
__global__ void __launch_bounds__(256)
ln_kernel(const float* __restrict__ a, const float* __restrict__ g,
          const float* __restrict__ be, float* __restrict__ out,
          __nv_bfloat16* __restrict__ ohi, __nv_bfloat16* __restrict__ olo)
{
    const int row = blockIdx.x;
    const float* ar = a + (size_t)row * Dq;
    float v[3];
    float s = 0.f, s2 = 0.f;
#pragma unroll
    for (int i = 0; i < 3; i++) {
        int d = threadIdx.x + i * 256;
        float x = ar[d];
        v[i] = x;
        s += x; s2 = fmaf(x, x, s2);
    }
    __shared__ float rs[8], rs2[8];
#pragma unroll
    for (int o = 16; o; o >>= 1) { s += __shfl_xor_sync(0xffffffffu, s, o); s2 += __shfl_xor_sync(0xffffffffu, s2, o); }
    const int warp = threadIdx.x >> 5, lane = threadIdx.x & 31;
    if (lane == 0) { rs[warp] = s; rs2[warp] = s2; }
    __syncthreads();
    if (warp == 0) {
        float t  = (lane < 8) ? rs[lane]  : 0.f;
        float t2 = (lane < 8) ? rs2[lane] : 0.f;
#pragma unroll
        for (int o = 4; o; o >>= 1) { t += __shfl_xor_sync(0xffffffffu, t, o); t2 += __shfl_xor_sync(0xffffffffu, t2, o); }
        if (lane == 0) { rs[0] = t; rs2[0] = t2; }
    }
    __syncthreads();
    const float mu  = rs[0] * (1.f / Dq);
    const float var = rs2[0] * (1.f / Dq) - mu * mu;
    const float inv = rsqrtf(var + 1e-5f);
#pragma unroll
    for (int i = 0; i < 3; i++) {
        int d = threadIdx.x + i * 256;
        float y = (v[i] - mu) * inv * g[d] + be[d];
        const size_t idx = (size_t)row * Dq + d;
        out[idx] = y;
        __nv_bfloat16 h = __float2bfloat16(y);
        ohi[idx] = h;
        olo[idx] = __float2bfloat16(y - __bfloat162float(h));
    }
}

// ---------------- LN2: fused gate-weighted expert reduction ------------------------
__global__ void __launch_bounds__(256)
ln2_kernel(const float* __restrict__ x, const float* __restrict__ y,
           const float* __restrict__ gates, const float* __restrict__ g,
           const float* __restrict__ be, float* __restrict__ out)
{
    const int row = blockIdx.x;
    __shared__ float sg[Eq];
    if (threadIdx.x < Eq) sg[threadIdx.x] = gates[(size_t)row * Eq + threadIdx.x];
    __syncthreads();
    float v[3];
    float s = 0.f, s2 = 0.f;
#pragma unroll
    for (int i = 0; i < 3; i++) {
        int d = threadIdx.x + i * 256;
        float val = x[(size_t)row * Dq + d];
#pragma unroll
        for (int e = 0; e < Eq; e++)
            val = fmaf(sg[e], y[(size_t)e * MPAD * Dq + (size_t)row * Dq + d], val);
        v[i] = val;
        s += val; s2 = fmaf(val, val, s2);
    }
    __shared__ float rs[8], rs2[8];
#pragma unroll
    for (int o = 16; o; o >>= 1) { s += __shfl_xor_sync(0xffffffffu, s, o); s2 += __shfl_xor_sync(0xffffffffu, s2, o); }
    const int warp = threadIdx.x >> 5, lane = threadIdx.x & 31;
    if (lane == 0) { rs[warp] = s; rs2[warp] = s2; }
    __syncthreads();
    if (warp == 0) {
        float t  = (lane < 8) ? rs[lane]  : 0.f;
        float t2 = (lane < 8) ? rs2[lane] : 0.f;
#pragma unroll
        for (int o = 4; o; o >>= 1) { t += __shfl_xor_sync(0xffffffffu, t, o); t2 += __shfl_xor_sync(0xffffffffu, t2, o); }
        if (lane == 0) { rs[0] = t; rs2[0] = t2; }
    }
    __syncthreads();
    const float mu  = rs[0] * (1.f / Dq);
    const float var = rs2[0] * (1.f / Dq) - mu * mu;
    const float inv = rsqrtf(var + 1e-5f);
#pragma unroll
    for (int i = 0; i < 3; i++) {
        int d = threadIdx.x + i * 256;
        out[(size_t)row * Dq + d] = (v[i] - mu) * inv * g[d] + be[d];
    }
}

// =================================================================================
extern "C" void kernel_launch(void* const* d_in, const int* in_sizes, int n_in,
                              void* d_out, int out_size)
{
    const float* q   = (const float*)d_in[0];
    const float* k   = (const float*)d_in[1];
    const float* v   = (const float*)d_in[2];
    const float* Wq  = (const float*)d_in[3];
    const float* bq  = (const float*)d_in[4];
    const float* Wk  = (const float*)d_in[5];
    const float* bk  = (const float*)d_in[6];
    const float* Wv  = (const float*)d_in[7];
    const float* bv  = (const float*)d_in[8];
    const float* Wo  = (const float*)d_in[9];
    const float* bo  = (const float*)d_in[10];
    const float* ln1g= (const float*)d_in[11];
    const float* ln1b= (const float*)d_in[12];
    const float* ln2g= (const float*)d_in[13];
    const float* ln2b= (const float*)d_in[14];
    const float* Wg  = (const float*)d_in[15];
    const float* bg  = (const float*)d_in[16];
    const float* W1  = (const float*)d_in[17];
    const float* b1  = (const float*)d_in[18];
    const float* W2  = (const float*)d_in[19];
    const float* b2  = (const float*)d_in[20];
    float* out = (float*)d_out;

    float *p_qh, *p_kh, *p_vh, *p_ctx, *p_tmp, *p_x, *p_y, *p_gates;
    __nv_bfloat16 *p_inhi, *p_inlo, *p_xhi, *p_xlo, *p_hhi, *p_hlo;
    __nv_bfloat16 *p_w1h, *p_w1l, *p_w2h, *p_w2l;
    __nv_bfloat16 *p_wqh, *p_wql, *p_wkh, *p_wkl, *p_wvh, *p_wvl, *p_woh, *p_wol;
    cudaGetSymbolAddress((void**)&p_qh,   d_qh);
    cudaGetSymbolAddress((void**)&p_kh,   d_kh);
    cudaGetSymbolAddress((void**)&p_vh,   d_vh);
    cudaGetSymbolAddress((void**)&p_ctx,  d_ctx);
    cudaGetSymbolAddress((void**)&p_tmp,  d_tmp);
    cudaGetSymbolAddress((void**)&p_x,    d_x);
    cudaGetSymbolAddress((void**)&p_y,    d_y);
    cudaGetSymbolAddress((void**)&p_gates,d_gates);
    cudaGetSymbolAddress((void**)&p_inhi, d_inhi);
    cudaGetSymbolAddress((void**)&p_inlo, d_inlo);
    cudaGetSymbolAddress((void**)&p_xhi,  d_xhi);
    cudaGetSymbolAddress((void**)&p_xlo,  d_xlo);
    cudaGetSymbolAddress((void**)&p_hhi,  d_hhi);
    cudaGetSymbolAddress((void**)&p_hlo,  d_hlo);
    cudaGetSymbolAddress((void**)&p_w1h,  d_w1t_hi);
    cudaGetSymbolAddress((void**)&p_w1l,  d_w1t_lo);
    cudaGetSymbolAddress((void**)&p_w2h,  d_w2t_hi);
    cudaGetSymbolAddress((void**)&p_w2l,  d_w2t_lo);
    cudaGetSymbolAddress((void**)&p_wqh,  d_wqt_hi);
    cudaGetSymbolAddress((void**)&p_wql,  d_wqt_lo);
    cudaGetSymbolAddress((void**)&p_wkh,  d_wkt_hi);
    cudaGetSymbolAddress((void**)&p_wkl,  d_wkt_lo);
    cudaGetSymbolAddress((void**)&p_wvh,  d_wvt_hi);
    cudaGetSymbolAddress((void**)&p_wvl,  d_wvt_lo);
    cudaGetSymbolAddress((void**)&p_woh,  d_wot_hi);
    cudaGetSymbolAddress((void**)&p_wol,  d_wot_lo);

    const dim3 blk(256);
    const dim3 gridD(Dq / TN, NTOK / TM);       // TM128 QKV/O grid (3, 49)
    const dim3 grid1(Fq / 256, MPAD / 256, Eq); // (12, 25, 8)
    const dim3 grid2(Dq / 256, MPAD / 256, Eq); // (3, 25, 8)
    const int n4 = NTOK * Dq / 4;
    const int sgrid = (n4 + 255) / 256;

    cudaFuncSetAttribute(tc_gemm<2>,  cudaFuncAttributeMaxDynamicSharedMemorySize, TC_SMEM);
    cudaFuncSetAttribute(tc_gemm<3>,  cudaFuncAttributeMaxDynamicSharedMemorySize, TC_SMEM);
    cudaFuncSetAttribute(tc_gemm2<0>, cudaFuncAttributeMaxDynamicSharedMemorySize, TC2_SMEM);
    cudaFuncSetAttribute(tc_gemm2<1>, cudaFuncAttributeMaxDynamicSharedMemorySize, TC2_SMEM);

    // weight transpose + bf16 split
    transpose_split<<<dim3(Dq/32, Dq/32, 1), blk>>>(Wq, p_wqh, p_wql, Dq, Dq);
    transpose_split<<<dim3(Dq/32, Dq/32, 1), blk>>>(Wk, p_wkh, p_wkl, Dq, Dq);
    transpose_split<<<dim3(Dq/32, Dq/32, 1), blk>>>(Wv, p_wvh, p_wvl, Dq, Dq);
    transpose_split<<<dim3(Dq/32, Dq/32, 1), blk>>>(Wo, p_woh, p_wol, Dq, Dq);
    transpose_split<<<dim3(Dq/32, Fq/32, Eq), blk>>>(W1, p_w1h, p_w1l, Dq, Fq);
    transpose_split<<<dim3(Fq/32, Dq/32, Eq), blk>>>(W2, p_w2h, p_w2l, Fq, Dq);

    // QKV projections (TM128 tc)
    split_bf16<<<sgrid, blk>>>(q, p_inhi, p_inlo, n4);
    tc_gemm<2><<<gridD, blk, TC_SMEM>>>(p_inhi, p_inlo, p_wqh, p_wql, bq,
                                        nullptr, p_qh, NTOK, Dq, Dq);
    split_bf16<<<sgrid, blk>>>(k, p_inhi, p_inlo, n4);
    tc_gemm<2><<<gridD, blk, TC_SMEM>>>(p_inhi, p_inlo, p_wkh, p_wkl, bk,
                                        nullptr, p_kh, NTOK, Dq, Dq);
    split_bf16<<<sgrid, blk>>>(v, p_inhi, p_inlo, n4);
    tc_gemm<2><<<gridD, blk, TC_SMEM>>>(p_inhi, p_inlo, p_wvh, p_wvl, bv,
                                        nullptr, p_vh, NTOK, Dq, Dq);

    // attention (2 CTAs per (b,h))
    const int smem_attn = (Sq * KPAD + Sq * DHq + 8 * 208 + 8 * DHq) * (int)sizeof(float);
    cudaFuncSetAttribute(attn_kernel, cudaFuncAttributeMaxDynamicSharedMemorySize, smem_attn);
    attn_kernel<<<dim3(Bq * Hq, 2), blk, smem_attn>>>(p_qh, p_kh, p_vh, p_ctx);

    // O projection + residual(q), LN1 (emits split-bf16 x)
    split_bf16<<<sgrid, blk>>>(p_ctx, p_inhi, p_inlo, n4);
    tc_gemm<3><<<gridD, blk, TC_SMEM>>>(p_inhi, p_inlo, p_woh, p_wol, bo,
                                        q, p_tmp, NTOK, Dq, Dq);
    ln_kernel<<<NTOK, blk>>>(p_tmp, ln1g, ln1b, p_x, p_xhi, p_xlo);

    // gate softmax
    gate_kernel<<<(NTOK * 32 + 255) / 256, blk>>>(p_x, Wg, bg, p_gates);

    // MoE: single z-merged launch per GEMM
    tc_gemm2<0><<<grid1, blk, TC2_SMEM>>>(
        p_xhi, p_xlo, p_w1h, p_w1l, b1, nullptr, p_hhi, p_hlo,
        Fq, Dq, (size_t)0, (size_t)Fq * Dq, (size_t)Fq, (size_t)MPAD * Fq);
    tc_gemm2<1><<<grid2, blk, TC2_SMEM>>>(
        p_hhi, p_hlo, p_w2h, p_w2l, b2, p_y, nullptr, nullptr,
        Dq, Fq, (size_t)MPAD * Fq, (size_t)Dq * Fq, (size_t)Dq, (size_t)MPAD * Dq);

    // residual + gate-weighted expert sum + LN2 -> output
    ln2_kernel<<<NTOK, blk>>>(p_x, p_y, p_gates, ln2g, ln2b, out);
}

// round 6
// speedup vs baseline: 4.7219x; 1.0031x over previous
#include <cuda_runtime.h>
#include <cuda_bf16.h>
#include <math.h>
#include <stdint.h>

#define Bq 32
#define Sq 196
#define Dq 768
#define Hq 12
#define Eq 8
#define Fq 3072
#define DHq 64
#define NTOK (Bq*Sq)   // 6272
#define MPAD 6400      // NTOK padded to multiple of 256

#define HAS_TCGEN05 (defined(__CUDA_ARCH_FEAT_SM103_ALL) || defined(__CUDA_ARCH_FEAT_SM100_ALL))

// ---------------- scratch (device globals; no allocation allowed) -------------
__device__ __align__(256) float d_qh [NTOK*Dq];
__device__ __align__(256) float d_kh [NTOK*Dq];
__device__ __align__(256) float d_vh [NTOK*Dq];
__device__ __align__(256) float d_ctx[NTOK*Dq];
__device__ __align__(256) float d_tmp[NTOK*Dq];
__device__ __align__(256) float d_x  [NTOK*Dq];
__device__ __align__(256) float d_y  [Eq*MPAD*Dq];      // per-expert FFN outputs
__device__ __align__(256) float d_gates[MPAD*Eq];

__device__ __align__(256) __nv_bfloat16 d_inhi[NTOK*Dq];
__device__ __align__(256) __nv_bfloat16 d_inlo[NTOK*Dq];
__device__ __align__(256) __nv_bfloat16 d_xhi[MPAD*Dq];
__device__ __align__(256) __nv_bfloat16 d_xlo[MPAD*Dq];
__device__ __align__(256) __nv_bfloat16 d_hhi[Eq*MPAD*Fq];
__device__ __align__(256) __nv_bfloat16 d_hlo[Eq*MPAD*Fq];
__device__ __align__(256) __nv_bfloat16 d_w1t_hi[Eq*Fq*Dq]; // [E][F][D]
__device__ __align__(256) __nv_bfloat16 d_w1t_lo[Eq*Fq*Dq];
__device__ __align__(256) __nv_bfloat16 d_w2t_hi[Eq*Dq*Fq]; // [E][D][F]
__device__ __align__(256) __nv_bfloat16 d_w2t_lo[Eq*Dq*Fq];
__device__ __align__(256) __nv_bfloat16 d_wqt_hi[Dq*Dq];
__device__ __align__(256) __nv_bfloat16 d_wqt_lo[Dq*Dq];
__device__ __align__(256) __nv_bfloat16 d_wkt_hi[Dq*Dq];
__device__ __align__(256) __nv_bfloat16 d_wkt_lo[Dq*Dq];
__device__ __align__(256) __nv_bfloat16 d_wvt_hi[Dq*Dq];
__device__ __align__(256) __nv_bfloat16 d_wvt_lo[Dq*Dq];
__device__ __align__(256) __nv_bfloat16 d_wot_hi[Dq*Dq];
__device__ __align__(256) __nv_bfloat16 d_wot_lo[Dq*Dq];

// ======================= PTX helpers ==========================================
__device__ __forceinline__ uint32_t smem_u32(const void* p) {
    uint32_t a;
    asm("{ .reg .u64 t; cvta.to.shared.u64 t, %1; cvt.u32.u64 %0, t; }" : "=r"(a) : "l"(p));
    return a;
}

#if HAS_TCGEN05
__device__ __forceinline__ bool elect_one() {
    uint32_t p;
    asm volatile("{\n .reg .pred p;\n elect.sync _|p, 0xFFFFFFFF;\n selp.b32 %0,1,0,p;\n}" : "=r"(p));
    return p != 0;
}
#define MBARRIER_INIT(addr, cnt) \
    asm volatile("mbarrier.init.shared.b64 [%0], %1;" :: "r"((uint32_t)(addr)), "r"((uint32_t)(cnt)) : "memory")
#define MBARRIER_INVAL(addr) \
    asm volatile("mbarrier.inval.shared.b64 [%0];" :: "r"((uint32_t)(addr)) : "memory")
#define MBARRIER_WAIT_PARITY(mbar_smem_addr, phase_parity) do { \
    uint32_t _mbar = (uint32_t)(mbar_smem_addr); \
    uint32_t _parity = (uint32_t)(phase_parity); \
    uint32_t _done; \
    asm volatile( \
        "{\n\t.reg .pred p;\n\t" \
        "mbarrier.try_wait.parity.acquire.cta.shared::cta.b64 p, [%1], %2;\n\t" \
        "selp.b32 %0, 1, 0, p;\n\t}" \
        : "=r"(_done) : "r"(_mbar), "r"(_parity) : "memory"); \
    if (!_done) { \
        asm volatile( \
            "{\n\t.reg .pred P1;\n\t" \
            "WAIT_LOOP_%=:\n\t" \
            "mbarrier.try_wait.parity.acquire.cta.shared::cta.b64 P1, [%0], %1, 0x989680;\n\t" \
            "@P1 bra.uni WAIT_DONE_%=;\n\t" \
            "bra.uni WAIT_LOOP_%=;\n\t" \
            "WAIT_DONE_%=:\n\t}" \
            :: "r"(_mbar), "r"(_parity) : "memory"); \
    } \
} while(0)
#define TCGEN05_ALLOC(smem_result_addr, nCols) \
    asm volatile("tcgen05.alloc.cta_group::1.sync.aligned.shared::cta.b32 [%0], %1;" \
        :: "r"((uint32_t)(smem_result_addr)), "r"((uint32_t)(nCols)) : "memory")
#define TCGEN05_DEALLOC(tmem_addr, nCols) \
    asm volatile("tcgen05.dealloc.cta_group::1.sync.aligned.b32 %0, %1;" :: "r"(tmem_addr), "r"(nCols))
#define TCGEN05_RELINQ() \
    asm volatile("tcgen05.relinquish_alloc_permit.cta_group::1.sync.aligned;")
#define TCGEN05_COMMIT(mbar_smem_addr) \
    asm volatile("tcgen05.commit.cta_group::1.mbarrier::arrive::one.shared::cluster.b64 [%0];" \
        :: "r"((uint32_t)(mbar_smem_addr)) : "memory")
#define TCGEN05_FENCE_AFTER()  asm volatile("tcgen05.fence::after_thread_sync;" ::: "memory")
#define TCGEN05_FENCE_BEFORE() asm volatile("tcgen05.fence::before_thread_sync;" ::: "memory")
#define TCGEN05_WAIT_LD() asm volatile("tcgen05.wait::ld.sync.aligned;" ::: "memory")
#define FENCE_ASYNC_SHARED() asm volatile("fence.proxy.async.shared::cta;" ::: "memory")
#define CP_ASYNC16(dst, src) \
    asm volatile("cp.async.cg.shared.global [%0], [%1], 16;" :: "r"((uint32_t)(dst)), "l"(src))
#define CP_COMMIT() asm volatile("cp.async.commit_group;" ::: "memory")
#define CP_WAIT(n)  asm volatile("cp.async.wait_group %0;" :: "n"(n) : "memory")
#define TCGEN05_LD_32X32B_X32(r, tmem_addr) \
    asm volatile( \
        "tcgen05.ld.sync.aligned.32x32b.x32.b32 " \
        "{%0, %1, %2, %3, %4, %5, %6, %7, " \
        " %8, %9, %10, %11, %12, %13, %14, %15, " \
        " %16, %17, %18, %19, %20, %21, %22, %23, " \
        " %24, %25, %26, %27, %28, %29, %30, %31}, [%32];" \
        : "=r"((r)[0]),  "=r"((r)[1]),  "=r"((r)[2]),  "=r"((r)[3]), \
          "=r"((r)[4]),  "=r"((r)[5]),  "=r"((r)[6]),  "=r"((r)[7]), \
          "=r"((r)[8]),  "=r"((r)[9]),  "=r"((r)[10]), "=r"((r)[11]), \
          "=r"((r)[12]), "=r"((r)[13]), "=r"((r)[14]), "=r"((r)[15]), \
          "=r"((r)[16]), "=r"((r)[17]), "=r"((r)[18]), "=r"((r)[19]), \
          "=r"((r)[20]), "=r"((r)[21]), "=r"((r)[22]), "=r"((r)[23]), \
          "=r"((r)[24]), "=r"((r)[25]), "=r"((r)[26]), "=r"((r)[27]), \
          "=r"((r)[28]), "=r"((r)[29]), "=r"((r)[30]), "=r"((r)[31]) \
        : "r"(tmem_addr))

// K-major SW128 descriptor (128B rows): layout=2, version=1, SBO=64, LBO=1
static constexpr uint64_t DESC_SW128 =
    (uint64_t(2) << 61) | (uint64_t(1) << 46) | (uint64_t(64) << 32) | (uint64_t(1) << 16);
// K-major SW64 descriptor (64B rows): layout=4, version=1, SBO=32, LBO=1
static constexpr uint64_t DESC_SW64 =
    (uint64_t(4) << 61) | (uint64_t(1) << 46) | (uint64_t(32) << 32) | (uint64_t(1) << 16);
#define MKD128(a) (DESC_SW128 | ((uint64_t)((a) >> 4) & 0x3FFF))
#define MKD64(a)  (DESC_SW64  | ((uint64_t)((a) >> 4) & 0x3FFF))

__device__ __forceinline__ void mma_bf16_ss(uint32_t d, uint64_t ad, uint64_t bd,
                                            uint32_t idesc, uint32_t en) {
    asm volatile(
        "{\n\t.reg .pred p;\n\tsetp.ne.u32 p, %5, 0;\n\t"
        "tcgen05.mma.cta_group::1.kind::f16 [%0], %1, %2, %3, {%4,%4,%4,%4}, p;\n\t}"
        :: "r"(d), "l"(ad), "l"(bd), "r"(idesc), "r"(0u), "r"(en) : "memory");
}
#endif // HAS_TCGEN05

// ======================= TM128 tc GEMM (QKV / O-proj) =========================
// MODE 2: Cf = acc + bias        MODE 3: Cf = acc + bias + res
#define TM 128
#define TN 256
#define TK 64
#define STAGE_BYTES 98304
#define SM_A_HI 0
#define SM_A_LO 16384
#define SM_B_HI 32768
#define SM_B_LO 65536
#define SM_DATA 1024
#define TC_SMEM (SM_DATA + 2*STAGE_BYTES)

#if HAS_TCGEN05
static constexpr uint32_t IDESC_BF16 =
    (1u << 4) | (1u << 7) | (1u << 10) | ((256 / 8) << 17) | ((128 / 16) << 24);

__device__ __forceinline__ void load_slab128(
    uint32_t sbase, int stage,
    const __nv_bfloat16* __restrict__ Ahi, const __nv_bfloat16* __restrict__ Alo,
    const __nv_bfloat16* __restrict__ Bhi, const __nv_bfloat16* __restrict__ Blo,
    int m0, int n0, int k0, int K)
{
    const int tid = threadIdx.x;
    const uint32_t base = sbase + SM_DATA + stage * STAGE_BYTES;
#pragma unroll
    for (int i = 0; i < 4; i++) {
        int idx = i * 256 + tid;
        int row = idx >> 3, c4 = idx & 7;
        int off = row * 128 + c4 * 16;
        int sw  = off ^ ((off >> 3) & 0x70);
        size_t g = (size_t)(m0 + row) * K + k0 + c4 * 8;
        CP_ASYNC16(base + SM_A_HI + sw, Ahi + g);
        CP_ASYNC16(base + SM_A_LO + sw, Alo + g);
    }
#pragma unroll
    for (int i = 0; i < 8; i++) {
        int idx = i * 256 + tid;
        int row = idx >> 3, c4 = idx & 7;
        int off = row * 128 + c4 * 16;
        int sw  = off ^ ((off >> 3) & 0x70);
        size_t g = (size_t)(n0 + row) * K + k0 + c4 * 8;
        CP_ASYNC16(base + SM_B_HI + sw, Bhi + g);
        CP_ASYNC16(base + SM_B_LO + sw, Blo + g);
    }
    CP_COMMIT();
}
#endif

template<int MODE>
__global__ void __launch_bounds__(256)
tc_gemm(const __nv_bfloat16* __restrict__ Ahi, const __nv_bfloat16* __restrict__ Alo,
        const __nv_bfloat16* __restrict__ Bhi, const __nv_bfloat16* __restrict__ Blo,
        const float* __restrict__ bias, const float* __restrict__ res,
        float* __restrict__ Cf, int M, int N, int K)
{
    extern __shared__ char smx[];
#if HAS_TCGEN05
    const uint32_t sb = smem_u32(smx);
    const int tid = threadIdx.x;
    const int wid = tid >> 5, lane = tid & 31;
    const int m0 = blockIdx.y * TM, n0 = blockIdx.x * TN;

    if (wid == 0) { TCGEN05_ALLOC(sb, 256); TCGEN05_RELINQ(); }
    if (tid == 0) { MBARRIER_INIT(sb + 8, 1); MBARRIER_INIT(sb + 16, 1); }
    __syncthreads();
    uint32_t tmem;
    asm volatile("ld.shared.b32 %0, [%1];" : "=r"(tmem) : "r"(sb));

    const int NS = K / TK;
    load_slab128(sb, 0, Ahi, Alo, Bhi, Blo, m0, n0, 0, K);

    int ph0 = 0, ph1 = 0;
    for (int s = 0; s < NS; s++) {
        const int buf = s & 1;
        if (s + 1 < NS) {
            const int nb = 1 - buf;
            if (s >= 1) {
                if (nb == 0) { MBARRIER_WAIT_PARITY(sb + 8,  ph0); ph0 ^= 1; }
                else         { MBARRIER_WAIT_PARITY(sb + 16, ph1); ph1 ^= 1; }
            }
            load_slab128(sb, nb, Ahi, Alo, Bhi, Blo, m0, n0, (s + 1) * TK, K);
            CP_WAIT(1);
        } else {
            CP_WAIT(0);
        }
        FENCE_ASYNC_SHARED();
        __syncthreads();
        if (wid == 0) {
            TCGEN05_FENCE_AFTER();
            if (elect_one()) {
                const uint32_t tb = sb + SM_DATA + buf * STAGE_BYTES;
                const uint64_t ah = MKD128(tb + SM_A_HI);
                const uint64_t al = MKD128(tb + SM_A_LO);
                const uint64_t bh = MKD128(tb + SM_B_HI);
                const uint64_t bl = MKD128(tb + SM_B_LO);
#pragma unroll
                for (int ks = 0; ks < 4; ks++) {
                    const uint32_t en0 = (s == 0 && ks == 0) ? 0u : 1u;
                    mma_bf16_ss(tmem, ah + ks * 2, bh + ks * 2, IDESC_BF16, en0);
                    mma_bf16_ss(tmem, ah + ks * 2, bl + ks * 2, IDESC_BF16, 1u);
                    mma_bf16_ss(tmem, al + ks * 2, bh + ks * 2, IDESC_BF16, 1u);
                }
                TCGEN05_COMMIT(sb + 8 + buf * 8);
            }
        }
    }
    {
        const int lb = (NS - 1) & 1;
        if (lb == 0) { MBARRIER_WAIT_PARITY(sb + 8,  ph0); }
        else         { MBARRIER_WAIT_PARITY(sb + 16, ph1); }
    }
    TCGEN05_FENCE_AFTER();

    const int sub = wid & 3;
    const int cg  = wid >> 2;
    const int row = m0 + sub * 32 + lane;
#pragma unroll
    for (int ch = 0; ch < 4; ch++) {
        const int colb = cg * 128 + ch * 32;
        uint32_t r[32];
        TCGEN05_LD_32X32B_X32(r, tmem + colb);
        TCGEN05_WAIT_LD();
        const size_t base = (size_t)row * N + n0 + colb;
        const float4* bv = (const float4*)(bias + n0 + colb);
        float4* dst = (float4*)(Cf + base);
        const float4* rv = (MODE == 3) ? (const float4*)(res + base) : nullptr;
#pragma unroll
        for (int i = 0; i < 8; i++) {
            float4 b4 = bv[i];
            float4 o;
            o.x = __uint_as_float(r[i * 4 + 0]) + b4.x;
            o.y = __uint_as_float(r[i * 4 + 1]) + b4.y;
            o.z = __uint_as_float(r[i * 4 + 2]) + b4.z;
            o.w = __uint_as_float(r[i * 4 + 3]) + b4.w;
            if (MODE == 3) {
                float4 t = rv[i];
                o.x += t.x; o.y += t.y; o.z += t.z; o.w += t.w;
            }
            dst[i] = o;
        }
    }
    TCGEN05_FENCE_BEFORE();
    __syncthreads();
    if (tid == 0) { MBARRIER_INVAL(sb + 8); MBARRIER_INVAL(sb + 16); }
    __syncthreads();
    if (wid == 0) TCGEN05_DEALLOC(tmem, 256);
#else
    // SIMT fallback
    float* As = (float*)smx;
    float* Bs = As + 16 * 128;
    const int tid = threadIdx.x;
    const int m0 = blockIdx.y * TM, n0x = blockIdx.x * TN;
    const int tx = tid & 15, ty = tid >> 4;
    const int mr = ty * 8, nr = tx * 8;
    for (int half = 0; half < 2; half++) {
        const int n0 = n0x + half * 128;
        float acc[8][8];
#pragma unroll
        for (int i = 0; i < 8; i++)
#pragma unroll
            for (int j = 0; j < 8; j++) acc[i][j] = 0.f;
        for (int k0 = 0; k0 < K; k0 += 16) {
            __syncthreads();
#pragma unroll
            for (int i = 0; i < 8; i++) {
                int idx = i * 256 + tid;
                int kk = idx >> 7, mm = idx & 127;
                size_t ga = (size_t)(m0 + mm) * K + k0 + kk;
                size_t gb = (size_t)(n0 + mm) * K + k0 + kk;
                As[kk * 128 + mm] = __bfloat162float(Ahi[ga]) + __bfloat162float(Alo[ga]);
                Bs[kk * 128 + mm] = __bfloat162float(Bhi[gb]) + __bfloat162float(Blo[gb]);
            }
            __syncthreads();
#pragma unroll
            for (int kk = 0; kk < 16; kk++) {
                float a0[8], b0[8];
#pragma unroll
                for (int i = 0; i < 8; i++) a0[i] = As[kk * 128 + mr + i];
#pragma unroll
                for (int j = 0; j < 8; j++) b0[j] = Bs[kk * 128 + nr + j];
#pragma unroll
                for (int i = 0; i < 8; i++)
#pragma unroll
                    for (int j = 0; j < 8; j++)
                        acc[i][j] = fmaf(a0[i], b0[j], acc[i][j]);
            }
        }
#pragma unroll
        for (int i = 0; i < 8; i++) {
            const int row = m0 + mr + i;
#pragma unroll
            for (int j = 0; j < 8; j++) {
                const int col = n0 + nr + j;
                const size_t idx = (size_t)row * N + col;
                float v = acc[i][j] + bias[col];
                if (MODE == 2) Cf[idx] = v;
                else           Cf[idx] = v + res[idx];
            }
        }
    }
#endif
}

// ======================= TM256 tc GEMM (MoE, z = expert) ======================
// two 128-row A tiles share the B slab; two accumulators (TMEM cols 0 / 256)
// MODE 0: gelu(acc+bias) -> split bf16 Chi/Clo   MODE 1: Cf = acc + bias
#define T2K 32
#define ST2_BYTES 65536
#define S2_A0HI 0
#define S2_A0LO 8192
#define S2_A1HI 16384
#define S2_A1LO 24576
#define S2_BHI  32768
#define S2_BLO  49152
#define TC2_SMEM (1024 + 3*ST2_BYTES)   // 197632

#if HAS_TCGEN05
__device__ __forceinline__ void load_slab256(
    uint32_t sbase, int stage,
    const __nv_bfloat16* __restrict__ Ahi, const __nv_bfloat16* __restrict__ Alo,
    const __nv_bfloat16* __restrict__ Bhi, const __nv_bfloat16* __restrict__ Blo,
    int m0, int n0, int k0, int K)
{
    const int tid = threadIdx.x;
    const uint32_t base = sbase + 1024 + stage * ST2_BYTES;
    // A: 256 rows x 32 bf16 (64B rows), SW64
#pragma unroll
    for (int i = 0; i < 4; i++) {
        int idx = i * 256 + tid;           // 0..1023
        int row = idx >> 2, c4 = idx & 3;  // row 0..255
        int off = (row & 127) * 64 + c4 * 16;
        int sw  = off ^ ((off >> 3) & 0x30);
        int tb  = (row >> 7) * 16384;      // A0 or A1 region
        size_t g = (size_t)(m0 + row) * K + k0 + c4 * 8;
        CP_ASYNC16(base + S2_A0HI + tb + sw, Ahi + g);
        CP_ASYNC16(base + S2_A0LO + tb + sw, Alo + g);
    }
    // B: 256 rows x 32 bf16
#pragma unroll
    for (int i = 0; i < 4; i++) {
        int idx = i * 256 + tid;
        int row = idx >> 2, c4 = idx & 3;
        int off = row * 64 + c4 * 16;
        int sw  = off ^ ((off >> 3) & 0x30);
        size_t g = (size_t)(n0 + row) * K + k0 + c4 * 8;
        CP_ASYNC16(base + S2_BHI + sw, Bhi + g);
        CP_ASYNC16(base + S2_BLO + sw, Blo + g);
    }
    CP_COMMIT();
}
#endif

template<int MODE>
__global__ void __launch_bounds__(256)
tc_gemm2(const __nv_bfloat16* __restrict__ Ahi, const __nv_bfloat16* __restrict__ Alo,
         const __nv_bfloat16* __restrict__ Bhi, const __nv_bfloat16* __restrict__ Blo,
         const float* __restrict__ bias, float* __restrict__ Cf,
         __nv_bfloat16* __restrict__ Chi, __nv_bfloat16* __restrict__ Clo,
         int N, int K, size_t sA, size_t sB, size_t sBias, size_t sC)
{
    extern __shared__ char smx[];
    const int z = blockIdx.z;
    Ahi += z * sA; Alo += z * sA;
    Bhi += z * sB; Blo += z * sB;
    bias += z * sBias;
    if (MODE == 0) { Chi += z * sC; Clo += z * sC; }
    else           { Cf  += z * sC; }
#if HAS_TCGEN05
    const uint32_t sb = smem_u32(smx);
    const int tid = threadIdx.x;
    const int wid = tid >> 5, lane = tid & 31;
    const int m0 = blockIdx.y * 256, n0 = blockIdx.x * 256;

    if (wid == 0) { TCGEN05_ALLOC(sb, 512); TCGEN05_RELINQ(); }
    if (tid == 0) {
        MBARRIER_INIT(sb + 8, 1); MBARRIER_INIT(sb + 16, 1); MBARRIER_INIT(sb + 24, 1);
    }
    __syncthreads();
    uint32_t tmem;
    asm volatile("ld.shared.b32 %0, [%1];" : "=r"(tmem) : "r"(sb));

    const int NS = K / T2K;
    load_slab256(sb, 0, Ahi, Alo, Bhi, Blo, m0, n0, 0, K);
    load_slab256(sb, 1, Ahi, Alo, Bhi, Blo, m0, n0, T2K, K);

    int phase[3] = {0, 0, 0};
    for (int s = 0; s < NS; s++) {
        const int st = s % 3;
        if (s + 2 < NS) {
            const int stn = (s + 2) % 3;
            if (s + 2 >= 3) {
                MBARRIER_WAIT_PARITY(sb + 8 + stn * 8, phase[stn]);
                phase[stn] ^= 1;
            }
            load_slab256(sb, stn, Ahi, Alo, Bhi, Blo, m0, n0, (s + 2) * T2K, K);
            CP_WAIT(2);
        } else if (s + 1 < NS) {
            CP_WAIT(1);
        } else {
            CP_WAIT(0);
        }
        FENCE_ASYNC_SHARED();
        __syncthreads();
        if (wid == 0) {
            TCGEN05_FENCE_AFTER();
            if (elect_one()) {
                const uint32_t tb = sb + 1024 + st * ST2_BYTES;
                const uint64_t a0h = MKD64(tb + S2_A0HI);
                const uint64_t a0l = MKD64(tb + S2_A0LO);
                const uint64_t a1h = MKD64(tb + S2_A1HI);
                const uint64_t a1l = MKD64(tb + S2_A1LO);
                const uint64_t bh  = MKD64(tb + S2_BHI);
                const uint64_t bl  = MKD64(tb + S2_BLO);
#pragma unroll
                for (int ks = 0; ks < 2; ks++) {
                    const uint32_t en0 = (s == 0 && ks == 0) ? 0u : 1u;
                    mma_bf16_ss(tmem,       a0h + ks * 2, bh + ks * 2, IDESC_BF16, en0);
                    mma_bf16_ss(tmem,       a0h + ks * 2, bl + ks * 2, IDESC_BF16, 1u);
                    mma_bf16_ss(tmem,       a0l + ks * 2, bh + ks * 2, IDESC_BF16, 1u);
                    mma_bf16_ss(tmem + 256, a1h + ks * 2, bh + ks * 2, IDESC_BF16, en0);
                    mma_bf16_ss(tmem + 256, a1h + ks * 2, bl + ks * 2, IDESC_BF16, 1u);
                    mma_bf16_ss(tmem + 256, a1l + ks * 2, bh + ks * 2, IDESC_BF16, 1u);
                }
                TCGEN05_COMMIT(sb + 8 + st * 8);
            }
        }
    }
    {
        const int stl = (NS - 1) % 3;
        MBARRIER_WAIT_PARITY(sb + 8 + stl * 8, phase[stl]);
    }
    TCGEN05_FENCE_AFTER();

    // epilogue: warps 0-3 -> acc0 (rows m0..+127), warps 4-7 -> acc1
    const int accSel = wid >> 2;
    const int sub = wid & 3;
    const int row = m0 + accSel * 128 + sub * 32 + lane;
    const uint32_t tacc = tmem + accSel * 256;
#pragma unroll
    for (int ch = 0; ch < 8; ch++) {
        const int colb = ch * 32;
        uint32_t r[32];
        TCGEN05_LD_32X32B_X32(r, tacc + colb);
        TCGEN05_WAIT_LD();
        const size_t base = (size_t)row * N + n0 + colb;
        const float4* bv = (const float4*)(bias + n0 + colb);
        if (MODE == 0) {
            uint4* dh = (uint4*)(Chi + base);
            uint4* dl = (uint4*)(Clo + base);
#pragma unroll
            for (int i = 0; i < 4; i++) {
                uint32_t hp[4], lp[4];
#pragma unroll
                for (int p = 0; p < 4; p++) {
                    float4 b4 = bv[i * 2 + (p >> 1)];
                    float b0 = (p & 1) ? b4.z : b4.x;
                    float b1 = (p & 1) ? b4.w : b4.y;
                    float v0 = __uint_as_float(r[i * 8 + p * 2 + 0]) + b0;
                    float v1 = __uint_as_float(r[i * 8 + p * 2 + 1]) + b1;
                    float g0 = 0.5f * v0 * (1.f + erff(v0 * 0.70710678118654752f));
                    float g1 = 0.5f * v1 * (1.f + erff(v1 * 0.70710678118654752f));
                    __nv_bfloat16 h0 = __float2bfloat16(g0);
                    __nv_bfloat16 h1 = __float2bfloat16(g1);
                    __nv_bfloat16 l0 = __float2bfloat16(g0 - __bfloat162float(h0));
                    __nv_bfloat16 l1 = __float2bfloat16(g1 - __bfloat162float(h1));
                    hp[p] = (uint32_t)__bfloat16_as_ushort(h0) |
                            ((uint32_t)__bfloat16_as_ushort(h1) << 16);
                    lp[p] = (uint32_t)__bfloat16_as_ushort(l0) |
                            ((uint32_t)__bfloat16_as_ushort(l1) << 16);
                }
                dh[i] = make_uint4(hp[0], hp[1], hp[2], hp[3]);
                dl[i] = make_uint4(lp[0], lp[1], lp[2], lp[3]);
            }
        } else {
            float4* dst = (float4*)(Cf + base);
#pragma unroll
            for (int i = 0; i < 8; i++) {
                float4 b4 = bv[i];
                float4 o;
                o.x = __uint_as_float(r[i * 4 + 0]) + b4.x;
                o.y = __uint_as_float(r[i * 4 + 1]) + b4.y;
                o.z = __uint_as_float(r[i * 4 + 2]) + b4.z;
                o.w = __uint_as_float(r[i * 4 + 3]) + b4.w;
                dst[i] = o;
            }
        }
    }
    TCGEN05_FENCE_BEFORE();
    __syncthreads();
    if (tid == 0) {
        MBARRIER_INVAL(sb + 8); MBARRIER_INVAL(sb + 16); MBARRIER_INVAL(sb + 24);
    }
    __syncthreads();
    if (wid == 0) TCGEN05_DEALLOC(tmem, 512);
#else
    // SIMT fallback: 4 sub-blocks of 128x128
    float* As = (float*)smx;
    float* Bs = As + 16 * 128;
    const int tid = threadIdx.x;
    const int tx = tid & 15, ty = tid >> 4;
    const int mr = ty * 8, nr = tx * 8;
    for (int mh = 0; mh < 2; mh++)
    for (int nh = 0; nh < 2; nh++) {
        const int m0 = blockIdx.y * 256 + mh * 128;
        const int n0 = blockIdx.x * 256 + nh * 128;
        float acc[8][8];
#pragma unroll
        for (int i = 0; i < 8; i++)
#pragma unroll
            for (int j = 0; j < 8; j++) acc[i][j] = 0.f;
        for (int k0 = 0; k0 < K; k0 += 16) {
            __syncthreads();
#pragma unroll
            for (int i = 0; i < 8; i++) {
                int idx = i * 256 + tid;
                int kk = idx >> 7, mm = idx & 127;
                size_t ga = (size_t)(m0 + mm) * K + k0 + kk;
                size_t gb = (size_t)(n0 + mm) * K + k0 + kk;
                As[kk * 128 + mm] = __bfloat162float(Ahi[ga]) + __bfloat162float(Alo[ga]);
                Bs[kk * 128 + mm] = __bfloat162float(Bhi[gb]) + __bfloat162float(Blo[gb]);
            }
            __syncthreads();
#pragma unroll
            for (int kk = 0; kk < 16; kk++) {
                float a0[8], b0[8];
#pragma unroll
                for (int i = 0; i < 8; i++) a0[i] = As[kk * 128 + mr + i];
#pragma unroll
                for (int j = 0; j < 8; j++) b0[j] = Bs[kk * 128 + nr + j];
#pragma unroll
                for (int i = 0; i < 8; i++)
#pragma unroll
                    for (int j = 0; j < 8; j++)
                        acc[i][j] = fmaf(a0[i], b0[j], acc[i][j]);
            }
        }
#pragma unroll
        for (int i = 0; i < 8; i++) {
            const int row = m0 + mr + i;
#pragma unroll
            for (int j = 0; j < 8; j++) {
                const int col = n0 + nr + j;
                const size_t idx = (size_t)row * N + col;
                float v = acc[i][j] + bias[col];
                if (MODE == 0) {
                    float g = 0.5f * v * (1.f + erff(v * 0.70710678118654752f));
                    __nv_bfloat16 h = __float2bfloat16(g);
                    Chi[idx] = h;
                    Clo[idx] = __float2bfloat16(g - __bfloat162float(h));
                } else {
                    Cf[idx] = v;
                }
            }
        }
    }
#endif
}

// ---------------- transpose + bf16 split: W[e][K][N] -> T[e][N][K] -------------
__global__ void __launch_bounds__(256)
transpose_split(const float* __restrict__ W, __nv_bfloat16* __restrict__ Thi,
                __nv_bfloat16* __restrict__ Tlo, int K, int N)
{
    __shared__ float t[32][33];
    const int e = blockIdx.z;
    const float* Wp = W + (size_t)e * K * N;
    __nv_bfloat16* th = Thi + (size_t)e * K * N;
    __nv_bfloat16* tl = Tlo + (size_t)e * K * N;
    const int k0 = blockIdx.x * 32, n0 = blockIdx.y * 32;
    const int x = threadIdx.x & 31, y = threadIdx.x >> 5;
#pragma unroll
    for (int i = 0; i < 32; i += 8)
        t[y + i][x] = Wp[(size_t)(k0 + y + i) * N + n0 + x];
    __syncthreads();
#pragma unroll
    for (int i = 0; i < 32; i += 8) {
        float v = t[x][y + i];
        __nv_bfloat16 h = __float2bfloat16(v);
        float lo = v - __bfloat162float(h);
        const size_t idx = (size_t)(n0 + y + i) * K + k0 + x;
        th[idx] = h;
        tl[idx] = __float2bfloat16(lo);
    }
}

// ---------------- fp32 -> split bf16 ---------------------------------------------
__global__ void __launch_bounds__(256)
split_bf16(const float* __restrict__ x, __nv_bfloat16* __restrict__ hi,
           __nv_bfloat16* __restrict__ lo, int n4)
{
    int i = blockIdx.x * 256 + threadIdx.x;
    if (i >= n4) return;
    float4 v = ((const float4*)x)[i];
    __nv_bfloat16 h0 = __float2bfloat16(v.x), h1 = __float2bfloat16(v.y);
    __nv_bfloat16 h2 = __float2bfloat16(v.z), h3 = __float2bfloat16(v.w);
    uint2 hp, lp;
    hp.x = (uint32_t)__bfloat16_as_ushort(h0) | ((uint32_t)__bfloat16_as_ushort(h1) << 16);
    hp.y = (uint32_t)__bfloat16_as_ushort(h2) | ((uint32_t)__bfloat16_as_ushort(h3) << 16);
    __nv_bfloat16 l0 = __float2bfloat16(v.x - __bfloat162float(h0));
    __nv_bfloat16 l1 = __float2bfloat16(v.y - __bfloat162float(h1));
    __nv_bfloat16 l2 = __float2bfloat16(v.z - __bfloat162float(h2));
    __nv_bfloat16 l3 = __float2bfloat16(v.w - __bfloat162float(h3));
    lp.x = (uint32_t)__bfloat16_as_ushort(l0) | ((uint32_t)__bfloat16_as_ushort(l1) << 16);
    lp.y = (uint32_t)__bfloat16_as_ushort(l2) | ((uint32_t)__bfloat16_as_ushort(l3) << 16);
    ((uint2*)hi)[i] = hp;
    ((uint2*)lo)[i] = lp;
}

// ---------------- attention: 2 CTAs per (b,h), 98 queries each ------------------
#define KPAD 65
__global__ void __launch_bounds__(256)
attn_kernel(const float* __restrict__ qh, const float* __restrict__ kh,
            const float* __restrict__ vh, float* __restrict__ ctx)
{
    const int b = blockIdx.x / Hq;
    const int h = blockIdx.x % Hq;
    const int qbase = blockIdx.y * 98;
    const int qend  = min(196, qbase + 98);
    extern __shared__ float sm[];
    float* Ks = sm;
    float* Vs = Ks + Sq * KPAD;
    float* Ps = Vs + Sq * DHq;
    float* Qs = Ps + 8 * 208;
    const int tid = threadIdx.x;
    for (int i = tid; i < Sq * DHq; i += 256) {
        int s = i / DHq, d = i % DHq;
        size_t gidx = (size_t)(b * Sq + s) * Dq + h * DHq + d;
        Ks[s * KPAD + d] = kh[gidx];
        Vs[s * DHq  + d] = vh[gidx];
    }
    __syncthreads();
    const int warp = tid >> 5, lane = tid & 31;
    float* p    = Ps + warp * 208;
    float* qrow = Qs + warp * DHq;
    for (int q = qbase + warp; q < qend; q += 8) {
        for (int d = lane; d < DHq; d += 32)
            qrow[d] = qh[(size_t)(b * Sq + q) * Dq + h * DHq + d];
        __syncwarp();
        float lmax = -1e30f;
        for (int col = lane; col < Sq; col += 32) {
            float s = 0.f;
            const float* kr = Ks + col * KPAD;
#pragma unroll 16
            for (int d = 0; d < DHq; d++) s = fmaf(qrow[d], kr[d], s);
            s *= 0.125f;
            p[col] = s;
            lmax = fmaxf(lmax, s);
        }
#pragma unroll
        for (int o = 16; o; o >>= 1) lmax = fmaxf(lmax, __shfl_xor_sync(0xffffffffu, lmax, o));
        float lsum = 0.f;
        for (int col = lane; col < Sq; col += 32) {
            float e = __expf(p[col] - lmax);
            p[col] = e;
            lsum += e;
        }
#pragma unroll
        for (int o = 16; o; o >>= 1) lsum += __shfl_xor_sync(0xffffffffu, lsum, o);
        const float inv = 1.f / lsum;
        __syncwarp();
        for (int d = lane; d < DHq; d += 32) {
            float a = 0.f;
            for (int k = 0; k < Sq; k++) a = fmaf(p[k], Vs[k * DHq + d], a);
            ctx[(size_t)(b * Sq + q) * Dq + h * DHq + d] = a * inv;
        }
        __syncwarp();
    }
}

// ---------------- gate softmax ----------------------------------------------------
__global__ void __launch_bounds__(256)
gate_kernel(const float* __restrict__ x, const float* __restrict__ Wg,
            const float* __restrict__ bg, float* __restrict__ gates)
{
    const int warp = (blockIdx.x * 256 + threadIdx.x) >> 5;
    const int lane = threadIdx.x & 31;
    if (warp >= NTOK) return;
    const float* xr = x + (size_t)warp * Dq;
    float lg[Eq];
#pragma unroll
    for (int e = 0; e < Eq; e++) lg[e] = 0.f;
    for (int d = lane; d < Dq; d += 32) {
        float xv = xr[d];
#pragma unroll
        for (int e = 0; e < Eq; e++) lg[e] = fmaf(xv, Wg[d * Eq + e], lg[e]);
    }
#pragma unroll
    for (int e = 0; e < Eq; e++)
#pragma unroll
        for (int o = 16; o; o >>= 1) lg[e] += __shfl_xor_sync(0xffffffffu, lg[e], o);
    if (lane == 0) {
        float m = -1e30f;
#pragma unroll
        for (int e = 0; e < Eq; e++) { lg[e] += bg[e]; m = fmaxf(m, lg[e]); }
        float s = 0.f;
#pragma unroll
        for (int e = 0; e < Eq; e++) { lg[e] = __expf(lg[e] - m); s += lg[e]; }
        float inv = 1.f / s;
#pragma unroll
        for (int e = 0; e < Eq; e++) gates[(size_t)warp * Eq + e] = lg[e] * inv;
    }
}

// ---------------- LN1 (emits split-bf16) -------------------------------------------
__global__ void __launch_bounds__(256)
ln_kernel(const float* __restrict__ a, const float* __restrict__ g,
          const float* __restrict__ be, float* __restrict__ out,
          __nv_bfloat16* __restrict__ ohi, __nv_bfloat16* __restrict__ olo)
{
    const int row = blockIdx.x;
    const float* ar = a + (size_t)row * Dq;
    float v[3];
    float s = 0.f, s2 = 0.f;
#pragma unroll
    for (int i = 0; i < 3; i++) {
        int d = threadIdx.x + i * 256;
        float x = ar[d];
        v[i] = x;
        s += x; s2 = fmaf(x, x, s2);
    }
    __shared__ float rs[8], rs2[8];
#pragma unroll
    for (int o = 16; o; o >>= 1) { s += __shfl_xor_sync(0xffffffffu, s, o); s2 += __shfl_xor_sync(0xffffffffu, s2, o); }
    const int warp = threadIdx.x >> 5, lane = threadIdx.x & 31;
    if (lane == 0) { rs[warp] = s; rs2[warp] = s2; }
    __syncthreads();
    if (warp == 0) {
        float t  = (lane < 8) ? rs[lane]  : 0.f;
        float t2 = (lane < 8) ? rs2[lane] : 0.f;
#pragma unroll
        for (int o = 4; o; o >>= 1) { t += __shfl_xor_sync(0xffffffffu, t, o); t2 += __shfl_xor_sync(0xffffffffu, t2, o); }
        if (lane == 0) { rs[0] = t; rs2[0] = t2; }
    }
    __syncthreads();
    const float mu  = rs[0] * (1.f / Dq);
    const float var = rs2[0] * (1.f / Dq) - mu * mu;
    const float inv = rsqrtf(var + 1e-5f);
#pragma unroll
    for (int i = 0; i < 3; i++) {
        int d = threadIdx.x + i * 256;
        float y = (v[i] - mu) * inv * g[d] + be[d];
        const size_t idx = (size_t)row * Dq + d;
        out[idx] = y;
        __nv_bfloat16 h = __float2bfloat16(y);
        ohi[idx] = h;
        olo[idx] = __float2bfloat16(y - __bfloat162float(h));
    }
}

// ---------------- LN2: fused gate-weighted expert reduction ------------------------
__global__ void __launch_bounds__(256)
ln2_kernel(const float* __restrict__ x, const float* __restrict__ y,
           const float* __restrict__ gates, const float* __restrict__ g,
           const float* __restrict__ be, float* __restrict__ out)
{
    const int row = blockIdx.x;
    __shared__ float sg[Eq];
    if (threadIdx.x < Eq) sg[threadIdx.x] = gates[(size_t)row * Eq + threadIdx.x];
    __syncthreads();
    float v[3];
    float s = 0.f, s2 = 0.f;
#pragma unroll
    for (int i = 0; i < 3; i++) {
        int d = threadIdx.x + i * 256;
        float val = x[(size_t)row * Dq + d];
#pragma unroll
        for (int e = 0; e < Eq; e++)
            val = fmaf(sg[e], y[(size_t)e * MPAD * Dq + (size_t)row * Dq + d], val);
        v[i] = val;
        s += val; s2 = fmaf(val, val, s2);
    }
    __shared__ float rs[8], rs2[8];
#pragma unroll
    for (int o = 16; o; o >>= 1) { s += __shfl_xor_sync(0xffffffffu, s, o); s2 += __shfl_xor_sync(0xffffffffu, s2, o); }
    const int warp = threadIdx.x >> 5, lane = threadIdx.x & 31;
    if (lane == 0) { rs[warp] = s; rs2[warp] = s2; }
    __syncthreads();
    if (warp == 0) {
        float t  = (lane < 8) ? rs[lane]  : 0.f;
        float t2 = (lane < 8) ? rs2[lane] : 0.f;
#pragma unroll
        for (int o = 4; o; o >>= 1) { t += __shfl_xor_sync(0xffffffffu, t, o); t2 += __shfl_xor_sync(0xffffffffu, t2, o); }
        if (lane == 0) { rs[0] = t; rs2[0] = t2; }
    }
    __syncthreads();
    const float mu  = rs[0] * (1.f / Dq);
    const float var = rs2[0] * (1.f / Dq) - mu * mu;
    const float inv = rsqrtf(var + 1e-5f);
#pragma unroll
    for (int i = 0; i < 3; i++) {
        int d = threadIdx.x + i * 256;
        out[(size_t)row * Dq + d] = (v[i] - mu) * inv * g[d] + be[d];
    }
}

// =================================================================================
extern "C" void kernel_launch(void* const* d_in, const int* in_sizes, int n_in,
                              void* d_out, int out_size)
{
    const float* q   = (const float*)d_in[0];
    const float* k   = (const float*)d_in[1];
    const float* v   = (const float*)d_in[2];
    const float* Wq  = (const float*)d_in[3];
    const float* bq  = (const float*)d_in[4];
    const float* Wk  = (const float*)d_in[5];
    const float* bk  = (const float*)d_in[6];
    const float* Wv  = (const float*)d_in[7];
    const float* bv  = (const float*)d_in[8];
    const float* Wo  = (const float*)d_in[9];
    const float* bo  = (const float*)d_in[10];
    const float* ln1g= (const float*)d_in[11];
    const float* ln1b= (const float*)d_in[12];
    const float* ln2g= (const float*)d_in[13];
    const float* ln2b= (const float*)d_in[14];
    const float* Wg  = (const float*)d_in[15];
    const float* bg  = (const float*)d_in[16];
    const float* W1  = (const float*)d_in[17];
    const float* b1  = (const float*)d_in[18];
    const float* W2  = (const float*)d_in[19];
    const float* b2  = (const float*)d_in[20];
    float* out = (float*)d_out;

    float *p_qh, *p_kh, *p_vh, *p_ctx, *p_tmp, *p_x, *p_y, *p_gates;
    __nv_bfloat16 *p_inhi, *p_inlo, *p_xhi, *p_xlo, *p_hhi, *p_hlo;
    __nv_bfloat16 *p_w1h, *p_w1l, *p_w2h, *p_w2l;
    __nv_bfloat16 *p_wqh, *p_wql, *p_wkh, *p_wkl, *p_wvh, *p_wvl, *p_woh, *p_wol;
    cudaGetSymbolAddress((void**)&p_qh,   d_qh);
    cudaGetSymbolAddress((void**)&p_kh,   d_kh);
    cudaGetSymbolAddress((void**)&p_vh,   d_vh);
    cudaGetSymbolAddress((void**)&p_ctx,  d_ctx);
    cudaGetSymbolAddress((void**)&p_tmp,  d_tmp);
    cudaGetSymbolAddress((void**)&p_x,    d_x);
    cudaGetSymbolAddress((void**)&p_y,    d_y);
    cudaGetSymbolAddress((void**)&p_gates,d_gates);
    cudaGetSymbolAddress((void**)&p_inhi, d_inhi);
    cudaGetSymbolAddress((void**)&p_inlo, d_inlo);
    cudaGetSymbolAddress((void**)&p_xhi,  d_xhi);
    cudaGetSymbolAddress((void**)&p_xlo,  d_xlo);
    cudaGetSymbolAddress((void**)&p_hhi,  d_hhi);
    cudaGetSymbolAddress((void**)&p_hlo,  d_hlo);
    cudaGetSymbolAddress((void**)&p_w1h,  d_w1t_hi);
    cudaGetSymbolAddress((void**)&p_w1l,  d_w1t_lo);
    cudaGetSymbolAddress((void**)&p_w2h,  d_w2t_hi);
    cudaGetSymbolAddress((void**)&p_w2l,  d_w2t_lo);
    cudaGetSymbolAddress((void**)&p_wqh,  d_wqt_hi);
    cudaGetSymbolAddress((void**)&p_wql,  d_wqt_lo);
    cudaGetSymbolAddress((void**)&p_wkh,  d_wkt_hi);
    cudaGetSymbolAddress((void**)&p_wkl,  d_wkt_lo);
    cudaGetSymbolAddress((void**)&p_wvh,  d_wvt_hi);
    cudaGetSymbolAddress((void**)&p_wvl,  d_wvt_lo);
    cudaGetSymbolAddress((void**)&p_woh,  d_wot_hi);
    cudaGetSymbolAddress((void**)&p_wol,  d_wot_lo);

    const dim3 blk(256);
    const dim3 gridD(Dq / TN, NTOK / TM);       // TM128 QKV/O grid (3, 49)
    const dim3 grid1(Fq / 256, MPAD / 256, Eq); // (12, 25, 8)
    const dim3 grid2(Dq / 256, MPAD / 256, Eq); // (3, 25, 8)
    const int n4 = NTOK * Dq / 4;
    const int sgrid = (n4 + 255) / 256;

    cudaFuncSetAttribute(tc_gemm<2>,  cudaFuncAttributeMaxDynamicSharedMemorySize, TC_SMEM);
    cudaFuncSetAttribute(tc_gemm<3>,  cudaFuncAttributeMaxDynamicSharedMemorySize, TC_SMEM);
    cudaFuncSetAttribute(tc_gemm2<0>, cudaFuncAttributeMaxDynamicSharedMemorySize, TC2_SMEM);
    cudaFuncSetAttribute(tc_gemm2<1>, cudaFuncAttributeMaxDynamicSharedMemorySize, TC2_SMEM);

    // weight transpose + bf16 split
    transpose_split<<<dim3(Dq/32, Dq/32, 1), blk>>>(Wq, p_wqh, p_wql, Dq, Dq);
    transpose_split<<<dim3(Dq/32, Dq/32, 1), blk>>>(Wk, p_wkh, p_wkl, Dq, Dq);
    transpose_split<<<dim3(Dq/32, Dq/32, 1), blk>>>(Wv, p_wvh, p_wvl, Dq, Dq);
    transpose_split<<<dim3(Dq/32, Dq/32, 1), blk>>>(Wo, p_woh, p_wol, Dq, Dq);
    transpose_split<<<dim3(Dq/32, Fq/32, Eq), blk>>>(W1, p_w1h, p_w1l, Dq, Fq);
    transpose_split<<<dim3(Fq/32, Dq/32, Eq), blk>>>(W2, p_w2h, p_w2l, Fq, Dq);

    // QKV projections (TM128 tc)
    split_bf16<<<sgrid, blk>>>(q, p_inhi, p_inlo, n4);
    tc_gemm<2><<<gridD, blk, TC_SMEM>>>(p_inhi, p_inlo, p_wqh, p_wql, bq,
                                        nullptr, p_qh, NTOK, Dq, Dq);
    split_bf16<<<sgrid, blk>>>(k, p_inhi, p_inlo, n4);
    tc_gemm<2><<<gridD, blk, TC_SMEM>>>(p_inhi, p_inlo, p_wkh, p_wkl, bk,
                                        nullptr, p_kh, NTOK, Dq, Dq);
    split_bf16<<<sgrid, blk>>>(v, p_inhi, p_inlo, n4);
    tc_gemm<2><<<gridD, blk, TC_SMEM>>>(p_inhi, p_inlo, p_wvh, p_wvl, bv,
                                        nullptr, p_vh, NTOK, Dq, Dq);

    // attention (2 CTAs per (b,h))
    const int smem_attn = (Sq * KPAD + Sq * DHq + 8 * 208 + 8 * DHq) * (int)sizeof(float);
    cudaFuncSetAttribute(attn_kernel, cudaFuncAttributeMaxDynamicSharedMemorySize, smem_attn);
    attn_kernel<<<dim3(Bq * Hq, 2), blk, smem_attn>>>(p_qh, p_kh, p_vh, p_ctx);

    // O projection + residual(q), LN1 (emits split-bf16 x)
    split_bf16<<<sgrid, blk>>>(p_ctx, p_inhi, p_inlo, n4);
    tc_gemm<3><<<gridD, blk, TC_SMEM>>>(p_inhi, p_inlo, p_woh, p_wol, bo,
                                        q, p_tmp, NTOK, Dq, Dq);
    ln_kernel<<<NTOK, blk>>>(p_tmp, ln1g, ln1b, p_x, p_xhi, p_xlo);

    // gate softmax
    gate_kernel<<<(NTOK * 32 + 255) / 256, blk>>>(p_x, Wg, bg, p_gates);

    // MoE: single z-merged launch per GEMM
    tc_gemm2<0><<<grid1, blk, TC2_SMEM>>>(
        p_xhi, p_xlo, p_w1h, p_w1l, b1, nullptr, p_hhi, p_hlo,
        Fq, Dq, (size_t)0, (size_t)Fq * Dq, (size_t)Fq, (size_t)MPAD * Fq);
    tc_gemm2<1><<<grid2, blk, TC2_SMEM>>>(
        p_hhi, p_hlo, p_w2h, p_w2l, b2, p_y, nullptr, nullptr,
        Dq, Fq, (size_t)MPAD * Fq, (size_t)Dq * Fq, (size_t)Dq, (size_t)MPAD * Dq);

    // residual + gate-weighted expert sum + LN2 -> output
    ln2_kernel<<<NTOK, blk>>>(p_x, p_y, p_gates, ln2g, ln2b, out);
}

// round 7
// speedup vs baseline: 5.6738x; 1.2016x over previous
#include <cuda_runtime.h>
#include <cuda.h>
#include <cuda_bf16.h>
#include <math.h>
#include <stdint.h>

#define Bq 32
#define Sq 196
#define Dq 768
#define Hq 12
#define Eq 8
#define Fq 3072
#define DHq 64
#define NTOK (Bq*Sq)
#define MPAD 6400

#define HAS_TCGEN05 (defined(__CUDA_ARCH_FEAT_SM103_ALL) || defined(__CUDA_ARCH_FEAT_SM100_ALL))

// ---------------- scratch ------------------------------------------------------
__device__ __align__(256) float d_qh [NTOK*Dq];
__device__ __align__(256) float d_kh [NTOK*Dq];
__device__ __align__(256) float d_vh [NTOK*Dq];
__device__ __align__(256) float d_ctx[NTOK*Dq];
__device__ __align__(256) float d_tmp[NTOK*Dq];
__device__ __align__(256) float d_x  [NTOK*Dq];
__device__ __align__(256) float d_y  [Eq*MPAD*Dq];
__device__ __align__(256) float d_gates[MPAD*Eq];

__device__ __align__(256) __nv_bfloat16 d_inhi[NTOK*Dq];
__device__ __align__(256) __nv_bfloat16 d_inlo[NTOK*Dq];
__device__ __align__(256) __nv_bfloat16 d_xhi[MPAD*Dq];
__device__ __align__(256) __nv_bfloat16 d_xlo[MPAD*Dq];
__device__ __align__(256) __nv_bfloat16 d_hhi[Eq*MPAD*Fq];
__device__ __align__(256) __nv_bfloat16 d_hlo[Eq*MPAD*Fq];
__device__ __align__(256) __nv_bfloat16 d_w1t_hi[Eq*Fq*Dq];
__device__ __align__(256) __nv_bfloat16 d_w1t_lo[Eq*Fq*Dq];
__device__ __align__(256) __nv_bfloat16 d_w2t_hi[Eq*Dq*Fq];
__device__ __align__(256) __nv_bfloat16 d_w2t_lo[Eq*Dq*Fq];
__device__ __align__(256) __nv_bfloat16 d_wqt_hi[Dq*Dq];
__device__ __align__(256) __nv_bfloat16 d_wqt_lo[Dq*Dq];
__device__ __align__(256) __nv_bfloat16 d_wkt_hi[Dq*Dq];
__device__ __align__(256) __nv_bfloat16 d_wkt_lo[Dq*Dq];
__device__ __align__(256) __nv_bfloat16 d_wvt_hi[Dq*Dq];
__device__ __align__(256) __nv_bfloat16 d_wvt_lo[Dq*Dq];
__device__ __align__(256) __nv_bfloat16 d_wot_hi[Dq*Dq];
__device__ __align__(256) __nv_bfloat16 d_wot_lo[Dq*Dq];

// ---------------- PTX helpers ---------------------------------------------------
__device__ __forceinline__ uint32_t smem_u32(const void* p) {
    uint32_t a;
    asm("{ .reg .u64 t; cvta.to.shared.u64 t, %1; cvt.u32.u64 %0, t; }" : "=r"(a) : "l"(p));
    return a;
}

#if HAS_TCGEN05
__device__ __forceinline__ bool elect_one() {
    uint32_t p;
    asm volatile("{\n .reg .pred p;\n elect.sync _|p, 0xFFFFFFFF;\n selp.b32 %0,1,0,p;\n}" : "=r"(p));
    return p != 0;
}
#define MBARRIER_INIT(addr, cnt) \
    asm volatile("mbarrier.init.shared.b64 [%0], %1;" :: "r"((uint32_t)(addr)), "r"((uint32_t)(cnt)) : "memory")
#define MBARRIER_INVAL(addr) \
    asm volatile("mbarrier.inval.shared.b64 [%0];" :: "r"((uint32_t)(addr)) : "memory")
#define MBARRIER_EXPECT_TX(addr, tx) \
    asm volatile("mbarrier.arrive.expect_tx.shared.b64 _, [%0], %1;" \
        :: "r"((uint32_t)(addr)), "r"((uint32_t)(tx)) : "memory")
#define MBARRIER_WAIT_PARITY(mbar, par) do { \
    uint32_t _m = (uint32_t)(mbar), _p = (uint32_t)(par), _d; \
    asm volatile("{\n\t.reg .pred p;\n\t" \
        "mbarrier.try_wait.parity.acquire.cta.shared::cta.b64 p, [%1], %2;\n\t" \
        "selp.b32 %0, 1, 0, p;\n\t}" : "=r"(_d) : "r"(_m), "r"(_p) : "memory"); \
    if (!_d) { \
        asm volatile("{\n\t.reg .pred P1;\n\t" \
            "WL_%=:\n\t" \
            "mbarrier.try_wait.parity.acquire.cta.shared::cta.b64 P1, [%0], %1, 0x989680;\n\t" \
            "@P1 bra.uni WD_%=;\n\tbra.uni WL_%=;\n\tWD_%=:\n\t}" \
            :: "r"(_m), "r"(_p) : "memory"); \
    } \
} while(0)
#define TCGEN05_ALLOC(a, n) \
    asm volatile("tcgen05.alloc.cta_group::1.sync.aligned.shared::cta.b32 [%0], %1;" \
        :: "r"((uint32_t)(a)), "r"((uint32_t)(n)) : "memory")
#define TCGEN05_DEALLOC(t, n) \
    asm volatile("tcgen05.dealloc.cta_group::1.sync.aligned.b32 %0, %1;" :: "r"(t), "r"(n))
#define TCGEN05_RELINQ() \
    asm volatile("tcgen05.relinquish_alloc_permit.cta_group::1.sync.aligned;")
#define TCGEN05_COMMIT(m) \
    asm volatile("tcgen05.commit.cta_group::1.mbarrier::arrive::one.shared::cluster.b64 [%0];" \
        :: "r"((uint32_t)(m)) : "memory")
#define TCGEN05_FENCE_AFTER()  asm volatile("tcgen05.fence::after_thread_sync;" ::: "memory")
#define TCGEN05_FENCE_BEFORE() asm volatile("tcgen05.fence::before_thread_sync;" ::: "memory")
#define TCGEN05_WAIT_LD() asm volatile("tcgen05.wait::ld.sync.aligned;" ::: "memory")
#define FENCE_ASYNC_SHARED() asm volatile("fence.proxy.async.shared::cta;" ::: "memory")
#define CP_ASYNC16(dst, src) \
    asm volatile("cp.async.cg.shared.global [%0], [%1], 16;" :: "r"((uint32_t)(dst)), "l"(src))
#define CP_COMMIT() asm volatile("cp.async.commit_group;" ::: "memory")
#define CP_WAIT(n)  asm volatile("cp.async.wait_group %0;" :: "n"(n) : "memory")
#define TMA_LOAD_3D(sm, map, cx, cy, cz, mb) \
    asm volatile("cp.async.bulk.tensor.3d.shared::cta.global.tile.mbarrier::complete_tx::bytes " \
        "[%0], [%1, {%2, %3, %4}], [%5];" \
        :: "r"((uint32_t)(sm)), "l"(map), "r"((int32_t)(cx)), "r"((int32_t)(cy)), \
           "r"((int32_t)(cz)), "r"((uint32_t)(mb)) : "memory")
#define TCGEN05_LD_32X32B_X32(r, ta) \
    asm volatile("tcgen05.ld.sync.aligned.32x32b.x32.b32 " \
        "{%0, %1, %2, %3, %4, %5, %6, %7, %8, %9, %10, %11, %12, %13, %14, %15, " \
        " %16, %17, %18, %19, %20, %21, %22, %23, %24, %25, %26, %27, %28, %29, %30, %31}, [%32];" \
        : "=r"((r)[0]), "=r"((r)[1]), "=r"((r)[2]), "=r"((r)[3]), "=r"((r)[4]), "=r"((r)[5]), \
          "=r"((r)[6]), "=r"((r)[7]), "=r"((r)[8]), "=r"((r)[9]), "=r"((r)[10]), "=r"((r)[11]), \
          "=r"((r)[12]), "=r"((r)[13]), "=r"((r)[14]), "=r"((r)[15]), "=r"((r)[16]), "=r"((r)[17]), \
          "=r"((r)[18]), "=r"((r)[19]), "=r"((r)[20]), "=r"((r)[21]), "=r"((r)[22]), "=r"((r)[23]), \
          "=r"((r)[24]), "=r"((r)[25]), "=r"((r)[26]), "=r"((r)[27]), "=r"((r)[28]), "=r"((r)[29]), \
          "=r"((r)[30]), "=r"((r)[31]) : "r"(ta))

static constexpr uint64_t DESC_SW128 =
    (uint64_t(2) << 61) | (uint64_t(1) << 46) | (uint64_t(64) << 32) | (uint64_t(1) << 16);
static constexpr uint64_t DESC_SW64 =
    (uint64_t(4) << 61) | (uint64_t(1) << 46) | (uint64_t(32) << 32) | (uint64_t(1) << 16);
#define MKD128(a) (DESC_SW128 | ((uint64_t)((a) >> 4) & 0x3FFF))
#define MKD64(a)  (DESC_SW64  | ((uint64_t)((a) >> 4) & 0x3FFF))

__device__ __forceinline__ void mma_bf16_ss(uint32_t d, uint64_t ad, uint64_t bd,
                                            uint32_t idesc, uint32_t en) {
    asm volatile(
        "{\n\t.reg .pred p;\n\tsetp.ne.u32 p, %5, 0;\n\t"
        "tcgen05.mma.cta_group::1.kind::f16 [%0], %1, %2, %3, {%4,%4,%4,%4}, p;\n\t}"
        :: "r"(d), "l"(ad), "l"(bd), "r"(idesc), "r"(0u), "r"(en) : "memory");
}
static constexpr uint32_t IDESC_BF16 =
    (1u << 4) | (1u << 7) | (1u << 10) | ((256 / 8) << 17) | ((128 / 16) << 24);
#endif

// ======================= TM128 tc GEMM (QKV / O-proj) =========================
#define TM 128
#define TN 256
#define TK 64
#define STAGE_BYTES 98304
#define SM_DATA 1024
#define TC_SMEM (SM_DATA + 2*STAGE_BYTES)

#if HAS_TCGEN05
__device__ __forceinline__ void load_slab128(
    uint32_t sbase, int stage,
    const __nv_bfloat16* __restrict__ Ahi, const __nv_bfloat16* __restrict__ Alo,
    const __nv_bfloat16* __restrict__ Bhi, const __nv_bfloat16* __restrict__ Blo,
    int m0, int n0, int k0, int K)
{
    const int tid = threadIdx.x;
    const uint32_t base = sbase + SM_DATA + stage * STAGE_BYTES;
#pragma unroll
    for (int i = 0; i < 4; i++) {
        int idx = i * 256 + tid;
        int row = idx >> 3, c4 = idx & 7;
        int off = row * 128 + c4 * 16;
        int sw  = off ^ ((off >> 3) & 0x70);
        size_t g = (size_t)(m0 + row) * K + k0 + c4 * 8;
        CP_ASYNC16(base + sw, Ahi + g);
        CP_ASYNC16(base + 16384 + sw, Alo + g);
    }
#pragma unroll
    for (int i = 0; i < 8; i++) {
        int idx = i * 256 + tid;
        int row = idx >> 3, c4 = idx & 7;
        int off = row * 128 + c4 * 16;
        int sw  = off ^ ((off >> 3) & 0x70);
        size_t g = (size_t)(n0 + row) * K + k0 + c4 * 8;
        CP_ASYNC16(base + 32768 + sw, Bhi + g);
        CP_ASYNC16(base + 65536 + sw, Blo + g);
    }
    CP_COMMIT();
}
#endif

template<int MODE>   // 2: C=AW+b   3: C=AW+b+res
__global__ void __launch_bounds__(256)
tc_gemm(const __nv_bfloat16* __restrict__ Ahi, const __nv_bfloat16* __restrict__ Alo,
        const __nv_bfloat16* __restrict__ Bhi, const __nv_bfloat16* __restrict__ Blo,
        const float* __restrict__ bias, const float* __restrict__ res,
        float* __restrict__ Cf, int M, int N, int K)
{
    extern __shared__ __align__(1024) char smx[];
#if HAS_TCGEN05
    const uint32_t sb = smem_u32(smx);
    const int tid = threadIdx.x;
    const int wid = tid >> 5, lane = tid & 31;
    const int m0 = blockIdx.y * TM, n0 = blockIdx.x * TN;

    if (wid == 0) { TCGEN05_ALLOC(sb, 256); TCGEN05_RELINQ(); }
    if (tid == 0) { MBARRIER_INIT(sb + 8, 1); MBARRIER_INIT(sb + 16, 1); }
    __syncthreads();
    uint32_t tmem;
    asm volatile("ld.shared.b32 %0, [%1];" : "=r"(tmem) : "r"(sb));

    const int NS = K / TK;
    load_slab128(sb, 0, Ahi, Alo, Bhi, Blo, m0, n0, 0, K);
    int ph0 = 0, ph1 = 0;
    for (int s = 0; s < NS; s++) {
        const int buf = s & 1;
        if (s + 1 < NS) {
            const int nb = 1 - buf;
            if (s >= 1) {
                if (nb == 0) { MBARRIER_WAIT_PARITY(sb + 8,  ph0); ph0 ^= 1; }
                else         { MBARRIER_WAIT_PARITY(sb + 16, ph1); ph1 ^= 1; }
            }
            load_slab128(sb, nb, Ahi, Alo, Bhi, Blo, m0, n0, (s + 1) * TK, K);
            CP_WAIT(1);
        } else {
            CP_WAIT(0);
        }
        FENCE_ASYNC_SHARED();
        __syncthreads();
        if (wid == 0) {
            TCGEN05_FENCE_AFTER();
            if (elect_one()) {
                const uint32_t tb = sb + SM_DATA + buf * STAGE_BYTES;
                const uint64_t ah = MKD128(tb), al = MKD128(tb + 16384);
                const uint64_t bh = MKD128(tb + 32768), bl = MKD128(tb + 65536);
#pragma unroll
                for (int ks = 0; ks < 4; ks++) {
                    const uint32_t en0 = (s == 0 && ks == 0) ? 0u : 1u;
                    mma_bf16_ss(tmem, ah + ks * 2, bh + ks * 2, IDESC_BF16, en0);
                    mma_bf16_ss(tmem, ah + ks * 2, bl + ks * 2, IDESC_BF16, 1u);
                    mma_bf16_ss(tmem, al + ks * 2, bh + ks * 2, IDESC_BF16, 1u);
                }
                TCGEN05_COMMIT(sb + 8 + buf * 8);
            }
        }
    }
    if (((NS - 1) & 1) == 0) { MBARRIER_WAIT_PARITY(sb + 8,  ph0); }
    else                     { MBARRIER_WAIT_PARITY(sb + 16, ph1); }
    TCGEN05_FENCE_AFTER();

    const int sub = wid & 3, cg = wid >> 2;
    const int row = m0 + sub * 32 + lane;
#pragma unroll
    for (int ch = 0; ch < 4; ch++) {
        const int colb = cg * 128 + ch * 32;
        uint32_t r[32];
        TCGEN05_LD_32X32B_X32(r, tmem + colb);
        TCGEN05_WAIT_LD();
        const size_t base = (size_t)row * N + n0 + colb;
        const float4* bv = (const float4*)(bias + n0 + colb);
        float4* dst = (float4*)(Cf + base);
        const float4* rv = (MODE == 3) ? (const float4*)(res + base) : nullptr;
#pragma unroll
        for (int i = 0; i < 8; i++) {
            float4 b4 = bv[i];
            float4 o;
            o.x = __uint_as_float(r[i*4+0]) + b4.x;
            o.y = __uint_as_float(r[i*4+1]) + b4.y;
            o.z = __uint_as_float(r[i*4+2]) + b4.z;
            o.w = __uint_as_float(r[i*4+3]) + b4.w;
            if (MODE == 3) { float4 t = rv[i]; o.x += t.x; o.y += t.y; o.z += t.z; o.w += t.w; }
            dst[i] = o;
        }
    }
    TCGEN05_FENCE_BEFORE();
    __syncthreads();
    if (tid == 0) { MBARRIER_INVAL(sb + 8); MBARRIER_INVAL(sb + 16); }
    __syncthreads();
    if (wid == 0) TCGEN05_DEALLOC(tmem, 256);
#else
    float* As = (float*)smx;
    float* Bs = As + 16 * 128;
    const int tid = threadIdx.x;
    const int m0 = blockIdx.y * TM, n0x = blockIdx.x * TN;
    const int tx = tid & 15, ty = tid >> 4;
    const int mr = ty * 8, nr = tx * 8;
    for (int half = 0; half < 2; half++) {
        const int n0 = n0x + half * 128;
        float acc[8][8];
#pragma unroll
        for (int i = 0; i < 8; i++)
#pragma unroll
            for (int j = 0; j < 8; j++) acc[i][j] = 0.f;
        for (int k0 = 0; k0 < K; k0 += 16) {
            __syncthreads();
#pragma unroll
            for (int i = 0; i < 8; i++) {
                int idx = i * 256 + tid;
                int kk = idx >> 7, mm = idx & 127;
                size_t ga = (size_t)(m0 + mm) * K + k0 + kk;
                size_t gb = (size_t)(n0 + mm) * K + k0 + kk;
                As[kk*128+mm] = __bfloat162float(Ahi[ga]) + __bfloat162float(Alo[ga]);
                Bs[kk*128+mm] = __bfloat162float(Bhi[gb]) + __bfloat162float(Blo[gb]);
            }
            __syncthreads();
#pragma unroll
            for (int kk = 0; kk < 16; kk++) {
                float a0[8], b0[8];
#pragma unroll
                for (int i = 0; i < 8; i++) a0[i] = As[kk*128+mr+i];
#pragma unroll
                for (int j = 0; j < 8; j++) b0[j] = Bs[kk*128+nr+j];
#pragma unroll
                for (int i = 0; i < 8; i++)
#pragma unroll
                    for (int j = 0; j < 8; j++)
                        acc[i][j] = fmaf(a0[i], b0[j], acc[i][j]);
            }
        }
#pragma unroll
        for (int i = 0; i < 8; i++) {
            const int row = m0 + mr + i;
#pragma unroll
            for (int j = 0; j < 8; j++) {
                const int col = n0 + nr + j;
                const size_t idx = (size_t)row * N + col;
                float v = acc[i][j] + bias[col];
                if (MODE == 2) Cf[idx] = v; else Cf[idx] = v + res[idx];
            }
        }
    }
#endif
}

// ======================= MoE GEMM: TMA producer/consumer ======================
// tile M256 x N256, TK=32, SW64, 3 stages x 64KB, z = expert
// MODE 0: gelu(acc+bias) -> split bf16    MODE 1: Cf = acc + bias
#define T2K 32
#define ST2 65536
#define TC2_SMEM (1024 + 3*ST2)

template<int MODE>
__global__ void __launch_bounds__(256)
tc_gemm2(const __grid_constant__ CUtensorMap mAh, const __grid_constant__ CUtensorMap mAl,
         const __grid_constant__ CUtensorMap mBh, const __grid_constant__ CUtensorMap mBl,
         const float* __restrict__ bias, float* __restrict__ Cf,
         __nv_bfloat16* __restrict__ Chi, __nv_bfloat16* __restrict__ Clo,
         int N, int K, size_t sBias, size_t sC,
         const __nv_bfloat16* __restrict__ Ahi, const __nv_bfloat16* __restrict__ Alo,
         const __nv_bfloat16* __restrict__ Bhi, const __nv_bfloat16* __restrict__ Blo,
         size_t sA, size_t sB)
{
    extern __shared__ __align__(1024) char smx[];
    const int z = blockIdx.z;
    bias += z * sBias;
#if HAS_TCGEN05
    const uint32_t sb = smem_u32(smx);
    const int tid = threadIdx.x;
    const int wid = tid >> 5, lane = tid & 31;
    const int m0 = blockIdx.y * 256, n0 = blockIdx.x * 256;
    const int za = (MODE == 0) ? 0 : z;

    if (wid == 0) { TCGEN05_ALLOC(sb, 512); TCGEN05_RELINQ(); }
    if (tid == 0) {
        MBARRIER_INIT(sb + 8,  1); MBARRIER_INIT(sb + 16, 1); MBARRIER_INIT(sb + 24, 1); // full
        MBARRIER_INIT(sb + 32, 1); MBARRIER_INIT(sb + 40, 1); MBARRIER_INIT(sb + 48, 1); // empty
        MBARRIER_INIT(sb + 56, 1);                                                        // done
        FENCE_ASYNC_SHARED();
    }
    __syncthreads();
    uint32_t tmem;
    asm volatile("ld.shared.b32 %0, [%1];" : "=r"(tmem) : "r"(sb));

    const int NS = K / T2K;
    if (wid == 1) {
        if (elect_one()) {
            for (int s = 0; s < NS; s++) {
                const int st = s % 3;
                if (s >= 3) MBARRIER_WAIT_PARITY(sb + 32 + st * 8, ((s / 3) - 1) & 1);
                MBARRIER_EXPECT_TX(sb + 8 + st * 8, 65536u);
                const uint32_t stb = sb + 1024 + st * ST2;
                const int k0 = s * T2K;
                TMA_LOAD_3D(stb,         &mAh, k0, m0, za, sb + 8 + st * 8);
                TMA_LOAD_3D(stb + 16384, &mAl, k0, m0, za, sb + 8 + st * 8);
                TMA_LOAD_3D(stb + 32768, &mBh, k0, n0, z,  sb + 8 + st * 8);
                TMA_LOAD_3D(stb + 49152, &mBl, k0, n0, z,  sb + 8 + st * 8);
            }
        }
    } else if (wid == 0) {
        TCGEN05_FENCE_AFTER();
        if (elect_one()) {
            for (int s = 0; s < NS; s++) {
                const int st = s % 3;
                MBARRIER_WAIT_PARITY(sb + 8 + st * 8, (s / 3) & 1);
                const uint32_t tb = sb + 1024 + st * ST2;
                const uint64_t a0h = MKD64(tb),         a0l = MKD64(tb + 16384);
                const uint64_t a1h = a0h + 512,         a1l = a0l + 512; // rows 128..255
                const uint64_t bh  = MKD64(tb + 32768), bl  = MKD64(tb + 49152);
#pragma unroll
                for (int ks = 0; ks < 2; ks++) {
                    const uint32_t en0 = (s == 0 && ks == 0) ? 0u : 1u;
                    mma_bf16_ss(tmem,       a0h + ks * 2, bh + ks * 2, IDESC_BF16, en0);
                    mma_bf16_ss(tmem,       a0h + ks * 2, bl + ks * 2, IDESC_BF16, 1u);
                    mma_bf16_ss(tmem,       a0l + ks * 2, bh + ks * 2, IDESC_BF16, 1u);
                    mma_bf16_ss(tmem + 256, a1h + ks * 2, bh + ks * 2, IDESC_BF16, en0);
                    mma_bf16_ss(tmem + 256, a1h + ks * 2, bl + ks * 2, IDESC_BF16, 1u);
                    mma_bf16_ss(tmem + 256, a1l + ks * 2, bh + ks * 2, IDESC_BF16, 1u);
                }
                TCGEN05_COMMIT(sb + 32 + st * 8);
            }
            TCGEN05_COMMIT(sb + 56);
        }
    }

    MBARRIER_WAIT_PARITY(sb + 56, 0);
    TCGEN05_FENCE_AFTER();

    const int accSel = wid >> 2, sub = wid & 3;
    const int row = m0 + accSel * 128 + sub * 32 + lane;
    const uint32_t tacc = tmem + accSel * 256;
    if (MODE == 0) { Chi += z * sC; Clo += z * sC; }
    else           { Cf  += z * sC; }
#pragma unroll
    for (int ch = 0; ch < 8; ch++) {
        const int colb = ch * 32;
        uint32_t r[32];
        TCGEN05_LD_32X32B_X32(r, tacc + colb);
        TCGEN05_WAIT_LD();
        const size_t base = (size_t)row * N + n0 + colb;
        const float4* bv = (const float4*)(bias + n0 + colb);
        if (MODE == 0) {
            uint4* dh = (uint4*)(Chi + base);
            uint4* dl = (uint4*)(Clo + base);
#pragma unroll
            for (int i = 0; i < 4; i++) {
                uint32_t hp[4], lp[4];
#pragma unroll
                for (int p = 0; p < 4; p++) {
                    float4 b4 = bv[i * 2 + (p >> 1)];
                    float b0 = (p & 1) ? b4.z : b4.x;
                    float b1 = (p & 1) ? b4.w : b4.y;
                    float v0 = __uint_as_float(r[i*8+p*2+0]) + b0;
                    float v1 = __uint_as_float(r[i*8+p*2+1]) + b1;
                    float g0 = 0.5f * v0 * (1.f + erff(v0 * 0.70710678118654752f));
                    float g1 = 0.5f * v1 * (1.f + erff(v1 * 0.70710678118654752f));
                    __nv_bfloat16 h0 = __float2bfloat16(g0);
                    __nv_bfloat16 h1 = __float2bfloat16(g1);
                    __nv_bfloat16 l0 = __float2bfloat16(g0 - __bfloat162float(h0));
                    __nv_bfloat16 l1 = __float2bfloat16(g1 - __bfloat162float(h1));
                    hp[p] = (uint32_t)__bfloat16_as_ushort(h0) | ((uint32_t)__bfloat16_as_ushort(h1) << 16);
                    lp[p] = (uint32_t)__bfloat16_as_ushort(l0) | ((uint32_t)__bfloat16_as_ushort(l1) << 16);
                }
                dh[i] = make_uint4(hp[0], hp[1], hp[2], hp[3]);
                dl[i] = make_uint4(lp[0], lp[1], lp[2], lp[3]);
            }
        } else {
            float4* dst = (float4*)(Cf + base);
#pragma unroll
            for (int i = 0; i < 8; i++) {
                float4 b4 = bv[i];
                float4 o;
                o.x = __uint_as_float(r[i*4+0]) + b4.x;
                o.y = __uint_as_float(r[i*4+1]) + b4.y;
                o.z = __uint_as_float(r[i*4+2]) + b4.z;
                o.w = __uint_as_float(r[i*4+3]) + b4.w;
                dst[i] = o;
            }
        }
    }
    TCGEN05_FENCE_BEFORE();
    __syncthreads();
    if (tid == 0) {
        MBARRIER_INVAL(sb + 8);  MBARRIER_INVAL(sb + 16); MBARRIER_INVAL(sb + 24);
        MBARRIER_INVAL(sb + 32); MBARRIER_INVAL(sb + 40); MBARRIER_INVAL(sb + 48);
        MBARRIER_INVAL(sb + 56);
    }
    __syncthreads();
    if (wid == 0) TCGEN05_DEALLOC(tmem, 512);
#else
    // SIMT fallback
    const __nv_bfloat16* Ah = Ahi + (size_t)((MODE == 0) ? 0 : z) * sA;
    const __nv_bfloat16* Al = Alo + (size_t)((MODE == 0) ? 0 : z) * sA;
    const __nv_bfloat16* Bh = Bhi + (size_t)z * sB;
    const __nv_bfloat16* Bl = Blo + (size_t)z * sB;
    if (MODE == 0) { Chi += z * sC; Clo += z * sC; }
    else           { Cf  += z * sC; }
    float* As = (float*)smx;
    float* Bs = As + 16 * 128;
    const int tid = threadIdx.x;
    const int tx = tid & 15, ty = tid >> 4;
    const int mr = ty * 8, nr = tx * 8;
    for (int mh = 0; mh < 2; mh++)
    for (int nh = 0; nh < 2; nh++) {
        const int m0 = blockIdx.y * 256 + mh * 128;
        const int n0 = blockIdx.x * 256 + nh * 128;
        float acc[8][8];
#pragma unroll
        for (int i = 0; i < 8; i++)
#pragma unroll
            for (int j = 0; j < 8; j++) acc[i][j] = 0.f;
        for (int k0 = 0; k0 < K; k0 += 16) {
            __syncthreads();
#pragma unroll
            for (int i = 0; i < 8; i++) {
                int idx = i * 256 + tid;
                int kk = idx >> 7, mm = idx & 127;
                size_t ga = (size_t)(m0 + mm) * K + k0 + kk;
                size_t gb = (size_t)(n0 + mm) * K + k0 + kk;
                As[kk*128+mm] = __bfloat162float(Ah[ga]) + __bfloat162float(Al[ga]);
                Bs[kk*128+mm] = __bfloat162float(Bh[gb]) + __bfloat162float(Bl[gb]);
            }
            __syncthreads();
#pragma unroll
            for (int kk = 0; kk < 16; kk++) {
                float a0[8], b0[8];
#pragma unroll
                for (int i = 0; i < 8; i++) a0[i] = As[kk*128+mr+i];
#pragma unroll
                for (int j = 0; j < 8; j++) b0[j] = Bs[kk*128+nr+j];
#pragma unroll
                for (int i = 0; i < 8; i++)
#pragma unroll
                    for (int j = 0; j < 8; j++)
                        acc[i][j] = fmaf(a0[i], b0[j], acc[i][j]);
            }
        }
#pragma unroll
        for (int i = 0; i < 8; i++) {
            const int row = m0 + mr + i;
#pragma unroll
            for (int j = 0; j < 8; j++) {
                const int col = n0 + nr + j;
                const size_t idx = (size_t)row * N + col;
                float v = acc[i][j] + bias[col];
                if (MODE == 0) {
                    float g = 0.5f * v * (1.f + erff(v * 0.70710678118654752f));
                    __nv_bfloat16 h = __float2bfloat16(g);
                    Chi[idx] = h;
                    Clo[idx] = __float2bfloat16(g - __bfloat162float(h));
                } else Cf[idx] = v;
            }
        }
    }
#endif
}

// ---------------- transpose + split -----------------------------------------------
__global__ void __launch_bounds__(256)
transpose_split(const float* __restrict__ W, __nv_bfloat16* __restrict__ Thi,
                __nv_bfloat16* __restrict__ Tlo, int K, int N)
{
    __shared__ float t[32][33];
    const int e = blockIdx.z;
    const float* Wp = W + (size_t)e * K * N;
    __nv_bfloat16* th = Thi + (size_t)e * K * N;
    __nv_bfloat16* tl = Tlo + (size_t)e * K * N;
    const int k0 = blockIdx.x * 32, n0 = blockIdx.y * 32;
    const int x = threadIdx.x & 31, y = threadIdx.x >> 5;
#pragma unroll
    for (int i = 0; i < 32; i += 8)
        t[y + i][x] = Wp[(size_t)(k0 + y + i) * N + n0 + x];
    __syncthreads();
#pragma unroll
    for (int i = 0; i < 32; i += 8) {
        float v = t[x][y + i];
        __nv_bfloat16 h = __float2bfloat16(v);
        const size_t idx = (size_t)(n0 + y + i) * K + k0 + x;
        th[idx] = h;
        tl[idx] = __float2bfloat16(v - __bfloat162float(h));
    }
}

// ---------------- fp32 -> split bf16 -----------------------------------------------
__global__ void __launch_bounds__(256)
split_bf16(const float* __restrict__ x, __nv_bfloat16* __restrict__ hi,
           __nv_bfloat16* __restrict__ lo, int n4)
{
    int i = blockIdx.x * 256 + threadIdx.x;
    if (i >= n4) return;
    float4 v = ((const float4*)x)[i];
    __nv_bfloat16 h0 = __float2bfloat16(v.x), h1 = __float2bfloat16(v.y);
    __nv_bfloat16 h2 = __float2bfloat16(v.z), h3 = __float2bfloat16(v.w);
    uint2 hp, lp;
    hp.x = (uint32_t)__bfloat16_as_ushort(h0) | ((uint32_t)__bfloat16_as_ushort(h1) << 16);
    hp.y = (uint32_t)__bfloat16_as_ushort(h2) | ((uint32_t)__bfloat16_as_ushort(h3) << 16);
    __nv_bfloat16 l0 = __float2bfloat16(v.x - __bfloat162float(h0));
    __nv_bfloat16 l1 = __float2bfloat16(v.y - __bfloat162float(h1));
    __nv_bfloat16 l2 = __float2bfloat16(v.z - __bfloat162float(h2));
    __nv_bfloat16 l3 = __float2bfloat16(v.w - __bfloat162float(h3));
    lp.x = (uint32_t)__bfloat16_as_ushort(l0) | ((uint32_t)__bfloat16_as_ushort(l1) << 16);
    lp.y = (uint32_t)__bfloat16_as_ushort(l2) | ((uint32_t)__bfloat16_as_ushort(l3) << 16);
    ((uint2*)hi)[i] = hp;
    ((uint2*)lo)[i] = lp;
}

// ---------------- attention: 4 CTAs per (b,h) --------------------------------------
#define KPAD 65
__global__ void __launch_bounds__(256)
attn_kernel(const float* __restrict__ qh, const float* __restrict__ kh,
            const float* __restrict__ vh, float* __restrict__ ctx)
{
    const int b = blockIdx.x / Hq;
    const int h = blockIdx.x % Hq;
    const int qbase = blockIdx.y * 49;
    const int qend  = min(196, qbase + 49);
    extern __shared__ float sm[];
    float* Ks = sm;
    float* Vs = Ks + Sq * KPAD;
    float* Ps = Vs + Sq * DHq;
    float* Qs = Ps + 8 * 208;
    const int tid = threadIdx.x;
    for (int i = tid; i < Sq * DHq; i += 256) {
        int s = i / DHq, d = i % DHq;
        size_t gidx = (size_t)(b * Sq + s) * Dq + h * DHq + d;
        Ks[s * KPAD + d] = kh[gidx];
        Vs[s * DHq  + d] = vh[gidx];
    }
    __syncthreads();
    const int warp = tid >> 5, lane = tid & 31;
    float* p    = Ps + warp * 208;
    float* qrow = Qs + warp * DHq;
    for (int q = qbase + warp; q < qend; q += 8) {
        for (int d = lane; d < DHq; d += 32)
            qrow[d] = qh[(size_t)(b * Sq + q) * Dq + h * DHq + d];
        __syncwarp();
        float lmax = -1e30f;
        for (int col = lane; col < Sq; col += 32) {
            float s = 0.f;
            const float* kr = Ks + col * KPAD;
#pragma unroll 16
            for (int d = 0; d < DHq; d++) s = fmaf(qrow[d], kr[d], s);
            s *= 0.125f;
            p[col] = s;
            lmax = fmaxf(lmax, s);
        }
#pragma unroll
        for (int o = 16; o; o >>= 1) lmax = fmaxf(lmax, __shfl_xor_sync(0xffffffffu, lmax, o));
        float lsum = 0.f;
        for (int col = lane; col < Sq; col += 32) {
            float e = __expf(p[col] - lmax);
            p[col] = e;
            lsum += e;
        }
#pragma unroll
        for (int o = 16; o; o >>= 1) lsum += __shfl_xor_sync(0xffffffffu, lsum, o);
        const float inv = 1.f / lsum;
        __syncwarp();
        for (int d = lane; d < DHq; d += 32) {
            float a = 0.f;
            for (int k = 0; k < Sq; k++) a = fmaf(p[k], Vs[k * DHq + d], a);
            ctx[(size_t)(b * Sq + q) * Dq + h * DHq + d] = a * inv;
        }
        __syncwarp();
    }
}

// ---------------- gate softmax ------------------------------------------------------
__global__ void __launch_bounds__(256)
gate_kernel(const float* __restrict__ x, const float* __restrict__ Wg,
            const float* __restrict__ bg, float* __restrict__ gates)
{
    const int warp = (blockIdx.x * 256 + threadIdx.x) >> 5;
    const int lane = threadIdx.x & 31;
    if (warp >= NTOK) return;
    const float* xr = x + (size_t)warp * Dq;
    float lg[Eq];
#pragma unroll
    for (int e = 0; e < Eq; e++) lg[e] = 0.f;
    for (int d = lane; d < Dq; d += 32) {
        float xv = xr[d];
#pragma unroll
        for (int e = 0; e < Eq; e++) lg[e] = fmaf(xv, Wg[d * Eq + e], lg[e]);
    }
#pragma unroll
    for (int e = 0; e < Eq; e++)
#pragma unroll
        for (int o = 16; o; o >>= 1) lg[e] += __shfl_xor_sync(0xffffffffu, lg[e], o);
    if (lane == 0) {
        float m = -1e30f;
#pragma unroll
        for (int e = 0; e < Eq; e++) { lg[e] += bg[e]; m = fmaxf(m, lg[e]); }
        float s = 0.f;
#pragma unroll
        for (int e = 0; e < Eq; e++) { lg[e] = __expf(lg[e] - m); s += lg[e]; }
        float inv = 1.f / s;
#pragma unroll
        for (int e = 0; e < Eq; e++) gates[(size_t)warp * Eq + e] = lg[e] * inv;
    }
}

// ---------------- LN1 (emits split-bf16) ---------------------------------------------
__global__ void __launch_bounds__(256)
ln_kernel(const float* __restrict__ a, const float* __restrict__ g,
          const float* __restrict__ be, float* __restrict__ out,
          __nv_bfloat16* __restrict__ ohi, __nv_bfloat16* __restrict__ olo)
{
    const int row = blockIdx.x;
    const float* ar = a + (size_t)row * Dq;
    float v[3];
    float s = 0.f, s2 = 0.f;
#pragma unroll
    for (int i = 0; i < 3; i++) {
        int d = threadIdx.x + i * 256;
        float x = ar[d];
        v[i] = x;
        s += x; s2 = fmaf(x, x, s2);
    }
    __shared__ float rs[8], rs2[8];
#pragma unroll
    for (int o = 16; o; o >>= 1) { s += __shfl_xor_sync(0xffffffffu, s, o); s2 += __shfl_xor_sync(0xffffffffu, s2, o); }
    const int warp = threadIdx.x >> 5, lane = threadIdx.x & 31;
    if (lane == 0) { rs[warp] = s; rs2[warp] = s2; }
    __syncthreads();
    if (warp == 0) {
        float t  = (lane < 8) ? rs[lane]  : 0.f;
        float t2 = (lane < 8) ? rs2[lane] : 0.f;
#pragma unroll
        for (int o = 4; o; o >>= 1) { t += __shfl_xor_sync(0xffffffffu, t, o); t2 += __shfl_xor_sync(0xffffffffu, t2, o); }
        if (lane == 0) { rs[0] = t; rs2[0] = t2; }
    }
    __syncthreads();
    const float mu  = rs[0] * (1.f / Dq);
    const float var = rs2[0] * (1.f / Dq) - mu * mu;
    const float inv = rsqrtf(var + 1e-5f);
#pragma unroll
    for (int i = 0; i < 3; i++) {
        int d = threadIdx.x + i * 256;
        float y = (v[i] - mu) * inv * g[d] + be[d];
        const size_t idx = (size_t)row * Dq + d;
        out[idx] = y;
        __nv_bfloat16 h = __float2bfloat16(y);
        ohi[idx] = h;
        olo[idx] = __float2bfloat16(y - __bfloat162float(h));
    }
}

// ---------------- LN2: fused gate-weighted expert reduction --------------------------
__global__ void __launch_bounds__(256)
ln2_kernel(const float* __restrict__ x, const float* __restrict__ y,
           const float* __restrict__ gates, const float* __restrict__ g,
           const float* __restrict__ be, float* __restrict__ out)
{
    const int row = blockIdx.x;
    __shared__ float sg[Eq];
    if (threadIdx.x < Eq) sg[threadIdx.x] = gates[(size_t)row * Eq + threadIdx.x];
    __syncthreads();
    float v[3];
    float s = 0.f, s2 = 0.f;
#pragma unroll
    for (int i = 0; i < 3; i++) {
        int d = threadIdx.x + i * 256;
        float val = x[(size_t)row * Dq + d];
#pragma unroll
        for (int e = 0; e < Eq; e++)
            val = fmaf(sg[e], y[(size_t)e * MPAD * Dq + (size_t)row * Dq + d], val);
        v[i] = val;
        s += val; s2 = fmaf(val, val, s2);
    }
    __shared__ float rs[8], rs2[8];
#pragma unroll
    for (int o = 16; o; o >>= 1) { s += __shfl_xor_sync(0xffffffffu, s, o); s2 += __shfl_xor_sync(0xffffffffu, s2, o); }
    const int warp = threadIdx.x >> 5, lane = threadIdx.x & 31;
    if (lane == 0) { rs[warp] = s; rs2[warp] = s2; }
    __syncthreads();
    if (warp == 0) {
        float t  = (lane < 8) ? rs[lane]  : 0.f;
        float t2 = (lane < 8) ? rs2[lane] : 0.f;
#pragma unroll
        for (int o = 4; o; o >>= 1) { t += __shfl_xor_sync(0xffffffffu, t, o); t2 += __shfl_xor_sync(0xffffffffu, t2, o); }
        if (lane == 0) { rs[0] = t; rs2[0] = t2; }
    }
    __syncthreads();
    const float mu  = rs[0] * (1.f / Dq);
    const float var = rs2[0] * (1.f / Dq) - mu * mu;
    const float inv = rsqrtf(var + 1e-5f);
#pragma unroll
    for (int i = 0; i < 3; i++) {
        int d = threadIdx.x + i * 256;
        out[(size_t)row * Dq + d] = (v[i] - mu) * inv * g[d] + be[d];
    }
}

// ====================================================================================
typedef CUresult (*EncFn)(CUtensorMap*, CUtensorMapDataType, cuuint32_t, void*,
                          const cuuint64_t*, const cuuint64_t*, const cuuint32_t*,
                          const cuuint32_t*, CUtensorMapInterleave, CUtensorMapSwizzle,
                          CUtensorMapL2promotion, CUtensorMapFloatOOBfill);

static void make_map(EncFn enc, CUtensorMap* m, void* ptr,
                     uint64_t d0, uint64_t d1, uint64_t d2)
{
    cuuint64_t dims[3] = {d0, d1, d2};
    cuuint64_t strides[2] = {d0 * 2, d0 * d1 * 2};
    cuuint32_t box[3] = {32, 256, 1};
    cuuint32_t es[3] = {1, 1, 1};
    enc(m, CU_TENSOR_MAP_DATA_TYPE_BFLOAT16, 3, ptr, dims, strides, box, es,
        CU_TENSOR_MAP_INTERLEAVE_NONE, CU_TENSOR_MAP_SWIZZLE_64B,
        CU_TENSOR_MAP_L2_PROMOTION_L2_128B, CU_TENSOR_MAP_FLOAT_OOB_FILL_NONE);
}

extern "C" void kernel_launch(void* const* d_in, const int* in_sizes, int n_in,
                              void* d_out, int out_size)
{
    const float* q   = (const float*)d_in[0];
    const float* k   = (const float*)d_in[1];
    const float* v   = (const float*)d_in[2];
    const float* Wq  = (const float*)d_in[3];
    const float* bq  = (const float*)d_in[4];
    const float* Wk  = (const float*)d_in[5];
    const float* bk  = (const float*)d_in[6];
    const float* Wv  = (const float*)d_in[7];
    const float* bv  = (const float*)d_in[8];
    const float* Wo  = (const float*)d_in[9];
    const float* bo  = (const float*)d_in[10];
    const float* ln1g= (const float*)d_in[11];
    const float* ln1b= (const float*)d_in[12];
    const float* ln2g= (const float*)d_in[13];
    const float* ln2b= (const float*)d_in[14];
    const float* Wg  = (const float*)d_in[15];
    const float* bg  = (const float*)d_in[16];
    const float* W1  = (const float*)d_in[17];
    const float* b1  = (const float*)d_in[18];
    const float* W2  = (const float*)d_in[19];
    const float* b2  = (const float*)d_in[20];
    float* out = (float*)d_out;

    float *p_qh, *p_kh, *p_vh, *p_ctx, *p_tmp, *p_x, *p_y, *p_gates;
    __nv_bfloat16 *p_inhi, *p_inlo, *p_xhi, *p_xlo, *p_hhi, *p_hlo;
    __nv_bfloat16 *p_w1h, *p_w1l, *p_w2h, *p_w2l;
    __nv_bfloat16 *p_wqh, *p_wql, *p_wkh, *p_wkl, *p_wvh, *p_wvl, *p_woh, *p_wol;
    cudaGetSymbolAddress((void**)&p_qh,   d_qh);
    cudaGetSymbolAddress((void**)&p_kh,   d_kh);
    cudaGetSymbolAddress((void**)&p_vh,   d_vh);
    cudaGetSymbolAddress((void**)&p_ctx,  d_ctx);
    cudaGetSymbolAddress((void**)&p_tmp,  d_tmp);
    cudaGetSymbolAddress((void**)&p_x,    d_x);
    cudaGetSymbolAddress((void**)&p_y,    d_y);
    cudaGetSymbolAddress((void**)&p_gates,d_gates);
    cudaGetSymbolAddress((void**)&p_inhi, d_inhi);
    cudaGetSymbolAddress((void**)&p_inlo, d_inlo);
    cudaGetSymbolAddress((void**)&p_xhi,  d_xhi);
    cudaGetSymbolAddress((void**)&p_xlo,  d_xlo);
    cudaGetSymbolAddress((void**)&p_hhi,  d_hhi);
    cudaGetSymbolAddress((void**)&p_hlo,  d_hlo);
    cudaGetSymbolAddress((void**)&p_w1h,  d_w1t_hi);
    cudaGetSymbolAddress((void**)&p_w1l,  d_w1t_lo);
    cudaGetSymbolAddress((void**)&p_w2h,  d_w2t_hi);
    cudaGetSymbolAddress((void**)&p_w2l,  d_w2t_lo);
    cudaGetSymbolAddress((void**)&p_wqh,  d_wqt_hi);
    cudaGetSymbolAddress((void**)&p_wql,  d_wqt_lo);
    cudaGetSymbolAddress((void**)&p_wkh,  d_wkt_hi);
    cudaGetSymbolAddress((void**)&p_wkl,  d_wkt_lo);
    cudaGetSymbolAddress((void**)&p_wvh,  d_wvt_hi);
    cudaGetSymbolAddress((void**)&p_wvl,  d_wvt_lo);
    cudaGetSymbolAddress((void**)&p_woh,  d_wot_hi);
    cudaGetSymbolAddress((void**)&p_wol,  d_wot_lo);

    // driver entry point for tensormap encode (runtime API; no -lcuda needed)
    static EncFn enc = nullptr;
    if (!enc) {
        void* fp = nullptr;
        cudaDriverEntryPointQueryResult st;
        cudaGetDriverEntryPointByVersion("cuTensorMapEncodeTiled", &fp, 12000,
                                         cudaEnableDefault, &st);
        enc = (EncFn)fp;
    }
    CUtensorMap mXh, mXl, mHh, mHl, mW1h, mW1l, mW2h, mW2l;
    make_map(enc, &mXh, p_xhi, Dq, MPAD, 1);
    make_map(enc, &mXl, p_xlo, Dq, MPAD, 1);
    make_map(enc, &mHh, p_hhi, Fq, MPAD, Eq);
    make_map(enc, &mHl, p_hlo, Fq, MPAD, Eq);
    make_map(enc, &mW1h, p_w1h, Dq, Fq, Eq);
    make_map(enc, &mW1l, p_w1l, Dq, Fq, Eq);
    make_map(enc, &mW2h, p_w2h, Fq, Dq, Eq);
    make_map(enc, &mW2l, p_w2l, Fq, Dq, Eq);

    const dim3 blk(256);
    const dim3 gridD(Dq / TN, NTOK / TM);
    const dim3 grid1(Fq / 256, MPAD / 256, Eq);
    const dim3 grid2(Dq / 256, MPAD / 256, Eq);
    const int n4 = NTOK * Dq / 4;
    const int sgrid = (n4 + 255) / 256;

    cudaFuncSetAttribute(tc_gemm<2>,  cudaFuncAttributeMaxDynamicSharedMemorySize, TC_SMEM);
    cudaFuncSetAttribute(tc_gemm<3>,  cudaFuncAttributeMaxDynamicSharedMemorySize, TC_SMEM);
    cudaFuncSetAttribute(tc_gemm2<0>, cudaFuncAttributeMaxDynamicSharedMemorySize, TC2_SMEM);
    cudaFuncSetAttribute(tc_gemm2<1>, cudaFuncAttributeMaxDynamicSharedMemorySize, TC2_SMEM);

    transpose_split<<<dim3(Dq/32, Dq/32, 1), blk>>>(Wq, p_wqh, p_wql, Dq, Dq);
    transpose_split<<<dim3(Dq/32, Dq/32, 1), blk>>>(Wk, p_wkh, p_wkl, Dq, Dq);
    transpose_split<<<dim3(Dq/32, Dq/32, 1), blk>>>(Wv, p_wvh, p_wvl, Dq, Dq);
    transpose_split<<<dim3(Dq/32, Dq/32, 1), blk>>>(Wo, p_woh, p_wol, Dq, Dq);
    transpose_split<<<dim3(Dq/32, Fq/32, Eq), blk>>>(W1, p_w1h, p_w1l, Dq, Fq);
    transpose_split<<<dim3(Fq/32, Dq/32, Eq), blk>>>(W2, p_w2h, p_w2l, Fq, Dq);

    split_bf16<<<sgrid, blk>>>(q, p_inhi, p_inlo, n4);
    tc_gemm<2><<<gridD, blk, TC_SMEM>>>(p_inhi, p_inlo, p_wqh, p_wql, bq,
                                        nullptr, p_qh, NTOK, Dq, Dq);
    split_bf16<<<sgrid, blk>>>(k, p_inhi, p_inlo, n4);
    tc_gemm<2><<<gridD, blk, TC_SMEM>>>(p_inhi, p_inlo, p_wkh, p_wkl, bk,
                                        nullptr, p_kh, NTOK, Dq, Dq);
    split_bf16<<<sgrid, blk>>>(v, p_inhi, p_inlo, n4);
    tc_gemm<2><<<gridD, blk, TC_SMEM>>>(p_inhi, p_inlo, p_wvh, p_wvl, bv,
                                        nullptr, p_vh, NTOK, Dq, Dq);

    const int smem_attn = (Sq * KPAD + Sq * DHq + 8 * 208 + 8 * DHq) * (int)sizeof(float);
    cudaFuncSetAttribute(attn_kernel, cudaFuncAttributeMaxDynamicSharedMemorySize, smem_attn);
    attn_kernel<<<dim3(Bq * Hq, 4), blk, smem_attn>>>(p_qh, p_kh, p_vh, p_ctx);

    split_bf16<<<sgrid, blk>>>(p_ctx, p_inhi, p_inlo, n4);
    tc_gemm<3><<<gridD, blk, TC_SMEM>>>(p_inhi, p_inlo, p_woh, p_wol, bo,
                                        q, p_tmp, NTOK, Dq, Dq);
    ln_kernel<<<NTOK, blk>>>(p_tmp, ln1g, ln1b, p_x, p_xhi, p_xlo);

    gate_kernel<<<(NTOK * 32 + 255) / 256, blk>>>(p_x, Wg, bg, p_gates);

    tc_gemm2<0><<<grid1, blk, TC2_SMEM>>>(
        mXh, mXl, mW1h, mW1l, b1, nullptr, p_hhi, p_hlo,
        Fq, Dq, (size_t)Fq, (size_t)MPAD * Fq,
        p_xhi, p_xlo, p_w1h, p_w1l, (size_t)0, (size_t)Fq * Dq);
    tc_gemm2<1><<<grid2, blk, TC2_SMEM>>>(
        mHh, mHl, mW2h, mW2l, b2, p_y, nullptr, nullptr,
        Dq, Fq, (size_t)Dq, (size_t)MPAD * Dq,
        p_hhi, p_hlo, p_w2h, p_w2l, (size_t)MPAD * Fq, (size_t)Dq * Fq);

    ln2_kernel<<<NTOK, blk>>>(p_x, p_y, p_gates, ln2g, ln2b, out);
}

// round 8
// speedup vs baseline: 6.6352x; 1.1694x over previous
#include <cuda_runtime.h>
#include <cuda.h>
#include <cuda_bf16.h>
#include <math.h>
#include <stdint.h>

#define Bq 32
#define Sq 196
#define Dq 768
#define Hq 12
#define Eq 8
#define Fq 3072
#define DHq 64
#define NTOK (Bq*Sq)
#define MPAD 6400

#define HAS_TCGEN05 (defined(__CUDA_ARCH_FEAT_SM103_ALL) || defined(__CUDA_ARCH_FEAT_SM100_ALL))

// ---------------- scratch ------------------------------------------------------
__device__ __align__(256) float d_qh [NTOK*Dq];
__device__ __align__(256) float d_kh [NTOK*Dq];
__device__ __align__(256) float d_vh [NTOK*Dq];
__device__ __align__(256) float d_ctx[NTOK*Dq];
__device__ __align__(256) float d_tmp[NTOK*Dq];
__device__ __align__(256) float d_x  [NTOK*Dq];
__device__ __align__(256) float d_y  [Eq*MPAD*Dq];
__device__ __align__(256) float d_gates[MPAD*Eq];

__device__ __align__(256) __nv_bfloat16 d_inhi[NTOK*Dq];
__device__ __align__(256) __nv_bfloat16 d_inlo[NTOK*Dq];
__device__ __align__(256) __nv_bfloat16 d_xhi[MPAD*Dq];
__device__ __align__(256) __nv_bfloat16 d_xlo[MPAD*Dq];
__device__ __align__(256) __nv_bfloat16 d_hhi[Eq*MPAD*Fq];
__device__ __align__(256) __nv_bfloat16 d_hlo[Eq*MPAD*Fq];
__device__ __align__(256) __nv_bfloat16 d_w1t_hi[Eq*Fq*Dq];   // hi only (MoE B-side)
__device__ __align__(256) __nv_bfloat16 d_w2t_hi[Eq*Dq*Fq];   // hi only
__device__ __align__(256) __nv_bfloat16 d_wqt_hi[Dq*Dq];
__device__ __align__(256) __nv_bfloat16 d_wqt_lo[Dq*Dq];
__device__ __align__(256) __nv_bfloat16 d_wkt_hi[Dq*Dq];
__device__ __align__(256) __nv_bfloat16 d_wkt_lo[Dq*Dq];
__device__ __align__(256) __nv_bfloat16 d_wvt_hi[Dq*Dq];
__device__ __align__(256) __nv_bfloat16 d_wvt_lo[Dq*Dq];
__device__ __align__(256) __nv_bfloat16 d_wot_hi[Dq*Dq];
__device__ __align__(256) __nv_bfloat16 d_wot_lo[Dq*Dq];

// ---------------- PTX helpers ---------------------------------------------------
__device__ __forceinline__ uint32_t smem_u32(const void* p) {
    uint32_t a;
    asm("{ .reg .u64 t; cvta.to.shared.u64 t, %1; cvt.u32.u64 %0, t; }" : "=r"(a) : "l"(p));
    return a;
}

#if HAS_TCGEN05
__device__ __forceinline__ bool elect_one() {
    uint32_t p;
    asm volatile("{\n .reg .pred p;\n elect.sync _|p, 0xFFFFFFFF;\n selp.b32 %0,1,0,p;\n}" : "=r"(p));
    return p != 0;
}
#define MBARRIER_INIT(addr, cnt) \
    asm volatile("mbarrier.init.shared.b64 [%0], %1;" :: "r"((uint32_t)(addr)), "r"((uint32_t)(cnt)) : "memory")
#define MBARRIER_INVAL(addr) \
    asm volatile("mbarrier.inval.shared.b64 [%0];" :: "r"((uint32_t)(addr)) : "memory")
#define MBARRIER_EXPECT_TX(addr, tx) \
    asm volatile("mbarrier.arrive.expect_tx.shared.b64 _, [%0], %1;" \
        :: "r"((uint32_t)(addr)), "r"((uint32_t)(tx)) : "memory")
#define MBARRIER_WAIT_PARITY(mbar, par) do { \
    uint32_t _m = (uint32_t)(mbar), _p = (uint32_t)(par), _d; \
    asm volatile("{\n\t.reg .pred p;\n\t" \
        "mbarrier.try_wait.parity.acquire.cta.shared::cta.b64 p, [%1], %2;\n\t" \
        "selp.b32 %0, 1, 0, p;\n\t}" : "=r"(_d) : "r"(_m), "r"(_p) : "memory"); \
    if (!_d) { \
        asm volatile("{\n\t.reg .pred P1;\n\t" \
            "WL_%=:\n\t" \
            "mbarrier.try_wait.parity.acquire.cta.shared::cta.b64 P1, [%0], %1, 0x989680;\n\t" \
            "@P1 bra.uni WD_%=;\n\tbra.uni WL_%=;\n\tWD_%=:\n\t}" \
            :: "r"(_m), "r"(_p) : "memory"); \
    } \
} while(0)
#define TCGEN05_ALLOC(a, n) \
    asm volatile("tcgen05.alloc.cta_group::1.sync.aligned.shared::cta.b32 [%0], %1;" \
        :: "r"((uint32_t)(a)), "r"((uint32_t)(n)) : "memory")
#define TCGEN05_DEALLOC(t, n) \
    asm volatile("tcgen05.dealloc.cta_group::1.sync.aligned.b32 %0, %1;" :: "r"(t), "r"(n))
#define TCGEN05_RELINQ() \
    asm volatile("tcgen05.relinquish_alloc_permit.cta_group::1.sync.aligned;")
#define TCGEN05_COMMIT(m) \
    asm volatile("tcgen05.commit.cta_group::1.mbarrier::arrive::one.shared::cluster.b64 [%0];" \
        :: "r"((uint32_t)(m)) : "memory")
#define TCGEN05_FENCE_AFTER()  asm volatile("tcgen05.fence::after_thread_sync;" ::: "memory")
#define TCGEN05_FENCE_BEFORE() asm volatile("tcgen05.fence::before_thread_sync;" ::: "memory")
#define TCGEN05_WAIT_LD() asm volatile("tcgen05.wait::ld.sync.aligned;" ::: "memory")
#define FENCE_ASYNC_SHARED() asm volatile("fence.proxy.async.shared::cta;" ::: "memory")
#define CP_ASYNC16(dst, src) \
    asm volatile("cp.async.cg.shared.global [%0], [%1], 16;" :: "r"((uint32_t)(dst)), "l"(src))
#define CP_COMMIT() asm volatile("cp.async.commit_group;" ::: "memory")
#define CP_WAIT(n)  asm volatile("cp.async.wait_group %0;" :: "n"(n) : "memory")
#define TMA_LOAD_3D(sm, map, cx, cy, cz, mb) \
    asm volatile("cp.async.bulk.tensor.3d.shared::cta.global.tile.mbarrier::complete_tx::bytes " \
        "[%0], [%1, {%2, %3, %4}], [%5];" \
        :: "r"((uint32_t)(sm)), "l"(map), "r"((int32_t)(cx)), "r"((int32_t)(cy)), \
           "r"((int32_t)(cz)), "r"((uint32_t)(mb)) : "memory")
#define TCGEN05_LD_32X32B_X32(r, ta) \
    asm volatile("tcgen05.ld.sync.aligned.32x32b.x32.b32 " \
        "{%0, %1, %2, %3, %4, %5, %6, %7, %8, %9, %10, %11, %12, %13, %14, %15, " \
        " %16, %17, %18, %19, %20, %21, %22, %23, %24, %25, %26, %27, %28, %29, %30, %31}, [%32];" \
        : "=r"((r)[0]), "=r"((r)[1]), "=r"((r)[2]), "=r"((r)[3]), "=r"((r)[4]), "=r"((r)[5]), \
          "=r"((r)[6]), "=r"((r)[7]), "=r"((r)[8]), "=r"((r)[9]), "=r"((r)[10]), "=r"((r)[11]), \
          "=r"((r)[12]), "=r"((r)[13]), "=r"((r)[14]), "=r"((r)[15]), "=r"((r)[16]), "=r"((r)[17]), \
          "=r"((r)[18]), "=r"((r)[19]), "=r"((r)[20]), "=r"((r)[21]), "=r"((r)[22]), "=r"((r)[23]), \
          "=r"((r)[24]), "=r"((r)[25]), "=r"((r)[26]), "=r"((r)[27]), "=r"((r)[28]), "=r"((r)[29]), \
          "=r"((r)[30]), "=r"((r)[31]) : "r"(ta))

static constexpr uint64_t DESC_SW128 =
    (uint64_t(2) << 61) | (uint64_t(1) << 46) | (uint64_t(64) << 32) | (uint64_t(1) << 16);
static constexpr uint64_t DESC_SW64 =
    (uint64_t(4) << 61) | (uint64_t(1) << 46) | (uint64_t(32) << 32) | (uint64_t(1) << 16);
#define MKD128(a) (DESC_SW128 | ((uint64_t)((a) >> 4) & 0x3FFF))
#define MKD64(a)  (DESC_SW64  | ((uint64_t)((a) >> 4) & 0x3FFF))

__device__ __forceinline__ void mma_bf16_ss(uint32_t d, uint64_t ad, uint64_t bd,
                                            uint32_t idesc, uint32_t en) {
    asm volatile(
        "{\n\t.reg .pred p;\n\tsetp.ne.u32 p, %5, 0;\n\t"
        "tcgen05.mma.cta_group::1.kind::f16 [%0], %1, %2, %3, {%4,%4,%4,%4}, p;\n\t}"
        :: "r"(d), "l"(ad), "l"(bd), "r"(idesc), "r"(0u), "r"(en) : "memory");
}
static constexpr uint32_t IDESC_BF16 =
    (1u << 4) | (1u << 7) | (1u << 10) | ((256 / 8) << 17) | ((128 / 16) << 24);
#endif

// ======================= TM128 tc GEMM (QKV / O-proj, full 3-term) ==============
#define TM 128
#define TN 256
#define TK 64
#define STAGE_BYTES 98304
#define SM_DATA 1024
#define TC_SMEM (SM_DATA + 2*STAGE_BYTES)

#if HAS_TCGEN05
__device__ __forceinline__ void load_slab128(
    uint32_t sbase, int stage,
    const __nv_bfloat16* __restrict__ Ahi, const __nv_bfloat16* __restrict__ Alo,
    const __nv_bfloat16* __restrict__ Bhi, const __nv_bfloat16* __restrict__ Blo,
    int m0, int n0, int k0, int K)
{
    const int tid = threadIdx.x;
    const uint32_t base = sbase + SM_DATA + stage * STAGE_BYTES;
#pragma unroll
    for (int i = 0; i < 4; i++) {
        int idx = i * 256 + tid;
        int row = idx >> 3, c4 = idx & 7;
        int off = row * 128 + c4 * 16;
        int sw  = off ^ ((off >> 3) & 0x70);
        size_t g = (size_t)(m0 + row) * K + k0 + c4 * 8;
        CP_ASYNC16(base + sw, Ahi + g);
        CP_ASYNC16(base + 16384 + sw, Alo + g);
    }
#pragma unroll
    for (int i = 0; i < 8; i++) {
        int idx = i * 256 + tid;
        int row = idx >> 3, c4 = idx & 7;
        int off = row * 128 + c4 * 16;
        int sw  = off ^ ((off >> 3) & 0x70);
        size_t g = (size_t)(n0 + row) * K + k0 + c4 * 8;
        CP_ASYNC16(base + 32768 + sw, Bhi + g);
        CP_ASYNC16(base + 65536 + sw, Blo + g);
    }
    CP_COMMIT();
}
#endif

template<int MODE>   // 2: C=AW+b   3: C=AW+b+res
__global__ void __launch_bounds__(256)
tc_gemm(const __nv_bfloat16* __restrict__ Ahi, const __nv_bfloat16* __restrict__ Alo,
        const __nv_bfloat16* __restrict__ Bhi, const __nv_bfloat16* __restrict__ Blo,
        const float* __restrict__ bias, const float* __restrict__ res,
        float* __restrict__ Cf, int M, int N, int K)
{
    extern __shared__ __align__(1024) char smx[];
#if HAS_TCGEN05
    const uint32_t sb = smem_u32(smx);
    const int tid = threadIdx.x;
    const int wid = tid >> 5, lane = tid & 31;
    const int m0 = blockIdx.y * TM, n0 = blockIdx.x * TN;

    if (wid == 0) { TCGEN05_ALLOC(sb, 256); TCGEN05_RELINQ(); }
    if (tid == 0) { MBARRIER_INIT(sb + 8, 1); MBARRIER_INIT(sb + 16, 1); }
    __syncthreads();
    uint32_t tmem;
    asm volatile("ld.shared.b32 %0, [%1];" : "=r"(tmem) : "r"(sb));

    const int NS = K / TK;
    load_slab128(sb, 0, Ahi, Alo, Bhi, Blo, m0, n0, 0, K);
    int ph0 = 0, ph1 = 0;
    for (int s = 0; s < NS; s++) {
        const int buf = s & 1;
        if (s + 1 < NS) {
            const int nb = 1 - buf;
            if (s >= 1) {
                if (nb == 0) { MBARRIER_WAIT_PARITY(sb + 8,  ph0); ph0 ^= 1; }
                else         { MBARRIER_WAIT_PARITY(sb + 16, ph1); ph1 ^= 1; }
            }
            load_slab128(sb, nb, Ahi, Alo, Bhi, Blo, m0, n0, (s + 1) * TK, K);
            CP_WAIT(1);
        } else {
            CP_WAIT(0);
        }
        FENCE_ASYNC_SHARED();
        __syncthreads();
        if (wid == 0) {
            TCGEN05_FENCE_AFTER();
            if (elect_one()) {
                const uint32_t tb = sb + SM_DATA + buf * STAGE_BYTES;
                const uint64_t ah = MKD128(tb), al = MKD128(tb + 16384);
                const uint64_t bh = MKD128(tb + 32768), bl = MKD128(tb + 65536);
#pragma unroll
                for (int ks = 0; ks < 4; ks++) {
                    const uint32_t en0 = (s == 0 && ks == 0) ? 0u : 1u;
                    mma_bf16_ss(tmem, ah + ks * 2, bh + ks * 2, IDESC_BF16, en0);
                    mma_bf16_ss(tmem, ah + ks * 2, bl + ks * 2, IDESC_BF16, 1u);
                    mma_bf16_ss(tmem, al + ks * 2, bh + ks * 2, IDESC_BF16, 1u);
                }
                TCGEN05_COMMIT(sb + 8 + buf * 8);
            }
        }
    }
    if (((NS - 1) & 1) == 0) { MBARRIER_WAIT_PARITY(sb + 8,  ph0); }
    else                     { MBARRIER_WAIT_PARITY(sb + 16, ph1); }
    TCGEN05_FENCE_AFTER();

    const int sub = wid & 3, cg = wid >> 2;
    const int row = m0 + sub * 32 + lane;
#pragma unroll
    for (int ch = 0; ch < 4; ch++) {
        const int colb = cg * 128 + ch * 32;
        uint32_t r[32];
        TCGEN05_LD_32X32B_X32(r, tmem + colb);
        TCGEN05_WAIT_LD();
        const size_t base = (size_t)row * N + n0 + colb;
        const float4* bv = (const float4*)(bias + n0 + colb);
        float4* dst = (float4*)(Cf + base);
        const float4* rv = (MODE == 3) ? (const float4*)(res + base) : nullptr;
#pragma unroll
        for (int i = 0; i < 8; i++) {
            float4 b4 = bv[i];
            float4 o;
            o.x = __uint_as_float(r[i*4+0]) + b4.x;
            o.y = __uint_as_float(r[i*4+1]) + b4.y;
            o.z = __uint_as_float(r[i*4+2]) + b4.z;
            o.w = __uint_as_float(r[i*4+3]) + b4.w;
            if (MODE == 3) { float4 t = rv[i]; o.x += t.x; o.y += t.y; o.z += t.z; o.w += t.w; }
            dst[i] = o;
        }
    }
    TCGEN05_FENCE_BEFORE();
    __syncthreads();
    if (tid == 0) { MBARRIER_INVAL(sb + 8); MBARRIER_INVAL(sb + 16); }
    __syncthreads();
    if (wid == 0) TCGEN05_DEALLOC(tmem, 256);
#else
    float* As = (float*)smx;
    float* Bs = As + 16 * 128;
    const int tid = threadIdx.x;
    const int m0 = blockIdx.y * TM, n0x = blockIdx.x * TN;
    const int tx = tid & 15, ty = tid >> 4;
    const int mr = ty * 8, nr = tx * 8;
    for (int half = 0; half < 2; half++) {
        const int n0 = n0x + half * 128;
        float acc[8][8];
#pragma unroll
        for (int i = 0; i < 8; i++)
#pragma unroll
            for (int j = 0; j < 8; j++) acc[i][j] = 0.f;
        for (int k0 = 0; k0 < K; k0 += 16) {
            __syncthreads();
#pragma unroll
            for (int i = 0; i < 8; i++) {
                int idx = i * 256 + tid;
                int kk = idx >> 7, mm = idx & 127;
                size_t ga = (size_t)(m0 + mm) * K + k0 + kk;
                size_t gb = (size_t)(n0 + mm) * K + k0 + kk;
                As[kk*128+mm] = __bfloat162float(Ahi[ga]) + __bfloat162float(Alo[ga]);
                Bs[kk*128+mm] = __bfloat162float(Bhi[gb]) + __bfloat162float(Blo[gb]);
            }
            __syncthreads();
#pragma unroll
            for (int kk = 0; kk < 16; kk++) {
                float a0[8], b0[8];
#pragma unroll
                for (int i = 0; i < 8; i++) a0[i] = As[kk*128+mr+i];
#pragma unroll
                for (int j = 0; j < 8; j++) b0[j] = Bs[kk*128+nr+j];
#pragma unroll
                for (int i = 0; i < 8; i++)
#pragma unroll
                    for (int j = 0; j < 8; j++)
                        acc[i][j] = fmaf(a0[i], b0[j], acc[i][j]);
            }
        }
#pragma unroll
        for (int i = 0; i < 8; i++) {
            const int row = m0 + mr + i;
#pragma unroll
            for (int j = 0; j < 8; j++) {
                const int col = n0 + nr + j;
                const size_t idx = (size_t)row * N + col;
                float v = acc[i][j] + bias[col];
                if (MODE == 2) Cf[idx] = v; else Cf[idx] = v + res[idx];
            }
        }
    }
#endif
}

// ======================= MoE GEMM: TMA producer/consumer, B=bf16-hi only ========
// tile M256 x N256, TK=32, SW64, 4 stages x 48KB, z = expert, 8 MMAs/slab
#define T2K 32
#define ST2 49152
#define TC2_SMEM (1024 + 4*ST2)   // 197632

template<int MODE>   // 0: gelu->split bf16    1: Cf = acc + bias
__global__ void __launch_bounds__(256)
tc_gemm2(const __grid_constant__ CUtensorMap mAh, const __grid_constant__ CUtensorMap mAl,
         const __grid_constant__ CUtensorMap mBh,
         const float* __restrict__ bias, float* __restrict__ Cf,
         __nv_bfloat16* __restrict__ Chi, __nv_bfloat16* __restrict__ Clo,
         int N, int K, size_t sBias, size_t sC,
         const __nv_bfloat16* __restrict__ Ahi, const __nv_bfloat16* __restrict__ Alo,
         const __nv_bfloat16* __restrict__ Bh, size_t sA, size_t sB)
{
    extern __shared__ __align__(1024) char smx[];
    const int z = blockIdx.z;
    bias += z * sBias;
#if HAS_TCGEN05
    const uint32_t sb = smem_u32(smx);
    const int tid = threadIdx.x;
    const int wid = tid >> 5, lane = tid & 31;
    const int m0 = blockIdx.y * 256, n0 = blockIdx.x * 256;
    const int za = (MODE == 0) ? 0 : z;

    if (wid == 0) { TCGEN05_ALLOC(sb, 512); TCGEN05_RELINQ(); }
    if (tid == 0) {
        // full at 8..32, empty at 40..64, done 72
        MBARRIER_INIT(sb + 8,  1); MBARRIER_INIT(sb + 16, 1);
        MBARRIER_INIT(sb + 24, 1); MBARRIER_INIT(sb + 32, 1);
        MBARRIER_INIT(sb + 40, 1); MBARRIER_INIT(sb + 48, 1);
        MBARRIER_INIT(sb + 56, 1); MBARRIER_INIT(sb + 64, 1);
        MBARRIER_INIT(sb + 72, 1);
        FENCE_ASYNC_SHARED();
    }
    __syncthreads();
    uint32_t tmem;
    asm volatile("ld.shared.b32 %0, [%1];" : "=r"(tmem) : "r"(sb));

    const int NS = K / T2K;
    if (wid == 1) {
        if (elect_one()) {
            for (int s = 0; s < NS; s++) {
                const int st = s & 3;
                if (s >= 4) MBARRIER_WAIT_PARITY(sb + 40 + st * 8, ((s >> 2) - 1) & 1);
                MBARRIER_EXPECT_TX(sb + 8 + st * 8, 49152u);
                const uint32_t stb = sb + 1024 + st * ST2;
                const int k0 = s * T2K;
                TMA_LOAD_3D(stb,         &mAh, k0, m0, za, sb + 8 + st * 8);
                TMA_LOAD_3D(stb + 16384, &mAl, k0, m0, za, sb + 8 + st * 8);
                TMA_LOAD_3D(stb + 32768, &mBh, k0, n0, z,  sb + 8 + st * 8);
            }
        }
    } else if (wid == 0) {
        TCGEN05_FENCE_AFTER();
        if (elect_one()) {
            for (int s = 0; s < NS; s++) {
                const int st = s & 3;
                MBARRIER_WAIT_PARITY(sb + 8 + st * 8, (s >> 2) & 1);
                const uint32_t tb = sb + 1024 + st * ST2;
                const uint64_t a0h = MKD64(tb),        a0l = MKD64(tb + 16384);
                const uint64_t a1h = a0h + 512,        a1l = a0l + 512;  // rows 128..255
                const uint64_t bh  = MKD64(tb + 32768);
#pragma unroll
                for (int ks = 0; ks < 2; ks++) {
                    const uint32_t en0 = (s == 0 && ks == 0) ? 0u : 1u;
                    mma_bf16_ss(tmem,       a0h + ks * 2, bh + ks * 2, IDESC_BF16, en0);
                    mma_bf16_ss(tmem,       a0l + ks * 2, bh + ks * 2, IDESC_BF16, 1u);
                    mma_bf16_ss(tmem + 256, a1h + ks * 2, bh + ks * 2, IDESC_BF16, en0);
                    mma_bf16_ss(tmem + 256, a1l + ks * 2, bh + ks * 2, IDESC_BF16, 1u);
                }
                TCGEN05_COMMIT(sb + 40 + st * 8);
            }
            TCGEN05_COMMIT(sb + 72);
        }
    }

    MBARRIER_WAIT_PARITY(sb + 72, 0);
    TCGEN05_FENCE_AFTER();

    const int accSel = wid >> 2, sub = wid & 3;
    const int row = m0 + accSel * 128 + sub * 32 + lane;
    const uint32_t tacc = tmem + accSel * 256;
    if (MODE == 0) { Chi += z * sC; Clo += z * sC; }
    else           { Cf  += z * sC; }
#pragma unroll
    for (int ch = 0; ch < 8; ch++) {
        const int colb = ch * 32;
        uint32_t r[32];
        TCGEN05_LD_32X32B_X32(r, tacc + colb);
        TCGEN05_WAIT_LD();
        const size_t base = (size_t)row * N + n0 + colb;
        const float4* bv = (const float4*)(bias + n0 + colb);
        if (MODE == 0) {
            uint4* dh = (uint4*)(Chi + base);
            uint4* dl = (uint4*)(Clo + base);
#pragma unroll
            for (int i = 0; i < 4; i++) {
                uint32_t hp[4], lp[4];
#pragma unroll
                for (int p = 0; p < 4; p++) {
                    float4 b4 = bv[i * 2 + (p >> 1)];
                    float b0 = (p & 1) ? b4.z : b4.x;
                    float b1 = (p & 1) ? b4.w : b4.y;
                    float v0 = __uint_as_float(r[i*8+p*2+0]) + b0;
                    float v1 = __uint_as_float(r[i*8+p*2+1]) + b1;
                    float g0 = 0.5f * v0 * (1.f + erff(v0 * 0.70710678118654752f));
                    float g1 = 0.5f * v1 * (1.f + erff(v1 * 0.70710678118654752f));
                    __nv_bfloat16 h0 = __float2bfloat16(g0);
                    __nv_bfloat16 h1 = __float2bfloat16(g1);
                    __nv_bfloat16 l0 = __float2bfloat16(g0 - __bfloat162float(h0));
                    __nv_bfloat16 l1 = __float2bfloat16(g1 - __bfloat162float(h1));
                    hp[p] = (uint32_t)__bfloat16_as_ushort(h0) | ((uint32_t)__bfloat16_as_ushort(h1) << 16);
                    lp[p] = (uint32_t)__bfloat16_as_ushort(l0) | ((uint32_t)__bfloat16_as_ushort(l1) << 16);
                }
                dh[i] = make_uint4(hp[0], hp[1], hp[2], hp[3]);
                dl[i] = make_uint4(lp[0], lp[1], lp[2], lp[3]);
            }
        } else {
            float4* dst = (float4*)(Cf + base);
#pragma unroll
            for (int i = 0; i < 8; i++) {
                float4 b4 = bv[i];
                float4 o;
                o.x = __uint_as_float(r[i*4+0]) + b4.x;
                o.y = __uint_as_float(r[i*4+1]) + b4.y;
                o.z = __uint_as_float(r[i*4+2]) + b4.z;
                o.w = __uint_as_float(r[i*4+3]) + b4.w;
                dst[i] = o;
            }
        }
    }
    TCGEN05_FENCE_BEFORE();
    __syncthreads();
    if (tid == 0) {
        MBARRIER_INVAL(sb + 8);  MBARRIER_INVAL(sb + 16); MBARRIER_INVAL(sb + 24);
        MBARRIER_INVAL(sb + 32); MBARRIER_INVAL(sb + 40); MBARRIER_INVAL(sb + 48);
        MBARRIER_INVAL(sb + 56); MBARRIER_INVAL(sb + 64); MBARRIER_INVAL(sb + 72);
    }
    __syncthreads();
    if (wid == 0) TCGEN05_DEALLOC(tmem, 512);
#else
    // SIMT fallback (B = hi only)
    const __nv_bfloat16* Ah = Ahi + (size_t)((MODE == 0) ? 0 : z) * sA;
    const __nv_bfloat16* Al = Alo + (size_t)((MODE == 0) ? 0 : z) * sA;
    const __nv_bfloat16* Bp = Bh + (size_t)z * sB;
    if (MODE == 0) { Chi += z * sC; Clo += z * sC; }
    else           { Cf  += z * sC; }
    float* As = (float*)smx;
    float* Bs = As + 16 * 128;
    const int tid = threadIdx.x;
    const int tx = tid & 15, ty = tid >> 4;
    const int mr = ty * 8, nr = tx * 8;
    for (int mh = 0; mh < 2; mh++)
    for (int nh = 0; nh < 2; nh++) {
        const int m0 = blockIdx.y * 256 + mh * 128;
        const int n0 = blockIdx.x * 256 + nh * 128;
        float acc[8][8];
#pragma unroll
        for (int i = 0; i < 8; i++)
#pragma unroll
            for (int j = 0; j < 8; j++) acc[i][j] = 0.f;
        for (int k0 = 0; k0 < K; k0 += 16) {
            __syncthreads();
#pragma unroll
            for (int i = 0; i < 8; i++) {
                int idx = i * 256 + tid;
                int kk = idx >> 7, mm = idx & 127;
                size_t ga = (size_t)(m0 + mm) * K + k0 + kk;
                size_t gb = (size_t)(n0 + mm) * K + k0 + kk;
                As[kk*128+mm] = __bfloat162float(Ah[ga]) + __bfloat162float(Al[ga]);
                Bs[kk*128+mm] = __bfloat162float(Bp[gb]);
            }
            __syncthreads();
#pragma unroll
            for (int kk = 0; kk < 16; kk++) {
                float a0[8], b0[8];
#pragma unroll
                for (int i = 0; i < 8; i++) a0[i] = As[kk*128+mr+i];
#pragma unroll
                for (int j = 0; j < 8; j++) b0[j] = Bs[kk*128+nr+j];
#pragma unroll
                for (int i = 0; i < 8; i++)
#pragma unroll
                    for (int j = 0; j < 8; j++)
                        acc[i][j] = fmaf(a0[i], b0[j], acc[i][j]);
            }
        }
#pragma unroll
        for (int i = 0; i < 8; i++) {
            const int row = m0 + mr + i;
#pragma unroll
            for (int j = 0; j < 8; j++) {
                const int col = n0 + nr + j;
                const size_t idx = (size_t)row * N + col;
                float v = acc[i][j] + bias[col];
                if (MODE == 0) {
                    float g = 0.5f * v * (1.f + erff(v * 0.70710678118654752f));
                    __nv_bfloat16 h = __float2bfloat16(g);
                    Chi[idx] = h;
                    Clo[idx] = __float2bfloat16(g - __bfloat162float(h));
                } else Cf[idx] = v;
            }
        }
    }
#endif
}

// ---------------- transpose + split (lo optional) ----------------------------------
__global__ void __launch_bounds__(256)
transpose_split(const float* __restrict__ W, __nv_bfloat16* __restrict__ Thi,
                __nv_bfloat16* __restrict__ Tlo, int K, int N)
{
    __shared__ float t[32][33];
    const int e = blockIdx.z;
    const float* Wp = W + (size_t)e * K * N;
    __nv_bfloat16* th = Thi + (size_t)e * K * N;
    __nv_bfloat16* tl = Tlo ? Tlo + (size_t)e * K * N : nullptr;
    const int k0 = blockIdx.x * 32, n0 = blockIdx.y * 32;
    const int x = threadIdx.x & 31, y = threadIdx.x >> 5;
#pragma unroll
    for (int i = 0; i < 32; i += 8)
        t[y + i][x] = Wp[(size_t)(k0 + y + i) * N + n0 + x];
    __syncthreads();
#pragma unroll
    for (int i = 0; i < 32; i += 8) {
        float v = t[x][y + i];
        __nv_bfloat16 h = __float2bfloat16(v);
        const size_t idx = (size_t)(n0 + y + i) * K + k0 + x;
        th[idx] = h;
        if (tl) tl[idx] = __float2bfloat16(v - __bfloat162float(h));
    }
}

// ---------------- fp32 -> split bf16 -----------------------------------------------
__global__ void __launch_bounds__(256)
split_bf16(const float* __restrict__ x, __nv_bfloat16* __restrict__ hi,
           __nv_bfloat16* __restrict__ lo, int n4)
{
    int i = blockIdx.x * 256 + threadIdx.x;
    if (i >= n4) return;
    float4 v = ((const float4*)x)[i];
    __nv_bfloat16 h0 = __float2bfloat16(v.x), h1 = __float2bfloat16(v.y);
    __nv_bfloat16 h2 = __float2bfloat16(v.z), h3 = __float2bfloat16(v.w);
    uint2 hp, lp;
    hp.x = (uint32_t)__bfloat16_as_ushort(h0) | ((uint32_t)__bfloat16_as_ushort(h1) << 16);
    hp.y = (uint32_t)__bfloat16_as_ushort(h2) | ((uint32_t)__bfloat16_as_ushort(h3) << 16);
    __nv_bfloat16 l0 = __float2bfloat16(v.x - __bfloat162float(h0));
    __nv_bfloat16 l1 = __float2bfloat16(v.y - __bfloat162float(h1));
    __nv_bfloat16 l2 = __float2bfloat16(v.z - __bfloat162float(h2));
    __nv_bfloat16 l3 = __float2bfloat16(v.w - __bfloat162float(h3));
    lp.x = (uint32_t)__bfloat16_as_ushort(l0) | ((uint32_t)__bfloat16_as_ushort(l1) << 16);
    lp.y = (uint32_t)__bfloat16_as_ushort(l2) | ((uint32_t)__bfloat16_as_ushort(l3) << 16);
    ((uint2*)hi)[i] = hp;
    ((uint2*)lo)[i] = lp;
}

// ---------------- attention: 4 CTAs per (b,h) --------------------------------------
#define KPAD 65
__global__ void __launch_bounds__(256)
attn_kernel(const float* __restrict__ qh, const float* __restrict__ kh,
            const float* __restrict__ vh, float* __restrict__ ctx)
{
    const int b = blockIdx.x / Hq;
    const int h = blockIdx.x % Hq;
    const int qbase = blockIdx.y * 49;
    const int qend  = min(196, qbase + 49);
    extern __shared__ float sm[];
    float* Ks = sm;
    float* Vs = Ks + Sq * KPAD;
    float* Ps = Vs + Sq * DHq;
    float* Qs = Ps + 8 * 208;
    const int tid = threadIdx.x;
    for (int i = tid; i < Sq * DHq; i += 256) {
        int s = i / DHq, d = i % DHq;
        size_t gidx = (size_t)(b * Sq + s) * Dq + h * DHq + d;
        Ks[s * KPAD + d] = kh[gidx];
        Vs[s * DHq  + d] = vh[gidx];
    }
    __syncthreads();
    const int warp = tid >> 5, lane = tid & 31;
    float* p    = Ps + warp * 208;
    float* qrow = Qs + warp * DHq;
    for (int q = qbase + warp; q < qend; q += 8) {
        for (int d = lane; d < DHq; d += 32)
            qrow[d] = qh[(size_t)(b * Sq + q) * Dq + h * DHq + d];
        __syncwarp();
        float lmax = -1e30f;
        for (int col = lane; col < Sq; col += 32) {
            float s = 0.f;
            const float* kr = Ks + col * KPAD;
#pragma unroll 16
            for (int d = 0; d < DHq; d++) s = fmaf(qrow[d], kr[d], s);
            s *= 0.125f;
            p[col] = s;
            lmax = fmaxf(lmax, s);
        }
#pragma unroll
        for (int o = 16; o; o >>= 1) lmax = fmaxf(lmax, __shfl_xor_sync(0xffffffffu, lmax, o));
        float lsum = 0.f;
        for (int col = lane; col < Sq; col += 32) {
            float e = __expf(p[col] - lmax);
            p[col] = e;
            lsum += e;
        }
#pragma unroll
        for (int o = 16; o; o >>= 1) lsum += __shfl_xor_sync(0xffffffffu, lsum, o);
        const float inv = 1.f / lsum;
        __syncwarp();
        for (int d = lane; d < DHq; d += 32) {
            float a = 0.f;
            for (int k = 0; k < Sq; k++) a = fmaf(p[k], Vs[k * DHq + d], a);
            ctx[(size_t)(b * Sq + q) * Dq + h * DHq + d] = a * inv;
        }
        __syncwarp();
    }
}

// ---------------- gate softmax ------------------------------------------------------
__global__ void __launch_bounds__(256)
gate_kernel(const float* __restrict__ x, const float* __restrict__ Wg,
            const float* __restrict__ bg, float* __restrict__ gates)
{
    const int warp = (blockIdx.x * 256 + threadIdx.x) >> 5;
    const int lane = threadIdx.x & 31;
    if (warp >= NTOK) return;
    const float* xr = x + (size_t)warp * Dq;
    float lg[Eq];
#pragma unroll
    for (int e = 0; e < Eq; e++) lg[e] = 0.f;
    for (int d = lane; d < Dq; d += 32) {
        float xv = xr[d];
#pragma unroll
        for (int e = 0; e < Eq; e++) lg[e] = fmaf(xv, Wg[d * Eq + e], lg[e]);
    }
#pragma unroll
    for (int e = 0; e < Eq; e++)
#pragma unroll
        for (int o = 16; o; o >>= 1) lg[e] += __shfl_xor_sync(0xffffffffu, lg[e], o);
    if (lane == 0) {
        float m = -1e30f;
#pragma unroll
        for (int e = 0; e < Eq; e++) { lg[e] += bg[e]; m = fmaxf(m, lg[e]); }
        float s = 0.f;
#pragma unroll
        for (int e = 0; e < Eq; e++) { lg[e] = __expf(lg[e] - m); s += lg[e]; }
        float inv = 1.f / s;
#pragma unroll
        for (int e = 0; e < Eq; e++) gates[(size_t)warp * Eq + e] = lg[e] * inv;
    }
}

// ---------------- LN1 (emits split-bf16) ---------------------------------------------
__global__ void __launch_bounds__(256)
ln_kernel(const float* __restrict__ a, const float* __restrict__ g,
          const float* __restrict__ be, float* __restrict__ out,
          __nv_bfloat16* __restrict__ ohi, __nv_bfloat16* __restrict__ olo)
{
    const int row = blockIdx.x;
    const float* ar = a + (size_t)row * Dq;
    float v[3];
    float s = 0.f, s2 = 0.f;
#pragma unroll
    for (int i = 0; i < 3; i++) {
        int d = threadIdx.x + i * 256;
        float x = ar[d];
        v[i] = x;
        s += x; s2 = fmaf(x, x, s2);
    }
    __shared__ float rs[8], rs2[8];
#pragma unroll
    for (int o = 16; o; o >>= 1) { s += __shfl_xor_sync(0xffffffffu, s, o); s2 += __shfl_xor_sync(0xffffffffu, s2, o); }
    const int warp = threadIdx.x >> 5, lane = threadIdx.x & 31;
    if (lane == 0) { rs[warp] = s; rs2[warp] = s2; }
    __syncthreads();
    if (warp == 0) {
        float t  = (lane < 8) ? rs[lane]  : 0.f;
        float t2 = (lane < 8) ? rs2[lane] : 0.f;
#pragma unroll
        for (int o = 4; o; o >>= 1) { t += __shfl_xor_sync(0xffffffffu, t, o); t2 += __shfl_xor_sync(0xffffffffu, t2, o); }
        if (lane == 0) { rs[0] = t; rs2[0] = t2; }
    }
    __syncthreads();
    const float mu  = rs[0] * (1.f / Dq);
    const float var = rs2[0] * (1.f / Dq) - mu * mu;
    const float inv = rsqrtf(var + 1e-5f);
#pragma unroll
    for (int i = 0; i < 3; i++) {
        int d = threadIdx.x + i * 256;
        float y = (v[i] - mu) * inv * g[d] + be[d];
        const size_t idx = (size_t)row * Dq + d;
        out[idx] = y;
        __nv_bfloat16 h = __float2bfloat16(y);
        ohi[idx] = h;
        olo[idx] = __float2bfloat16(y - __bfloat162float(h));
    }
}

// ---------------- LN2: fused gate-weighted expert reduction --------------------------
__global__ void __launch_bounds__(256)
ln2_kernel(const float* __restrict__ x, const float* __restrict__ y,
           const float* __restrict__ gates, const float* __restrict__ g,
           const float* __restrict__ be, float* __restrict__ out)
{
    const int row = blockIdx.x;
    __shared__ float sg[Eq];
    if (threadIdx.x < Eq) sg[threadIdx.x] = gates[(size_t)row * Eq + threadIdx.x];
    __syncthreads();
    float v[3];
    float s = 0.f, s2 = 0.f;
#pragma unroll
    for (int i = 0; i < 3; i++) {
        int d = threadIdx.x + i * 256;
        float val = x[(size_t)row * Dq + d];
#pragma unroll
        for (int e = 0; e < Eq; e++)
            val = fmaf(sg[e], y[(size_t)e * MPAD * Dq + (size_t)row * Dq + d], val);
        v[i] = val;
        s += val; s2 = fmaf(val, val, s2);
    }
    __shared__ float rs[8], rs2[8];
#pragma unroll
    for (int o = 16; o; o >>= 1) { s += __shfl_xor_sync(0xffffffffu, s, o); s2 += __shfl_xor_sync(0xffffffffu, s2, o); }
    const int warp = threadIdx.x >> 5, lane = threadIdx.x & 31;
    if (lane == 0) { rs[warp] = s; rs2[warp] = s2; }
    __syncthreads();
    if (warp == 0) {
        float t  = (lane < 8) ? rs[lane]  : 0.f;
        float t2 = (lane < 8) ? rs2[lane] : 0.f;
#pragma unroll
        for (int o = 4; o; o >>= 1) { t += __shfl_xor_sync(0xffffffffu, t, o); t2 += __shfl_xor_sync(0xffffffffu, t2, o); }
        if (lane == 0) { rs[0] = t; rs2[0] = t2; }
    }
    __syncthreads();
    const float mu  = rs[0] * (1.f / Dq);
    const float var = rs2[0] * (1.f / Dq) - mu * mu;
    const float inv = rsqrtf(var + 1e-5f);
#pragma unroll
    for (int i = 0; i < 3; i++) {
        int d = threadIdx.x + i * 256;
        out[(size_t)row * Dq + d] = (v[i] - mu) * inv * g[d] + be[d];
    }
}

// ====================================================================================
typedef CUresult (*EncFn)(CUtensorMap*, CUtensorMapDataType, cuuint32_t, void*,
                          const cuuint64_t*, const cuuint64_t*, const cuuint32_t*,
                          const cuuint32_t*, CUtensorMapInterleave, CUtensorMapSwizzle,
                          CUtensorMapL2promotion, CUtensorMapFloatOOBfill);

static void make_map(EncFn enc, CUtensorMap* m, void* ptr,
                     uint64_t d0, uint64_t d1, uint64_t d2)
{
    cuuint64_t dims[3] = {d0, d1, d2};
    cuuint64_t strides[2] = {d0 * 2, d0 * d1 * 2};
    cuuint32_t box[3] = {32, 256, 1};
    cuuint32_t es[3] = {1, 1, 1};
    enc(m, CU_TENSOR_MAP_DATA_TYPE_BFLOAT16, 3, ptr, dims, strides, box, es,
        CU_TENSOR_MAP_INTERLEAVE_NONE, CU_TENSOR_MAP_SWIZZLE_64B,
        CU_TENSOR_MAP_L2_PROMOTION_L2_128B, CU_TENSOR_MAP_FLOAT_OOB_FILL_NONE);
}

extern "C" void kernel_launch(void* const* d_in, const int* in_sizes, int n_in,
                              void* d_out, int out_size)
{
    const float* q   = (const float*)d_in[0];
    const float* k   = (const float*)d_in[1];
    const float* v   = (const float*)d_in[2];
    const float* Wq  = (const float*)d_in[3];
    const float* bq  = (const float*)d_in[4];
    const float* Wk  = (const float*)d_in[5];
    const float* bk  = (const float*)d_in[6];
    const float* Wv  = (const float*)d_in[7];
    const float* bv  = (const float*)d_in[8];
    const float* Wo  = (const float*)d_in[9];
    const float* bo  = (const float*)d_in[10];
    const float* ln1g= (const float*)d_in[11];
    const float* ln1b= (const float*)d_in[12];
    const float* ln2g= (const float*)d_in[13];
    const float* ln2b= (const float*)d_in[14];
    const float* Wg  = (const float*)d_in[15];
    const float* bg  = (const float*)d_in[16];
    const float* W1  = (const float*)d_in[17];
    const float* b1  = (const float*)d_in[18];
    const float* W2  = (const float*)d_in[19];
    const float* b2  = (const float*)d_in[20];
    float* out = (float*)d_out;

    float *p_qh, *p_kh, *p_vh, *p_ctx, *p_tmp, *p_x, *p_y, *p_gates;
    __nv_bfloat16 *p_inhi, *p_inlo, *p_xhi, *p_xlo, *p_hhi, *p_hlo;
    __nv_bfloat16 *p_w1h, *p_w2h;
    __nv_bfloat16 *p_wqh, *p_wql, *p_wkh, *p_wkl, *p_wvh, *p_wvl, *p_woh, *p_wol;
    cudaGetSymbolAddress((void**)&p_qh,   d_qh);
    cudaGetSymbolAddress((void**)&p_kh,   d_kh);
    cudaGetSymbolAddress((void**)&p_vh,   d_vh);
    cudaGetSymbolAddress((void**)&p_ctx,  d_ctx);
    cudaGetSymbolAddress((void**)&p_tmp,  d_tmp);
    cudaGetSymbolAddress((void**)&p_x,    d_x);
    cudaGetSymbolAddress((void**)&p_y,    d_y);
    cudaGetSymbolAddress((void**)&p_gates,d_gates);
    cudaGetSymbolAddress((void**)&p_inhi, d_inhi);
    cudaGetSymbolAddress((void**)&p_inlo, d_inlo);
    cudaGetSymbolAddress((void**)&p_xhi,  d_xhi);
    cudaGetSymbolAddress((void**)&p_xlo,  d_xlo);
    cudaGetSymbolAddress((void**)&p_hhi,  d_hhi);
    cudaGetSymbolAddress((void**)&p_hlo,  d_hlo);
    cudaGetSymbolAddress((void**)&p_w1h,  d_w1t_hi);
    cudaGetSymbolAddress((void**)&p_w2h,  d_w2t_hi);
    cudaGetSymbolAddress((void**)&p_wqh,  d_wqt_hi);
    cudaGetSymbolAddress((void**)&p_wql,  d_wqt_lo);
    cudaGetSymbolAddress((void**)&p_wkh,  d_wkt_hi);
    cudaGetSymbolAddress((void**)&p_wkl,  d_wkt_lo);
    cudaGetSymbolAddress((void**)&p_wvh,  d_wvt_hi);
    cudaGetSymbolAddress((void**)&p_wvl,  d_wvt_lo);
    cudaGetSymbolAddress((void**)&p_woh,  d_wot_hi);
    cudaGetSymbolAddress((void**)&p_wol,  d_wot_lo);

    static EncFn enc = nullptr;
    if (!enc) {
        void* fp = nullptr;
        cudaDriverEntryPointQueryResult st;
        cudaGetDriverEntryPointByVersion("cuTensorMapEncodeTiled", &fp, 12000,
                                         cudaEnableDefault, &st);
        enc = (EncFn)fp;
    }
    CUtensorMap mXh, mXl, mHh, mHl, mW1h, mW2h;
    make_map(enc, &mXh, p_xhi, Dq, MPAD, 1);
    make_map(enc, &mXl, p_xlo, Dq, MPAD, 1);
    make_map(enc, &mHh, p_hhi, Fq, MPAD, Eq);
    make_map(enc, &mHl, p_hlo, Fq, MPAD, Eq);
    make_map(enc, &mW1h, p_w1h, Dq, Fq, Eq);
    make_map(enc, &mW2h, p_w2h, Fq, Dq, Eq);

    const dim3 blk(256);
    const dim3 gridD(Dq / TN, NTOK / TM);
    const dim3 grid1(Fq / 256, MPAD / 256, Eq);
    const dim3 grid2(Dq / 256, MPAD / 256, Eq);
    const int n4 = NTOK * Dq / 4;
    const int sgrid = (n4 + 255) / 256;

    cudaFuncSetAttribute(tc_gemm<2>,  cudaFuncAttributeMaxDynamicSharedMemorySize, TC_SMEM);
    cudaFuncSetAttribute(tc_gemm<3>,  cudaFuncAttributeMaxDynamicSharedMemorySize, TC_SMEM);
    cudaFuncSetAttribute(tc_gemm2<0>, cudaFuncAttributeMaxDynamicSharedMemorySize, TC2_SMEM);
    cudaFuncSetAttribute(tc_gemm2<1>, cudaFuncAttributeMaxDynamicSharedMemorySize, TC2_SMEM);

    transpose_split<<<dim3(Dq/32, Dq/32, 1), blk>>>(Wq, p_wqh, p_wql, Dq, Dq);
    transpose_split<<<dim3(Dq/32, Dq/32, 1), blk>>>(Wk, p_wkh, p_wkl, Dq, Dq);
    transpose_split<<<dim3(Dq/32, Dq/32, 1), blk>>>(Wv, p_wvh, p_wvl, Dq, Dq);
    transpose_split<<<dim3(Dq/32, Dq/32, 1), blk>>>(Wo, p_woh, p_wol, Dq, Dq);
    transpose_split<<<dim3(Dq/32, Fq/32, Eq), blk>>>(W1, p_w1h, nullptr, Dq, Fq);
    transpose_split<<<dim3(Fq/32, Dq/32, Eq), blk>>>(W2, p_w2h, nullptr, Fq, Dq);

    split_bf16<<<sgrid, blk>>>(q, p_inhi, p_inlo, n4);
    tc_gemm<2><<<gridD, blk, TC_SMEM>>>(p_inhi, p_inlo, p_wqh, p_wql, bq,
                                        nullptr, p_qh, NTOK, Dq, Dq);
    split_bf16<<<sgrid, blk>>>(k, p_inhi, p_inlo, n4);
    tc_gemm<2><<<gridD, blk, TC_SMEM>>>(p_inhi, p_inlo, p_wkh, p_wkl, bk,
                                        nullptr, p_kh, NTOK, Dq, Dq);
    split_bf16<<<sgrid, blk>>>(v, p_inhi, p_inlo, n4);
    tc_gemm<2><<<gridD, blk, TC_SMEM>>>(p_inhi, p_inlo, p_wvh, p_wvl, bv,
                                        nullptr, p_vh, NTOK, Dq, Dq);

    const int smem_attn = (Sq * KPAD + Sq * DHq + 8 * 208 + 8 * DHq) * (int)sizeof(float);
    cudaFuncSetAttribute(attn_kernel, cudaFuncAttributeMaxDynamicSharedMemorySize, smem_attn);
    attn_kernel<<<dim3(Bq * Hq, 4), blk, smem_attn>>>(p_qh, p_kh, p_vh, p_ctx);

    split_bf16<<<sgrid, blk>>>(p_ctx, p_inhi, p_inlo, n4);
    tc_gemm<3><<<gridD, blk, TC_SMEM>>>(p_inhi, p_inlo, p_woh, p_wol, bo,
                                        q, p_tmp, NTOK, Dq, Dq);
    ln_kernel<<<NTOK, blk>>>(p_tmp, ln1g, ln1b, p_x, p_xhi, p_xlo);

    gate_kernel<<<(NTOK * 32 + 255) / 256, blk>>>(p_x, Wg, bg, p_gates);

    tc_gemm2<0><<<grid1, blk, TC2_SMEM>>>(
        mXh, mXl, mW1h, b1, nullptr, p_hhi, p_hlo,
        Fq, Dq, (size_t)Fq, (size_t)MPAD * Fq,
        p_xhi, p_xlo, p_w1h, (size_t)0, (size_t)Fq * Dq);
    tc_gemm2<1><<<grid2, blk, TC2_SMEM>>>(
        mHh, mHl, mW2h, b2, p_y, nullptr, nullptr,
        Dq, Fq, (size_t)Dq, (size_t)MPAD * Dq,
        p_hhi, p_hlo, p_w2h, (size_t)MPAD * Fq, (size_t)Dq * Fq);

    ln2_kernel<<<NTOK, blk>>>(p_x, p_y, p_gates, ln2g, ln2b, out);
}

// round 9
// speedup vs baseline: 7.0414x; 1.0612x over previous
#include <cuda_runtime.h>
#include <cuda.h>
#include <cuda_bf16.h>
#include <math.h>
#include <stdint.h>

#define Bq 32
#define Sq 196
#define Dq 768
#define Hq 12
#define Eq 8
#define Fq 3072
#define DHq 64
#define NTOK (Bq*Sq)
#define MPAD 6400

#define HAS_TCGEN05 (defined(__CUDA_ARCH_FEAT_SM103_ALL) || defined(__CUDA_ARCH_FEAT_SM100_ALL))

// ---------------- scratch ------------------------------------------------------
__device__ __align__(256) float d_qkvh[3*NTOK*Dq];     // q/k/v head projections
__device__ __align__(256) float d_ctx[NTOK*Dq];
__device__ __align__(256) float d_tmp[NTOK*Dq];
__device__ __align__(256) float d_x  [NTOK*Dq];
__device__ __align__(256) float d_y  [Eq*MPAD*Dq];
__device__ __align__(256) float d_gates[MPAD*Eq];

__device__ __align__(256) __nv_bfloat16 d_inhi[NTOK*Dq];
__device__ __align__(256) __nv_bfloat16 d_inlo[NTOK*Dq];
__device__ __align__(256) __nv_bfloat16 d_xhi[MPAD*Dq];
__device__ __align__(256) __nv_bfloat16 d_xlo[MPAD*Dq];
__device__ __align__(256) __nv_bfloat16 d_hhi[Eq*MPAD*Fq];  // also hosts q/k/v splits early
__device__ __align__(256) __nv_bfloat16 d_hlo[Eq*MPAD*Fq];
__device__ __align__(256) __nv_bfloat16 d_w1t_hi[Eq*Fq*Dq];   // hi only (MoE B-side)
__device__ __align__(256) __nv_bfloat16 d_w2t_hi[Eq*Dq*Fq];   // hi only
__device__ __align__(256) __nv_bfloat16 d_wqkvt_hi[3*Dq*Dq];  // contiguous Wq|Wk|Wv
__device__ __align__(256) __nv_bfloat16 d_wqkvt_lo[3*Dq*Dq];
__device__ __align__(256) __nv_bfloat16 d_wot_hi[Dq*Dq];
__device__ __align__(256) __nv_bfloat16 d_wot_lo[Dq*Dq];

// ---------------- PTX helpers ---------------------------------------------------
__device__ __forceinline__ uint32_t smem_u32(const void* p) {
    uint32_t a;
    asm("{ .reg .u64 t; cvta.to.shared.u64 t, %1; cvt.u32.u64 %0, t; }" : "=r"(a) : "l"(p));
    return a;
}

#if HAS_TCGEN05
__device__ __forceinline__ bool elect_one() {
    uint32_t p;
    asm volatile("{\n .reg .pred p;\n elect.sync _|p, 0xFFFFFFFF;\n selp.b32 %0,1,0,p;\n}" : "=r"(p));
    return p != 0;
}
#define MBARRIER_INIT(addr, cnt) \
    asm volatile("mbarrier.init.shared.b64 [%0], %1;" :: "r"((uint32_t)(addr)), "r"((uint32_t)(cnt)) : "memory")
#define MBARRIER_INVAL(addr) \
    asm volatile("mbarrier.inval.shared.b64 [%0];" :: "r"((uint32_t)(addr)) : "memory")
#define MBARRIER_EXPECT_TX(addr, tx) \
    asm volatile("mbarrier.arrive.expect_tx.shared.b64 _, [%0], %1;" \
        :: "r"((uint32_t)(addr)), "r"((uint32_t)(tx)) : "memory")
#define MBARRIER_WAIT_PARITY(mbar, par) do { \
    uint32_t _m = (uint32_t)(mbar), _p = (uint32_t)(par), _d; \
    asm volatile("{\n\t.reg .pred p;\n\t" \
        "mbarrier.try_wait.parity.acquire.cta.shared::cta.b64 p, [%1], %2;\n\t" \
        "selp.b32 %0, 1, 0, p;\n\t}" : "=r"(_d) : "r"(_m), "r"(_p) : "memory"); \
    if (!_d) { \
        asm volatile("{\n\t.reg .pred P1;\n\t" \
            "WL_%=:\n\t" \
            "mbarrier.try_wait.parity.acquire.cta.shared::cta.b64 P1, [%0], %1, 0x989680;\n\t" \
            "@P1 bra.uni WD_%=;\n\tbra.uni WL_%=;\n\tWD_%=:\n\t}" \
            :: "r"(_m), "r"(_p) : "memory"); \
    } \
} while(0)
#define TCGEN05_ALLOC(a, n) \
    asm volatile("tcgen05.alloc.cta_group::1.sync.aligned.shared::cta.b32 [%0], %1;" \
        :: "r"((uint32_t)(a)), "r"((uint32_t)(n)) : "memory")
#define TCGEN05_DEALLOC(t, n) \
    asm volatile("tcgen05.dealloc.cta_group::1.sync.aligned.b32 %0, %1;" :: "r"(t), "r"(n))
#define TCGEN05_RELINQ() \
    asm volatile("tcgen05.relinquish_alloc_permit.cta_group::1.sync.aligned;")
#define TCGEN05_COMMIT(m) \
    asm volatile("tcgen05.commit.cta_group::1.mbarrier::arrive::one.shared::cluster.b64 [%0];" \
        :: "r"((uint32_t)(m)) : "memory")
#define TCGEN05_FENCE_AFTER()  asm volatile("tcgen05.fence::after_thread_sync;" ::: "memory")
#define TCGEN05_FENCE_BEFORE() asm volatile("tcgen05.fence::before_thread_sync;" ::: "memory")
#define TCGEN05_WAIT_LD() asm volatile("tcgen05.wait::ld.sync.aligned;" ::: "memory")
#define FENCE_ASYNC_SHARED() asm volatile("fence.proxy.async.shared::cta;" ::: "memory")
#define CP_ASYNC16(dst, src) \
    asm volatile("cp.async.cg.shared.global [%0], [%1], 16;" :: "r"((uint32_t)(dst)), "l"(src))
#define CP_COMMIT() asm volatile("cp.async.commit_group;" ::: "memory")
#define CP_WAIT(n)  asm volatile("cp.async.wait_group %0;" :: "n"(n) : "memory")
#define TMA_LOAD_3D(sm, map, cx, cy, cz, mb) \
    asm volatile("cp.async.bulk.tensor.3d.shared::cta.global.tile.mbarrier::complete_tx::bytes " \
        "[%0], [%1, {%2, %3, %4}], [%5];" \
        :: "r"((uint32_t)(sm)), "l"(map), "r"((int32_t)(cx)), "r"((int32_t)(cy)), \
           "r"((int32_t)(cz)), "r"((uint32_t)(mb)) : "memory")
#define TCGEN05_LD_32X32B_X32(r, ta) \
    asm volatile("tcgen05.ld.sync.aligned.32x32b.x32.b32 " \
        "{%0, %1, %2, %3, %4, %5, %6, %7, %8, %9, %10, %11, %12, %13, %14, %15, " \
        " %16, %17, %18, %19, %20, %21, %22, %23, %24, %25, %26, %27, %28, %29, %30, %31}, [%32];" \
        : "=r"((r)[0]), "=r"((r)[1]), "=r"((r)[2]), "=r"((r)[3]), "=r"((r)[4]), "=r"((r)[5]), \
          "=r"((r)[6]), "=r"((r)[7]), "=r"((r)[8]), "=r"((r)[9]), "=r"((r)[10]), "=r"((r)[11]), \
          "=r"((r)[12]), "=r"((r)[13]), "=r"((r)[14]), "=r"((r)[15]), "=r"((r)[16]), "=r"((r)[17]), \
          "=r"((r)[18]), "=r"((r)[19]), "=r"((r)[20]), "=r"((r)[21]), "=r"((r)[22]), "=r"((r)[23]), \
          "=r"((r)[24]), "=r"((r)[25]), "=r"((r)[26]), "=r"((r)[27]), "=r"((r)[28]), "=r"((r)[29]), \
          "=r"((r)[30]), "=r"((r)[31]) : "r"(ta))

static constexpr uint64_t DESC_SW128 =
    (uint64_t(2) << 61) | (uint64_t(1) << 46) | (uint64_t(64) << 32) | (uint64_t(1) << 16);
static constexpr uint64_t DESC_SW64 =
    (uint64_t(4) << 61) | (uint64_t(1) << 46) | (uint64_t(32) << 32) | (uint64_t(1) << 16);
#define MKD128(a) (DESC_SW128 | ((uint64_t)((a) >> 4) & 0x3FFF))
#define MKD64(a)  (DESC_SW64  | ((uint64_t)((a) >> 4) & 0x3FFF))

__device__ __forceinline__ void mma_bf16_ss(uint32_t d, uint64_t ad, uint64_t bd,
                                            uint32_t idesc, uint32_t en) {
    asm volatile(
        "{\n\t.reg .pred p;\n\tsetp.ne.u32 p, %5, 0;\n\t"
        "tcgen05.mma.cta_group::1.kind::f16 [%0], %1, %2, %3, {%4,%4,%4,%4}, p;\n\t}"
        :: "r"(d), "l"(ad), "l"(bd), "r"(idesc), "r"(0u), "r"(en) : "memory");
}
static constexpr uint32_t IDESC_BF16 =
    (1u << 4) | (1u << 7) | (1u << 10) | ((256 / 8) << 17) | ((128 / 16) << 24);
#endif

// ======================= TM128 tc GEMM (QKV batched / O-proj) ===================
// MODE 2: Cf = AW + bias(z), z-batched   MODE 3: Cf = AW + bias + res
#define TM 128
#define TN 256
#define TK 64
#define STAGE_BYTES 98304
#define SM_DATA 1024
#define TC_SMEM (SM_DATA + 2*STAGE_BYTES)

#if HAS_TCGEN05
__device__ __forceinline__ void load_slab128(
    uint32_t sbase, int stage,
    const __nv_bfloat16* __restrict__ Ahi, const __nv_bfloat16* __restrict__ Alo,
    const __nv_bfloat16* __restrict__ Bhi, const __nv_bfloat16* __restrict__ Blo,
    int m0, int n0, int k0, int K)
{
    const int tid = threadIdx.x;
    const uint32_t base = sbase + SM_DATA + stage * STAGE_BYTES;
#pragma unroll
    for (int i = 0; i < 4; i++) {
        int idx = i * 256 + tid;
        int row = idx >> 3, c4 = idx & 7;
        int off = row * 128 + c4 * 16;
        int sw  = off ^ ((off >> 3) & 0x70);
        size_t g = (size_t)(m0 + row) * K + k0 + c4 * 8;
        CP_ASYNC16(base + sw, Ahi + g);
        CP_ASYNC16(base + 16384 + sw, Alo + g);
    }
#pragma unroll
    for (int i = 0; i < 8; i++) {
        int idx = i * 256 + tid;
        int row = idx >> 3, c4 = idx & 7;
        int off = row * 128 + c4 * 16;
        int sw  = off ^ ((off >> 3) & 0x70);
        size_t g = (size_t)(n0 + row) * K + k0 + c4 * 8;
        CP_ASYNC16(base + 32768 + sw, Bhi + g);
        CP_ASYNC16(base + 65536 + sw, Blo + g);
    }
    CP_COMMIT();
}
#endif

template<int MODE>
__global__ void __launch_bounds__(256)
tc_gemm(const __nv_bfloat16* __restrict__ Ahi, const __nv_bfloat16* __restrict__ Alo,
        const __nv_bfloat16* __restrict__ Bhi, const __nv_bfloat16* __restrict__ Blo,
        const float* __restrict__ b0, const float* __restrict__ b1,
        const float* __restrict__ b2, const float* __restrict__ res,
        float* __restrict__ Cf, int M, int N, int K,
        size_t sA, size_t sB, size_t sC)
{
    extern __shared__ __align__(1024) char smx[];
    const int z = blockIdx.z;
    Ahi += z * sA; Alo += z * sA;
    Bhi += z * sB; Blo += z * sB;
    Cf  += z * sC;
    const float* bias = (z == 0) ? b0 : (z == 1) ? b1 : b2;
#if HAS_TCGEN05
    const uint32_t sb = smem_u32(smx);
    const int tid = threadIdx.x;
    const int wid = tid >> 5, lane = tid & 31;
    const int m0 = blockIdx.y * TM, n0 = blockIdx.x * TN;

    if (wid == 0) { TCGEN05_ALLOC(sb, 256); TCGEN05_RELINQ(); }
    if (tid == 0) { MBARRIER_INIT(sb + 8, 1); MBARRIER_INIT(sb + 16, 1); }
    __syncthreads();
    uint32_t tmem;
    asm volatile("ld.shared.b32 %0, [%1];" : "=r"(tmem) : "r"(sb));

    const int NS = K / TK;
    load_slab128(sb, 0, Ahi, Alo, Bhi, Blo, m0, n0, 0, K);
    int ph0 = 0, ph1 = 0;
    for (int s = 0; s < NS; s++) {
        const int buf = s & 1;
        if (s + 1 < NS) {
            const int nb = 1 - buf;
            if (s >= 1) {
                if (nb == 0) { MBARRIER_WAIT_PARITY(sb + 8,  ph0); ph0 ^= 1; }
                else         { MBARRIER_WAIT_PARITY(sb + 16, ph1); ph1 ^= 1; }
            }
            load_slab128(sb, nb, Ahi, Alo, Bhi, Blo, m0, n0, (s + 1) * TK, K);
            CP_WAIT(1);
        } else {
            CP_WAIT(0);
        }
        FENCE_ASYNC_SHARED();
        __syncthreads();
        if (wid == 0) {
            TCGEN05_FENCE_AFTER();
            if (elect_one()) {
                const uint32_t tb = sb + SM_DATA + buf * STAGE_BYTES;
                const uint64_t ah = MKD128(tb), al = MKD128(tb + 16384);
                const uint64_t bh = MKD128(tb + 32768), bl = MKD128(tb + 65536);
#pragma unroll
                for (int ks = 0; ks < 4; ks++) {
                    const uint32_t en0 = (s == 0 && ks == 0) ? 0u : 1u;
                    mma_bf16_ss(tmem, ah + ks * 2, bh + ks * 2, IDESC_BF16, en0);
                    mma_bf16_ss(tmem, ah + ks * 2, bl + ks * 2, IDESC_BF16, 1u);
                    mma_bf16_ss(tmem, al + ks * 2, bh + ks * 2, IDESC_BF16, 1u);
                }
                TCGEN05_COMMIT(sb + 8 + buf * 8);
            }
        }
    }
    if (((NS - 1) & 1) == 0) { MBARRIER_WAIT_PARITY(sb + 8,  ph0); }
    else                     { MBARRIER_WAIT_PARITY(sb + 16, ph1); }
    TCGEN05_FENCE_AFTER();

    const int sub = wid & 3, cg = wid >> 2;
    const int row = m0 + sub * 32 + lane;
#pragma unroll
    for (int ch = 0; ch < 4; ch++) {
        const int colb = cg * 128 + ch * 32;
        uint32_t r[32];
        TCGEN05_LD_32X32B_X32(r, tmem + colb);
        TCGEN05_WAIT_LD();
        const size_t base = (size_t)row * N + n0 + colb;
        const float4* bv = (const float4*)(bias + n0 + colb);
        float4* dst = (float4*)(Cf + base);
        const float4* rv = (MODE == 3) ? (const float4*)(res + base) : nullptr;
#pragma unroll
        for (int i = 0; i < 8; i++) {
            float4 b4 = bv[i];
            float4 o;
            o.x = __uint_as_float(r[i*4+0]) + b4.x;
            o.y = __uint_as_float(r[i*4+1]) + b4.y;
            o.z = __uint_as_float(r[i*4+2]) + b4.z;
            o.w = __uint_as_float(r[i*4+3]) + b4.w;
            if (MODE == 3) { float4 t = rv[i]; o.x += t.x; o.y += t.y; o.z += t.z; o.w += t.w; }
            dst[i] = o;
        }
    }
    TCGEN05_FENCE_BEFORE();
    __syncthreads();
    if (tid == 0) { MBARRIER_INVAL(sb + 8); MBARRIER_INVAL(sb + 16); }
    __syncthreads();
    if (wid == 0) TCGEN05_DEALLOC(tmem, 256);
#else
    float* As = (float*)smx;
    float* Bs = As + 16 * 128;
    const int tid = threadIdx.x;
    const int m0 = blockIdx.y * TM, n0x = blockIdx.x * TN;
    const int tx = tid & 15, ty = tid >> 4;
    const int mr = ty * 8, nr = tx * 8;
    for (int half = 0; half < 2; half++) {
        const int n0 = n0x + half * 128;
        float acc[8][8];
#pragma unroll
        for (int i = 0; i < 8; i++)
#pragma unroll
            for (int j = 0; j < 8; j++) acc[i][j] = 0.f;
        for (int k0 = 0; k0 < K; k0 += 16) {
            __syncthreads();
#pragma unroll
            for (int i = 0; i < 8; i++) {
                int idx = i * 256 + tid;
                int kk = idx >> 7, mm = idx & 127;
                size_t ga = (size_t)(m0 + mm) * K + k0 + kk;
                size_t gb = (size_t)(n0 + mm) * K + k0 + kk;
                As[kk*128+mm] = __bfloat162float(Ahi[ga]) + __bfloat162float(Alo[ga]);
                Bs[kk*128+mm] = __bfloat162float(Bhi[gb]) + __bfloat162float(Blo[gb]);
            }
            __syncthreads();
#pragma unroll
            for (int kk = 0; kk < 16; kk++) {
                float a0[8], b0r[8];
#pragma unroll
                for (int i = 0; i < 8; i++) a0[i] = As[kk*128+mr+i];
#pragma unroll
                for (int j = 0; j < 8; j++) b0r[j] = Bs[kk*128+nr+j];
#pragma unroll
                for (int i = 0; i < 8; i++)
#pragma unroll
                    for (int j = 0; j < 8; j++)
                        acc[i][j] = fmaf(a0[i], b0r[j], acc[i][j]);
            }
        }
#pragma unroll
        for (int i = 0; i < 8; i++) {
            const int row = m0 + mr + i;
#pragma unroll
            for (int j = 0; j < 8; j++) {
                const int col = n0 + nr + j;
                const size_t idx = (size_t)row * N + col;
                float v = acc[i][j] + bias[col];
                if (MODE == 2) Cf[idx] = v; else Cf[idx] = v + res[idx];
            }
        }
    }
#endif
}

// ======================= MoE GEMM: TMA producer/consumer, B=bf16-hi only ========
// tile M256 x N256, TK=32, SW64, 4 stages x 48KB, z = expert, 8 MMAs/slab
#define T2K 32
#define ST2 49152
#define TC2_SMEM (1024 + 4*ST2)   // 197632

template<int MODE>   // 0: gelu->split bf16    1: Cf = acc + bias
__global__ void __launch_bounds__(256)
tc_gemm2(const __grid_constant__ CUtensorMap mAh, const __grid_constant__ CUtensorMap mAl,
         const __grid_constant__ CUtensorMap mBh,
         const float* __restrict__ bias, float* __restrict__ Cf,
         __nv_bfloat16* __restrict__ Chi, __nv_bfloat16* __restrict__ Clo,
         int N, int K, size_t sBias, size_t sC,
         const __nv_bfloat16* __restrict__ Ahi, const __nv_bfloat16* __restrict__ Alo,
         const __nv_bfloat16* __restrict__ Bh, size_t sA, size_t sB)
{
    extern __shared__ __align__(1024) char smx[];
    const int z = blockIdx.z;
    bias += z * sBias;
#if HAS_TCGEN05
    const uint32_t sb = smem_u32(smx);
    const int tid = threadIdx.x;
    const int wid = tid >> 5, lane = tid & 31;
    const int m0 = blockIdx.y * 256, n0 = blockIdx.x * 256;
    const int za = (MODE == 0) ? 0 : z;

    if (wid == 0) { TCGEN05_ALLOC(sb, 512); TCGEN05_RELINQ(); }
    if (tid == 0) {
        MBARRIER_INIT(sb + 8,  1); MBARRIER_INIT(sb + 16, 1);
        MBARRIER_INIT(sb + 24, 1); MBARRIER_INIT(sb + 32, 1);
        MBARRIER_INIT(sb + 40, 1); MBARRIER_INIT(sb + 48, 1);
        MBARRIER_INIT(sb + 56, 1); MBARRIER_INIT(sb + 64, 1);
        MBARRIER_INIT(sb + 72, 1);
        FENCE_ASYNC_SHARED();
    }
    __syncthreads();
    uint32_t tmem;
    asm volatile("ld.shared.b32 %0, [%1];" : "=r"(tmem) : "r"(sb));

    const int NS = K / T2K;
    if (wid == 1) {
        if (elect_one()) {
            for (int s = 0; s < NS; s++) {
                const int st = s & 3;
                if (s >= 4) MBARRIER_WAIT_PARITY(sb + 40 + st * 8, ((s >> 2) - 1) & 1);
                MBARRIER_EXPECT_TX(sb + 8 + st * 8, 49152u);
                const uint32_t stb = sb + 1024 + st * ST2;
                const int k0 = s * T2K;
                TMA_LOAD_3D(stb,         &mAh, k0, m0, za, sb + 8 + st * 8);
                TMA_LOAD_3D(stb + 16384, &mAl, k0, m0, za, sb + 8 + st * 8);
                TMA_LOAD_3D(stb + 32768, &mBh, k0, n0, z,  sb + 8 + st * 8);
            }
        }
    } else if (wid == 0) {
        TCGEN05_FENCE_AFTER();
        if (elect_one()) {
            for (int s = 0; s < NS; s++) {
                const int st = s & 3;
                MBARRIER_WAIT_PARITY(sb + 8 + st * 8, (s >> 2) & 1);
                const uint32_t tb = sb + 1024 + st * ST2;
                const uint64_t a0h = MKD64(tb),        a0l = MKD64(tb + 16384);
                const uint64_t a1h = a0h + 512,        a1l = a0l + 512;
                const uint64_t bh  = MKD64(tb + 32768);
#pragma unroll
                for (int ks = 0; ks < 2; ks++) {
                    const uint32_t en0 = (s == 0 && ks == 0) ? 0u : 1u;
                    mma_bf16_ss(tmem,       a0h + ks * 2, bh + ks * 2, IDESC_BF16, en0);
                    mma_bf16_ss(tmem,       a0l + ks * 2, bh + ks * 2, IDESC_BF16, 1u);
                    mma_bf16_ss(tmem + 256, a1h + ks * 2, bh + ks * 2, IDESC_BF16, en0);
                    mma_bf16_ss(tmem + 256, a1l + ks * 2, bh + ks * 2, IDESC_BF16, 1u);
                }
                TCGEN05_COMMIT(sb + 40 + st * 8);
            }
            TCGEN05_COMMIT(sb + 72);
        }
    }

    MBARRIER_WAIT_PARITY(sb + 72, 0);
    TCGEN05_FENCE_AFTER();

    const int accSel = wid >> 2, sub = wid & 3;
    const int row = m0 + accSel * 128 + sub * 32 + lane;
    const uint32_t tacc = tmem + accSel * 256;
    if (MODE == 0) { Chi += z * sC; Clo += z * sC; }
    else           { Cf  += z * sC; }
#pragma unroll
    for (int ch = 0; ch < 8; ch++) {
        const int colb = ch * 32;
        uint32_t r[32];
        TCGEN05_LD_32X32B_X32(r, tacc + colb);
        TCGEN05_WAIT_LD();
        const size_t base = (size_t)row * N + n0 + colb;
        const float4* bv = (const float4*)(bias + n0 + colb);
        if (MODE == 0) {
            uint4* dh = (uint4*)(Chi + base);
            uint4* dl = (uint4*)(Clo + base);
#pragma unroll
            for (int i = 0; i < 4; i++) {
                uint32_t hp[4], lp[4];
#pragma unroll
                for (int p = 0; p < 4; p++) {
                    float4 b4 = bv[i * 2 + (p >> 1)];
                    float b0 = (p & 1) ? b4.z : b4.x;
                    float b1 = (p & 1) ? b4.w : b4.y;
                    float v0 = __uint_as_float(r[i*8+p*2+0]) + b0;
                    float v1 = __uint_as_float(r[i*8+p*2+1]) + b1;
                    float g0 = 0.5f * v0 * (1.f + erff(v0 * 0.70710678118654752f));
                    float g1 = 0.5f * v1 * (1.f + erff(v1 * 0.70710678118654752f));
                    __nv_bfloat16 h0 = __float2bfloat16(g0);
                    __nv_bfloat16 h1 = __float2bfloat16(g1);
                    __nv_bfloat16 l0 = __float2bfloat16(g0 - __bfloat162float(h0));
                    __nv_bfloat16 l1 = __float2bfloat16(g1 - __bfloat162float(h1));
                    hp[p] = (uint32_t)__bfloat16_as_ushort(h0) | ((uint32_t)__bfloat16_as_ushort(h1) << 16);
                    lp[p] = (uint32_t)__bfloat16_as_ushort(l0) | ((uint32_t)__bfloat16_as_ushort(l1) << 16);
                }
                dh[i] = make_uint4(hp[0], hp[1], hp[2], hp[3]);
                dl[i] = make_uint4(lp[0], lp[1], lp[2], lp[3]);
            }
        } else {
            float4* dst = (float4*)(Cf + base);
#pragma unroll
            for (int i = 0; i < 8; i++) {
                float4 b4 = bv[i];
                float4 o;
                o.x = __uint_as_float(r[i*4+0]) + b4.x;
                o.y = __uint_as_float(r[i*4+1]) + b4.y;
                o.z = __uint_as_float(r[i*4+2]) + b4.z;
                o.w = __uint_as_float(r[i*4+3]) + b4.w;
                dst[i] = o;
            }
        }
    }
    TCGEN05_FENCE_BEFORE();
    __syncthreads();
    if (tid == 0) {
        MBARRIER_INVAL(sb + 8);  MBARRIER_INVAL(sb + 16); MBARRIER_INVAL(sb + 24);
        MBARRIER_INVAL(sb + 32); MBARRIER_INVAL(sb + 40); MBARRIER_INVAL(sb + 48);
        MBARRIER_INVAL(sb + 56); MBARRIER_INVAL(sb + 64); MBARRIER_INVAL(sb + 72);
    }
    __syncthreads();
    if (wid == 0) TCGEN05_DEALLOC(tmem, 512);
#else
    const __nv_bfloat16* Ah = Ahi + (size_t)((MODE == 0) ? 0 : z) * sA;
    const __nv_bfloat16* Al = Alo + (size_t)((MODE == 0) ? 0 : z) * sA;
    const __nv_bfloat16* Bp = Bh + (size_t)z * sB;
    if (MODE == 0) { Chi += z * sC; Clo += z * sC; }
    else           { Cf  += z * sC; }
    float* As = (float*)smx;
    float* Bs = As + 16 * 128;
    const int tid = threadIdx.x;
    const int tx = tid & 15, ty = tid >> 4;
    const int mr = ty * 8, nr = tx * 8;
    for (int mh = 0; mh < 2; mh++)
    for (int nh = 0; nh < 2; nh++) {
        const int m0 = blockIdx.y * 256 + mh * 128;
        const int n0 = blockIdx.x * 256 + nh * 128;
        float acc[8][8];
#pragma unroll
        for (int i = 0; i < 8; i++)
#pragma unroll
            for (int j = 0; j < 8; j++) acc[i][j] = 0.f;
        for (int k0 = 0; k0 < K; k0 += 16) {
            __syncthreads();
#pragma unroll
            for (int i = 0; i < 8; i++) {
                int idx = i * 256 + tid;
                int kk = idx >> 7, mm = idx & 127;
                size_t ga = (size_t)(m0 + mm) * K + k0 + kk;
                size_t gb = (size_t)(n0 + mm) * K + k0 + kk;
                As[kk*128+mm] = __bfloat162float(Ah[ga]) + __bfloat162float(Al[ga]);
                Bs[kk*128+mm] = __bfloat162float(Bp[gb]);
            }
            __syncthreads();
#pragma unroll
            for (int kk = 0; kk < 16; kk++) {
                float a0[8], b0[8];
#pragma unroll
                for (int i = 0; i < 8; i++) a0[i] = As[kk*128+mr+i];
#pragma unroll
                for (int j = 0; j < 8; j++) b0[j] = Bs[kk*128+nr+j];
#pragma unroll
                for (int i = 0; i < 8; i++)
#pragma unroll
                    for (int j = 0; j < 8; j++)
                        acc[i][j] = fmaf(a0[i], b0[j], acc[i][j]);
            }
        }
#pragma unroll
        for (int i = 0; i < 8; i++) {
            const int row = m0 + mr + i;
#pragma unroll
            for (int j = 0; j < 8; j++) {
                const int col = n0 + nr + j;
                const size_t idx = (size_t)row * N + col;
                float v = acc[i][j] + bias[col];
                if (MODE == 0) {
                    float g = 0.5f * v * (1.f + erff(v * 0.70710678118654752f));
                    __nv_bfloat16 h = __float2bfloat16(g);
                    Chi[idx] = h;
                    Clo[idx] = __float2bfloat16(g - __bfloat162float(h));
                } else Cf[idx] = v;
            }
        }
    }
#endif
}

// ---------------- transpose v2: W[e][K][N] -> T[e][N][K], vectorized ----------------
// tile 64(k) x 32(n); stores pack 2 bf16 per uint32 -> 128B/warp both directions
__global__ void __launch_bounds__(256)
transpose_split(const float* __restrict__ W, __nv_bfloat16* __restrict__ Thi,
                __nv_bfloat16* __restrict__ Tlo, int K, int N)
{
    __shared__ float t[64][33];
    const int e = blockIdx.z;
    const float* Wp = W + (size_t)e * K * N;
    __nv_bfloat16* th = Thi + (size_t)e * K * N;
    __nv_bfloat16* tl = Tlo ? Tlo + (size_t)e * K * N : nullptr;
    const int k0 = blockIdx.x * 64, n0 = blockIdx.y * 32;
    const int tid = threadIdx.x;
#pragma unroll
    for (int i = 0; i < 8; i++) {
        int idx = i * 256 + tid;           // 0..2047
        int r = idx >> 5, c = idx & 31;
        t[r][c] = Wp[(size_t)(k0 + r) * N + n0 + c];
    }
    __syncthreads();
#pragma unroll
    for (int i = 0; i < 4; i++) {
        int idx = i * 256 + tid;           // 0..1023
        int c = idx >> 5, j = idx & 31;
        float v0 = t[2 * j][c], v1 = t[2 * j + 1][c];
        __nv_bfloat16 h0 = __float2bfloat16(v0);
        __nv_bfloat16 h1 = __float2bfloat16(v1);
        const size_t base = (size_t)(n0 + c) * K + k0 + 2 * j;
        *(uint32_t*)(th + base) =
            (uint32_t)__bfloat16_as_ushort(h0) | ((uint32_t)__bfloat16_as_ushort(h1) << 16);
        if (tl) {
            __nv_bfloat16 l0 = __float2bfloat16(v0 - __bfloat162float(h0));
            __nv_bfloat16 l1 = __float2bfloat16(v1 - __bfloat162float(h1));
            *(uint32_t*)(tl + base) =
                (uint32_t)__bfloat16_as_ushort(l0) | ((uint32_t)__bfloat16_as_ushort(l1) << 16);
        }
    }
}

// ---------------- batched q/k/v split (3 segments) ----------------------------------
__global__ void __launch_bounds__(256)
split3_bf16(const float* __restrict__ q, const float* __restrict__ k,
            const float* __restrict__ v, __nv_bfloat16* __restrict__ hi,
            __nv_bfloat16* __restrict__ lo, int n4)
{
    const int seg = blockIdx.y;
    const float* x = (seg == 0) ? q : (seg == 1) ? k : v;
    int i = blockIdx.x * 256 + threadIdx.x;
    if (i >= n4) return;
    float4 val = ((const float4*)x)[i];
    __nv_bfloat16 h0 = __float2bfloat16(val.x), h1 = __float2bfloat16(val.y);
    __nv_bfloat16 h2 = __float2bfloat16(val.z), h3 = __float2bfloat16(val.w);
    uint2 hp, lp;
    hp.x = (uint32_t)__bfloat16_as_ushort(h0) | ((uint32_t)__bfloat16_as_ushort(h1) << 16);
    hp.y = (uint32_t)__bfloat16_as_ushort(h2) | ((uint32_t)__bfloat16_as_ushort(h3) << 16);
    __nv_bfloat16 l0 = __float2bfloat16(val.x - __bfloat162float(h0));
    __nv_bfloat16 l1 = __float2bfloat16(val.y - __bfloat162float(h1));
    __nv_bfloat16 l2 = __float2bfloat16(val.z - __bfloat162float(h2));
    __nv_bfloat16 l3 = __float2bfloat16(val.w - __bfloat162float(h3));
    lp.x = (uint32_t)__bfloat16_as_ushort(l0) | ((uint32_t)__bfloat16_as_ushort(l1) << 16);
    lp.y = (uint32_t)__bfloat16_as_ushort(l2) | ((uint32_t)__bfloat16_as_ushort(l3) << 16);
    const size_t off = (size_t)seg * n4 + i;
    ((uint2*)hi)[off] = hp;
    ((uint2*)lo)[off] = lp;
}

// ---------------- single split (ctx) -------------------------------------------------
__global__ void __launch_bounds__(256)
split_bf16(const float* __restrict__ x, __nv_bfloat16* __restrict__ hi,
           __nv_bfloat16* __restrict__ lo, int n4)
{
    int i = blockIdx.x * 256 + threadIdx.x;
    if (i >= n4) return;
    float4 v = ((const float4*)x)[i];
    __nv_bfloat16 h0 = __float2bfloat16(v.x), h1 = __float2bfloat16(v.y);
    __nv_bfloat16 h2 = __float2bfloat16(v.z), h3 = __float2bfloat16(v.w);
    uint2 hp, lp;
    hp.x = (uint32_t)__bfloat16_as_ushort(h0) | ((uint32_t)__bfloat16_as_ushort(h1) << 16);
    hp.y = (uint32_t)__bfloat16_as_ushort(h2) | ((uint32_t)__bfloat16_as_ushort(h3) << 16);
    __nv_bfloat16 l0 = __float2bfloat16(v.x - __bfloat162float(h0));
    __nv_bfloat16 l1 = __float2bfloat16(v.y - __bfloat162float(h1));
    __nv_bfloat16 l2 = __float2bfloat16(v.z - __bfloat162float(h2));
    __nv_bfloat16 l3 = __float2bfloat16(v.w - __bfloat162float(h3));
    lp.x = (uint32_t)__bfloat16_as_ushort(l0) | ((uint32_t)__bfloat16_as_ushort(l1) << 16);
    lp.y = (uint32_t)__bfloat16_as_ushort(l2) | ((uint32_t)__bfloat16_as_ushort(l3) << 16);
    ((uint2*)hi)[i] = hp;
    ((uint2*)lo)[i] = lp;
}

// ---------------- attention: 4 CTAs per (b,h) --------------------------------------
#define KPAD 65
__global__ void __launch_bounds__(256)
attn_kernel(const float* __restrict__ qh, const float* __restrict__ kh,
            const float* __restrict__ vh, float* __restrict__ ctx)
{
    const int b = blockIdx.x / Hq;
    const int h = blockIdx.x % Hq;
    const int qbase = blockIdx.y * 49;
    const int qend  = min(196, qbase + 49);
    extern __shared__ float sm[];
    float* Ks = sm;
    float* Vs = Ks + Sq * KPAD;
    float* Ps = Vs + Sq * DHq;
    float* Qs = Ps + 8 * 208;
    const int tid = threadIdx.x;
    for (int i = tid; i < Sq * DHq; i += 256) {
        int s = i / DHq, d = i % DHq;
        size_t gidx = (size_t)(b * Sq + s) * Dq + h * DHq + d;
        Ks[s * KPAD + d] = kh[gidx];
        Vs[s * DHq  + d] = vh[gidx];
    }
    __syncthreads();
    const int warp = tid >> 5, lane = tid & 31;
    float* p    = Ps + warp * 208;
    float* qrow = Qs + warp * DHq;
    for (int q = qbase + warp; q < qend; q += 8) {
        for (int d = lane; d < DHq; d += 32)
            qrow[d] = qh[(size_t)(b * Sq + q) * Dq + h * DHq + d];
        __syncwarp();
        float lmax = -1e30f;
        for (int col = lane; col < Sq; col += 32) {
            float s = 0.f;
            const float* kr = Ks + col * KPAD;
#pragma unroll 16
            for (int d = 0; d < DHq; d++) s = fmaf(qrow[d], kr[d], s);
            s *= 0.125f;
            p[col] = s;
            lmax = fmaxf(lmax, s);
        }
#pragma unroll
        for (int o = 16; o; o >>= 1) lmax = fmaxf(lmax, __shfl_xor_sync(0xffffffffu, lmax, o));
        float lsum = 0.f;
        for (int col = lane; col < Sq; col += 32) {
            float e = __expf(p[col] - lmax);
            p[col] = e;
            lsum += e;
        }
#pragma unroll
        for (int o = 16; o; o >>= 1) lsum += __shfl_xor_sync(0xffffffffu, lsum, o);
        const float inv = 1.f / lsum;
        __syncwarp();
        for (int d = lane; d < DHq; d += 32) {
            float a = 0.f;
            for (int k = 0; k < Sq; k++) a = fmaf(p[k], Vs[k * DHq + d], a);
            ctx[(size_t)(b * Sq + q) * Dq + h * DHq + d] = a * inv;
        }
        __syncwarp();
    }
}

// ---------------- gate softmax ------------------------------------------------------
__global__ void __launch_bounds__(256)
gate_kernel(const float* __restrict__ x, const float* __restrict__ Wg,
            const float* __restrict__ bg, float* __restrict__ gates)
{
    const int warp = (blockIdx.x * 256 + threadIdx.x) >> 5;
    const int lane = threadIdx.x & 31;
    if (warp >= NTOK) return;
    const float* xr = x + (size_t)warp * Dq;
    float lg[Eq];
#pragma unroll
    for (int e = 0; e < Eq; e++) lg[e] = 0.f;
    for (int d = lane; d < Dq; d += 32) {
        float xv = xr[d];
#pragma unroll
        for (int e = 0; e < Eq; e++) lg[e] = fmaf(xv, Wg[d * Eq + e], lg[e]);
    }
#pragma unroll
    for (int e = 0; e < Eq; e++)
#pragma unroll
        for (int o = 16; o; o >>= 1) lg[e] += __shfl_xor_sync(0xffffffffu, lg[e], o);
    if (lane == 0) {
        float m = -1e30f;
#pragma unroll
        for (int e = 0; e < Eq; e++) { lg[e] += bg[e]; m = fmaxf(m, lg[e]); }
        float s = 0.f;
#pragma unroll
        for (int e = 0; e < Eq; e++) { lg[e] = __expf(lg[e] - m); s += lg[e]; }
        float inv = 1.f / s;
#pragma unroll
        for (int e = 0; e < Eq; e++) gates[(size_t)warp * Eq + e] = lg[e] * inv;
    }
}

// ---------------- LN1 (emits split-bf16) ---------------------------------------------
__global__ void __launch_bounds__(256)
ln_kernel(const float* __restrict__ a, const float* __restrict__ g,
          const float* __restrict__ be, float* __restrict__ out,
          __nv_bfloat16* __restrict__ ohi, __nv_bfloat16* __restrict__ olo)
{
    const int row = blockIdx.x;
    const float* ar = a + (size_t)row * Dq;
    float v[3];
    float s = 0.f, s2 = 0.f;
#pragma unroll
    for (int i = 0; i < 3; i++) {
        int d = threadIdx.x + i * 256;
        float x = ar[d];
        v[i] = x;
        s += x; s2 = fmaf(x, x, s2);
    }
    __shared__ float rs[8], rs2[8];
#pragma unroll
    for (int o = 16; o; o >>= 1) { s += __shfl_xor_sync(0xffffffffu, s, o); s2 += __shfl_xor_sync(0xffffffffu, s2, o); }
    const int warp = threadIdx.x >> 5, lane = threadIdx.x & 31;
    if (lane == 0) { rs[warp] = s; rs2[warp] = s2; }
    __syncthreads();
    if (warp == 0) {
        float t  = (lane < 8) ? rs[lane]  : 0.f;
        float t2 = (lane < 8) ? rs2[lane] : 0.f;
#pragma unroll
        for (int o = 4; o; o >>= 1) { t += __shfl_xor_sync(0xffffffffu, t, o); t2 += __shfl_xor_sync(0xffffffffu, t2, o); }
        if (lane == 0) { rs[0] = t; rs2[0] = t2; }
    }
    __syncthreads();
    const float mu  = rs[0] * (1.f / Dq);
    const float var = rs2[0] * (1.f / Dq) - mu * mu;
    const float inv = rsqrtf(var + 1e-5f);
#pragma unroll
    for (int i = 0; i < 3; i++) {
        int d = threadIdx.x + i * 256;
        float y = (v[i] - mu) * inv * g[d] + be[d];
        const size_t idx = (size_t)row * Dq + d;
        out[idx] = y;
        __nv_bfloat16 h = __float2bfloat16(y);
        ohi[idx] = h;
        olo[idx] = __float2bfloat16(y - __bfloat162float(h));
    }
}

// ---------------- LN2: fused gate-weighted expert reduction --------------------------
__global__ void __launch_bounds__(256)
ln2_kernel(const float* __restrict__ x, const float* __restrict__ y,
           const float* __restrict__ gates, const float* __restrict__ g,
           const float* __restrict__ be, float* __restrict__ out)
{
    const int row = blockIdx.x;
    __shared__ float sg[Eq];
    if (threadIdx.x < Eq) sg[threadIdx.x] = gates[(size_t)row * Eq + threadIdx.x];
    __syncthreads();
    float v[3];
    float s = 0.f, s2 = 0.f;
#pragma unroll
    for (int i = 0; i < 3; i++) {
        int d = threadIdx.x + i * 256;
        float val = x[(size_t)row * Dq + d];
#pragma unroll
        for (int e = 0; e < Eq; e++)
            val = fmaf(sg[e], y[(size_t)e * MPAD * Dq + (size_t)row * Dq + d], val);
        v[i] = val;
        s += val; s2 = fmaf(val, val, s2);
    }
    __shared__ float rs[8], rs2[8];
#pragma unroll
    for (int o = 16; o; o >>= 1) { s += __shfl_xor_sync(0xffffffffu, s, o); s2 += __shfl_xor_sync(0xffffffffu, s2, o); }
    const int warp = threadIdx.x >> 5, lane = threadIdx.x & 31;
    if (lane == 0) { rs[warp] = s; rs2[warp] = s2; }
    __syncthreads();
    if (warp == 0) {
        float t  = (lane < 8) ? rs[lane]  : 0.f;
        float t2 = (lane < 8) ? rs2[lane] : 0.f;
#pragma unroll
        for (int o = 4; o; o >>= 1) { t += __shfl_xor_sync(0xffffffffu, t, o); t2 += __shfl_xor_sync(0xffffffffu, t2, o); }
        if (lane == 0) { rs[0] = t; rs2[0] = t2; }
    }
    __syncthreads();
    const float mu  = rs[0] * (1.f / Dq);
    const float var = rs2[0] * (1.f / Dq) - mu * mu;
    const float inv = rsqrtf(var + 1e-5f);
#pragma unroll
    for (int i = 0; i < 3; i++) {
        int d = threadIdx.x + i * 256;
        out[(size_t)row * Dq + d] = (v[i] - mu) * inv * g[d] + be[d];
    }
}

// ====================================================================================
typedef CUresult (*EncFn)(CUtensorMap*, CUtensorMapDataType, cuuint32_t, void*,
                          const cuuint64_t*, const cuuint64_t*, const cuuint32_t*,
                          const cuuint32_t*, CUtensorMapInterleave, CUtensorMapSwizzle,
                          CUtensorMapL2promotion, CUtensorMapFloatOOBfill);

static void make_map(EncFn enc, CUtensorMap* m, void* ptr,
                     uint64_t d0, uint64_t d1, uint64_t d2)
{
    cuuint64_t dims[3] = {d0, d1, d2};
    cuuint64_t strides[2] = {d0 * 2, d0 * d1 * 2};
    cuuint32_t box[3] = {32, 256, 1};
    cuuint32_t es[3] = {1, 1, 1};
    enc(m, CU_TENSOR_MAP_DATA_TYPE_BFLOAT16, 3, ptr, dims, strides, box, es,
        CU_TENSOR_MAP_INTERLEAVE_NONE, CU_TENSOR_MAP_SWIZZLE_64B,
        CU_TENSOR_MAP_L2_PROMOTION_L2_128B, CU_TENSOR_MAP_FLOAT_OOB_FILL_NONE);
}

extern "C" void kernel_launch(void* const* d_in, const int* in_sizes, int n_in,
                              void* d_out, int out_size)
{
    const float* q   = (const float*)d_in[0];
    const float* k   = (const float*)d_in[1];
    const float* v   = (const float*)d_in[2];
    const float* Wq  = (const float*)d_in[3];
    const float* bq  = (const float*)d_in[4];
    const float* Wk  = (const float*)d_in[5];
    const float* bk  = (const float*)d_in[6];
    const float* Wv  = (const float*)d_in[7];
    const float* bv  = (const float*)d_in[8];
    const float* Wo  = (const float*)d_in[9];
    const float* bo  = (const float*)d_in[10];
    const float* ln1g= (const float*)d_in[11];
    const float* ln1b= (const float*)d_in[12];
    const float* ln2g= (const float*)d_in[13];
    const float* ln2b= (const float*)d_in[14];
    const float* Wg  = (const float*)d_in[15];
    const float* bg  = (const float*)d_in[16];
    const float* W1  = (const float*)d_in[17];
    const float* b1  = (const float*)d_in[18];
    const float* W2  = (const float*)d_in[19];
    const float* b2  = (const float*)d_in[20];
    float* out = (float*)d_out;

    float *p_qkvh, *p_ctx, *p_tmp, *p_x, *p_y, *p_gates;
    __nv_bfloat16 *p_inhi, *p_inlo, *p_xhi, *p_xlo, *p_hhi, *p_hlo;
    __nv_bfloat16 *p_w1h, *p_w2h, *p_wqkvh, *p_wqkvl, *p_woh, *p_wol;
    cudaGetSymbolAddress((void**)&p_qkvh, d_qkvh);
    cudaGetSymbolAddress((void**)&p_ctx,  d_ctx);
    cudaGetSymbolAddress((void**)&p_tmp,  d_tmp);
    cudaGetSymbolAddress((void**)&p_x,    d_x);
    cudaGetSymbolAddress((void**)&p_y,    d_y);
    cudaGetSymbolAddress((void**)&p_gates,d_gates);
    cudaGetSymbolAddress((void**)&p_inhi, d_inhi);
    cudaGetSymbolAddress((void**)&p_inlo, d_inlo);
    cudaGetSymbolAddress((void**)&p_xhi,  d_xhi);
    cudaGetSymbolAddress((void**)&p_xlo,  d_xlo);
    cudaGetSymbolAddress((void**)&p_hhi,  d_hhi);
    cudaGetSymbolAddress((void**)&p_hlo,  d_hlo);
    cudaGetSymbolAddress((void**)&p_w1h,  d_w1t_hi);
    cudaGetSymbolAddress((void**)&p_w2h,  d_w2t_hi);
    cudaGetSymbolAddress((void**)&p_wqkvh, d_wqkvt_hi);
    cudaGetSymbolAddress((void**)&p_wqkvl, d_wqkvt_lo);
    cudaGetSymbolAddress((void**)&p_woh,  d_wot_hi);
    cudaGetSymbolAddress((void**)&p_wol,  d_wot_lo);

    static EncFn enc = nullptr;
    if (!enc) {
        void* fp = nullptr;
        cudaDriverEntryPointQueryResult st;
        cudaGetDriverEntryPointByVersion("cuTensorMapEncodeTiled", &fp, 12000,
                                         cudaEnableDefault, &st);
        enc = (EncFn)fp;
    }
    CUtensorMap mXh, mXl, mHh, mHl, mW1h, mW2h;
    make_map(enc, &mXh, p_xhi, Dq, MPAD, 1);
    make_map(enc, &mXl, p_xlo, Dq, MPAD, 1);
    make_map(enc, &mHh, p_hhi, Fq, MPAD, Eq);
    make_map(enc, &mHl, p_hlo, Fq, MPAD, Eq);
    make_map(enc, &mW1h, p_w1h, Dq, Fq, Eq);
    make_map(enc, &mW2h, p_w2h, Fq, Dq, Eq);

    const dim3 blk(256);
    const dim3 gridQKV(Dq / TN, NTOK / TM, 3);  // (3, 49, 3)
    const dim3 gridO(Dq / TN, NTOK / TM, 1);
    const dim3 grid1(Fq / 256, MPAD / 256, Eq);
    const dim3 grid2(Dq / 256, MPAD / 256, Eq);
    const int n4 = NTOK * Dq / 4;
    const int sgrid = (n4 + 255) / 256;
    const size_t segQ = (size_t)NTOK * Dq;

    cudaFuncSetAttribute(tc_gemm<2>,  cudaFuncAttributeMaxDynamicSharedMemorySize, TC_SMEM);
    cudaFuncSetAttribute(tc_gemm<3>,  cudaFuncAttributeMaxDynamicSharedMemorySize, TC_SMEM);
    cudaFuncSetAttribute(tc_gemm2<0>, cudaFuncAttributeMaxDynamicSharedMemorySize, TC2_SMEM);
    cudaFuncSetAttribute(tc_gemm2<1>, cudaFuncAttributeMaxDynamicSharedMemorySize, TC2_SMEM);

    // qkv split buffers carved from the (currently idle) h region
    __nv_bfloat16* p_qkvshi = p_hhi;
    __nv_bfloat16* p_qkvslo = p_hlo;

    // launch order arranged so ncu (-s 5 -c 1) captures the batched QKV tc_gemm
    transpose_split<<<dim3(Dq/64, Dq/32, 1), blk>>>(Wq, p_wqkvh,            p_wqkvl,            Dq, Dq); // 0
    transpose_split<<<dim3(Dq/64, Dq/32, 1), blk>>>(Wk, p_wqkvh + Dq*Dq,    p_wqkvl + Dq*Dq,    Dq, Dq); // 1
    transpose_split<<<dim3(Dq/64, Dq/32, 1), blk>>>(Wv, p_wqkvh + 2*Dq*Dq,  p_wqkvl + 2*Dq*Dq,  Dq, Dq); // 2
    split3_bf16<<<dim3(sgrid, 3), blk>>>(q, k, v, p_qkvshi, p_qkvslo, n4);                               // 3
    transpose_split<<<dim3(Dq/64, Fq/32, Eq), blk>>>(W1, p_w1h, nullptr, Dq, Fq);                        // 4
    tc_gemm<2><<<gridQKV, blk, TC_SMEM>>>(p_qkvshi, p_qkvslo, p_wqkvh, p_wqkvl,                          // 5 (profiled)
                                          bq, bk, bv, nullptr, p_qkvh,
                                          NTOK, Dq, Dq, segQ, (size_t)Dq * Dq, segQ);
    const int smem_attn = (Sq * KPAD + Sq * DHq + 8 * 208 + 8 * DHq) * (int)sizeof(float);
    cudaFuncSetAttribute(attn_kernel, cudaFuncAttributeMaxDynamicSharedMemorySize, smem_attn);
    attn_kernel<<<dim3(Bq * Hq, 4), blk, smem_attn>>>(p_qkvh, p_qkvh + segQ, p_qkvh + 2 * segQ, p_ctx);  // 6
    transpose_split<<<dim3(Dq/64, Dq/32, 1), blk>>>(Wo, p_woh, p_wol, Dq, Dq);                           // 7
    split_bf16<<<sgrid, blk>>>(p_ctx, p_inhi, p_inlo, n4);                                               // 8
    transpose_split<<<dim3(Fq/64, Dq/32, Eq), blk>>>(W2, p_w2h, nullptr, Fq, Dq);                        // 9
    tc_gemm<3><<<gridO, blk, TC_SMEM>>>(p_inhi, p_inlo, p_woh, p_wol,
                                        bo, bo, bo, q, p_tmp, NTOK, Dq, Dq, 0, 0, 0);                    // 10
    ln_kernel<<<NTOK, blk>>>(p_tmp, ln1g, ln1b, p_x, p_xhi, p_xlo);                                      // 11
    gate_kernel<<<(NTOK * 32 + 255) / 256, blk>>>(p_x, Wg, bg, p_gates);                                 // 12

    tc_gemm2<0><<<grid1, blk, TC2_SMEM>>>(
        mXh, mXl, mW1h, b1, nullptr, p_hhi, p_hlo,
        Fq, Dq, (size_t)Fq, (size_t)MPAD * Fq,
        p_xhi, p_xlo, p_w1h, (size_t)0, (size_t)Fq * Dq);                                                // 13
    tc_gemm2<1><<<grid2, blk, TC2_SMEM>>>(
        mHh, mHl, mW2h, b2, p_y, nullptr, nullptr,
        Dq, Fq, (size_t)Dq, (size_t)MPAD * Dq,
        p_hhi, p_hlo, p_w2h, (size_t)MPAD * Fq, (size_t)Dq * Fq);                                        // 14

    ln2_kernel<<<NTOK, blk>>>(p_x, p_y, p_gates, ln2g, ln2b, out);                                       // 15
}

// round 10
// speedup vs baseline: 8.7880x; 1.2480x over previous
#include <cuda_runtime.h>
#include <cuda.h>
#include <cuda_bf16.h>
#include <math.h>
#include <stdint.h>

#define Bq 32
#define Sq 196
#define Dq 768
#define Hq 12
#define Eq 8
#define Fq 3072
#define DHq 64
#define NTOK (Bq*Sq)
#define MPAD 6400

#define HAS_TCGEN05 (defined(__CUDA_ARCH_FEAT_SM103_ALL) || defined(__CUDA_ARCH_FEAT_SM100_ALL))

// ---------------- scratch ------------------------------------------------------
__device__ __align__(256) float d_qkvh[3*NTOK*Dq];
__device__ __align__(256) float d_ctx[NTOK*Dq];
__device__ __align__(256) float d_tmp[NTOK*Dq];
__device__ __align__(256) float d_x  [NTOK*Dq];
__device__ __align__(256) float d_y  [Eq*MPAD*Dq];
__device__ __align__(256) float d_gates[MPAD*Eq];

__device__ __align__(256) __nv_bfloat16 d_inhi[NTOK*Dq];
__device__ __align__(256) __nv_bfloat16 d_inlo[NTOK*Dq];
__device__ __align__(256) __nv_bfloat16 d_xhi[MPAD*Dq];
__device__ __align__(256) __nv_bfloat16 d_xlo[MPAD*Dq];
__device__ __align__(256) __nv_bfloat16 d_hhi[Eq*MPAD*Fq];  // also hosts q/k/v splits early
__device__ __align__(256) __nv_bfloat16 d_hlo[Eq*MPAD*Fq];  // only used as qkv-lo staging now
__device__ __align__(256) __nv_bfloat16 d_w1t_hi[Eq*Fq*Dq];
__device__ __align__(256) __nv_bfloat16 d_w2t_hi[Eq*Dq*Fq];
__device__ __align__(256) __nv_bfloat16 d_wqkvt_hi[3*Dq*Dq];
__device__ __align__(256) __nv_bfloat16 d_wqkvt_lo[3*Dq*Dq];
__device__ __align__(256) __nv_bfloat16 d_wot_hi[Dq*Dq];
__device__ __align__(256) __nv_bfloat16 d_wot_lo[Dq*Dq];

// ---------------- PTX helpers ---------------------------------------------------
__device__ __forceinline__ uint32_t smem_u32(const void* p) {
    uint32_t a;
    asm("{ .reg .u64 t; cvta.to.shared.u64 t, %1; cvt.u32.u64 %0, t; }" : "=r"(a) : "l"(p));
    return a;
}

#if HAS_TCGEN05
__device__ __forceinline__ bool elect_one() {
    uint32_t p;
    asm volatile("{\n .reg .pred p;\n elect.sync _|p, 0xFFFFFFFF;\n selp.b32 %0,1,0,p;\n}" : "=r"(p));
    return p != 0;
}
#define MBARRIER_INIT(addr, cnt) \
    asm volatile("mbarrier.init.shared.b64 [%0], %1;" :: "r"((uint32_t)(addr)), "r"((uint32_t)(cnt)) : "memory")
#define MBARRIER_INVAL(addr) \
    asm volatile("mbarrier.inval.shared.b64 [%0];" :: "r"((uint32_t)(addr)) : "memory")
#define MBARRIER_EXPECT_TX(addr, tx) \
    asm volatile("mbarrier.arrive.expect_tx.shared.b64 _, [%0], %1;" \
        :: "r"((uint32_t)(addr)), "r"((uint32_t)(tx)) : "memory")
#define MBARRIER_WAIT_PARITY(mbar, par) do { \
    uint32_t _m = (uint32_t)(mbar), _p = (uint32_t)(par), _d; \
    asm volatile("{\n\t.reg .pred p;\n\t" \
        "mbarrier.try_wait.parity.acquire.cta.shared::cta.b64 p, [%1], %2;\n\t" \
        "selp.b32 %0, 1, 0, p;\n\t}" : "=r"(_d) : "r"(_m), "r"(_p) : "memory"); \
    if (!_d) { \
        asm volatile("{\n\t.reg .pred P1;\n\t" \
            "WL_%=:\n\t" \
            "mbarrier.try_wait.parity.acquire.cta.shared::cta.b64 P1, [%0], %1, 0x989680;\n\t" \
            "@P1 bra.uni WD_%=;\n\tbra.uni WL_%=;\n\tWD_%=:\n\t}" \
            :: "r"(_m), "r"(_p) : "memory"); \
    } \
} while(0)
#define TCGEN05_ALLOC(a, n) \
    asm volatile("tcgen05.alloc.cta_group::1.sync.aligned.shared::cta.b32 [%0], %1;" \
        :: "r"((uint32_t)(a)), "r"((uint32_t)(n)) : "memory")
#define TCGEN05_DEALLOC(t, n) \
    asm volatile("tcgen05.dealloc.cta_group::1.sync.aligned.b32 %0, %1;" :: "r"(t), "r"(n))
#define TCGEN05_RELINQ() \
    asm volatile("tcgen05.relinquish_alloc_permit.cta_group::1.sync.aligned;")
#define TCGEN05_COMMIT(m) \
    asm volatile("tcgen05.commit.cta_group::1.mbarrier::arrive::one.shared::cluster.b64 [%0];" \
        :: "r"((uint32_t)(m)) : "memory")
#define TCGEN05_FENCE_AFTER()  asm volatile("tcgen05.fence::after_thread_sync;" ::: "memory")
#define TCGEN05_FENCE_BEFORE() asm volatile("tcgen05.fence::before_thread_sync;" ::: "memory")
#define TCGEN05_WAIT_LD() asm volatile("tcgen05.wait::ld.sync.aligned;" ::: "memory")
#define FENCE_ASYNC_SHARED() asm volatile("fence.proxy.async.shared::cta;" ::: "memory")
#define CP_ASYNC16(dst, src) \
    asm volatile("cp.async.cg.shared.global [%0], [%1], 16;" :: "r"((uint32_t)(dst)), "l"(src))
#define CP_COMMIT() asm volatile("cp.async.commit_group;" ::: "memory")
#define CP_WAIT(n)  asm volatile("cp.async.wait_group %0;" :: "n"(n) : "memory")
#define TMA_LOAD_3D(sm, map, cx, cy, cz, mb) \
    asm volatile("cp.async.bulk.tensor.3d.shared::cta.global.tile.mbarrier::complete_tx::bytes " \
        "[%0], [%1, {%2, %3, %4}], [%5];" \
        :: "r"((uint32_t)(sm)), "l"(map), "r"((int32_t)(cx)), "r"((int32_t)(cy)), \
           "r"((int32_t)(cz)), "r"((uint32_t)(mb)) : "memory")
#define TCGEN05_LD_32X32B_X32(r, ta) \
    asm volatile("tcgen05.ld.sync.aligned.32x32b.x32.b32 " \
        "{%0, %1, %2, %3, %4, %5, %6, %7, %8, %9, %10, %11, %12, %13, %14, %15, " \
        " %16, %17, %18, %19, %20, %21, %22, %23, %24, %25, %26, %27, %28, %29, %30, %31}, [%32];" \
        : "=r"((r)[0]), "=r"((r)[1]), "=r"((r)[2]), "=r"((r)[3]), "=r"((r)[4]), "=r"((r)[5]), \
          "=r"((r)[6]), "=r"((r)[7]), "=r"((r)[8]), "=r"((r)[9]), "=r"((r)[10]), "=r"((r)[11]), \
          "=r"((r)[12]), "=r"((r)[13]), "=r"((r)[14]), "=r"((r)[15]), "=r"((r)[16]), "=r"((r)[17]), \
          "=r"((r)[18]), "=r"((r)[19]), "=r"((r)[20]), "=r"((r)[21]), "=r"((r)[22]), "=r"((r)[23]), \
          "=r"((r)[24]), "=r"((r)[25]), "=r"((r)[26]), "=r"((r)[27]), "=r"((r)[28]), "=r"((r)[29]), \
          "=r"((r)[30]), "=r"((r)[31]) : "r"(ta))

static constexpr uint64_t DESC_SW128 =
    (uint64_t(2) << 61) | (uint64_t(1) << 46) | (uint64_t(64) << 32) | (uint64_t(1) << 16);
static constexpr uint64_t DESC_SW64 =
    (uint64_t(4) << 61) | (uint64_t(1) << 46) | (uint64_t(32) << 32) | (uint64_t(1) << 16);
#define MKD128(a) (DESC_SW128 | ((uint64_t)((a) >> 4) & 0x3FFF))
#define MKD64(a)  (DESC_SW64  | ((uint64_t)((a) >> 4) & 0x3FFF))

__device__ __forceinline__ void mma_bf16_ss(uint32_t d, uint64_t ad, uint64_t bd,
                                            uint32_t idesc, uint32_t en) {
    asm volatile(
        "{\n\t.reg .pred p;\n\tsetp.ne.u32 p, %5, 0;\n\t"
        "tcgen05.mma.cta_group::1.kind::f16 [%0], %1, %2, %3, {%4,%4,%4,%4}, p;\n\t}"
        :: "r"(d), "l"(ad), "l"(bd), "r"(idesc), "r"(0u), "r"(en) : "memory");
}
static constexpr uint32_t IDESC_BF16 =
    (1u << 4) | (1u << 7) | (1u << 10) | ((256 / 8) << 17) | ((128 / 16) << 24);
#endif

// ======================= TM128 tc GEMM (QKV batched / O-proj) ===================
#define TM 128
#define TN 256
#define TK 64
#define STAGE_BYTES 98304
#define SM_DATA 1024
#define TC_SMEM (SM_DATA + 2*STAGE_BYTES)

#if HAS_TCGEN05
__device__ __forceinline__ void load_slab128(
    uint32_t sbase, int stage,
    const __nv_bfloat16* __restrict__ Ahi, const __nv_bfloat16* __restrict__ Alo,
    const __nv_bfloat16* __restrict__ Bhi, const __nv_bfloat16* __restrict__ Blo,
    int m0, int n0, int k0, int K)
{
    const int tid = threadIdx.x;
    const uint32_t base = sbase + SM_DATA + stage * STAGE_BYTES;
#pragma unroll
    for (int i = 0; i < 4; i++) {
        int idx = i * 256 + tid;
        int row = idx >> 3, c4 = idx & 7;
        int off = row * 128 + c4 * 16;
        int sw  = off ^ ((off >> 3) & 0x70);
        size_t g = (size_t)(m0 + row) * K + k0 + c4 * 8;
        CP_ASYNC16(base + sw, Ahi + g);
        CP_ASYNC16(base + 16384 + sw, Alo + g);
    }
#pragma unroll
    for (int i = 0; i < 8; i++) {
        int idx = i * 256 + tid;
        int row = idx >> 3, c4 = idx & 7;
        int off = row * 128 + c4 * 16;
        int sw  = off ^ ((off >> 3) & 0x70);
        size_t g = (size_t)(n0 + row) * K + k0 + c4 * 8;
        CP_ASYNC16(base + 32768 + sw, Bhi + g);
        CP_ASYNC16(base + 65536 + sw, Blo + g);
    }
    CP_COMMIT();
}
#endif

template<int MODE>   // 2: z-batched C=AW+b(z)   3: C=AW+b+res
__global__ void __launch_bounds__(256)
tc_gemm(const __nv_bfloat16* __restrict__ Ahi, const __nv_bfloat16* __restrict__ Alo,
        const __nv_bfloat16* __restrict__ Bhi, const __nv_bfloat16* __restrict__ Blo,
        const float* __restrict__ b0, const float* __restrict__ b1,
        const float* __restrict__ b2, const float* __restrict__ res,
        float* __restrict__ Cf, int M, int N, int K,
        size_t sA, size_t sB, size_t sC)
{
    extern __shared__ __align__(1024) char smx[];
    const int z = blockIdx.z;
    Ahi += z * sA; Alo += z * sA;
    Bhi += z * sB; Blo += z * sB;
    Cf  += z * sC;
    const float* bias = (z == 0) ? b0 : (z == 1) ? b1 : b2;
#if HAS_TCGEN05
    const uint32_t sb = smem_u32(smx);
    const int tid = threadIdx.x;
    const int wid = tid >> 5, lane = tid & 31;
    const int m0 = blockIdx.y * TM, n0 = blockIdx.x * TN;

    if (wid == 0) { TCGEN05_ALLOC(sb, 256); TCGEN05_RELINQ(); }
    if (tid == 0) { MBARRIER_INIT(sb + 8, 1); MBARRIER_INIT(sb + 16, 1); }
    __syncthreads();
    uint32_t tmem;
    asm volatile("ld.shared.b32 %0, [%1];" : "=r"(tmem) : "r"(sb));

    const int NS = K / TK;
    load_slab128(sb, 0, Ahi, Alo, Bhi, Blo, m0, n0, 0, K);
    int ph0 = 0, ph1 = 0;
    for (int s = 0; s < NS; s++) {
        const int buf = s & 1;
        if (s + 1 < NS) {
            const int nb = 1 - buf;
            if (s >= 1) {
                if (nb == 0) { MBARRIER_WAIT_PARITY(sb + 8,  ph0); ph0 ^= 1; }
                else         { MBARRIER_WAIT_PARITY(sb + 16, ph1); ph1 ^= 1; }
            }
            load_slab128(sb, nb, Ahi, Alo, Bhi, Blo, m0, n0, (s + 1) * TK, K);
            CP_WAIT(1);
        } else {
            CP_WAIT(0);
        }
        FENCE_ASYNC_SHARED();
        __syncthreads();
        if (wid == 0) {
            TCGEN05_FENCE_AFTER();
            if (elect_one()) {
                const uint32_t tb = sb + SM_DATA + buf * STAGE_BYTES;
                const uint64_t ah = MKD128(tb), al = MKD128(tb + 16384);
                const uint64_t bh = MKD128(tb + 32768), bl = MKD128(tb + 65536);
#pragma unroll
                for (int ks = 0; ks < 4; ks++) {
                    const uint32_t en0 = (s == 0 && ks == 0) ? 0u : 1u;
                    mma_bf16_ss(tmem, ah + ks * 2, bh + ks * 2, IDESC_BF16, en0);
                    mma_bf16_ss(tmem, ah + ks * 2, bl + ks * 2, IDESC_BF16, 1u);
                    mma_bf16_ss(tmem, al + ks * 2, bh + ks * 2, IDESC_BF16, 1u);
                }
                TCGEN05_COMMIT(sb + 8 + buf * 8);
            }
        }
    }
    if (((NS - 1) & 1) == 0) { MBARRIER_WAIT_PARITY(sb + 8,  ph0); }
    else                     { MBARRIER_WAIT_PARITY(sb + 16, ph1); }
    TCGEN05_FENCE_AFTER();

    const int sub = wid & 3, cg = wid >> 2;
    const int row = m0 + sub * 32 + lane;
#pragma unroll
    for (int ch = 0; ch < 4; ch++) {
        const int colb = cg * 128 + ch * 32;
        uint32_t r[32];
        TCGEN05_LD_32X32B_X32(r, tmem + colb);
        TCGEN05_WAIT_LD();
        const size_t base = (size_t)row * N + n0 + colb;
        const float4* bv = (const float4*)(bias + n0 + colb);
        float4* dst = (float4*)(Cf + base);
        const float4* rv = (MODE == 3) ? (const float4*)(res + base) : nullptr;
#pragma unroll
        for (int i = 0; i < 8; i++) {
            float4 b4 = bv[i];
            float4 o;
            o.x = __uint_as_float(r[i*4+0]) + b4.x;
            o.y = __uint_as_float(r[i*4+1]) + b4.y;
            o.z = __uint_as_float(r[i*4+2]) + b4.z;
            o.w = __uint_as_float(r[i*4+3]) + b4.w;
            if (MODE == 3) { float4 t = rv[i]; o.x += t.x; o.y += t.y; o.z += t.z; o.w += t.w; }
            dst[i] = o;
        }
    }
    TCGEN05_FENCE_BEFORE();
    __syncthreads();
    if (tid == 0) { MBARRIER_INVAL(sb + 8); MBARRIER_INVAL(sb + 16); }
    __syncthreads();
    if (wid == 0) TCGEN05_DEALLOC(tmem, 256);
#else
    float* As = (float*)smx;
    float* Bs = As + 16 * 128;
    const int tid = threadIdx.x;
    const int m0 = blockIdx.y * TM, n0x = blockIdx.x * TN;
    const int tx = tid & 15, ty = tid >> 4;
    const int mr = ty * 8, nr = tx * 8;
    for (int half = 0; half < 2; half++) {
        const int n0 = n0x + half * 128;
        float acc[8][8];
#pragma unroll
        for (int i = 0; i < 8; i++)
#pragma unroll
            for (int j = 0; j < 8; j++) acc[i][j] = 0.f;
        for (int k0 = 0; k0 < K; k0 += 16) {
            __syncthreads();
#pragma unroll
            for (int i = 0; i < 8; i++) {
                int idx = i * 256 + tid;
                int kk = idx >> 7, mm = idx & 127;
                size_t ga = (size_t)(m0 + mm) * K + k0 + kk;
                size_t gb = (size_t)(n0 + mm) * K + k0 + kk;
                As[kk*128+mm] = __bfloat162float(Ahi[ga]) + __bfloat162float(Alo[ga]);
                Bs[kk*128+mm] = __bfloat162float(Bhi[gb]) + __bfloat162float(Blo[gb]);
            }
            __syncthreads();
#pragma unroll
            for (int kk = 0; kk < 16; kk++) {
                float a0[8], b0r[8];
#pragma unroll
                for (int i = 0; i < 8; i++) a0[i] = As[kk*128+mr+i];
#pragma unroll
                for (int j = 0; j < 8; j++) b0r[j] = Bs[kk*128+nr+j];
#pragma unroll
                for (int i = 0; i < 8; i++)
#pragma unroll
                    for (int j = 0; j < 8; j++)
                        acc[i][j] = fmaf(a0[i], b0r[j], acc[i][j]);
            }
        }
#pragma unroll
        for (int i = 0; i < 8; i++) {
            const int row = m0 + mr + i;
#pragma unroll
            for (int j = 0; j < 8; j++) {
                const int col = n0 + nr + j;
                const size_t idx = (size_t)row * N + col;
                float v = acc[i][j] + bias[col];
                if (MODE == 2) Cf[idx] = v; else Cf[idx] = v + res[idx];
            }
        }
    }
#endif
}

// ======================= MoE GEMM: TMA producer/consumer ========================
// MODE 0 (up-proj):   A = x hi+lo, B = W1 hi; slab 48KB; 8 MMAs; 4 stages; gelu->bf16 hi
// MODE 1 (down-proj): A = h hi,    B = W2 hi; slab 32KB; 4 MMAs; 6 stages; Cf = acc+bias
#define T2K 32
#define TC2_SMEM (1024 + 196608)   // 197632 both modes

template<int MODE>
__global__ void __launch_bounds__(256)
tc_gemm2(const __grid_constant__ CUtensorMap mAh, const __grid_constant__ CUtensorMap mAl,
         const __grid_constant__ CUtensorMap mBh,
         const float* __restrict__ bias, float* __restrict__ Cf,
         __nv_bfloat16* __restrict__ Chi,
         int N, int K, size_t sBias, size_t sC,
         const __nv_bfloat16* __restrict__ Ahi, const __nv_bfloat16* __restrict__ Alo,
         const __nv_bfloat16* __restrict__ Bh, size_t sA, size_t sB)
{
    extern __shared__ __align__(1024) char smx[];
    const int z = blockIdx.z;
    bias += z * sBias;
#if HAS_TCGEN05
    constexpr int NST  = (MODE == 0) ? 4 : 6;
    constexpr int SLAB = (MODE == 0) ? 49152 : 32768;
    constexpr int BOFF = (MODE == 0) ? 32768 : 16384;
    const uint32_t sb = smem_u32(smx);
    const int tid = threadIdx.x;
    const int wid = tid >> 5, lane = tid & 31;
    const int m0 = blockIdx.y * 256, n0 = blockIdx.x * 256;
    const int za = (MODE == 0) ? 0 : z;

    if (wid == 0) { TCGEN05_ALLOC(sb, 512); TCGEN05_RELINQ(); }
    if (tid == 0) {
        // full[i] at 8+8i (i<6), empty[i] at 56+8i, done at 104
#pragma unroll
        for (int i = 0; i < 6; i++) { MBARRIER_INIT(sb + 8 + i * 8, 1); MBARRIER_INIT(sb + 56 + i * 8, 1); }
        MBARRIER_INIT(sb + 104, 1);
        FENCE_ASYNC_SHARED();
    }
    __syncthreads();
    uint32_t tmem;
    asm volatile("ld.shared.b32 %0, [%1];" : "=r"(tmem) : "r"(sb));

    const int NS = K / T2K;
    if (wid == 1) {
        if (elect_one()) {
            for (int s = 0; s < NS; s++) {
                const int st = s % NST;
                if (s >= NST) MBARRIER_WAIT_PARITY(sb + 56 + st * 8, ((s / NST) - 1) & 1);
                MBARRIER_EXPECT_TX(sb + 8 + st * 8, (uint32_t)SLAB);
                const uint32_t stb = sb + 1024 + st * SLAB;
                const int k0 = s * T2K;
                TMA_LOAD_3D(stb, &mAh, k0, m0, za, sb + 8 + st * 8);
                if (MODE == 0) TMA_LOAD_3D(stb + 16384, &mAl, k0, m0, za, sb + 8 + st * 8);
                TMA_LOAD_3D(stb + BOFF, &mBh, k0, n0, z, sb + 8 + st * 8);
            }
        }
    } else if (wid == 0) {
        TCGEN05_FENCE_AFTER();
        if (elect_one()) {
            for (int s = 0; s < NS; s++) {
                const int st = s % NST;
                MBARRIER_WAIT_PARITY(sb + 8 + st * 8, (s / NST) & 1);
                const uint32_t tb = sb + 1024 + st * SLAB;
                const uint64_t a0h = MKD64(tb);
                const uint64_t a1h = a0h + 512;       // rows 128..255
                const uint64_t a0l = MKD64(tb + 16384);
                const uint64_t a1l = a0l + 512;
                const uint64_t bh  = MKD64(tb + BOFF);
#pragma unroll
                for (int ks = 0; ks < 2; ks++) {
                    const uint32_t en0 = (s == 0 && ks == 0) ? 0u : 1u;
                    mma_bf16_ss(tmem,       a0h + ks * 2, bh + ks * 2, IDESC_BF16, en0);
                    if (MODE == 0)
                        mma_bf16_ss(tmem,   a0l + ks * 2, bh + ks * 2, IDESC_BF16, 1u);
                    mma_bf16_ss(tmem + 256, a1h + ks * 2, bh + ks * 2, IDESC_BF16, en0);
                    if (MODE == 0)
                        mma_bf16_ss(tmem + 256, a1l + ks * 2, bh + ks * 2, IDESC_BF16, 1u);
                }
                TCGEN05_COMMIT(sb + 56 + st * 8);
            }
            TCGEN05_COMMIT(sb + 104);
        }
    }

    MBARRIER_WAIT_PARITY(sb + 104, 0);
    TCGEN05_FENCE_AFTER();

    const int accSel = wid >> 2, sub = wid & 3;
    const int row = m0 + accSel * 128 + sub * 32 + lane;
    const uint32_t tacc = tmem + accSel * 256;
    if (MODE == 0) Chi += z * sC;
    else           Cf  += z * sC;
#pragma unroll
    for (int ch = 0; ch < 8; ch++) {
        const int colb = ch * 32;
        uint32_t r[32];
        TCGEN05_LD_32X32B_X32(r, tacc + colb);
        TCGEN05_WAIT_LD();
        const size_t base = (size_t)row * N + n0 + colb;
        const float4* bv = (const float4*)(bias + n0 + colb);
        if (MODE == 0) {
            uint4* dh = (uint4*)(Chi + base);
#pragma unroll
            for (int i = 0; i < 4; i++) {
                uint32_t hp[4];
#pragma unroll
                for (int p = 0; p < 4; p++) {
                    float4 b4 = bv[i * 2 + (p >> 1)];
                    float b0 = (p & 1) ? b4.z : b4.x;
                    float b1 = (p & 1) ? b4.w : b4.y;
                    float v0 = __uint_as_float(r[i*8+p*2+0]) + b0;
                    float v1 = __uint_as_float(r[i*8+p*2+1]) + b1;
                    float g0 = 0.5f * v0 * (1.f + erff(v0 * 0.70710678118654752f));
                    float g1 = 0.5f * v1 * (1.f + erff(v1 * 0.70710678118654752f));
                    hp[p] = (uint32_t)__bfloat16_as_ushort(__float2bfloat16(g0)) |
                            ((uint32_t)__bfloat16_as_ushort(__float2bfloat16(g1)) << 16);
                }
                dh[i] = make_uint4(hp[0], hp[1], hp[2], hp[3]);
            }
        } else {
            float4* dst = (float4*)(Cf + base);
#pragma unroll
            for (int i = 0; i < 8; i++) {
                float4 b4 = bv[i];
                float4 o;
                o.x = __uint_as_float(r[i*4+0]) + b4.x;
                o.y = __uint_as_float(r[i*4+1]) + b4.y;
                o.z = __uint_as_float(r[i*4+2]) + b4.z;
                o.w = __uint_as_float(r[i*4+3]) + b4.w;
                dst[i] = o;
            }
        }
    }
    TCGEN05_FENCE_BEFORE();
    __syncthreads();
    if (tid == 0) {
#pragma unroll
        for (int i = 0; i < 6; i++) { MBARRIER_INVAL(sb + 8 + i * 8); MBARRIER_INVAL(sb + 56 + i * 8); }
        MBARRIER_INVAL(sb + 104);
    }
    __syncthreads();
    if (wid == 0) TCGEN05_DEALLOC(tmem, 512);
#else
    const __nv_bfloat16* Ah = Ahi + (size_t)((MODE == 0) ? 0 : z) * sA;
    const __nv_bfloat16* Al = (MODE == 0) ? Alo : nullptr;
    const __nv_bfloat16* Bp = Bh + (size_t)z * sB;
    if (MODE == 0) Chi += z * sC;
    else           Cf  += z * sC;
    float* As = (float*)smx;
    float* Bs = As + 16 * 128;
    const int tid = threadIdx.x;
    const int tx = tid & 15, ty = tid >> 4;
    const int mr = ty * 8, nr = tx * 8;
    for (int mh = 0; mh < 2; mh++)
    for (int nh = 0; nh < 2; nh++) {
        const int m0 = blockIdx.y * 256 + mh * 128;
        const int n0 = blockIdx.x * 256 + nh * 128;
        float acc[8][8];
#pragma unroll
        for (int i = 0; i < 8; i++)
#pragma unroll
            for (int j = 0; j < 8; j++) acc[i][j] = 0.f;
        for (int k0 = 0; k0 < K; k0 += 16) {
            __syncthreads();
#pragma unroll
            for (int i = 0; i < 8; i++) {
                int idx = i * 256 + tid;
                int kk = idx >> 7, mm = idx & 127;
                size_t ga = (size_t)(m0 + mm) * K + k0 + kk;
                size_t gb = (size_t)(n0 + mm) * K + k0 + kk;
                float av = __bfloat162float(Ah[ga]);
                if (MODE == 0) av += __bfloat162float(Al[ga]);
                As[kk*128+mm] = av;
                Bs[kk*128+mm] = __bfloat162float(Bp[gb]);
            }
            __syncthreads();
#pragma unroll
            for (int kk = 0; kk < 16; kk++) {
                float a0[8], b0[8];
#pragma unroll
                for (int i = 0; i < 8; i++) a0[i] = As[kk*128+mr+i];
#pragma unroll
                for (int j = 0; j < 8; j++) b0[j] = Bs[kk*128+nr+j];
#pragma unroll
                for (int i = 0; i < 8; i++)
#pragma unroll
                    for (int j = 0; j < 8; j++)
                        acc[i][j] = fmaf(a0[i], b0[j], acc[i][j]);
            }
        }
#pragma unroll
        for (int i = 0; i < 8; i++) {
            const int row = m0 + mr + i;
#pragma unroll
            for (int j = 0; j < 8; j++) {
                const int col = n0 + nr + j;
                const size_t idx = (size_t)row * N + col;
                float v = acc[i][j] + bias[col];
                if (MODE == 0) {
                    float g = 0.5f * v * (1.f + erff(v * 0.70710678118654752f));
                    Chi[idx] = __float2bfloat16(g);
                } else Cf[idx] = v;
            }
        }
    }
#endif
}

// ---------------- transpose v2 -------------------------------------------------------
__global__ void __launch_bounds__(256)
transpose_split(const float* __restrict__ W, __nv_bfloat16* __restrict__ Thi,
                __nv_bfloat16* __restrict__ Tlo, int K, int N)
{
    __shared__ float t[64][33];
    const int e = blockIdx.z;
    const float* Wp = W + (size_t)e * K * N;
    __nv_bfloat16* th = Thi + (size_t)e * K * N;
    __nv_bfloat16* tl = Tlo ? Tlo + (size_t)e * K * N : nullptr;
    const int k0 = blockIdx.x * 64, n0 = blockIdx.y * 32;
    const int tid = threadIdx.x;
#pragma unroll
    for (int i = 0; i < 8; i++) {
        int idx = i * 256 + tid;
        int r = idx >> 5, c = idx & 31;
        t[r][c] = Wp[(size_t)(k0 + r) * N + n0 + c];
    }
    __syncthreads();
#pragma unroll
    for (int i = 0; i < 4; i++) {
        int idx = i * 256 + tid;
        int c = idx >> 5, j = idx & 31;
        float v0 = t[2 * j][c], v1 = t[2 * j + 1][c];
        __nv_bfloat16 h0 = __float2bfloat16(v0);
        __nv_bfloat16 h1 = __float2bfloat16(v1);
        const size_t base = (size_t)(n0 + c) * K + k0 + 2 * j;
        *(uint32_t*)(th + base) =
            (uint32_t)__bfloat16_as_ushort(h0) | ((uint32_t)__bfloat16_as_ushort(h1) << 16);
        if (tl) {
            __nv_bfloat16 l0 = __float2bfloat16(v0 - __bfloat162float(h0));
            __nv_bfloat16 l1 = __float2bfloat16(v1 - __bfloat162float(h1));
            *(uint32_t*)(tl + base) =
                (uint32_t)__bfloat16_as_ushort(l0) | ((uint32_t)__bfloat16_as_ushort(l1) << 16);
        }
    }
}

// ---------------- batched q/k/v split ------------------------------------------------
__global__ void __launch_bounds__(256)
split3_bf16(const float* __restrict__ q, const float* __restrict__ k,
            const float* __restrict__ v, __nv_bfloat16* __restrict__ hi,
            __nv_bfloat16* __restrict__ lo, int n4)
{
    const int seg = blockIdx.y;
    const float* x = (seg == 0) ? q : (seg == 1) ? k : v;
    int i = blockIdx.x * 256 + threadIdx.x;
    if (i >= n4) return;
    float4 val = ((const float4*)x)[i];
    __nv_bfloat16 h0 = __float2bfloat16(val.x), h1 = __float2bfloat16(val.y);
    __nv_bfloat16 h2 = __float2bfloat16(val.z), h3 = __float2bfloat16(val.w);
    uint2 hp, lp;
    hp.x = (uint32_t)__bfloat16_as_ushort(h0) | ((uint32_t)__bfloat16_as_ushort(h1) << 16);
    hp.y = (uint32_t)__bfloat16_as_ushort(h2) | ((uint32_t)__bfloat16_as_ushort(h3) << 16);
    __nv_bfloat16 l0 = __float2bfloat16(val.x - __bfloat162float(h0));
    __nv_bfloat16 l1 = __float2bfloat16(val.y - __bfloat162float(h1));
    __nv_bfloat16 l2 = __float2bfloat16(val.z - __bfloat162float(h2));
    __nv_bfloat16 l3 = __float2bfloat16(val.w - __bfloat162float(h3));
    lp.x = (uint32_t)__bfloat16_as_ushort(l0) | ((uint32_t)__bfloat16_as_ushort(l1) << 16);
    lp.y = (uint32_t)__bfloat16_as_ushort(l2) | ((uint32_t)__bfloat16_as_ushort(l3) << 16);
    const size_t off = (size_t)seg * n4 + i;
    ((uint2*)hi)[off] = hp;
    ((uint2*)lo)[off] = lp;
}

// ---------------- single split -------------------------------------------------------
__global__ void __launch_bounds__(256)
split_bf16(const float* __restrict__ x, __nv_bfloat16* __restrict__ hi,
           __nv_bfloat16* __restrict__ lo, int n4)
{
    int i = blockIdx.x * 256 + threadIdx.x;
    if (i >= n4) return;
    float4 v = ((const float4*)x)[i];
    __nv_bfloat16 h0 = __float2bfloat16(v.x), h1 = __float2bfloat16(v.y);
    __nv_bfloat16 h2 = __float2bfloat16(v.z), h3 = __float2bfloat16(v.w);
    uint2 hp, lp;
    hp.x = (uint32_t)__bfloat16_as_ushort(h0) | ((uint32_t)__bfloat16_as_ushort(h1) << 16);
    hp.y = (uint32_t)__bfloat16_as_ushort(h2) | ((uint32_t)__bfloat16_as_ushort(h3) << 16);
    __nv_bfloat16 l0 = __float2bfloat16(v.x - __bfloat162float(h0));
    __nv_bfloat16 l1 = __float2bfloat16(v.y - __bfloat162float(h1));
    __nv_bfloat16 l2 = __float2bfloat16(v.z - __bfloat162float(h2));
    __nv_bfloat16 l3 = __float2bfloat16(v.w - __bfloat162float(h3));
    lp.x = (uint32_t)__bfloat16_as_ushort(l0) | ((uint32_t)__bfloat16_as_ushort(l1) << 16);
    lp.y = (uint32_t)__bfloat16_as_ushort(l2) | ((uint32_t)__bfloat16_as_ushort(l3) << 16);
    ((uint2*)hi)[i] = hp;
    ((uint2*)lo)[i] = lp;
}

// ---------------- attention: 4 CTAs per (b,h) ----------------------------------------
#define KPAD 65
__global__ void __launch_bounds__(256)
attn_kernel(const float* __restrict__ qh, const float* __restrict__ kh,
            const float* __restrict__ vh, float* __restrict__ ctx)
{
    const int b = blockIdx.x / Hq;
    const int h = blockIdx.x % Hq;
    const int qbase = blockIdx.y * 49;
    const int qend  = min(196, qbase + 49);
    extern __shared__ float sm[];
    float* Ks = sm;
    float* Vs = Ks + Sq * KPAD;
    float* Ps = Vs + Sq * DHq;
    float* Qs = Ps + 8 * 208;
    const int tid = threadIdx.x;
    for (int i = tid; i < Sq * DHq; i += 256) {
        int s = i / DHq, d = i % DHq;
        size_t gidx = (size_t)(b * Sq + s) * Dq + h * DHq + d;
        Ks[s * KPAD + d] = kh[gidx];
        Vs[s * DHq  + d] = vh[gidx];
    }
    __syncthreads();
    const int warp = tid >> 5, lane = tid & 31;
    float* p    = Ps + warp * 208;
    float* qrow = Qs + warp * DHq;
    for (int q = qbase + warp; q < qend; q += 8) {
        for (int d = lane; d < DHq; d += 32)
            qrow[d] = qh[(size_t)(b * Sq + q) * Dq + h * DHq + d];
        __syncwarp();
        float lmax = -1e30f;
        for (int col = lane; col < Sq; col += 32) {
            float s = 0.f;
            const float* kr = Ks + col * KPAD;
#pragma unroll 16
            for (int d = 0; d < DHq; d++) s = fmaf(qrow[d], kr[d], s);
            s *= 0.125f;
            p[col] = s;
            lmax = fmaxf(lmax, s);
        }
#pragma unroll
        for (int o = 16; o; o >>= 1) lmax = fmaxf(lmax, __shfl_xor_sync(0xffffffffu, lmax, o));
        float lsum = 0.f;
        for (int col = lane; col < Sq; col += 32) {
            float e = __expf(p[col] - lmax);
            p[col] = e;
            lsum += e;
        }
#pragma unroll
        for (int o = 16; o; o >>= 1) lsum += __shfl_xor_sync(0xffffffffu, lsum, o);
        const float inv = 1.f / lsum;
        __syncwarp();
        for (int d = lane; d < DHq; d += 32) {
            float a = 0.f;
            for (int k = 0; k < Sq; k++) a = fmaf(p[k], Vs[k * DHq + d], a);
            ctx[(size_t)(b * Sq + q) * Dq + h * DHq + d] = a * inv;
        }
        __syncwarp();
    }
}

// ---------------- gate softmax --------------------------------------------------------
__global__ void __launch_bounds__(256)
gate_kernel(const float* __restrict__ x, const float* __restrict__ Wg,
            const float* __restrict__ bg, float* __restrict__ gates)
{
    const int warp = (blockIdx.x * 256 + threadIdx.x) >> 5;
    const int lane = threadIdx.x & 31;
    if (warp >= NTOK) return;
    const float* xr = x + (size_t)warp * Dq;
    float lg[Eq];
#pragma unroll
    for (int e = 0; e < Eq; e++) lg[e] = 0.f;
    for (int d = lane; d < Dq; d += 32) {
        float xv = xr[d];
#pragma unroll
        for (int e = 0; e < Eq; e++) lg[e] = fmaf(xv, Wg[d * Eq + e], lg[e]);
    }
#pragma unroll
    for (int e = 0; e < Eq; e++)
#pragma unroll
        for (int o = 16; o; o >>= 1) lg[e] += __shfl_xor_sync(0xffffffffu, lg[e], o);
    if (lane == 0) {
        float m = -1e30f;
#pragma unroll
        for (int e = 0; e < Eq; e++) { lg[e] += bg[e]; m = fmaxf(m, lg[e]); }
        float s = 0.f;
#pragma unroll
        for (int e = 0; e < Eq; e++) { lg[e] = __expf(lg[e] - m); s += lg[e]; }
        float inv = 1.f / s;
#pragma unroll
        for (int e = 0; e < Eq; e++) gates[(size_t)warp * Eq + e] = lg[e] * inv;
    }
}

// ---------------- LN1 (emits split-bf16) -----------------------------------------------
__global__ void __launch_bounds__(256)
ln_kernel(const float* __restrict__ a, const float* __restrict__ g,
          const float* __restrict__ be, float* __restrict__ out,
          __nv_bfloat16* __restrict__ ohi, __nv_bfloat16* __restrict__ olo)
{
    const int row = blockIdx.x;
    const float* ar = a + (size_t)row * Dq;
    float v[3];
    float s = 0.f, s2 = 0.f;
#pragma unroll
    for (int i = 0; i < 3; i++) {
        int d = threadIdx.x + i * 256;
        float x = ar[d];
        v[i] = x;
        s += x; s2 = fmaf(x, x, s2);
    }
    __shared__ float rs[8], rs2[8];
#pragma unroll
    for (int o = 16; o; o >>= 1) { s += __shfl_xor_sync(0xffffffffu, s, o); s2 += __shfl_xor_sync(0xffffffffu, s2, o); }
    const int warp = threadIdx.x >> 5, lane = threadIdx.x & 31;
    if (lane == 0) { rs[warp] = s; rs2[warp] = s2; }
    __syncthreads();
    if (warp == 0) {
        float t  = (lane < 8) ? rs[lane]  : 0.f;
        float t2 = (lane < 8) ? rs2[lane] : 0.f;
#pragma unroll
        for (int o = 4; o; o >>= 1) { t += __shfl_xor_sync(0xffffffffu, t, o); t2 += __shfl_xor_sync(0xffffffffu, t2, o); }
        if (lane == 0) { rs[0] = t; rs2[0] = t2; }
    }
    __syncthreads();
    const float mu  = rs[0] * (1.f / Dq);
    const float var = rs2[0] * (1.f / Dq) - mu * mu;
    const float inv = rsqrtf(var + 1e-5f);
#pragma unroll
    for (int i = 0; i < 3; i++) {
        int d = threadIdx.x + i * 256;
        float y = (v[i] - mu) * inv * g[d] + be[d];
        const size_t idx = (size_t)row * Dq + d;
        out[idx] = y;
        __nv_bfloat16 h = __float2bfloat16(y);
        ohi[idx] = h;
        olo[idx] = __float2bfloat16(y - __bfloat162float(h));
    }
}

// ---------------- LN2: fused gate-weighted expert reduction ----------------------------
__global__ void __launch_bounds__(256)
ln2_kernel(const float* __restrict__ x, const float* __restrict__ y,
           const float* __restrict__ gates, const float* __restrict__ g,
           const float* __restrict__ be, float* __restrict__ out)
{
    const int row = blockIdx.x;
    __shared__ float sg[Eq];
    if (threadIdx.x < Eq) sg[threadIdx.x] = gates[(size_t)row * Eq + threadIdx.x];
    __syncthreads();
    float v[3];
    float s = 0.f, s2 = 0.f;
#pragma unroll
    for (int i = 0; i < 3; i++) {
        int d = threadIdx.x + i * 256;
        float val = x[(size_t)row * Dq + d];
#pragma unroll
        for (int e = 0; e < Eq; e++)
            val = fmaf(sg[e], y[(size_t)e * MPAD * Dq + (size_t)row * Dq + d], val);
        v[i] = val;
        s += val; s2 = fmaf(val, val, s2);
    }
    __shared__ float rs[8], rs2[8];
#pragma unroll
    for (int o = 16; o; o >>= 1) { s += __shfl_xor_sync(0xffffffffu, s, o); s2 += __shfl_xor_sync(0xffffffffu, s2, o); }
    const int warp = threadIdx.x >> 5, lane = threadIdx.x & 31;
    if (lane == 0) { rs[warp] = s; rs2[warp] = s2; }
    __syncthreads();
    if (warp == 0) {
        float t  = (lane < 8) ? rs[lane]  : 0.f;
        float t2 = (lane < 8) ? rs2[lane] : 0.f;
#pragma unroll
        for (int o = 4; o; o >>= 1) { t += __shfl_xor_sync(0xffffffffu, t, o); t2 += __shfl_xor_sync(0xffffffffu, t2, o); }
        if (lane == 0) { rs[0] = t; rs2[0] = t2; }
    }
    __syncthreads();
    const float mu  = rs[0] * (1.f / Dq);
    const float var = rs2[0] * (1.f / Dq) - mu * mu;
    const float inv = rsqrtf(var + 1e-5f);
#pragma unroll
    for (int i = 0; i < 3; i++) {
        int d = threadIdx.x + i * 256;
        out[(size_t)row * Dq + d] = (v[i] - mu) * inv * g[d] + be[d];
    }
}

// ====================================================================================
typedef CUresult (*EncFn)(CUtensorMap*, CUtensorMapDataType, cuuint32_t, void*,
                          const cuuint64_t*, const cuuint64_t*, const cuuint32_t*,
                          const cuuint32_t*, CUtensorMapInterleave, CUtensorMapSwizzle,
                          CUtensorMapL2promotion, CUtensorMapFloatOOBfill);

static void make_map(EncFn enc, CUtensorMap* m, void* ptr,
                     uint64_t d0, uint64_t d1, uint64_t d2)
{
    cuuint64_t dims[3] = {d0, d1, d2};
    cuuint64_t strides[2] = {d0 * 2, d0 * d1 * 2};
    cuuint32_t box[3] = {32, 256, 1};
    cuuint32_t es[3] = {1, 1, 1};
    enc(m, CU_TENSOR_MAP_DATA_TYPE_BFLOAT16, 3, ptr, dims, strides, box, es,
        CU_TENSOR_MAP_INTERLEAVE_NONE, CU_TENSOR_MAP_SWIZZLE_64B,
        CU_TENSOR_MAP_L2_PROMOTION_L2_128B, CU_TENSOR_MAP_FLOAT_OOB_FILL_NONE);
}

extern "C" void kernel_launch(void* const* d_in, const int* in_sizes, int n_in,
                              void* d_out, int out_size)
{
    const float* q   = (const float*)d_in[0];
    const float* k   = (const float*)d_in[1];
    const float* v   = (const float*)d_in[2];
    const float* Wq  = (const float*)d_in[3];
    const float* bq  = (const float*)d_in[4];
    const float* Wk  = (const float*)d_in[5];
    const float* bk  = (const float*)d_in[6];
    const float* Wv  = (const float*)d_in[7];
    const float* bv  = (const float*)d_in[8];
    const float* Wo  = (const float*)d_in[9];
    const float* bo  = (const float*)d_in[10];
    const float* ln1g= (const float*)d_in[11];
    const float* ln1b= (const float*)d_in[12];
    const float* ln2g= (const float*)d_in[13];
    const float* ln2b= (const float*)d_in[14];
    const float* Wg  = (const float*)d_in[15];
    const float* bg  = (const float*)d_in[16];
    const float* W1  = (const float*)d_in[17];
    const float* b1  = (const float*)d_in[18];
    const float* W2  = (const float*)d_in[19];
    const float* b2  = (const float*)d_in[20];
    float* out = (float*)d_out;

    float *p_qkvh, *p_ctx, *p_tmp, *p_x, *p_y, *p_gates;
    __nv_bfloat16 *p_inhi, *p_inlo, *p_xhi, *p_xlo, *p_hhi, *p_hlo;
    __nv_bfloat16 *p_w1h, *p_w2h, *p_wqkvh, *p_wqkvl, *p_woh, *p_wol;
    cudaGetSymbolAddress((void**)&p_qkvh, d_qkvh);
    cudaGetSymbolAddress((void**)&p_ctx,  d_ctx);
    cudaGetSymbolAddress((void**)&p_tmp,  d_tmp);
    cudaGetSymbolAddress((void**)&p_x,    d_x);
    cudaGetSymbolAddress((void**)&p_y,    d_y);
    cudaGetSymbolAddress((void**)&p_gates,d_gates);
    cudaGetSymbolAddress((void**)&p_inhi, d_inhi);
    cudaGetSymbolAddress((void**)&p_inlo, d_inlo);
    cudaGetSymbolAddress((void**)&p_xhi,  d_xhi);
    cudaGetSymbolAddress((void**)&p_xlo,  d_xlo);
    cudaGetSymbolAddress((void**)&p_hhi,  d_hhi);
    cudaGetSymbolAddress((void**)&p_hlo,  d_hlo);
    cudaGetSymbolAddress((void**)&p_w1h,  d_w1t_hi);
    cudaGetSymbolAddress((void**)&p_w2h,  d_w2t_hi);
    cudaGetSymbolAddress((void**)&p_wqkvh, d_wqkvt_hi);
    cudaGetSymbolAddress((void**)&p_wqkvl, d_wqkvt_lo);
    cudaGetSymbolAddress((void**)&p_woh,  d_wot_hi);
    cudaGetSymbolAddress((void**)&p_wol,  d_wot_lo);

    static EncFn enc = nullptr;
    if (!enc) {
        void* fp = nullptr;
        cudaDriverEntryPointQueryResult st;
        cudaGetDriverEntryPointByVersion("cuTensorMapEncodeTiled", &fp, 12000,
                                         cudaEnableDefault, &st);
        enc = (EncFn)fp;
    }
    CUtensorMap mXh, mXl, mHh, mW1h, mW2h;
    make_map(enc, &mXh, p_xhi, Dq, MPAD, 1);
    make_map(enc, &mXl, p_xlo, Dq, MPAD, 1);
    make_map(enc, &mHh, p_hhi, Fq, MPAD, Eq);
    make_map(enc, &mW1h, p_w1h, Dq, Fq, Eq);
    make_map(enc, &mW2h, p_w2h, Fq, Dq, Eq);

    const dim3 blk(256);
    const dim3 gridQKV(Dq / TN, NTOK / TM, 3);
    const dim3 gridO(Dq / TN, NTOK / TM, 1);
    const dim3 grid1(Fq / 256, MPAD / 256, Eq);
    const dim3 grid2(Dq / 256, MPAD / 256, Eq);
    const int n4 = NTOK * Dq / 4;
    const int sgrid = (n4 + 255) / 256;
    const size_t segQ = (size_t)NTOK * Dq;

    cudaFuncSetAttribute(tc_gemm<2>,  cudaFuncAttributeMaxDynamicSharedMemorySize, TC_SMEM);
    cudaFuncSetAttribute(tc_gemm<3>,  cudaFuncAttributeMaxDynamicSharedMemorySize, TC_SMEM);
    cudaFuncSetAttribute(tc_gemm2<0>, cudaFuncAttributeMaxDynamicSharedMemorySize, TC2_SMEM);
    cudaFuncSetAttribute(tc_gemm2<1>, cudaFuncAttributeMaxDynamicSharedMemorySize, TC2_SMEM);

    __nv_bfloat16* p_qkvshi = p_hhi;   // staging in idle h region
    __nv_bfloat16* p_qkvslo = p_hlo;

    transpose_split<<<dim3(Dq/64, Dq/32, 1), blk>>>(Wq, p_wqkvh,           p_wqkvl,           Dq, Dq);
    transpose_split<<<dim3(Dq/64, Dq/32, 1), blk>>>(Wk, p_wqkvh + Dq*Dq,   p_wqkvl + Dq*Dq,   Dq, Dq);
    transpose_split<<<dim3(Dq/64, Dq/32, 1), blk>>>(Wv, p_wqkvh + 2*Dq*Dq, p_wqkvl + 2*Dq*Dq, Dq, Dq);
    split3_bf16<<<dim3(sgrid, 3), blk>>>(q, k, v, p_qkvshi, p_qkvslo, n4);
    transpose_split<<<dim3(Dq/64, Fq/32, Eq), blk>>>(W1, p_w1h, nullptr, Dq, Fq);
    tc_gemm<2><<<gridQKV, blk, TC_SMEM>>>(p_qkvshi, p_qkvslo, p_wqkvh, p_wqkvl,
                                          bq, bk, bv, nullptr, p_qkvh,
                                          NTOK, Dq, Dq, segQ, (size_t)Dq * Dq, segQ);
    const int smem_attn = (Sq * KPAD + Sq * DHq + 8 * 208 + 8 * DHq) * (int)sizeof(float);
    cudaFuncSetAttribute(attn_kernel, cudaFuncAttributeMaxDynamicSharedMemorySize, smem_attn);
    attn_kernel<<<dim3(Bq * Hq, 4), blk, smem_attn>>>(p_qkvh, p_qkvh + segQ, p_qkvh + 2 * segQ, p_ctx);
    transpose_split<<<dim3(Dq/64, Dq/32, 1), blk>>>(Wo, p_woh, p_wol, Dq, Dq);
    split_bf16<<<sgrid, blk>>>(p_ctx, p_inhi, p_inlo, n4);
    transpose_split<<<dim3(Fq/64, Dq/32, Eq), blk>>>(W2, p_w2h, nullptr, Fq, Dq);
    tc_gemm<3><<<gridO, blk, TC_SMEM>>>(p_inhi, p_inlo, p_woh, p_wol,
                                        bo, bo, bo, q, p_tmp, NTOK, Dq, Dq, 0, 0, 0);
    ln_kernel<<<NTOK, blk>>>(p_tmp, ln1g, ln1b, p_x, p_xhi, p_xlo);
    gate_kernel<<<(NTOK * 32 + 255) / 256, blk>>>(p_x, Wg, bg, p_gates);

    tc_gemm2<0><<<grid1, blk, TC2_SMEM>>>(
        mXh, mXl, mW1h, b1, nullptr, p_hhi,
        Fq, Dq, (size_t)Fq, (size_t)MPAD * Fq,
        p_xhi, p_xlo, p_w1h, (size_t)0, (size_t)Fq * Dq);
    tc_gemm2<1><<<grid2, blk, TC2_SMEM>>>(
        mHh, mHh, mW2h, b2, p_y, nullptr,
        Dq, Fq, (size_t)Dq, (size_t)MPAD * Dq,
        p_hhi, nullptr, p_w2h, (size_t)MPAD * Fq, (size_t)Dq * Fq);

    ln2_kernel<<<NTOK, blk>>>(p_x, p_y, p_gates, ln2g, ln2b, out);
}

// round 11
// speedup vs baseline: 9.2133x; 1.0484x over previous
#include <cuda_runtime.h>
#include <cuda.h>
#include <cuda_bf16.h>
#include <math.h>
#include <stdint.h>

#define Bq 32
#define Sq 196
#define Dq 768
#define Hq 12
#define Eq 8
#define Fq 3072
#define DHq 64
#define NTOK (Bq*Sq)
#define MPAD 6400

#define HAS_TCGEN05 (defined(__CUDA_ARCH_FEAT_SM103_ALL) || defined(__CUDA_ARCH_FEAT_SM100_ALL))

// ---------------- scratch ------------------------------------------------------
__device__ __align__(256) float d_qkvh[3*NTOK*Dq];
__device__ __align__(256) float d_ctx[NTOK*Dq];
__device__ __align__(256) float d_tmp[NTOK*Dq];
__device__ __align__(256) float d_x  [NTOK*Dq];
__device__ __align__(256) float d_y  [Eq*MPAD*Dq];
__device__ __align__(256) float d_gates[MPAD*Eq];

__device__ __align__(256) __nv_bfloat16 d_inhi[NTOK*Dq];
__device__ __align__(256) __nv_bfloat16 d_inlo[NTOK*Dq];
__device__ __align__(256) __nv_bfloat16 d_xhi[MPAD*Dq];
__device__ __align__(256) __nv_bfloat16 d_hhi[Eq*MPAD*Fq];  // h; also qkv-hi staging early
__device__ __align__(256) __nv_bfloat16 d_qlo[3*NTOK*Dq];   // qkv-lo staging
__device__ __align__(256) __nv_bfloat16 d_w1t_hi[Eq*Fq*Dq];
__device__ __align__(256) __nv_bfloat16 d_w2t_hi[Eq*Dq*Fq];
__device__ __align__(256) __nv_bfloat16 d_wqkvt_hi[3*Dq*Dq];
__device__ __align__(256) __nv_bfloat16 d_wqkvt_lo[3*Dq*Dq];
__device__ __align__(256) __nv_bfloat16 d_wot_hi[Dq*Dq];
__device__ __align__(256) __nv_bfloat16 d_wot_lo[Dq*Dq];

// ---------------- PTX helpers ---------------------------------------------------
__device__ __forceinline__ uint32_t smem_u32(const void* p) {
    uint32_t a;
    asm("{ .reg .u64 t; cvta.to.shared.u64 t, %1; cvt.u32.u64 %0, t; }" : "=r"(a) : "l"(p));
    return a;
}

#if HAS_TCGEN05
__device__ __forceinline__ bool elect_one() {
    uint32_t p;
    asm volatile("{\n .reg .pred p;\n elect.sync _|p, 0xFFFFFFFF;\n selp.b32 %0,1,0,p;\n}" : "=r"(p));
    return p != 0;
}
#define MBARRIER_INIT(addr, cnt) \
    asm volatile("mbarrier.init.shared.b64 [%0], %1;" :: "r"((uint32_t)(addr)), "r"((uint32_t)(cnt)) : "memory")
#define MBARRIER_INVAL(addr) \
    asm volatile("mbarrier.inval.shared.b64 [%0];" :: "r"((uint32_t)(addr)) : "memory")
#define MBARRIER_EXPECT_TX(addr, tx) \
    asm volatile("mbarrier.arrive.expect_tx.shared.b64 _, [%0], %1;" \
        :: "r"((uint32_t)(addr)), "r"((uint32_t)(tx)) : "memory")
#define MBARRIER_WAIT_PARITY(mbar, par) do { \
    uint32_t _m = (uint32_t)(mbar), _p = (uint32_t)(par), _d; \
    asm volatile("{\n\t.reg .pred p;\n\t" \
        "mbarrier.try_wait.parity.acquire.cta.shared::cta.b64 p, [%1], %2;\n\t" \
        "selp.b32 %0, 1, 0, p;\n\t}" : "=r"(_d) : "r"(_m), "r"(_p) : "memory"); \
    if (!_d) { \
        asm volatile("{\n\t.reg .pred P1;\n\t" \
            "WL_%=:\n\t" \
            "mbarrier.try_wait.parity.acquire.cta.shared::cta.b64 P1, [%0], %1, 0x989680;\n\t" \
            "@P1 bra.uni WD_%=;\n\tbra.uni WL_%=;\n\tWD_%=:\n\t}" \
            :: "r"(_m), "r"(_p) : "memory"); \
    } \
} while(0)
#define TCGEN05_ALLOC(a, n) \
    asm volatile("tcgen05.alloc.cta_group::1.sync.aligned.shared::cta.b32 [%0], %1;" \
        :: "r"((uint32_t)(a)), "r"((uint32_t)(n)) : "memory")
#define TCGEN05_DEALLOC(t, n) \
    asm volatile("tcgen05.dealloc.cta_group::1.sync.aligned.b32 %0, %1;" :: "r"(t), "r"(n))
#define TCGEN05_RELINQ() \
    asm volatile("tcgen05.relinquish_alloc_permit.cta_group::1.sync.aligned;")
#define TCGEN05_COMMIT(m) \
    asm volatile("tcgen05.commit.cta_group::1.mbarrier::arrive::one.shared::cluster.b64 [%0];" \
        :: "r"((uint32_t)(m)) : "memory")
#define TCGEN05_FENCE_AFTER()  asm volatile("tcgen05.fence::after_thread_sync;" ::: "memory")
#define TCGEN05_FENCE_BEFORE() asm volatile("tcgen05.fence::before_thread_sync;" ::: "memory")
#define TCGEN05_WAIT_LD() asm volatile("tcgen05.wait::ld.sync.aligned;" ::: "memory")
#define FENCE_ASYNC_SHARED() asm volatile("fence.proxy.async.shared::cta;" ::: "memory")
#define CP_ASYNC16(dst, src) \
    asm volatile("cp.async.cg.shared.global [%0], [%1], 16;" :: "r"((uint32_t)(dst)), "l"(src))
#define CP_COMMIT() asm volatile("cp.async.commit_group;" ::: "memory")
#define CP_WAIT(n)  asm volatile("cp.async.wait_group %0;" :: "n"(n) : "memory")
#define TMA_LOAD_3D(sm, map, cx, cy, cz, mb) \
    asm volatile("cp.async.bulk.tensor.3d.shared::cta.global.tile.mbarrier::complete_tx::bytes " \
        "[%0], [%1, {%2, %3, %4}], [%5];" \
        :: "r"((uint32_t)(sm)), "l"(map), "r"((int32_t)(cx)), "r"((int32_t)(cy)), \
           "r"((int32_t)(cz)), "r"((uint32_t)(mb)) : "memory")
#define TCGEN05_LD_32X32B_X32(r, ta) \
    asm volatile("tcgen05.ld.sync.aligned.32x32b.x32.b32 " \
        "{%0, %1, %2, %3, %4, %5, %6, %7, %8, %9, %10, %11, %12, %13, %14, %15, " \
        " %16, %17, %18, %19, %20, %21, %22, %23, %24, %25, %26, %27, %28, %29, %30, %31}, [%32];" \
        : "=r"((r)[0]), "=r"((r)[1]), "=r"((r)[2]), "=r"((r)[3]), "=r"((r)[4]), "=r"((r)[5]), \
          "=r"((r)[6]), "=r"((r)[7]), "=r"((r)[8]), "=r"((r)[9]), "=r"((r)[10]), "=r"((r)[11]), \
          "=r"((r)[12]), "=r"((r)[13]), "=r"((r)[14]), "=r"((r)[15]), "=r"((r)[16]), "=r"((r)[17]), \
          "=r"((r)[18]), "=r"((r)[19]), "=r"((r)[20]), "=r"((r)[21]), "=r"((r)[22]), "=r"((r)[23]), \
          "=r"((r)[24]), "=r"((r)[25]), "=r"((r)[26]), "=r"((r)[27]), "=r"((r)[28]), "=r"((r)[29]), \
          "=r"((r)[30]), "=r"((r)[31]) : "r"(ta))

static constexpr uint64_t DESC_SW128 =
    (uint64_t(2) << 61) | (uint64_t(1) << 46) | (uint64_t(64) << 32) | (uint64_t(1) << 16);
static constexpr uint64_t DESC_SW64 =
    (uint64_t(4) << 61) | (uint64_t(1) << 46) | (uint64_t(32) << 32) | (uint64_t(1) << 16);
#define MKD128(a) (DESC_SW128 | ((uint64_t)((a) >> 4) & 0x3FFF))
#define MKD64(a)  (DESC_SW64  | ((uint64_t)((a) >> 4) & 0x3FFF))

__device__ __forceinline__ void mma_bf16_ss(uint32_t d, uint64_t ad, uint64_t bd,
                                            uint32_t idesc, uint32_t en) {
    asm volatile(
        "{\n\t.reg .pred p;\n\tsetp.ne.u32 p, %5, 0;\n\t"
        "tcgen05.mma.cta_group::1.kind::f16 [%0], %1, %2, %3, {%4,%4,%4,%4}, p;\n\t}"
        :: "r"(d), "l"(ad), "l"(bd), "r"(idesc), "r"(0u), "r"(en) : "memory");
}
static constexpr uint32_t IDESC_BF16 =
    (1u << 4) | (1u << 7) | (1u << 10) | ((256 / 8) << 17) | ((128 / 16) << 24);
#endif

// ======================= TM128 tc GEMM (QKV batched / O-proj, 3-term) ===========
#define TM 128
#define TN 256
#define TK 64
#define STAGE_BYTES 98304
#define SM_DATA 1024
#define TC_SMEM (SM_DATA + 2*STAGE_BYTES)

#if HAS_TCGEN05
__device__ __forceinline__ void load_slab128(
    uint32_t sbase, int stage,
    const __nv_bfloat16* __restrict__ Ahi, const __nv_bfloat16* __restrict__ Alo,
    const __nv_bfloat16* __restrict__ Bhi, const __nv_bfloat16* __restrict__ Blo,
    int m0, int n0, int k0, int K)
{
    const int tid = threadIdx.x;
    const uint32_t base = sbase + SM_DATA + stage * STAGE_BYTES;
#pragma unroll
    for (int i = 0; i < 4; i++) {
        int idx = i * 256 + tid;
        int row = idx >> 3, c4 = idx & 7;
        int off = row * 128 + c4 * 16;
        int sw  = off ^ ((off >> 3) & 0x70);
        size_t g = (size_t)(m0 + row) * K + k0 + c4 * 8;
        CP_ASYNC16(base + sw, Ahi + g);
        CP_ASYNC16(base + 16384 + sw, Alo + g);
    }
#pragma unroll
    for (int i = 0; i < 8; i++) {
        int idx = i * 256 + tid;
        int row = idx >> 3, c4 = idx & 7;
        int off = row * 128 + c4 * 16;
        int sw  = off ^ ((off >> 3) & 0x70);
        size_t g = (size_t)(n0 + row) * K + k0 + c4 * 8;
        CP_ASYNC16(base + 32768 + sw, Bhi + g);
        CP_ASYNC16(base + 65536 + sw, Blo + g);
    }
    CP_COMMIT();
}
#endif

template<int MODE>   // 2: z-batched C=AW+b(z)   3: C=AW+b+res
__global__ void __launch_bounds__(256)
tc_gemm(const __nv_bfloat16* __restrict__ Ahi, const __nv_bfloat16* __restrict__ Alo,
        const __nv_bfloat16* __restrict__ Bhi, const __nv_bfloat16* __restrict__ Blo,
        const float* __restrict__ b0, const float* __restrict__ b1,
        const float* __restrict__ b2, const float* __restrict__ res,
        float* __restrict__ Cf, int M, int N, int K,
        size_t sA, size_t sB, size_t sC)
{
    extern __shared__ __align__(1024) char smx[];
    const int z = blockIdx.z;
    Ahi += z * sA; Alo += z * sA;
    Bhi += z * sB; Blo += z * sB;
    Cf  += z * sC;
    const float* bias = (z == 0) ? b0 : (z == 1) ? b1 : b2;
#if HAS_TCGEN05
    const uint32_t sb = smem_u32(smx);
    const int tid = threadIdx.x;
    const int wid = tid >> 5, lane = tid & 31;
    const int m0 = blockIdx.y * TM, n0 = blockIdx.x * TN;

    if (wid == 0) { TCGEN05_ALLOC(sb, 256); TCGEN05_RELINQ(); }
    if (tid == 0) { MBARRIER_INIT(sb + 8, 1); MBARRIER_INIT(sb + 16, 1); }
    __syncthreads();
    uint32_t tmem;
    asm volatile("ld.shared.b32 %0, [%1];" : "=r"(tmem) : "r"(sb));

    const int NS = K / TK;
    load_slab128(sb, 0, Ahi, Alo, Bhi, Blo, m0, n0, 0, K);
    int ph0 = 0, ph1 = 0;
    for (int s = 0; s < NS; s++) {
        const int buf = s & 1;
        if (s + 1 < NS) {
            const int nb = 1 - buf;
            if (s >= 1) {
                if (nb == 0) { MBARRIER_WAIT_PARITY(sb + 8,  ph0); ph0 ^= 1; }
                else         { MBARRIER_WAIT_PARITY(sb + 16, ph1); ph1 ^= 1; }
            }
            load_slab128(sb, nb, Ahi, Alo, Bhi, Blo, m0, n0, (s + 1) * TK, K);
            CP_WAIT(1);
        } else {
            CP_WAIT(0);
        }
        FENCE_ASYNC_SHARED();
        __syncthreads();
        if (wid == 0) {
            TCGEN05_FENCE_AFTER();
            if (elect_one()) {
                const uint32_t tb = sb + SM_DATA + buf * STAGE_BYTES;
                const uint64_t ah = MKD128(tb), al = MKD128(tb + 16384);
                const uint64_t bh = MKD128(tb + 32768), bl = MKD128(tb + 65536);
#pragma unroll
                for (int ks = 0; ks < 4; ks++) {
                    const uint32_t en0 = (s == 0 && ks == 0) ? 0u : 1u;
                    mma_bf16_ss(tmem, ah + ks * 2, bh + ks * 2, IDESC_BF16, en0);
                    mma_bf16_ss(tmem, ah + ks * 2, bl + ks * 2, IDESC_BF16, 1u);
                    mma_bf16_ss(tmem, al + ks * 2, bh + ks * 2, IDESC_BF16, 1u);
                }
                TCGEN05_COMMIT(sb + 8 + buf * 8);
            }
        }
    }
    if (((NS - 1) & 1) == 0) { MBARRIER_WAIT_PARITY(sb + 8,  ph0); }
    else                     { MBARRIER_WAIT_PARITY(sb + 16, ph1); }
    TCGEN05_FENCE_AFTER();

    const int sub = wid & 3, cg = wid >> 2;
    const int row = m0 + sub * 32 + lane;
#pragma unroll
    for (int ch = 0; ch < 4; ch++) {
        const int colb = cg * 128 + ch * 32;
        uint32_t r[32];
        TCGEN05_LD_32X32B_X32(r, tmem + colb);
        TCGEN05_WAIT_LD();
        const size_t base = (size_t)row * N + n0 + colb;
        const float4* bv = (const float4*)(bias + n0 + colb);
        float4* dst = (float4*)(Cf + base);
        const float4* rv = (MODE == 3) ? (const float4*)(res + base) : nullptr;
#pragma unroll
        for (int i = 0; i < 8; i++) {
            float4 b4 = bv[i];
            float4 o;
            o.x = __uint_as_float(r[i*4+0]) + b4.x;
            o.y = __uint_as_float(r[i*4+1]) + b4.y;
            o.z = __uint_as_float(r[i*4+2]) + b4.z;
            o.w = __uint_as_float(r[i*4+3]) + b4.w;
            if (MODE == 3) { float4 t = rv[i]; o.x += t.x; o.y += t.y; o.z += t.z; o.w += t.w; }
            dst[i] = o;
        }
    }
    TCGEN05_FENCE_BEFORE();
    __syncthreads();
    if (tid == 0) { MBARRIER_INVAL(sb + 8); MBARRIER_INVAL(sb + 16); }
    __syncthreads();
    if (wid == 0) TCGEN05_DEALLOC(tmem, 256);
#else
    float* As = (float*)smx;
    float* Bs = As + 16 * 128;
    const int tid = threadIdx.x;
    const int m0 = blockIdx.y * TM, n0x = blockIdx.x * TN;
    const int tx = tid & 15, ty = tid >> 4;
    const int mr = ty * 8, nr = tx * 8;
    for (int half = 0; half < 2; half++) {
        const int n0 = n0x + half * 128;
        float acc[8][8];
#pragma unroll
        for (int i = 0; i < 8; i++)
#pragma unroll
            for (int j = 0; j < 8; j++) acc[i][j] = 0.f;
        for (int k0 = 0; k0 < K; k0 += 16) {
            __syncthreads();
#pragma unroll
            for (int i = 0; i < 8; i++) {
                int idx = i * 256 + tid;
                int kk = idx >> 7, mm = idx & 127;
                size_t ga = (size_t)(m0 + mm) * K + k0 + kk;
                size_t gb = (size_t)(n0 + mm) * K + k0 + kk;
                As[kk*128+mm] = __bfloat162float(Ahi[ga]) + __bfloat162float(Alo[ga]);
                Bs[kk*128+mm] = __bfloat162float(Bhi[gb]) + __bfloat162float(Blo[gb]);
            }
            __syncthreads();
#pragma unroll
            for (int kk = 0; kk < 16; kk++) {
                float a0[8], b0r[8];
#pragma unroll
                for (int i = 0; i < 8; i++) a0[i] = As[kk*128+mr+i];
#pragma unroll
                for (int j = 0; j < 8; j++) b0r[j] = Bs[kk*128+nr+j];
#pragma unroll
                for (int i = 0; i < 8; i++)
#pragma unroll
                    for (int j = 0; j < 8; j++)
                        acc[i][j] = fmaf(a0[i], b0r[j], acc[i][j]);
            }
        }
#pragma unroll
        for (int i = 0; i < 8; i++) {
            const int row = m0 + mr + i;
#pragma unroll
            for (int j = 0; j < 8; j++) {
                const int col = n0 + nr + j;
                const size_t idx = (size_t)row * N + col;
                float v = acc[i][j] + bias[col];
                if (MODE == 2) Cf[idx] = v; else Cf[idx] = v + res[idx];
            }
        }
    }
#endif
}

// ======================= MoE GEMM: pure bf16, TMA producer/consumer =============
// both modes: A hi only, B hi only; slab 32KB; 4 MMAs/slab; 6 stages
// MODE 0: gelu(acc+bias) -> bf16 hi    MODE 1: Cf = acc + bias
#define T2K 32
#define SLAB2 32768
#define TC2_SMEM (1024 + 6*SLAB2)   // 197632

template<int MODE>
__global__ void __launch_bounds__(256)
tc_gemm2(const __grid_constant__ CUtensorMap mA, const __grid_constant__ CUtensorMap mB,
         const float* __restrict__ bias, float* __restrict__ Cf,
         __nv_bfloat16* __restrict__ Chi,
         int N, int K, size_t sBias, size_t sC,
         const __nv_bfloat16* __restrict__ A, const __nv_bfloat16* __restrict__ B,
         size_t sA, size_t sB)
{
    extern __shared__ __align__(1024) char smx[];
    const int z = blockIdx.z;
    bias += z * sBias;
#if HAS_TCGEN05
    const uint32_t sb = smem_u32(smx);
    const int tid = threadIdx.x;
    const int wid = tid >> 5, lane = tid & 31;
    const int m0 = blockIdx.y * 256, n0 = blockIdx.x * 256;
    const int za = (MODE == 0) ? 0 : z;

    if (wid == 0) { TCGEN05_ALLOC(sb, 512); TCGEN05_RELINQ(); }
    if (tid == 0) {
        // full[i] at 8+8i (i<6), empty[i] at 56+8i, done at 104
#pragma unroll
        for (int i = 0; i < 6; i++) { MBARRIER_INIT(sb + 8 + i * 8, 1); MBARRIER_INIT(sb + 56 + i * 8, 1); }
        MBARRIER_INIT(sb + 104, 1);
        FENCE_ASYNC_SHARED();
    }
    __syncthreads();
    uint32_t tmem;
    asm volatile("ld.shared.b32 %0, [%1];" : "=r"(tmem) : "r"(sb));

    const int NS = K / T2K;
    if (wid == 1) {
        if (elect_one()) {
            for (int s = 0; s < NS; s++) {
                const int st = s % 6;
                if (s >= 6) MBARRIER_WAIT_PARITY(sb + 56 + st * 8, ((s / 6) - 1) & 1);
                MBARRIER_EXPECT_TX(sb + 8 + st * 8, (uint32_t)SLAB2);
                const uint32_t stb = sb + 1024 + st * SLAB2;
                const int k0 = s * T2K;
                TMA_LOAD_3D(stb,         &mA, k0, m0, za, sb + 8 + st * 8);
                TMA_LOAD_3D(stb + 16384, &mB, k0, n0, z,  sb + 8 + st * 8);
            }
        }
    } else if (wid == 0) {
        TCGEN05_FENCE_AFTER();
        if (elect_one()) {
            for (int s = 0; s < NS; s++) {
                const int st = s % 6;
                MBARRIER_WAIT_PARITY(sb + 8 + st * 8, (s / 6) & 1);
                const uint32_t tb = sb + 1024 + st * SLAB2;
                const uint64_t a0 = MKD64(tb);
                const uint64_t a1 = a0 + 512;     // rows 128..255 (8192 B / 16)
                const uint64_t bh = MKD64(tb + 16384);
#pragma unroll
                for (int ks = 0; ks < 2; ks++) {
                    const uint32_t en0 = (s == 0 && ks == 0) ? 0u : 1u;
                    mma_bf16_ss(tmem,       a0 + ks * 2, bh + ks * 2, IDESC_BF16, en0);
                    mma_bf16_ss(tmem + 256, a1 + ks * 2, bh + ks * 2, IDESC_BF16, en0);
                }
                TCGEN05_COMMIT(sb + 56 + st * 8);
            }
            TCGEN05_COMMIT(sb + 104);
        }
    }

    MBARRIER_WAIT_PARITY(sb + 104, 0);
    TCGEN05_FENCE_AFTER();

    const int accSel = wid >> 2, sub = wid & 3;
    const int row = m0 + accSel * 128 + sub * 32 + lane;
    const uint32_t tacc = tmem + accSel * 256;
    if (MODE == 0) Chi += z * sC;
    else           Cf  += z * sC;
#pragma unroll
    for (int ch = 0; ch < 8; ch++) {
        const int colb = ch * 32;
        uint32_t r[32];
        TCGEN05_LD_32X32B_X32(r, tacc + colb);
        TCGEN05_WAIT_LD();
        const size_t base = (size_t)row * N + n0 + colb;
        const float4* bv = (const float4*)(bias + n0 + colb);
        if (MODE == 0) {
            uint4* dh = (uint4*)(Chi + base);
#pragma unroll
            for (int i = 0; i < 4; i++) {
                uint32_t hp[4];
#pragma unroll
                for (int p = 0; p < 4; p++) {
                    float4 b4 = bv[i * 2 + (p >> 1)];
                    float b0 = (p & 1) ? b4.z : b4.x;
                    float b1 = (p & 1) ? b4.w : b4.y;
                    float v0 = __uint_as_float(r[i*8+p*2+0]) + b0;
                    float v1 = __uint_as_float(r[i*8+p*2+1]) + b1;
                    float g0 = 0.5f * v0 * (1.f + erff(v0 * 0.70710678118654752f));
                    float g1 = 0.5f * v1 * (1.f + erff(v1 * 0.70710678118654752f));
                    hp[p] = (uint32_t)__bfloat16_as_ushort(__float2bfloat16(g0)) |
                            ((uint32_t)__bfloat16_as_ushort(__float2bfloat16(g1)) << 16);
                }
                dh[i] = make_uint4(hp[0], hp[1], hp[2], hp[3]);
            }
        } else {
            float4* dst = (float4*)(Cf + base);
#pragma unroll
            for (int i = 0; i < 8; i++) {
                float4 b4 = bv[i];
                float4 o;
                o.x = __uint_as_float(r[i*4+0]) + b4.x;
                o.y = __uint_as_float(r[i*4+1]) + b4.y;
                o.z = __uint_as_float(r[i*4+2]) + b4.z;
                o.w = __uint_as_float(r[i*4+3]) + b4.w;
                dst[i] = o;
            }
        }
    }
    TCGEN05_FENCE_BEFORE();
    __syncthreads();
    if (tid == 0) {
#pragma unroll
        for (int i = 0; i < 6; i++) { MBARRIER_INVAL(sb + 8 + i * 8); MBARRIER_INVAL(sb + 56 + i * 8); }
        MBARRIER_INVAL(sb + 104);
    }
    __syncthreads();
    if (wid == 0) TCGEN05_DEALLOC(tmem, 512);
#else
    const __nv_bfloat16* Ap = A + (size_t)((MODE == 0) ? 0 : z) * sA;
    const __nv_bfloat16* Bp = B + (size_t)z * sB;
    if (MODE == 0) Chi += z * sC;
    else           Cf  += z * sC;
    float* As = (float*)smx;
    float* Bs = As + 16 * 128;
    const int tid = threadIdx.x;
    const int tx = tid & 15, ty = tid >> 4;
    const int mr = ty * 8, nr = tx * 8;
    for (int mh = 0; mh < 2; mh++)
    for (int nh = 0; nh < 2; nh++) {
        const int m0 = blockIdx.y * 256 + mh * 128;
        const int n0 = blockIdx.x * 256 + nh * 128;
        float acc[8][8];
#pragma unroll
        for (int i = 0; i < 8; i++)
#pragma unroll
            for (int j = 0; j < 8; j++) acc[i][j] = 0.f;
        for (int k0 = 0; k0 < K; k0 += 16) {
            __syncthreads();
#pragma unroll
            for (int i = 0; i < 8; i++) {
                int idx = i * 256 + tid;
                int kk = idx >> 7, mm = idx & 127;
                size_t ga = (size_t)(m0 + mm) * K + k0 + kk;
                size_t gb = (size_t)(n0 + mm) * K + k0 + kk;
                As[kk*128+mm] = __bfloat162float(Ap[ga]);
                Bs[kk*128+mm] = __bfloat162float(Bp[gb]);
            }
            __syncthreads();
#pragma unroll
            for (int kk = 0; kk < 16; kk++) {
                float a0[8], b0[8];
#pragma unroll
                for (int i = 0; i < 8; i++) a0[i] = As[kk*128+mr+i];
#pragma unroll
                for (int j = 0; j < 8; j++) b0[j] = Bs[kk*128+nr+j];
#pragma unroll
                for (int i = 0; i < 8; i++)
#pragma unroll
                    for (int j = 0; j < 8; j++)
                        acc[i][j] = fmaf(a0[i], b0[j], acc[i][j]);
            }
        }
#pragma unroll
        for (int i = 0; i < 8; i++) {
            const int row = m0 + mr + i;
#pragma unroll
            for (int j = 0; j < 8; j++) {
                const int col = n0 + nr + j;
                const size_t idx = (size_t)row * N + col;
                float v = acc[i][j] + bias[col];
                if (MODE == 0) {
                    float g = 0.5f * v * (1.f + erff(v * 0.70710678118654752f));
                    Chi[idx] = __float2bfloat16(g);
                } else Cf[idx] = v;
            }
        }
    }
#endif
}

// ---------------- transpose v2 -------------------------------------------------------
__global__ void __launch_bounds__(256)
transpose_split(const float* __restrict__ W, __nv_bfloat16* __restrict__ Thi,
                __nv_bfloat16* __restrict__ Tlo, int K, int N)
{
    __shared__ float t[64][33];
    const int e = blockIdx.z;
    const float* Wp = W + (size_t)e * K * N;
    __nv_bfloat16* th = Thi + (size_t)e * K * N;
    __nv_bfloat16* tl = Tlo ? Tlo + (size_t)e * K * N : nullptr;
    const int k0 = blockIdx.x * 64, n0 = blockIdx.y * 32;
    const int tid = threadIdx.x;
#pragma unroll
    for (int i = 0; i < 8; i++) {
        int idx = i * 256 + tid;
        int r = idx >> 5, c = idx & 31;
        t[r][c] = Wp[(size_t)(k0 + r) * N + n0 + c];
    }
    __syncthreads();
#pragma unroll
    for (int i = 0; i < 4; i++) {
        int idx = i * 256 + tid;
        int c = idx >> 5, j = idx & 31;
        float v0 = t[2 * j][c], v1 = t[2 * j + 1][c];
        __nv_bfloat16 h0 = __float2bfloat16(v0);
        __nv_bfloat16 h1 = __float2bfloat16(v1);
        const size_t base = (size_t)(n0 + c) * K + k0 + 2 * j;
        *(uint32_t*)(th + base) =
            (uint32_t)__bfloat16_as_ushort(h0) | ((uint32_t)__bfloat16_as_ushort(h1) << 16);
        if (tl) {
            __nv_bfloat16 l0 = __float2bfloat16(v0 - __bfloat162float(h0));
            __nv_bfloat16 l1 = __float2bfloat16(v1 - __bfloat162float(h1));
            *(uint32_t*)(tl + base) =
                (uint32_t)__bfloat16_as_ushort(l0) | ((uint32_t)__bfloat16_as_ushort(l1) << 16);
        }
    }
}

// ---------------- batched q/k/v split ------------------------------------------------
__global__ void __launch_bounds__(256)
split3_bf16(const float* __restrict__ q, const float* __restrict__ k,
            const float* __restrict__ v, __nv_bfloat16* __restrict__ hi,
            __nv_bfloat16* __restrict__ lo, int n4)
{
    const int seg = blockIdx.y;
    const float* x = (seg == 0) ? q : (seg == 1) ? k : v;
    int i = blockIdx.x * 256 + threadIdx.x;
    if (i >= n4) return;
    float4 val = ((const float4*)x)[i];
    __nv_bfloat16 h0 = __float2bfloat16(val.x), h1 = __float2bfloat16(val.y);
    __nv_bfloat16 h2 = __float2bfloat16(val.z), h3 = __float2bfloat16(val.w);
    uint2 hp, lp;
    hp.x = (uint32_t)__bfloat16_as_ushort(h0) | ((uint32_t)__bfloat16_as_ushort(h1) << 16);
    hp.y = (uint32_t)__bfloat16_as_ushort(h2) | ((uint32_t)__bfloat16_as_ushort(h3) << 16);
    __nv_bfloat16 l0 = __float2bfloat16(val.x - __bfloat162float(h0));
    __nv_bfloat16 l1 = __float2bfloat16(val.y - __bfloat162float(h1));
    __nv_bfloat16 l2 = __float2bfloat16(val.z - __bfloat162float(h2));
    __nv_bfloat16 l3 = __float2bfloat16(val.w - __bfloat162float(h3));
    lp.x = (uint32_t)__bfloat16_as_ushort(l0) | ((uint32_t)__bfloat16_as_ushort(l1) << 16);
    lp.y = (uint32_t)__bfloat16_as_ushort(l2) | ((uint32_t)__bfloat16_as_ushort(l3) << 16);
    const size_t off = (size_t)seg * n4 + i;
    ((uint2*)hi)[off] = hp;
    ((uint2*)lo)[off] = lp;
}

// ---------------- single split (ctx, hi+lo) --------------------------------------------
__global__ void __launch_bounds__(256)
split_bf16(const float* __restrict__ x, __nv_bfloat16* __restrict__ hi,
           __nv_bfloat16* __restrict__ lo, int n4)
{
    int i = blockIdx.x * 256 + threadIdx.x;
    if (i >= n4) return;
    float4 v = ((const float4*)x)[i];
    __nv_bfloat16 h0 = __float2bfloat16(v.x), h1 = __float2bfloat16(v.y);
    __nv_bfloat16 h2 = __float2bfloat16(v.z), h3 = __float2bfloat16(v.w);
    uint2 hp, lp;
    hp.x = (uint32_t)__bfloat16_as_ushort(h0) | ((uint32_t)__bfloat16_as_ushort(h1) << 16);
    hp.y = (uint32_t)__bfloat16_as_ushort(h2) | ((uint32_t)__bfloat16_as_ushort(h3) << 16);
    __nv_bfloat16 l0 = __float2bfloat16(v.x - __bfloat162float(h0));
    __nv_bfloat16 l1 = __float2bfloat16(v.y - __bfloat162float(h1));
    __nv_bfloat16 l2 = __float2bfloat16(v.z - __bfloat162float(h2));
    __nv_bfloat16 l3 = __float2bfloat16(v.w - __bfloat162float(h3));
    lp.x = (uint32_t)__bfloat16_as_ushort(l0) | ((uint32_t)__bfloat16_as_ushort(l1) << 16);
    lp.y = (uint32_t)__bfloat16_as_ushort(l2) | ((uint32_t)__bfloat16_as_ushort(l3) << 16);
    ((uint2*)hi)[i] = hp;
    ((uint2*)lo)[i] = lp;
}

// ---------------- attention: 4 CTAs per (b,h) ------------------------------------------
#define KPAD 65
__global__ void __launch_bounds__(256)
attn_kernel(const float* __restrict__ qh, const float* __restrict__ kh,
            const float* __restrict__ vh, float* __restrict__ ctx)
{
    const int b = blockIdx.x / Hq;
    const int h = blockIdx.x % Hq;
    const int qbase = blockIdx.y * 49;
    const int qend  = min(196, qbase + 49);
    extern __shared__ float sm[];
    float* Ks = sm;
    float* Vs = Ks + Sq * KPAD;
    float* Ps = Vs + Sq * DHq;
    float* Qs = Ps + 8 * 208;
    const int tid = threadIdx.x;
    for (int i = tid; i < Sq * DHq; i += 256) {
        int s = i / DHq, d = i % DHq;
        size_t gidx = (size_t)(b * Sq + s) * Dq + h * DHq + d;
        Ks[s * KPAD + d] = kh[gidx];
        Vs[s * DHq  + d] = vh[gidx];
    }
    __syncthreads();
    const int warp = tid >> 5, lane = tid & 31;
    float* p    = Ps + warp * 208;
    float* qrow = Qs + warp * DHq;
    for (int q = qbase + warp; q < qend; q += 8) {
        for (int d = lane; d < DHq; d += 32)
            qrow[d] = qh[(size_t)(b * Sq + q) * Dq + h * DHq + d];
        __syncwarp();
        float lmax = -1e30f;
        for (int col = lane; col < Sq; col += 32) {
            float s = 0.f;
            const float* kr = Ks + col * KPAD;
#pragma unroll 16
            for (int d = 0; d < DHq; d++) s = fmaf(qrow[d], kr[d], s);
            s *= 0.125f;
            p[col] = s;
            lmax = fmaxf(lmax, s);
        }
#pragma unroll
        for (int o = 16; o; o >>= 1) lmax = fmaxf(lmax, __shfl_xor_sync(0xffffffffu, lmax, o));
        float lsum = 0.f;
        for (int col = lane; col < Sq; col += 32) {
            float e = __expf(p[col] - lmax);
            p[col] = e;
            lsum += e;
        }
#pragma unroll
        for (int o = 16; o; o >>= 1) lsum += __shfl_xor_sync(0xffffffffu, lsum, o);
        const float inv = 1.f / lsum;
        __syncwarp();
        for (int d = lane; d < DHq; d += 32) {
            float a = 0.f;
            for (int k = 0; k < Sq; k++) a = fmaf(p[k], Vs[k * DHq + d], a);
            ctx[(size_t)(b * Sq + q) * Dq + h * DHq + d] = a * inv;
        }
        __syncwarp();
    }
}

// ---------------- gate softmax ----------------------------------------------------------
__global__ void __launch_bounds__(256)
gate_kernel(const float* __restrict__ x, const float* __restrict__ Wg,
            const float* __restrict__ bg, float* __restrict__ gates)
{
    const int warp = (blockIdx.x * 256 + threadIdx.x) >> 5;
    const int lane = threadIdx.x & 31;
    if (warp >= NTOK) return;
    const float* xr = x + (size_t)warp * Dq;
    float lg[Eq];
#pragma unroll
    for (int e = 0; e < Eq; e++) lg[e] = 0.f;
    for (int d = lane; d < Dq; d += 32) {
        float xv = xr[d];
#pragma unroll
        for (int e = 0; e < Eq; e++) lg[e] = fmaf(xv, Wg[d * Eq + e], lg[e]);
    }
#pragma unroll
    for (int e = 0; e < Eq; e++)
#pragma unroll
        for (int o = 16; o; o >>= 1) lg[e] += __shfl_xor_sync(0xffffffffu, lg[e], o);
    if (lane == 0) {
        float m = -1e30f;
#pragma unroll
        for (int e = 0; e < Eq; e++) { lg[e] += bg[e]; m = fmaxf(m, lg[e]); }
        float s = 0.f;
#pragma unroll
        for (int e = 0; e < Eq; e++) { lg[e] = __expf(lg[e] - m); s += lg[e]; }
        float inv = 1.f / s;
#pragma unroll
        for (int e = 0; e < Eq; e++) gates[(size_t)warp * Eq + e] = lg[e] * inv;
    }
}

// ---------------- LN1 (emits bf16 hi) -----------------------------------------------------
__global__ void __launch_bounds__(256)
ln_kernel(const float* __restrict__ a, const float* __restrict__ g,
          const float* __restrict__ be, float* __restrict__ out,
          __nv_bfloat16* __restrict__ ohi)
{
    const int row = blockIdx.x;
    const float* ar = a + (size_t)row * Dq;
    float v[3];
    float s = 0.f, s2 = 0.f;
#pragma unroll
    for (int i = 0; i < 3; i++) {
        int d = threadIdx.x + i * 256;
        float x = ar[d];
        v[i] = x;
        s += x; s2 = fmaf(x, x, s2);
    }
    __shared__ float rs[8], rs2[8];
#pragma unroll
    for (int o = 16; o; o >>= 1) { s += __shfl_xor_sync(0xffffffffu, s, o); s2 += __shfl_xor_sync(0xffffffffu, s2, o); }
    const int warp = threadIdx.x >> 5, lane = threadIdx.x & 31;
    if (lane == 0) { rs[warp] = s; rs2[warp] = s2; }
    __syncthreads();
    if (warp == 0) {
        float t  = (lane < 8) ? rs[lane]  : 0.f;
        float t2 = (lane < 8) ? rs2[lane] : 0.f;
#pragma unroll
        for (int o = 4; o; o >>= 1) { t += __shfl_xor_sync(0xffffffffu, t, o); t2 += __shfl_xor_sync(0xffffffffu, t2, o); }
        if (lane == 0) { rs[0] = t; rs2[0] = t2; }
    }
    __syncthreads();
    const float mu  = rs[0] * (1.f / Dq);
    const float var = rs2[0] * (1.f / Dq) - mu * mu;
    const float inv = rsqrtf(var + 1e-5f);
#pragma unroll
    for (int i = 0; i < 3; i++) {
        int d = threadIdx.x + i * 256;
        float y = (v[i] - mu) * inv * g[d] + be[d];
        const size_t idx = (size_t)row * Dq + d;
        out[idx] = y;
        ohi[idx] = __float2bfloat16(y);
    }
}

// ---------------- LN2: fused gate-weighted expert reduction --------------------------------
__global__ void __launch_bounds__(256)
ln2_kernel(const float* __restrict__ x, const float* __restrict__ y,
           const float* __restrict__ gates, const float* __restrict__ g,
           const float* __restrict__ be, float* __restrict__ out)
{
    const int row = blockIdx.x;
    __shared__ float sg[Eq];
    if (threadIdx.x < Eq) sg[threadIdx.x] = gates[(size_t)row * Eq + threadIdx.x];
    __syncthreads();
    float v[3];
    float s = 0.f, s2 = 0.f;
#pragma unroll
    for (int i = 0; i < 3; i++) {
        int d = threadIdx.x + i * 256;
        float val = x[(size_t)row * Dq + d];
#pragma unroll
        for (int e = 0; e < Eq; e++)
            val = fmaf(sg[e], y[(size_t)e * MPAD * Dq + (size_t)row * Dq + d], val);
        v[i] = val;
        s += val; s2 = fmaf(val, val, s2);
    }
    __shared__ float rs[8], rs2[8];
#pragma unroll
    for (int o = 16; o; o >>= 1) { s += __shfl_xor_sync(0xffffffffu, s, o); s2 += __shfl_xor_sync(0xffffffffu, s2, o); }
    const int warp = threadIdx.x >> 5, lane = threadIdx.x & 31;
    if (lane == 0) { rs[warp] = s; rs2[warp] = s2; }
    __syncthreads();
    if (warp == 0) {
        float t  = (lane < 8) ? rs[lane]  : 0.f;
        float t2 = (lane < 8) ? rs2[lane] : 0.f;
#pragma unroll
        for (int o = 4; o; o >>= 1) { t += __shfl_xor_sync(0xffffffffu, t, o); t2 += __shfl_xor_sync(0xffffffffu, t2, o); }
        if (lane == 0) { rs[0] = t; rs2[0] = t2; }
    }
    __syncthreads();
    const float mu  = rs[0] * (1.f / Dq);
    const float var = rs2[0] * (1.f / Dq) - mu * mu;
    const float inv = rsqrtf(var + 1e-5f);
#pragma unroll
    for (int i = 0; i < 3; i++) {
        int d = threadIdx.x + i * 256;
        out[(size_t)row * Dq + d] = (v[i] - mu) * inv * g[d] + be[d];
    }
}

// ====================================================================================
typedef CUresult (*EncFn)(CUtensorMap*, CUtensorMapDataType, cuuint32_t, void*,
                          const cuuint64_t*, const cuuint64_t*, const cuuint32_t*,
                          const cuuint32_t*, CUtensorMapInterleave, CUtensorMapSwizzle,
                          CUtensorMapL2promotion, CUtensorMapFloatOOBfill);

static void make_map(EncFn enc, CUtensorMap* m, void* ptr,
                     uint64_t d0, uint64_t d1, uint64_t d2)
{
    cuuint64_t dims[3] = {d0, d1, d2};
    cuuint64_t strides[2] = {d0 * 2, d0 * d1 * 2};
    cuuint32_t box[3] = {32, 256, 1};
    cuuint32_t es[3] = {1, 1, 1};
    enc(m, CU_TENSOR_MAP_DATA_TYPE_BFLOAT16, 3, ptr, dims, strides, box, es,
        CU_TENSOR_MAP_INTERLEAVE_NONE, CU_TENSOR_MAP_SWIZZLE_64B,
        CU_TENSOR_MAP_L2_PROMOTION_L2_128B, CU_TENSOR_MAP_FLOAT_OOB_FILL_NONE);
}

extern "C" void kernel_launch(void* const* d_in, const int* in_sizes, int n_in,
                              void* d_out, int out_size)
{
    const float* q   = (const float*)d_in[0];
    const float* k   = (const float*)d_in[1];
    const float* v   = (const float*)d_in[2];
    const float* Wq  = (const float*)d_in[3];
    const float* bq  = (const float*)d_in[4];
    const float* Wk  = (const float*)d_in[5];
    const float* bk  = (const float*)d_in[6];
    const float* Wv  = (const float*)d_in[7];
    const float* bv  = (const float*)d_in[8];
    const float* Wo  = (const float*)d_in[9];
    const float* bo  = (const float*)d_in[10];
    const float* ln1g= (const float*)d_in[11];
    const float* ln1b= (const float*)d_in[12];
    const float* ln2g= (const float*)d_in[13];
    const float* ln2b= (const float*)d_in[14];
    const float* Wg  = (const float*)d_in[15];
    const float* bg  = (const float*)d_in[16];
    const float* W1  = (const float*)d_in[17];
    const float* b1  = (const float*)d_in[18];
    const float* W2  = (const float*)d_in[19];
    const float* b2  = (const float*)d_in[20];
    float* out = (float*)d_out;

    float *p_qkvh, *p_ctx, *p_tmp, *p_x, *p_y, *p_gates;
    __nv_bfloat16 *p_inhi, *p_inlo, *p_xhi, *p_hhi, *p_qlo;
    __nv_bfloat16 *p_w1h, *p_w2h, *p_wqkvh, *p_wqkvl, *p_woh, *p_wol;
    cudaGetSymbolAddress((void**)&p_qkvh, d_qkvh);
    cudaGetSymbolAddress((void**)&p_ctx,  d_ctx);
    cudaGetSymbolAddress((void**)&p_tmp,  d_tmp);
    cudaGetSymbolAddress((void**)&p_x,    d_x);
    cudaGetSymbolAddress((void**)&p_y,    d_y);
    cudaGetSymbolAddress((void**)&p_gates,d_gates);
    cudaGetSymbolAddress((void**)&p_inhi, d_inhi);
    cudaGetSymbolAddress((void**)&p_inlo, d_inlo);
    cudaGetSymbolAddress((void**)&p_xhi,  d_xhi);
    cudaGetSymbolAddress((void**)&p_hhi,  d_hhi);
    cudaGetSymbolAddress((void**)&p_qlo,  d_qlo);
    cudaGetSymbolAddress((void**)&p_w1h,  d_w1t_hi);
    cudaGetSymbolAddress((void**)&p_w2h,  d_w2t_hi);
    cudaGetSymbolAddress((void**)&p_wqkvh, d_wqkvt_hi);
    cudaGetSymbolAddress((void**)&p_wqkvl, d_wqkvt_lo);
    cudaGetSymbolAddress((void**)&p_woh,  d_wot_hi);
    cudaGetSymbolAddress((void**)&p_wol,  d_wot_lo);

    static EncFn enc = nullptr;
    static cudaStream_t s2 = nullptr;
    static cudaEvent_t evFork = nullptr, evJoin = nullptr;
    if (!enc) {
        void* fp = nullptr;
        cudaDriverEntryPointQueryResult st;
        cudaGetDriverEntryPointByVersion("cuTensorMapEncodeTiled", &fp, 12000,
                                         cudaEnableDefault, &st);
        enc = (EncFn)fp;
        cudaStreamCreateWithFlags(&s2, cudaStreamNonBlocking);
        cudaEventCreateWithFlags(&evFork, cudaEventDisableTiming);
        cudaEventCreateWithFlags(&evJoin, cudaEventDisableTiming);
    }
    CUtensorMap mXh, mHh, mW1h, mW2h;
    make_map(enc, &mXh, p_xhi, Dq, MPAD, 1);
    make_map(enc, &mHh, p_hhi, Fq, MPAD, Eq);
    make_map(enc, &mW1h, p_w1h, Dq, Fq, Eq);
    make_map(enc, &mW2h, p_w2h, Fq, Dq, Eq);

    const dim3 blk(256);
    const dim3 gridQKV(Dq / TN, NTOK / TM, 3);
    const dim3 gridO(Dq / TN, NTOK / TM, 1);
    const dim3 grid1(Fq / 256, MPAD / 256, Eq);
    const dim3 grid2(Dq / 256, MPAD / 256, Eq);
    const int n4 = NTOK * Dq / 4;
    const int sgrid = (n4 + 255) / 256;
    const size_t segQ = (size_t)NTOK * Dq;

    cudaFuncSetAttribute(tc_gemm<2>,  cudaFuncAttributeMaxDynamicSharedMemorySize, TC_SMEM);
    cudaFuncSetAttribute(tc_gemm<3>,  cudaFuncAttributeMaxDynamicSharedMemorySize, TC_SMEM);
    cudaFuncSetAttribute(tc_gemm2<0>, cudaFuncAttributeMaxDynamicSharedMemorySize, TC2_SMEM);
    cudaFuncSetAttribute(tc_gemm2<1>, cudaFuncAttributeMaxDynamicSharedMemorySize, TC2_SMEM);

    __nv_bfloat16* p_qkvshi = p_hhi;   // qkv-hi staging in idle h region

    // --- fork: W1/W2 transposes run concurrently on s2, joined before GEMM1 ---
    cudaEventRecord(evFork, 0);
    cudaStreamWaitEvent(s2, evFork, 0);
    transpose_split<<<dim3(Dq/64, Fq/32, Eq), blk, 0, s2>>>(W1, p_w1h, nullptr, Dq, Fq);
    transpose_split<<<dim3(Fq/64, Dq/32, Eq), blk, 0, s2>>>(W2, p_w2h, nullptr, Fq, Dq);
    cudaEventRecord(evJoin, s2);

    // --- main chain ---
    transpose_split<<<dim3(Dq/64, Dq/32, 1), blk>>>(Wq, p_wqkvh,           p_wqkvl,           Dq, Dq);
    transpose_split<<<dim3(Dq/64, Dq/32, 1), blk>>>(Wk, p_wqkvh + Dq*Dq,   p_wqkvl + Dq*Dq,   Dq, Dq);
    transpose_split<<<dim3(Dq/64, Dq/32, 1), blk>>>(Wv, p_wqkvh + 2*Dq*Dq, p_wqkvl + 2*Dq*Dq, Dq, Dq);
    split3_bf16<<<dim3(sgrid, 3), blk>>>(q, k, v, p_qkvshi, p_qlo, n4);
    tc_gemm<2><<<gridQKV, blk, TC_SMEM>>>(p_qkvshi, p_qlo, p_wqkvh, p_wqkvl,
                                          bq, bk, bv, nullptr, p_qkvh,
                                          NTOK, Dq, Dq, segQ, (size_t)Dq * Dq, segQ);
    const int smem_attn = (Sq * KPAD + Sq * DHq + 8 * 208 + 8 * DHq) * (int)sizeof(float);
    cudaFuncSetAttribute(attn_kernel, cudaFuncAttributeMaxDynamicSharedMemorySize, smem_attn);
    attn_kernel<<<dim3(Bq * Hq, 4), blk, smem_attn>>>(p_qkvh, p_qkvh + segQ, p_qkvh + 2 * segQ, p_ctx);
    transpose_split<<<dim3(Dq/64, Dq/32, 1), blk>>>(Wo, p_woh, p_wol, Dq, Dq);
    split_bf16<<<sgrid, blk>>>(p_ctx, p_inhi, p_inlo, n4);
    tc_gemm<3><<<gridO, blk, TC_SMEM>>>(p_inhi, p_inlo, p_woh, p_wol,
                                        bo, bo, bo, q, p_tmp, NTOK, Dq, Dq, 0, 0, 0);
    ln_kernel<<<NTOK, blk>>>(p_tmp, ln1g, ln1b, p_x, p_xhi);
    gate_kernel<<<(NTOK * 32 + 255) / 256, blk>>>(p_x, Wg, bg, p_gates);

    // --- join; MoE ---
    cudaStreamWaitEvent(0, evJoin, 0);
    tc_gemm2<0><<<grid1, blk, TC2_SMEM>>>(
        mXh, mW1h, b1, nullptr, p_hhi,
        Fq, Dq, (size_t)Fq, (size_t)MPAD * Fq,
        p_xhi, p_w1h, (size_t)0, (size_t)Fq * Dq);
    tc_gemm2<1><<<grid2, blk, TC2_SMEM>>>(
        mHh, mW2h, b2, p_y, nullptr,
        Dq, Fq, (size_t)Dq, (size_t)MPAD * Dq,
        p_hhi, p_w2h, (size_t)MPAD * Fq, (size_t)Dq * Fq);

    ln2_kernel<<<NTOK, blk>>>(p_x, p_y, p_gates, ln2g, ln2b, out);
}

// round 12
// speedup vs baseline: 11.3654x; 1.2336x over previous
#include <cuda_runtime.h>
#include <cuda.h>
#include <cuda_bf16.h>
#include <math.h>
#include <stdint.h>

#define Bq 32
#define Sq 196
#define Dq 768
#define Hq 12
#define Eq 8
#define Fq 3072
#define DHq 64
#define NTOK (Bq*Sq)
#define MPAD 6400

#define HAS_TCGEN05 (defined(__CUDA_ARCH_FEAT_SM103_ALL) || defined(__CUDA_ARCH_FEAT_SM100_ALL))

// ---------------- scratch ------------------------------------------------------
__device__ __align__(256) float d_qkvh[3*NTOK*Dq];
__device__ __align__(256) float d_ctx[NTOK*Dq];
__device__ __align__(256) float d_tmp[NTOK*Dq];
__device__ __align__(256) float d_x  [NTOK*Dq];
__device__ __align__(256) float d_y  [Eq*MPAD*Dq];
__device__ __align__(256) float d_gates[MPAD*Eq];

__device__ __align__(256) __nv_bfloat16 d_inhi[NTOK*Dq];
__device__ __align__(256) __nv_bfloat16 d_inlo[NTOK*Dq];
__device__ __align__(256) __nv_bfloat16 d_xhi[MPAD*Dq];
__device__ __align__(256) __nv_bfloat16 d_hhi[Eq*MPAD*Fq];  // h; also qkv-hi staging early
__device__ __align__(256) __nv_bfloat16 d_qlo[3*NTOK*Dq];   // qkv-lo staging
__device__ __align__(256) __nv_bfloat16 d_w1t_hi[Eq*Fq*Dq];
__device__ __align__(256) __nv_bfloat16 d_w2t_hi[Eq*Dq*Fq];
__device__ __align__(256) __nv_bfloat16 d_wqkvt_hi[3*Dq*Dq];
__device__ __align__(256) __nv_bfloat16 d_wqkvt_lo[3*Dq*Dq];
__device__ __align__(256) __nv_bfloat16 d_wot_hi[Dq*Dq];
__device__ __align__(256) __nv_bfloat16 d_wot_lo[Dq*Dq];

// ---------------- PTX helpers ---------------------------------------------------
__device__ __forceinline__ uint32_t smem_u32(const void* p) {
    uint32_t a;
    asm("{ .reg .u64 t; cvta.to.shared.u64 t, %1; cvt.u32.u64 %0, t; }" : "=r"(a) : "l"(p));
    return a;
}

#if HAS_TCGEN05
__device__ __forceinline__ bool elect_one() {
    uint32_t p;
    asm volatile("{\n .reg .pred p;\n elect.sync _|p, 0xFFFFFFFF;\n selp.b32 %0,1,0,p;\n}" : "=r"(p));
    return p != 0;
}
#define MBARRIER_INIT(addr, cnt) \
    asm volatile("mbarrier.init.shared.b64 [%0], %1;" :: "r"((uint32_t)(addr)), "r"((uint32_t)(cnt)) : "memory")
#define MBARRIER_INVAL(addr) \
    asm volatile("mbarrier.inval.shared.b64 [%0];" :: "r"((uint32_t)(addr)) : "memory")
#define MBARRIER_EXPECT_TX(addr, tx) \
    asm volatile("mbarrier.arrive.expect_tx.shared.b64 _, [%0], %1;" \
        :: "r"((uint32_t)(addr)), "r"((uint32_t)(tx)) : "memory")
#define MBARRIER_WAIT_PARITY(mbar, par) do { \
    uint32_t _m = (uint32_t)(mbar), _p = (uint32_t)(par), _d; \
    asm volatile("{\n\t.reg .pred p;\n\t" \
        "mbarrier.try_wait.parity.acquire.cta.shared::cta.b64 p, [%1], %2;\n\t" \
        "selp.b32 %0, 1, 0, p;\n\t}" : "=r"(_d) : "r"(_m), "r"(_p) : "memory"); \
    if (!_d) { \
        asm volatile("{\n\t.reg .pred P1;\n\t" \
            "WL_%=:\n\t" \
            "mbarrier.try_wait.parity.acquire.cta.shared::cta.b64 P1, [%0], %1, 0x989680;\n\t" \
            "@P1 bra.uni WD_%=;\n\tbra.uni WL_%=;\n\tWD_%=:\n\t}" \
            :: "r"(_m), "r"(_p) : "memory"); \
    } \
} while(0)
#define TCGEN05_ALLOC(a, n) \
    asm volatile("tcgen05.alloc.cta_group::1.sync.aligned.shared::cta.b32 [%0], %1;" \
        :: "r"((uint32_t)(a)), "r"((uint32_t)(n)) : "memory")
#define TCGEN05_DEALLOC(t, n) \
    asm volatile("tcgen05.dealloc.cta_group::1.sync.aligned.b32 %0, %1;" :: "r"(t), "r"(n))
#define TCGEN05_RELINQ() \
    asm volatile("tcgen05.relinquish_alloc_permit.cta_group::1.sync.aligned;")
#define TCGEN05_COMMIT(m) \
    asm volatile("tcgen05.commit.cta_group::1.mbarrier::arrive::one.shared::cluster.b64 [%0];" \
        :: "r"((uint32_t)(m)) : "memory")
#define TCGEN05_FENCE_AFTER()  asm volatile("tcgen05.fence::after_thread_sync;" ::: "memory")
#define TCGEN05_FENCE_BEFORE() asm volatile("tcgen05.fence::before_thread_sync;" ::: "memory")
#define TCGEN05_WAIT_LD() asm volatile("tcgen05.wait::ld.sync.aligned;" ::: "memory")
#define FENCE_ASYNC_SHARED() asm volatile("fence.proxy.async.shared::cta;" ::: "memory")
#define CP_ASYNC16(dst, src) \
    asm volatile("cp.async.cg.shared.global [%0], [%1], 16;" :: "r"((uint32_t)(dst)), "l"(src))
#define CP_COMMIT() asm volatile("cp.async.commit_group;" ::: "memory")
#define CP_WAIT(n)  asm volatile("cp.async.wait_group %0;" :: "n"(n) : "memory")
#define TMA_LOAD_3D(sm, map, cx, cy, cz, mb) \
    asm volatile("cp.async.bulk.tensor.3d.shared::cta.global.tile.mbarrier::complete_tx::bytes " \
        "[%0], [%1, {%2, %3, %4}], [%5];" \
        :: "r"((uint32_t)(sm)), "l"(map), "r"((int32_t)(cx)), "r"((int32_t)(cy)), \
           "r"((int32_t)(cz)), "r"((uint32_t)(mb)) : "memory")
#define TCGEN05_LD_32X32B_X32(r, ta) \
    asm volatile("tcgen05.ld.sync.aligned.32x32b.x32.b32 " \
        "{%0, %1, %2, %3, %4, %5, %6, %7, %8, %9, %10, %11, %12, %13, %14, %15, " \
        " %16, %17, %18, %19, %20, %21, %22, %23, %24, %25, %26, %27, %28, %29, %30, %31}, [%32];" \
        : "=r"((r)[0]), "=r"((r)[1]), "=r"((r)[2]), "=r"((r)[3]), "=r"((r)[4]), "=r"((r)[5]), \
          "=r"((r)[6]), "=r"((r)[7]), "=r"((r)[8]), "=r"((r)[9]), "=r"((r)[10]), "=r"((r)[11]), \
          "=r"((r)[12]), "=r"((r)[13]), "=r"((r)[14]), "=r"((r)[15]), "=r"((r)[16]), "=r"((r)[17]), \
          "=r"((r)[18]), "=r"((r)[19]), "=r"((r)[20]), "=r"((r)[21]), "=r"((r)[22]), "=r"((r)[23]), \
          "=r"((r)[24]), "=r"((r)[25]), "=r"((r)[26]), "=r"((r)[27]), "=r"((r)[28]), "=r"((r)[29]), \
          "=r"((r)[30]), "=r"((r)[31]) : "r"(ta))

static constexpr uint64_t DESC_SW128 =
    (uint64_t(2) << 61) | (uint64_t(1) << 46) | (uint64_t(64) << 32) | (uint64_t(1) << 16);
static constexpr uint64_t DESC_SW64 =
    (uint64_t(4) << 61) | (uint64_t(1) << 46) | (uint64_t(32) << 32) | (uint64_t(1) << 16);
#define MKD128(a) (DESC_SW128 | ((uint64_t)((a) >> 4) & 0x3FFF))
#define MKD64(a)  (DESC_SW64  | ((uint64_t)((a) >> 4) & 0x3FFF))

__device__ __forceinline__ void mma_bf16_ss(uint32_t d, uint64_t ad, uint64_t bd,
                                            uint32_t idesc, uint32_t en) {
    asm volatile(
        "{\n\t.reg .pred p;\n\tsetp.ne.u32 p, %5, 0;\n\t"
        "tcgen05.mma.cta_group::1.kind::f16 [%0], %1, %2, %3, {%4,%4,%4,%4}, p;\n\t}"
        :: "r"(d), "l"(ad), "l"(bd), "r"(idesc), "r"(0u), "r"(en) : "memory");
}
static constexpr uint32_t IDESC_BF16 =
    (1u << 4) | (1u << 7) | (1u << 10) | ((256 / 8) << 17) | ((128 / 16) << 24);
#endif

// ======================= TM128 tc GEMM (QKV batched / O-proj, 3-term) ===========
#define TM 128
#define TN 256
#define TK 64
#define STAGE_BYTES 98304
#define SM_DATA 1024
#define TC_SMEM (SM_DATA + 2*STAGE_BYTES)

#if HAS_TCGEN05
__device__ __forceinline__ void load_slab128(
    uint32_t sbase, int stage,
    const __nv_bfloat16* __restrict__ Ahi, const __nv_bfloat16* __restrict__ Alo,
    const __nv_bfloat16* __restrict__ Bhi, const __nv_bfloat16* __restrict__ Blo,
    int m0, int n0, int k0, int K)
{
    const int tid = threadIdx.x;
    const uint32_t base = sbase + SM_DATA + stage * STAGE_BYTES;
#pragma unroll
    for (int i = 0; i < 4; i++) {
        int idx = i * 256 + tid;
        int row = idx >> 3, c4 = idx & 7;
        int off = row * 128 + c4 * 16;
        int sw  = off ^ ((off >> 3) & 0x70);
        size_t g = (size_t)(m0 + row) * K + k0 + c4 * 8;
        CP_ASYNC16(base + sw, Ahi + g);
        CP_ASYNC16(base + 16384 + sw, Alo + g);
    }
#pragma unroll
    for (int i = 0; i < 8; i++) {
        int idx = i * 256 + tid;
        int row = idx >> 3, c4 = idx & 7;
        int off = row * 128 + c4 * 16;
        int sw  = off ^ ((off >> 3) & 0x70);
        size_t g = (size_t)(n0 + row) * K + k0 + c4 * 8;
        CP_ASYNC16(base + 32768 + sw, Bhi + g);
        CP_ASYNC16(base + 65536 + sw, Blo + g);
    }
    CP_COMMIT();
}
#endif

template<int MODE>   // 2: z-batched C=AW+b(z)   3: C=AW+b+res
__global__ void __launch_bounds__(256)
tc_gemm(const __nv_bfloat16* __restrict__ Ahi, const __nv_bfloat16* __restrict__ Alo,
        const __nv_bfloat16* __restrict__ Bhi, const __nv_bfloat16* __restrict__ Blo,
        const float* __restrict__ b0, const float* __restrict__ b1,
        const float* __restrict__ b2, const float* __restrict__ res,
        float* __restrict__ Cf, int M, int N, int K,
        size_t sA, size_t sB, size_t sC)
{
    extern __shared__ __align__(1024) char smx[];
    const int z = blockIdx.z;
    Ahi += z * sA; Alo += z * sA;
    Bhi += z * sB; Blo += z * sB;
    Cf  += z * sC;
    const float* bias = (z == 0) ? b0 : (z == 1) ? b1 : b2;
#if HAS_TCGEN05
    const uint32_t sb = smem_u32(smx);
    const int tid = threadIdx.x;
    const int wid = tid >> 5, lane = tid & 31;
    const int m0 = blockIdx.y * TM, n0 = blockIdx.x * TN;

    if (wid == 0) { TCGEN05_ALLOC(sb, 256); TCGEN05_RELINQ(); }
    if (tid == 0) { MBARRIER_INIT(sb + 8, 1); MBARRIER_INIT(sb + 16, 1); }
    __syncthreads();
    uint32_t tmem;
    asm volatile("ld.shared.b32 %0, [%1];" : "=r"(tmem) : "r"(sb));

    const int NS = K / TK;
    load_slab128(sb, 0, Ahi, Alo, Bhi, Blo, m0, n0, 0, K);
    int ph0 = 0, ph1 = 0;
    for (int s = 0; s < NS; s++) {
        const int buf = s & 1;
        if (s + 1 < NS) {
            const int nb = 1 - buf;
            if (s >= 1) {
                if (nb == 0) { MBARRIER_WAIT_PARITY(sb + 8,  ph0); ph0 ^= 1; }
                else         { MBARRIER_WAIT_PARITY(sb + 16, ph1); ph1 ^= 1; }
            }
            load_slab128(sb, nb, Ahi, Alo, Bhi, Blo, m0, n0, (s + 1) * TK, K);
            CP_WAIT(1);
        } else {
            CP_WAIT(0);
        }
        FENCE_ASYNC_SHARED();
        __syncthreads();
        if (wid == 0) {
            TCGEN05_FENCE_AFTER();
            if (elect_one()) {
                const uint32_t tb = sb + SM_DATA + buf * STAGE_BYTES;
                const uint64_t ah = MKD128(tb), al = MKD128(tb + 16384);
                const uint64_t bh = MKD128(tb + 32768), bl = MKD128(tb + 65536);
#pragma unroll
                for (int ks = 0; ks < 4; ks++) {
                    const uint32_t en0 = (s == 0 && ks == 0) ? 0u : 1u;
                    mma_bf16_ss(tmem, ah + ks * 2, bh + ks * 2, IDESC_BF16, en0);
                    mma_bf16_ss(tmem, ah + ks * 2, bl + ks * 2, IDESC_BF16, 1u);
                    mma_bf16_ss(tmem, al + ks * 2, bh + ks * 2, IDESC_BF16, 1u);
                }
                TCGEN05_COMMIT(sb + 8 + buf * 8);
            }
        }
    }
    if (((NS - 1) & 1) == 0) { MBARRIER_WAIT_PARITY(sb + 8,  ph0); }
    else                     { MBARRIER_WAIT_PARITY(sb + 16, ph1); }
    TCGEN05_FENCE_AFTER();

    const int sub = wid & 3, cg = wid >> 2;
    const int row = m0 + sub * 32 + lane;
#pragma unroll
    for (int ch = 0; ch < 4; ch++) {
        const int colb = cg * 128 + ch * 32;
        uint32_t r[32];
        TCGEN05_LD_32X32B_X32(r, tmem + colb);
        TCGEN05_WAIT_LD();
        const size_t base = (size_t)row * N + n0 + colb;
        const float4* bv = (const float4*)(bias + n0 + colb);
        float4* dst = (float4*)(Cf + base);
        const float4* rv = (MODE == 3) ? (const float4*)(res + base) : nullptr;
#pragma unroll
        for (int i = 0; i < 8; i++) {
            float4 b4 = bv[i];
            float4 o;
            o.x = __uint_as_float(r[i*4+0]) + b4.x;
            o.y = __uint_as_float(r[i*4+1]) + b4.y;
            o.z = __uint_as_float(r[i*4+2]) + b4.z;
            o.w = __uint_as_float(r[i*4+3]) + b4.w;
            if (MODE == 3) { float4 t = rv[i]; o.x += t.x; o.y += t.y; o.z += t.z; o.w += t.w; }
            dst[i] = o;
        }
    }
    TCGEN05_FENCE_BEFORE();
    __syncthreads();
    if (tid == 0) { MBARRIER_INVAL(sb + 8); MBARRIER_INVAL(sb + 16); }
    __syncthreads();
    if (wid == 0) TCGEN05_DEALLOC(tmem, 256);
#else
    float* As = (float*)smx;
    float* Bs = As + 16 * 128;
    const int tid = threadIdx.x;
    const int m0 = blockIdx.y * TM, n0x = blockIdx.x * TN;
    const int tx = tid & 15, ty = tid >> 4;
    const int mr = ty * 8, nr = tx * 8;
    for (int half = 0; half < 2; half++) {
        const int n0 = n0x + half * 128;
        float acc[8][8];
#pragma unroll
        for (int i = 0; i < 8; i++)
#pragma unroll
            for (int j = 0; j < 8; j++) acc[i][j] = 0.f;
        for (int k0 = 0; k0 < K; k0 += 16) {
            __syncthreads();
#pragma unroll
            for (int i = 0; i < 8; i++) {
                int idx = i * 256 + tid;
                int kk = idx >> 7, mm = idx & 127;
                size_t ga = (size_t)(m0 + mm) * K + k0 + kk;
                size_t gb = (size_t)(n0 + mm) * K + k0 + kk;
                As[kk*128+mm] = __bfloat162float(Ahi[ga]) + __bfloat162float(Alo[ga]);
                Bs[kk*128+mm] = __bfloat162float(Bhi[gb]) + __bfloat162float(Blo[gb]);
            }
            __syncthreads();
#pragma unroll
            for (int kk = 0; kk < 16; kk++) {
                float a0[8], b0r[8];
#pragma unroll
                for (int i = 0; i < 8; i++) a0[i] = As[kk*128+mr+i];
#pragma unroll
                for (int j = 0; j < 8; j++) b0r[j] = Bs[kk*128+nr+j];
#pragma unroll
                for (int i = 0; i < 8; i++)
#pragma unroll
                    for (int j = 0; j < 8; j++)
                        acc[i][j] = fmaf(a0[i], b0r[j], acc[i][j]);
            }
        }
#pragma unroll
        for (int i = 0; i < 8; i++) {
            const int row = m0 + mr + i;
#pragma unroll
            for (int j = 0; j < 8; j++) {
                const int col = n0 + nr + j;
                const size_t idx = (size_t)row * N + col;
                float v = acc[i][j] + bias[col];
                if (MODE == 2) Cf[idx] = v; else Cf[idx] = v + res[idx];
            }
        }
    }
#endif
}

// ======================= MoE GEMM: pure bf16, TMA producer/consumer =============
#define T2K 32
#define SLAB2 32768
#define TC2_SMEM (1024 + 6*SLAB2)   // 197632

template<int MODE>   // 0: gelu(acc+bias)->bf16   1: Cf = acc + bias
__global__ void __launch_bounds__(256)
tc_gemm2(const __grid_constant__ CUtensorMap mA, const __grid_constant__ CUtensorMap mB,
         const float* __restrict__ bias, float* __restrict__ Cf,
         __nv_bfloat16* __restrict__ Chi,
         int N, int K, size_t sBias, size_t sC,
         const __nv_bfloat16* __restrict__ A, const __nv_bfloat16* __restrict__ B,
         size_t sA, size_t sB)
{
    extern __shared__ __align__(1024) char smx[];
    const int z = blockIdx.z;
    bias += z * sBias;
#if HAS_TCGEN05
    const uint32_t sb = smem_u32(smx);
    const int tid = threadIdx.x;
    const int wid = tid >> 5, lane = tid & 31;
    const int m0 = blockIdx.y * 256, n0 = blockIdx.x * 256;
    const int za = (MODE == 0) ? 0 : z;

    if (wid == 0) { TCGEN05_ALLOC(sb, 512); TCGEN05_RELINQ(); }
    if (tid == 0) {
#pragma unroll
        for (int i = 0; i < 6; i++) { MBARRIER_INIT(sb + 8 + i * 8, 1); MBARRIER_INIT(sb + 56 + i * 8, 1); }
        MBARRIER_INIT(sb + 104, 1);
        FENCE_ASYNC_SHARED();
    }
    __syncthreads();
    uint32_t tmem;
    asm volatile("ld.shared.b32 %0, [%1];" : "=r"(tmem) : "r"(sb));

    const int NS = K / T2K;
    if (wid == 1) {
        if (elect_one()) {
            for (int s = 0; s < NS; s++) {
                const int st = s % 6;
                if (s >= 6) MBARRIER_WAIT_PARITY(sb + 56 + st * 8, ((s / 6) - 1) & 1);
                MBARRIER_EXPECT_TX(sb + 8 + st * 8, (uint32_t)SLAB2);
                const uint32_t stb = sb + 1024 + st * SLAB2;
                const int k0 = s * T2K;
                TMA_LOAD_3D(stb,         &mA, k0, m0, za, sb + 8 + st * 8);
                TMA_LOAD_3D(stb + 16384, &mB, k0, n0, z,  sb + 8 + st * 8);
            }
        }
    } else if (wid == 0) {
        TCGEN05_FENCE_AFTER();
        if (elect_one()) {
            for (int s = 0; s < NS; s++) {
                const int st = s % 6;
                MBARRIER_WAIT_PARITY(sb + 8 + st * 8, (s / 6) & 1);
                const uint32_t tb = sb + 1024 + st * SLAB2;
                const uint64_t a0 = MKD64(tb);
                const uint64_t a1 = a0 + 512;
                const uint64_t bh = MKD64(tb + 16384);
#pragma unroll
                for (int ks = 0; ks < 2; ks++) {
                    const uint32_t en0 = (s == 0 && ks == 0) ? 0u : 1u;
                    mma_bf16_ss(tmem,       a0 + ks * 2, bh + ks * 2, IDESC_BF16, en0);
                    mma_bf16_ss(tmem + 256, a1 + ks * 2, bh + ks * 2, IDESC_BF16, en0);
                }
                TCGEN05_COMMIT(sb + 56 + st * 8);
            }
            TCGEN05_COMMIT(sb + 104);
        }
    }

    MBARRIER_WAIT_PARITY(sb + 104, 0);
    TCGEN05_FENCE_AFTER();

    const int accSel = wid >> 2, sub = wid & 3;
    const int row = m0 + accSel * 128 + sub * 32 + lane;
    const uint32_t tacc = tmem + accSel * 256;
    if (MODE == 0) Chi += z * sC;
    else           Cf  += z * sC;
#pragma unroll
    for (int ch = 0; ch < 8; ch++) {
        const int colb = ch * 32;
        uint32_t r[32];
        TCGEN05_LD_32X32B_X32(r, tacc + colb);
        TCGEN05_WAIT_LD();
        const size_t base = (size_t)row * N + n0 + colb;
        const float4* bv = (const float4*)(bias + n0 + colb);
        if (MODE == 0) {
            uint4* dh = (uint4*)(Chi + base);
#pragma unroll
            for (int i = 0; i < 4; i++) {
                uint32_t hp[4];
#pragma unroll
                for (int p = 0; p < 4; p++) {
                    float4 b4 = bv[i * 2 + (p >> 1)];
                    float b0 = (p & 1) ? b4.z : b4.x;
                    float b1 = (p & 1) ? b4.w : b4.y;
                    float v0 = __uint_as_float(r[i*8+p*2+0]) + b0;
                    float v1 = __uint_as_float(r[i*8+p*2+1]) + b1;
                    float g0 = 0.5f * v0 * (1.f + erff(v0 * 0.70710678118654752f));
                    float g1 = 0.5f * v1 * (1.f + erff(v1 * 0.70710678118654752f));
                    hp[p] = (uint32_t)__bfloat16_as_ushort(__float2bfloat16(g0)) |
                            ((uint32_t)__bfloat16_as_ushort(__float2bfloat16(g1)) << 16);
                }
                dh[i] = make_uint4(hp[0], hp[1], hp[2], hp[3]);
            }
        } else {
            float4* dst = (float4*)(Cf + base);
#pragma unroll
            for (int i = 0; i < 8; i++) {
                float4 b4 = bv[i];
                float4 o;
                o.x = __uint_as_float(r[i*4+0]) + b4.x;
                o.y = __uint_as_float(r[i*4+1]) + b4.y;
                o.z = __uint_as_float(r[i*4+2]) + b4.z;
                o.w = __uint_as_float(r[i*4+3]) + b4.w;
                dst[i] = o;
            }
        }
    }
    TCGEN05_FENCE_BEFORE();
    __syncthreads();
    if (tid == 0) {
#pragma unroll
        for (int i = 0; i < 6; i++) { MBARRIER_INVAL(sb + 8 + i * 8); MBARRIER_INVAL(sb + 56 + i * 8); }
        MBARRIER_INVAL(sb + 104);
    }
    __syncthreads();
    if (wid == 0) TCGEN05_DEALLOC(tmem, 512);
#else
    const __nv_bfloat16* Ap = A + (size_t)((MODE == 0) ? 0 : z) * sA;
    const __nv_bfloat16* Bp = B + (size_t)z * sB;
    if (MODE == 0) Chi += z * sC;
    else           Cf  += z * sC;
    float* As = (float*)smx;
    float* Bs = As + 16 * 128;
    const int tid = threadIdx.x;
    const int tx = tid & 15, ty = tid >> 4;
    const int mr = ty * 8, nr = tx * 8;
    for (int mh = 0; mh < 2; mh++)
    for (int nh = 0; nh < 2; nh++) {
        const int m0 = blockIdx.y * 256 + mh * 128;
        const int n0 = blockIdx.x * 256 + nh * 128;
        float acc[8][8];
#pragma unroll
        for (int i = 0; i < 8; i++)
#pragma unroll
            for (int j = 0; j < 8; j++) acc[i][j] = 0.f;
        for (int k0 = 0; k0 < K; k0 += 16) {
            __syncthreads();
#pragma unroll
            for (int i = 0; i < 8; i++) {
                int idx = i * 256 + tid;
                int kk = idx >> 7, mm = idx & 127;
                size_t ga = (size_t)(m0 + mm) * K + k0 + kk;
                size_t gb = (size_t)(n0 + mm) * K + k0 + kk;
                As[kk*128+mm] = __bfloat162float(Ap[ga]);
                Bs[kk*128+mm] = __bfloat162float(Bp[gb]);
            }
            __syncthreads();
#pragma unroll
            for (int kk = 0; kk < 16; kk++) {
                float a0[8], b0[8];
#pragma unroll
                for (int i = 0; i < 8; i++) a0[i] = As[kk*128+mr+i];
#pragma unroll
                for (int j = 0; j < 8; j++) b0[j] = Bs[kk*128+nr+j];
#pragma unroll
                for (int i = 0; i < 8; i++)
#pragma unroll
                    for (int j = 0; j < 8; j++)
                        acc[i][j] = fmaf(a0[i], b0[j], acc[i][j]);
            }
        }
#pragma unroll
        for (int i = 0; i < 8; i++) {
            const int row = m0 + mr + i;
#pragma unroll
            for (int j = 0; j < 8; j++) {
                const int col = n0 + nr + j;
                const size_t idx = (size_t)row * N + col;
                float v = acc[i][j] + bias[col];
                if (MODE == 0) {
                    float g = 0.5f * v * (1.f + erff(v * 0.70710678118654752f));
                    Chi[idx] = __float2bfloat16(g);
                } else Cf[idx] = v;
            }
        }
    }
#endif
}

// ---------------- transpose v2 -------------------------------------------------------
__global__ void __launch_bounds__(256)
transpose_split(const float* __restrict__ W, __nv_bfloat16* __restrict__ Thi,
                __nv_bfloat16* __restrict__ Tlo, int K, int N)
{
    __shared__ float t[64][33];
    const int e = blockIdx.z;
    const float* Wp = W + (size_t)e * K * N;
    __nv_bfloat16* th = Thi + (size_t)e * K * N;
    __nv_bfloat16* tl = Tlo ? Tlo + (size_t)e * K * N : nullptr;
    const int k0 = blockIdx.x * 64, n0 = blockIdx.y * 32;
    const int tid = threadIdx.x;
#pragma unroll
    for (int i = 0; i < 8; i++) {
        int idx = i * 256 + tid;
        int r = idx >> 5, c = idx & 31;
        t[r][c] = Wp[(size_t)(k0 + r) * N + n0 + c];
    }
    __syncthreads();
#pragma unroll
    for (int i = 0; i < 4; i++) {
        int idx = i * 256 + tid;
        int c = idx >> 5, j = idx & 31;
        float v0 = t[2 * j][c], v1 = t[2 * j + 1][c];
        __nv_bfloat16 h0 = __float2bfloat16(v0);
        __nv_bfloat16 h1 = __float2bfloat16(v1);
        const size_t base = (size_t)(n0 + c) * K + k0 + 2 * j;
        *(uint32_t*)(th + base) =
            (uint32_t)__bfloat16_as_ushort(h0) | ((uint32_t)__bfloat16_as_ushort(h1) << 16);
        if (tl) {
            __nv_bfloat16 l0 = __float2bfloat16(v0 - __bfloat162float(h0));
            __nv_bfloat16 l1 = __float2bfloat16(v1 - __bfloat162float(h1));
            *(uint32_t*)(tl + base) =
                (uint32_t)__bfloat16_as_ushort(l0) | ((uint32_t)__bfloat16_as_ushort(l1) << 16);
        }
    }
}

// ---------------- batched q/k/v split ------------------------------------------------
__global__ void __launch_bounds__(256)
split3_bf16(const float* __restrict__ q, const float* __restrict__ k,
            const float* __restrict__ v, __nv_bfloat16* __restrict__ hi,
            __nv_bfloat16* __restrict__ lo, int n4)
{
    const int seg = blockIdx.y;
    const float* x = (seg == 0) ? q : (seg == 1) ? k : v;
    int i = blockIdx.x * 256 + threadIdx.x;
    if (i >= n4) return;
    float4 val = ((const float4*)x)[i];
    __nv_bfloat16 h0 = __float2bfloat16(val.x), h1 = __float2bfloat16(val.y);
    __nv_bfloat16 h2 = __float2bfloat16(val.z), h3 = __float2bfloat16(val.w);
    uint2 hp, lp;
    hp.x = (uint32_t)__bfloat16_as_ushort(h0) | ((uint32_t)__bfloat16_as_ushort(h1) << 16);
    hp.y = (uint32_t)__bfloat16_as_ushort(h2) | ((uint32_t)__bfloat16_as_ushort(h3) << 16);
    __nv_bfloat16 l0 = __float2bfloat16(val.x - __bfloat162float(h0));
    __nv_bfloat16 l1 = __float2bfloat16(val.y - __bfloat162float(h1));
    __nv_bfloat16 l2 = __float2bfloat16(val.z - __bfloat162float(h2));
    __nv_bfloat16 l3 = __float2bfloat16(val.w - __bfloat162float(h3));
    lp.x = (uint32_t)__bfloat16_as_ushort(l0) | ((uint32_t)__bfloat16_as_ushort(l1) << 16);
    lp.y = (uint32_t)__bfloat16_as_ushort(l2) | ((uint32_t)__bfloat16_as_ushort(l3) << 16);
    const size_t off = (size_t)seg * n4 + i;
    ((uint2*)hi)[off] = hp;
    ((uint2*)lo)[off] = lp;
}

// ---------------- single split (ctx, hi+lo) --------------------------------------------
__global__ void __launch_bounds__(256)
split_bf16(const float* __restrict__ x, __nv_bfloat16* __restrict__ hi,
           __nv_bfloat16* __restrict__ lo, int n4)
{
    int i = blockIdx.x * 256 + threadIdx.x;
    if (i >= n4) return;
    float4 v = ((const float4*)x)[i];
    __nv_bfloat16 h0 = __float2bfloat16(v.x), h1 = __float2bfloat16(v.y);
    __nv_bfloat16 h2 = __float2bfloat16(v.z), h3 = __float2bfloat16(v.w);
    uint2 hp, lp;
    hp.x = (uint32_t)__bfloat16_as_ushort(h0) | ((uint32_t)__bfloat16_as_ushort(h1) << 16);
    hp.y = (uint32_t)__bfloat16_as_ushort(h2) | ((uint32_t)__bfloat16_as_ushort(h3) << 16);
    __nv_bfloat16 l0 = __float2bfloat16(v.x - __bfloat162float(h0));
    __nv_bfloat16 l1 = __float2bfloat16(v.y - __bfloat162float(h1));
    __nv_bfloat16 l2 = __float2bfloat16(v.z - __bfloat162float(h2));
    __nv_bfloat16 l3 = __float2bfloat16(v.w - __bfloat162float(h3));
    lp.x = (uint32_t)__bfloat16_as_ushort(l0) | ((uint32_t)__bfloat16_as_ushort(l1) << 16);
    lp.y = (uint32_t)__bfloat16_as_ushort(l2) | ((uint32_t)__bfloat16_as_ushort(l3) << 16);
    ((uint2*)hi)[i] = hp;
    ((uint2*)lo)[i] = lp;
}

// ---------------- attention v2: 4-query register blocking, bf16 K ---------------------
// smem: K bf16 [196][72]  = 28224 B
//       V fp32 [196][64]  = 50176 B  @ 28224
//       Q fp32 [8][4][64] =  8192 B  @ 78400
//       P fp32 [8][4][200]= 25600 B  @ 86592    total 112192 B
#define ATT_V 28224
#define ATT_Q 78400
#define ATT_P 86592
#define ATT_SMEM 112192

__global__ void __launch_bounds__(256, 2)
attn_kernel(const float* __restrict__ qh, const float* __restrict__ kh,
            const float* __restrict__ vh, float* __restrict__ ctx)
{
    const int b = blockIdx.x / Hq;
    const int h = blockIdx.x % Hq;
    const int qbase = blockIdx.y * 49;
    const int qend  = min(196, qbase + 49);
    extern __shared__ __align__(16) char sm[];
    uint32_t* Ksp = (uint32_t*)sm;              // bf16 pairs, row stride 36 u32 (72 bf16)
    float* Vs = (float*)(sm + ATT_V);
    float* Qs = (float*)(sm + ATT_Q);
    float* Ps = (float*)(sm + ATT_P);
    const int tid = threadIdx.x;

    // load K (packed bf16) + V (fp32)
    for (int i = tid; i < Sq * 32; i += 256) {
        int s = i >> 5, dp = i & 31;
        size_t g = (size_t)(b * Sq + s) * Dq + h * DHq + 2 * dp;
        float2 kv = *(const float2*)(kh + g);
        __nv_bfloat16 k0 = __float2bfloat16(kv.x), k1 = __float2bfloat16(kv.y);
        Ksp[s * 36 + dp] = (uint32_t)__bfloat16_as_ushort(k0) |
                           ((uint32_t)__bfloat16_as_ushort(k1) << 16);
        *(float2*)(Vs + s * 64 + 2 * dp) = *(const float2*)(vh + g);
    }
    __syncthreads();

    const int warp = tid >> 5, lane = tid & 31;
    float* Qw = Qs + warp * 256;
    float* Pw = Ps + warp * 800;

    for (int q0 = qbase + warp * 4; q0 < qend; q0 += 32) {
        const int nq = min(4, qend - q0);
        // stage 4 query rows
#pragma unroll
        for (int qq = 0; qq < 4; qq++) {
            int qi = q0 + qq;
#pragma unroll
            for (int r = 0; r < 2; r++) {
                int d = lane + r * 32;
                Qw[qq * 64 + d] = (qi < qend) ?
                    qh[(size_t)(b * Sq + qi) * Dq + h * DHq + d] : 0.f;
            }
        }
        __syncwarp();

        // ---- QK: scores in registers, K loaded once per 4 queries ----
        float s4[4][7];
#pragma unroll
        for (int qq = 0; qq < 4; qq++)
#pragma unroll
            for (int c = 0; c < 7; c++) s4[qq][c] = 0.f;
#pragma unroll
        for (int d8 = 0; d8 < 8; d8++) {
            float qv[4][8];
#pragma unroll
            for (int qq = 0; qq < 4; qq++) {
                float4 a = *(float4*)(Qw + qq * 64 + d8 * 8);
                float4 bb = *(float4*)(Qw + qq * 64 + d8 * 8 + 4);
                qv[qq][0] = a.x;  qv[qq][1] = a.y;  qv[qq][2] = a.z;  qv[qq][3] = a.w;
                qv[qq][4] = bb.x; qv[qq][5] = bb.y; qv[qq][6] = bb.z; qv[qq][7] = bb.w;
            }
#pragma unroll
            for (int c = 0; c < 7; c++) {
                int col = lane + 32 * c;
                if (col < Sq) {
                    uint4 kp = *(uint4*)(Ksp + col * 36 + d8 * 4);
                    float kf[8];
                    kf[0] = __uint_as_float(kp.x << 16);
                    kf[1] = __uint_as_float(kp.x & 0xFFFF0000u);
                    kf[2] = __uint_as_float(kp.y << 16);
                    kf[3] = __uint_as_float(kp.y & 0xFFFF0000u);
                    kf[4] = __uint_as_float(kp.z << 16);
                    kf[5] = __uint_as_float(kp.z & 0xFFFF0000u);
                    kf[6] = __uint_as_float(kp.w << 16);
                    kf[7] = __uint_as_float(kp.w & 0xFFFF0000u);
#pragma unroll
                    for (int qq = 0; qq < 4; qq++) {
                        float s = s4[qq][c];
#pragma unroll
                        for (int e = 0; e < 8; e++) s = fmaf(kf[e], qv[qq][e], s);
                        s4[qq][c] = s;
                    }
                }
            }
        }

        // ---- softmax (per query) ----
        float inv[4];
#pragma unroll
        for (int qq = 0; qq < 4; qq++) {
            float m = -1e30f;
#pragma unroll
            for (int c = 0; c < 7; c++) {
                int col = lane + 32 * c;
                if (col < Sq) m = fmaxf(m, s4[qq][c] * 0.125f);
            }
#pragma unroll
            for (int o = 16; o; o >>= 1) m = fmaxf(m, __shfl_xor_sync(0xffffffffu, m, o));
            float sum = 0.f;
#pragma unroll
            for (int c = 0; c < 7; c++) {
                int col = lane + 32 * c;
                if (col < Sq) {
                    float e = __expf(s4[qq][c] * 0.125f - m);
                    Pw[qq * 200 + col] = e;
                    sum += e;
                }
            }
#pragma unroll
            for (int o = 16; o; o >>= 1) sum += __shfl_xor_sync(0xffffffffu, sum, o);
            inv[qq] = 1.f / sum;
        }
        __syncwarp();

        // ---- PV: lane owns 2 d-values, 4 queries at once ----
        float acc[4][2];
#pragma unroll
        for (int qq = 0; qq < 4; qq++) { acc[qq][0] = 0.f; acc[qq][1] = 0.f; }
        for (int k4 = 0; k4 < Sq; k4 += 4) {
            float pa[4][4];
#pragma unroll
            for (int qq = 0; qq < 4; qq++) {
                float4 p = *(float4*)(Pw + qq * 200 + k4);
                pa[qq][0] = p.x; pa[qq][1] = p.y; pa[qq][2] = p.z; pa[qq][3] = p.w;
            }
#pragma unroll
            for (int j = 0; j < 4; j++) {
                float2 vv = *(float2*)(Vs + (k4 + j) * 64 + 2 * lane);
#pragma unroll
                for (int qq = 0; qq < 4; qq++) {
                    acc[qq][0] = fmaf(pa[qq][j], vv.x, acc[qq][0]);
                    acc[qq][1] = fmaf(pa[qq][j], vv.y, acc[qq][1]);
                }
            }
        }
#pragma unroll
        for (int qq = 0; qq < 4; qq++) {
            if (qq < nq) {
                float2 o;
                o.x = acc[qq][0] * inv[qq];
                o.y = acc[qq][1] * inv[qq];
                *(float2*)(ctx + (size_t)(b * Sq + q0 + qq) * Dq + h * DHq + 2 * lane) = o;
            }
        }
        __syncwarp();
    }
}

// ---------------- gate softmax ----------------------------------------------------------
__global__ void __launch_bounds__(256)
gate_kernel(const float* __restrict__ x, const float* __restrict__ Wg,
            const float* __restrict__ bg, float* __restrict__ gates)
{
    const int warp = (blockIdx.x * 256 + threadIdx.x) >> 5;
    const int lane = threadIdx.x & 31;
    if (warp >= NTOK) return;
    const float* xr = x + (size_t)warp * Dq;
    float lg[Eq];
#pragma unroll
    for (int e = 0; e < Eq; e++) lg[e] = 0.f;
    for (int d = lane; d < Dq; d += 32) {
        float xv = xr[d];
#pragma unroll
        for (int e = 0; e < Eq; e++) lg[e] = fmaf(xv, Wg[d * Eq + e], lg[e]);
    }
#pragma unroll
    for (int e = 0; e < Eq; e++)
#pragma unroll
        for (int o = 16; o; o >>= 1) lg[e] += __shfl_xor_sync(0xffffffffu, lg[e], o);
    if (lane == 0) {
        float m = -1e30f;
#pragma unroll
        for (int e = 0; e < Eq; e++) { lg[e] += bg[e]; m = fmaxf(m, lg[e]); }
        float s = 0.f;
#pragma unroll
        for (int e = 0; e < Eq; e++) { lg[e] = __expf(lg[e] - m); s += lg[e]; }
        float inv = 1.f / s;
#pragma unroll
        for (int e = 0; e < Eq; e++) gates[(size_t)warp * Eq + e] = lg[e] * inv;
    }
}

// ---------------- LN1 (emits bf16 hi) -----------------------------------------------------
__global__ void __launch_bounds__(256)
ln_kernel(const float* __restrict__ a, const float* __restrict__ g,
          const float* __restrict__ be, float* __restrict__ out,
          __nv_bfloat16* __restrict__ ohi)
{
    const int row = blockIdx.x;
    const float* ar = a + (size_t)row * Dq;
    float v[3];
    float s = 0.f, s2 = 0.f;
#pragma unroll
    for (int i = 0; i < 3; i++) {
        int d = threadIdx.x + i * 256;
        float x = ar[d];
        v[i] = x;
        s += x; s2 = fmaf(x, x, s2);
    }
    __shared__ float rs[8], rs2[8];
#pragma unroll
    for (int o = 16; o; o >>= 1) { s += __shfl_xor_sync(0xffffffffu, s, o); s2 += __shfl_xor_sync(0xffffffffu, s2, o); }
    const int warp = threadIdx.x >> 5, lane = threadIdx.x & 31;
    if (lane == 0) { rs[warp] = s; rs2[warp] = s2; }
    __syncthreads();
    if (warp == 0) {
        float t  = (lane < 8) ? rs[lane]  : 0.f;
        float t2 = (lane < 8) ? rs2[lane] : 0.f;
#pragma unroll
        for (int o = 4; o; o >>= 1) { t += __shfl_xor_sync(0xffffffffu, t, o); t2 += __shfl_xor_sync(0xffffffffu, t2, o); }
        if (lane == 0) { rs[0] = t; rs2[0] = t2; }
    }
    __syncthreads();
    const float mu  = rs[0] * (1.f / Dq);
    const float var = rs2[0] * (1.f / Dq) - mu * mu;
    const float inv = rsqrtf(var + 1e-5f);
#pragma unroll
    for (int i = 0; i < 3; i++) {
        int d = threadIdx.x + i * 256;
        float y = (v[i] - mu) * inv * g[d] + be[d];
        const size_t idx = (size_t)row * Dq + d;
        out[idx] = y;
        ohi[idx] = __float2bfloat16(y);
    }
}

// ---------------- LN2: fused gate-weighted expert reduction --------------------------------
__global__ void __launch_bounds__(256)
ln2_kernel(const float* __restrict__ x, const float* __restrict__ y,
           const float* __restrict__ gates, const float* __restrict__ g,
           const float* __restrict__ be, float* __restrict__ out)
{
    const int row = blockIdx.x;
    __shared__ float sg[Eq];
    if (threadIdx.x < Eq) sg[threadIdx.x] = gates[(size_t)row * Eq + threadIdx.x];
    __syncthreads();
    float v[3];
    float s = 0.f, s2 = 0.f;
#pragma unroll
    for (int i = 0; i < 3; i++) {
        int d = threadIdx.x + i * 256;
        float val = x[(size_t)row * Dq + d];
#pragma unroll
        for (int e = 0; e < Eq; e++)
            val = fmaf(sg[e], y[(size_t)e * MPAD * Dq + (size_t)row * Dq + d], val);
        v[i] = val;
        s += val; s2 = fmaf(val, val, s2);
    }
    __shared__ float rs[8], rs2[8];
#pragma unroll
    for (int o = 16; o; o >>= 1) { s += __shfl_xor_sync(0xffffffffu, s, o); s2 += __shfl_xor_sync(0xffffffffu, s2, o); }
    const int warp = threadIdx.x >> 5, lane = threadIdx.x & 31;
    if (lane == 0) { rs[warp] = s; rs2[warp] = s2; }
    __syncthreads();
    if (warp == 0) {
        float t  = (lane < 8) ? rs[lane]  : 0.f;
        float t2 = (lane < 8) ? rs2[lane] : 0.f;
#pragma unroll
        for (int o = 4; o; o >>= 1) { t += __shfl_xor_sync(0xffffffffu, t, o); t2 += __shfl_xor_sync(0xffffffffu, t2, o); }
        if (lane == 0) { rs[0] = t; rs2[0] = t2; }
    }
    __syncthreads();
    const float mu  = rs[0] * (1.f / Dq);
    const float var = rs2[0] * (1.f / Dq) - mu * mu;
    const float inv = rsqrtf(var + 1e-5f);
#pragma unroll
    for (int i = 0; i < 3; i++) {
        int d = threadIdx.x + i * 256;
        out[(size_t)row * Dq + d] = (v[i] - mu) * inv * g[d] + be[d];
    }
}

// ====================================================================================
typedef CUresult (*EncFn)(CUtensorMap*, CUtensorMapDataType, cuuint32_t, void*,
                          const cuuint64_t*, const cuuint64_t*, const cuuint32_t*,
                          const cuuint32_t*, CUtensorMapInterleave, CUtensorMapSwizzle,
                          CUtensorMapL2promotion, CUtensorMapFloatOOBfill);

static void make_map(EncFn enc, CUtensorMap* m, void* ptr,
                     uint64_t d0, uint64_t d1, uint64_t d2)
{
    cuuint64_t dims[3] = {d0, d1, d2};
    cuuint64_t strides[2] = {d0 * 2, d0 * d1 * 2};
    cuuint32_t box[3] = {32, 256, 1};
    cuuint32_t es[3] = {1, 1, 1};
    enc(m, CU_TENSOR_MAP_DATA_TYPE_BFLOAT16, 3, ptr, dims, strides, box, es,
        CU_TENSOR_MAP_INTERLEAVE_NONE, CU_TENSOR_MAP_SWIZZLE_64B,
        CU_TENSOR_MAP_L2_PROMOTION_L2_128B, CU_TENSOR_MAP_FLOAT_OOB_FILL_NONE);
}

extern "C" void kernel_launch(void* const* d_in, const int* in_sizes, int n_in,
                              void* d_out, int out_size)
{
    const float* q   = (const float*)d_in[0];
    const float* k   = (const float*)d_in[1];
    const float* v   = (const float*)d_in[2];
    const float* Wq  = (const float*)d_in[3];
    const float* bq  = (const float*)d_in[4];
    const float* Wk  = (const float*)d_in[5];
    const float* bk  = (const float*)d_in[6];
    const float* Wv  = (const float*)d_in[7];
    const float* bv  = (const float*)d_in[8];
    const float* Wo  = (const float*)d_in[9];
    const float* bo  = (const float*)d_in[10];
    const float* ln1g= (const float*)d_in[11];
    const float* ln1b= (const float*)d_in[12];
    const float* ln2g= (const float*)d_in[13];
    const float* ln2b= (const float*)d_in[14];
    const float* Wg  = (const float*)d_in[15];
    const float* bg  = (const float*)d_in[16];
    const float* W1  = (const float*)d_in[17];
    const float* b1  = (const float*)d_in[18];
    const float* W2  = (const float*)d_in[19];
    const float* b2  = (const float*)d_in[20];
    float* out = (float*)d_out;

    float *p_qkvh, *p_ctx, *p_tmp, *p_x, *p_y, *p_gates;
    __nv_bfloat16 *p_inhi, *p_inlo, *p_xhi, *p_hhi, *p_qlo;
    __nv_bfloat16 *p_w1h, *p_w2h, *p_wqkvh, *p_wqkvl, *p_woh, *p_wol;
    cudaGetSymbolAddress((void**)&p_qkvh, d_qkvh);
    cudaGetSymbolAddress((void**)&p_ctx,  d_ctx);
    cudaGetSymbolAddress((void**)&p_tmp,  d_tmp);
    cudaGetSymbolAddress((void**)&p_x,    d_x);
    cudaGetSymbolAddress((void**)&p_y,    d_y);
    cudaGetSymbolAddress((void**)&p_gates,d_gates);
    cudaGetSymbolAddress((void**)&p_inhi, d_inhi);
    cudaGetSymbolAddress((void**)&p_inlo, d_inlo);
    cudaGetSymbolAddress((void**)&p_xhi,  d_xhi);
    cudaGetSymbolAddress((void**)&p_hhi,  d_hhi);
    cudaGetSymbolAddress((void**)&p_qlo,  d_qlo);
    cudaGetSymbolAddress((void**)&p_w1h,  d_w1t_hi);
    cudaGetSymbolAddress((void**)&p_w2h,  d_w2t_hi);
    cudaGetSymbolAddress((void**)&p_wqkvh, d_wqkvt_hi);
    cudaGetSymbolAddress((void**)&p_wqkvl, d_wqkvt_lo);
    cudaGetSymbolAddress((void**)&p_woh,  d_wot_hi);
    cudaGetSymbolAddress((void**)&p_wol,  d_wot_lo);

    static EncFn enc = nullptr;
    static cudaStream_t s2 = nullptr;
    static cudaEvent_t evFork = nullptr, evJoin = nullptr;
    if (!enc) {
        void* fp = nullptr;
        cudaDriverEntryPointQueryResult st;
        cudaGetDriverEntryPointByVersion("cuTensorMapEncodeTiled", &fp, 12000,
                                         cudaEnableDefault, &st);
        enc = (EncFn)fp;
        cudaStreamCreateWithFlags(&s2, cudaStreamNonBlocking);
        cudaEventCreateWithFlags(&evFork, cudaEventDisableTiming);
        cudaEventCreateWithFlags(&evJoin, cudaEventDisableTiming);
    }
    CUtensorMap mXh, mHh, mW1h, mW2h;
    make_map(enc, &mXh, p_xhi, Dq, MPAD, 1);
    make_map(enc, &mHh, p_hhi, Fq, MPAD, Eq);
    make_map(enc, &mW1h, p_w1h, Dq, Fq, Eq);
    make_map(enc, &mW2h, p_w2h, Fq, Dq, Eq);

    const dim3 blk(256);
    const dim3 gridQKV(Dq / TN, NTOK / TM, 3);
    const dim3 gridO(Dq / TN, NTOK / TM, 1);
    const dim3 grid1(Fq / 256, MPAD / 256, Eq);
    const dim3 grid2(Dq / 256, MPAD / 256, Eq);
    const int n4 = NTOK * Dq / 4;
    const int sgrid = (n4 + 255) / 256;
    const size_t segQ = (size_t)NTOK * Dq;

    cudaFuncSetAttribute(tc_gemm<2>,  cudaFuncAttributeMaxDynamicSharedMemorySize, TC_SMEM);
    cudaFuncSetAttribute(tc_gemm<3>,  cudaFuncAttributeMaxDynamicSharedMemorySize, TC_SMEM);
    cudaFuncSetAttribute(tc_gemm2<0>, cudaFuncAttributeMaxDynamicSharedMemorySize, TC2_SMEM);
    cudaFuncSetAttribute(tc_gemm2<1>, cudaFuncAttributeMaxDynamicSharedMemorySize, TC2_SMEM);
    cudaFuncSetAttribute(attn_kernel, cudaFuncAttributeMaxDynamicSharedMemorySize, ATT_SMEM);

    __nv_bfloat16* p_qkvshi = p_hhi;   // qkv-hi staging in idle h region

    // --- fork: W1/W2 transposes on s2, joined before GEMM1 ---
    cudaEventRecord(evFork, 0);
    cudaStreamWaitEvent(s2, evFork, 0);
    transpose_split<<<dim3(Dq/64, Fq/32, Eq), blk, 0, s2>>>(W1, p_w1h, nullptr, Dq, Fq);
    transpose_split<<<dim3(Fq/64, Dq/32, Eq), blk, 0, s2>>>(W2, p_w2h, nullptr, Fq, Dq);
    cudaEventRecord(evJoin, s2);

    // --- main chain ---
    transpose_split<<<dim3(Dq/64, Dq/32, 1), blk>>>(Wq, p_wqkvh,           p_wqkvl,           Dq, Dq);
    transpose_split<<<dim3(Dq/64, Dq/32, 1), blk>>>(Wk, p_wqkvh + Dq*Dq,   p_wqkvl + Dq*Dq,   Dq, Dq);
    transpose_split<<<dim3(Dq/64, Dq/32, 1), blk>>>(Wv, p_wqkvh + 2*Dq*Dq, p_wqkvl + 2*Dq*Dq, Dq, Dq);
    split3_bf16<<<dim3(sgrid, 3), blk>>>(q, k, v, p_qkvshi, p_qlo, n4);
    tc_gemm<2><<<gridQKV, blk, TC_SMEM>>>(p_qkvshi, p_qlo, p_wqkvh, p_wqkvl,
                                          bq, bk, bv, nullptr, p_qkvh,
                                          NTOK, Dq, Dq, segQ, (size_t)Dq * Dq, segQ);
    attn_kernel<<<dim3(Bq * Hq, 4), blk, ATT_SMEM>>>(p_qkvh, p_qkvh + segQ, p_qkvh + 2 * segQ, p_ctx);
    transpose_split<<<dim3(Dq/64, Dq/32, 1), blk>>>(Wo, p_woh, p_wol, Dq, Dq);
    split_bf16<<<sgrid, blk>>>(p_ctx, p_inhi, p_inlo, n4);
    tc_gemm<3><<<gridO, blk, TC_SMEM>>>(p_inhi, p_inlo, p_woh, p_wol,
                                        bo, bo, bo, q, p_tmp, NTOK, Dq, Dq, 0, 0, 0);
    ln_kernel<<<NTOK, blk>>>(p_tmp, ln1g, ln1b, p_x, p_xhi);
    gate_kernel<<<(NTOK * 32 + 255) / 256, blk>>>(p_x, Wg, bg, p_gates);

    // --- join; MoE ---
    cudaStreamWaitEvent(0, evJoin, 0);
    tc_gemm2<0><<<grid1, blk, TC2_SMEM>>>(
        mXh, mW1h, b1, nullptr, p_hhi,
        Fq, Dq, (size_t)Fq, (size_t)MPAD * Fq,
        p_xhi, p_w1h, (size_t)0, (size_t)Fq * Dq);
    tc_gemm2<1><<<grid2, blk, TC2_SMEM>>>(
        mHh, mW2h, b2, p_y, nullptr,
        Dq, Fq, (size_t)Dq, (size_t)MPAD * Dq,
        p_hhi, p_w2h, (size_t)MPAD * Fq, (size_t)Dq * Fq);

    ln2_kernel<<<NTOK, blk>>>(p_x, p_y, p_gates, ln2g, ln2b, out);
}